// round 2
// baseline (speedup 1.0000x reference)
#include <cuda_runtime.h>
#include <math.h>

// Problem constants
#define Bn  4
#define Ln  1024
#define En  1024
#define Hn  16
#define HDn 64
#define NT  33          // 2*CLIP+1
#define CLIPV 16
#define SCALEF 0.125f   // 1/sqrt(64)

// Scratch (device globals; no allocation allowed)
__device__ float gQ[Bn*Hn*Ln*HDn];   // [b][h][l][d]
__device__ float gK[Bn*Hn*Ln*HDn];
__device__ float gV[Bn*Hn*Ln*HDn];
__device__ float gY[Bn*Ln*En];       // [b][l][e]
__device__ float gRQ[Bn*Hn*Ln*NT];   // [bh][l][t], SCALE folded

// ---------------------------------------------------------------------------
// Tiled fp32 GEMM: C = A(MxK) @ W(NxK)^T + bias, optional head-layout store.
// BM=BN=128, BK=8, 256 threads, 8x8 per thread.
// ---------------------------------------------------------------------------
__global__ __launch_bounds__(256) void sgemm_kernel(
    const float* __restrict__ A, const float* __restrict__ W,
    const float* __restrict__ bias, float* __restrict__ Cout,
    int M, int N, int Kd, int head_layout)
{
    __shared__ float As[8][128];
    __shared__ float Bs[8][128];
    int tid = threadIdx.x;
    int lr = tid >> 1;            // 0..127
    int lc = (tid & 1) << 2;      // 0 or 4
    const float* Ap = A + (size_t)(blockIdx.y * 128 + lr) * Kd + lc;
    const float* Wp = W + (size_t)(blockIdx.x * 128 + lr) * Kd + lc;
    int tx = tid & 15, ty = tid >> 4;

    float acc[8][8];
#pragma unroll
    for (int u = 0; u < 8; u++)
#pragma unroll
        for (int v = 0; v < 8; v++) acc[u][v] = 0.f;

    for (int k0 = 0; k0 < Kd; k0 += 8) {
        float4 av = *(const float4*)(Ap + k0);
        float4 wv = *(const float4*)(Wp + k0);
        __syncthreads();
        As[lc + 0][lr] = av.x; As[lc + 1][lr] = av.y;
        As[lc + 2][lr] = av.z; As[lc + 3][lr] = av.w;
        Bs[lc + 0][lr] = wv.x; Bs[lc + 1][lr] = wv.y;
        Bs[lc + 2][lr] = wv.z; Bs[lc + 3][lr] = wv.w;
        __syncthreads();
#pragma unroll
        for (int kk = 0; kk < 8; kk++) {
            float ar[8], br[8];
            *(float4*)(ar)     = *(const float4*)&As[kk][ty * 8];
            *(float4*)(ar + 4) = *(const float4*)&As[kk][ty * 8 + 4];
            *(float4*)(br)     = *(const float4*)&Bs[kk][tx * 8];
            *(float4*)(br + 4) = *(const float4*)&Bs[kk][tx * 8 + 4];
#pragma unroll
            for (int u = 0; u < 8; u++)
#pragma unroll
                for (int v = 0; v < 8; v++)
                    acc[u][v] += ar[u] * br[v];
        }
    }

    int mbase = blockIdx.y * 128 + ty * 8;
    int nbase = blockIdx.x * 128 + tx * 8;
#pragma unroll
    for (int u = 0; u < 8; u++) {
        int m = mbase + u;
#pragma unroll
        for (int v = 0; v < 8; v += 4) {
            int n = nbase + v;
            float4 o;
            o.x = acc[u][v + 0] + bias[n + 0];
            o.y = acc[u][v + 1] + bias[n + 1];
            o.z = acc[u][v + 2] + bias[n + 2];
            o.w = acc[u][v + 3] + bias[n + 3];
            size_t off;
            if (head_layout) {
                int b = m >> 10, l = m & 1023, h = n >> 6, d = n & 63;
                off = ((size_t)b << 20) | ((size_t)h << 16) | ((size_t)l << 6) | (size_t)d;
            } else {
                off = (size_t)m * N + n;
            }
            *(float4*)(Cout + off) = o;
        }
    }
}

// ---------------------------------------------------------------------------
// RQ[row][t] = SCALE * dot(Q[row,:], rel_k[t,:]) ; row = bh*1024 + l
// block: 32 rows, 256 threads
// ---------------------------------------------------------------------------
__global__ __launch_bounds__(256) void rq_kernel(
    const float* __restrict__ Q, const float* __restrict__ relk,
    float* __restrict__ RQ)
{
    __shared__ float rk[NT][64];
    __shared__ float qs[32][64];
    int tid = threadIdx.x;
    int row0 = blockIdx.x * 32;
    for (int idx = tid; idx < NT * 64; idx += 256)
        rk[idx >> 6][idx & 63] = relk[idx];
    for (int idx = tid; idx < 32 * 64; idx += 256) {
        int r = idx >> 6, d = idx & 63;
        qs[r][d] = Q[(size_t)(row0 + r) * 64 + d];
    }
    __syncthreads();
    int r = tid >> 3;
    int g = tid & 7;
    for (int t = g; t < NT; t += 8) {
        float s = 0.f;
#pragma unroll
        for (int d = 0; d < 64; d++) s += qs[r][d] * rk[t][d];
        RQ[(size_t)(row0 + r) * NT + t] = s * SCALEF;
    }
}

// ---------------------------------------------------------------------------
// Fused flash attention with relative-position bias + rel_v bucket sums.
// grid: (16 q-tiles, 64 bh). 256 threads. 64 q-rows per block.
// ---------------------------------------------------------------------------
struct AttnSmem {
    float QsT[64][65];    // [d][i], SCALE folded
    float KsT[64][65];    // [d][j]
    float Vs[64][68];     // [j][d]
    float Ps[64][65];     // scores -> probs
    float RQs[64][NT];
    float Wb[64][NT];     // bucket weights (unnormalized)
    float relvs[NT][68];
    float mrow[64], lrow[64], alpha_s[64];
};

__global__ __launch_bounds__(256) void attn_kernel(
    const float* __restrict__ Q, const float* __restrict__ Kg,
    const float* __restrict__ Vg, const float* __restrict__ RQ,
    const float* __restrict__ relv, float* __restrict__ Y)
{
    extern __shared__ char smem_raw[];
    AttnSmem& s = *reinterpret_cast<AttnSmem*>(smem_raw);
    int tid = threadIdx.x;
    int bh = blockIdx.y;
    int i0 = blockIdx.x * 64;
    const float* Qb = Q + ((size_t)bh << 16) + (size_t)i0 * 64;
    const float* Kb = Kg + ((size_t)bh << 16);
    const float* Vb = Vg + ((size_t)bh << 16);
    const float* RQb = RQ + (size_t)(bh * 1024 + i0) * NT;

    // init loads
    {
        int r = tid >> 2;
        int dq = (tid & 3) << 4;
#pragma unroll
        for (int c = 0; c < 16; c += 4) {
            float4 v = *(const float4*)(Qb + r * 64 + dq + c);
            s.QsT[dq + c + 0][r] = v.x * SCALEF;
            s.QsT[dq + c + 1][r] = v.y * SCALEF;
            s.QsT[dq + c + 2][r] = v.z * SCALEF;
            s.QsT[dq + c + 3][r] = v.w * SCALEF;
        }
    }
    for (int idx = tid; idx < 64 * NT; idx += 256) {
        int i = idx / NT, t = idx % NT;
        s.RQs[i][t] = RQb[idx];
        s.Wb[i][t] = 0.f;
    }
    for (int idx = tid; idx < NT * 64; idx += 256)
        s.relvs[idx >> 6][idx & 63] = relv[idx];
    if (tid < 64) { s.mrow[tid] = -1e30f; s.lrow[tid] = 0.f; }

    float acc[16];
#pragma unroll
    for (int r = 0; r < 16; r++) acc[r] = 0.f;

    int tx = tid & 15, ty = tid >> 4;
    int i_acc = tid >> 2;
    int dbase = (tid & 3) << 4;

    for (int jt = 0; jt < 16; jt++) {
        int j0 = jt * 64;
        __syncthreads();
        // load K (transposed), V
        {
            int r = tid >> 2;
            int dq = (tid & 3) << 4;
#pragma unroll
            for (int c = 0; c < 16; c += 4) {
                float4 kv = *(const float4*)(Kb + (size_t)(j0 + r) * 64 + dq + c);
                s.KsT[dq + c + 0][r] = kv.x;
                s.KsT[dq + c + 1][r] = kv.y;
                s.KsT[dq + c + 2][r] = kv.z;
                s.KsT[dq + c + 3][r] = kv.w;
                float4 vv = *(const float4*)(Vb + (size_t)(j0 + r) * 64 + dq + c);
                *(float4*)&s.Vs[r][dq + c] = vv;
            }
        }
        __syncthreads();
        // S = Q K^T (+ rel bias)
        float cacc[4][4];
#pragma unroll
        for (int u = 0; u < 4; u++)
#pragma unroll
            for (int v = 0; v < 4; v++) cacc[u][v] = 0.f;
#pragma unroll
        for (int d = 0; d < 64; d++) {
            float a[4], bb[4];
#pragma unroll
            for (int u = 0; u < 4; u++) a[u] = s.QsT[d][ty * 4 + u];
#pragma unroll
            for (int v = 0; v < 4; v++) bb[v] = s.KsT[d][tx * 4 + v];
#pragma unroll
            for (int u = 0; u < 4; u++)
#pragma unroll
                for (int v = 0; v < 4; v++)
                    cacc[u][v] += a[u] * bb[v];
        }
#pragma unroll
        for (int u = 0; u < 4; u++) {
            int i = ty * 4 + u;
            int ig = i0 + i;
#pragma unroll
            for (int v = 0; v < 4; v++) {
                int j = tx * 4 + v;
                int dd = (j0 + j) - ig;
                dd = dd < -CLIPV ? -CLIPV : (dd > CLIPV ? CLIPV : dd);
                s.Ps[i][j] = cacc[u][v] + s.RQs[i][dd + CLIPV];
            }
        }
        __syncthreads();
        // per-row softmax state update (threads 0..63)
        if (tid < 64) {
            int i = tid;
            int ig = i0 + i;
            float mold = s.mrow[i];
            float mt = -1e30f;
#pragma unroll 8
            for (int j = 0; j < 64; j++) mt = fmaxf(mt, s.Ps[i][j]);
            float mnew = fmaxf(mold, mt);
            float alpha = __expf(mold - mnew);
#pragma unroll
            for (int t = 0; t < NT; t++) s.Wb[i][t] *= alpha;
            float rs = 0.f;
            for (int j = 0; j < 64; j++) {
                float p = __expf(s.Ps[i][j] - mnew);
                s.Ps[i][j] = p;
                rs += p;
                int dd = (j0 + j) - ig;
                dd = dd < -CLIPV ? -CLIPV : (dd > CLIPV ? CLIPV : dd);
                s.Wb[i][dd + CLIPV] += p;
            }
            s.lrow[i] = s.lrow[i] * alpha + rs;
            s.mrow[i] = mnew;
            s.alpha_s[i] = alpha;
        }
        __syncthreads();
        // acc = acc*alpha + P @ V
        {
            float alpha = s.alpha_s[i_acc];
#pragma unroll
            for (int r = 0; r < 16; r++) acc[r] *= alpha;
            for (int j = 0; j < 64; j++) {
                float p = s.Ps[i_acc][j];
                const float4* vp = (const float4*)&s.Vs[j][dbase];
                float4 v0 = vp[0], v1 = vp[1], v2 = vp[2], v3 = vp[3];
                acc[0]  += p * v0.x; acc[1]  += p * v0.y; acc[2]  += p * v0.z; acc[3]  += p * v0.w;
                acc[4]  += p * v1.x; acc[5]  += p * v1.y; acc[6]  += p * v1.z; acc[7]  += p * v1.w;
                acc[8]  += p * v2.x; acc[9]  += p * v2.y; acc[10] += p * v2.z; acc[11] += p * v2.w;
                acc[12] += p * v3.x; acc[13] += p * v3.y; acc[14] += p * v3.z; acc[15] += p * v3.w;
            }
        }
    }
    __syncthreads();
    // epilogue: + W @ rel_v, normalize, store
    {
        float inv = 1.f / s.lrow[i_acc];
#pragma unroll
        for (int t = 0; t < NT; t++) {
            float wv = s.Wb[i_acc][t];
            const float4* rp = (const float4*)&s.relvs[t][dbase];
            float4 r0 = rp[0], r1 = rp[1], r2 = rp[2], r3 = rp[3];
            acc[0]  += wv * r0.x; acc[1]  += wv * r0.y; acc[2]  += wv * r0.z; acc[3]  += wv * r0.w;
            acc[4]  += wv * r1.x; acc[5]  += wv * r1.y; acc[6]  += wv * r1.z; acc[7]  += wv * r1.w;
            acc[8]  += wv * r2.x; acc[9]  += wv * r2.y; acc[10] += wv * r2.z; acc[11] += wv * r2.w;
            acc[12] += wv * r3.x; acc[13] += wv * r3.y; acc[14] += wv * r3.z; acc[15] += wv * r3.w;
        }
#pragma unroll
        for (int r = 0; r < 16; r++) acc[r] *= inv;
        int b = bh >> 4, h = bh & 15;
        int l = i0 + i_acc;
        float* yp = Y + ((size_t)(b * 1024 + l)) * 1024 + h * 64 + dbase;
        *(float4*)(yp + 0)  = make_float4(acc[0],  acc[1],  acc[2],  acc[3]);
        *(float4*)(yp + 4)  = make_float4(acc[4],  acc[5],  acc[6],  acc[7]);
        *(float4*)(yp + 8)  = make_float4(acc[8],  acc[9],  acc[10], acc[11]);
        *(float4*)(yp + 12) = make_float4(acc[12], acc[13], acc[14], acc[15]);
    }
}

// ---------------------------------------------------------------------------

extern "C" void kernel_launch(void* const* d_in, const int* in_sizes, int n_in,
                              void* d_out, int out_size)
{
    const float* query = (const float*)d_in[0];
    const float* key   = (const float*)d_in[1];
    const float* value = (const float*)d_in[2];
    const float* wq = (const float*)d_in[3];
    const float* bq = (const float*)d_in[4];
    const float* wk = (const float*)d_in[5];
    const float* bk = (const float*)d_in[6];
    const float* wv = (const float*)d_in[7];
    const float* bv = (const float*)d_in[8];
    const float* wo = (const float*)d_in[9];
    const float* bo = (const float*)d_in[10];
    const float* relk = (const float*)d_in[11];
    const float* relv = (const float*)d_in[12];
    float* out = (float*)d_out;

    float *Qp, *Kp, *Vp, *Yp, *RQp;
    cudaGetSymbolAddress((void**)&Qp, gQ);
    cudaGetSymbolAddress((void**)&Kp, gK);
    cudaGetSymbolAddress((void**)&Vp, gV);
    cudaGetSymbolAddress((void**)&Yp, gY);
    cudaGetSymbolAddress((void**)&RQp, gRQ);

    dim3 gg(8, 32);  // N/128, M/128
    sgemm_kernel<<<gg, 256>>>(query, wq, bq, Qp, 4096, 1024, 1024, 1);
    sgemm_kernel<<<gg, 256>>>(key,   wk, bk, Kp, 4096, 1024, 1024, 1);
    sgemm_kernel<<<gg, 256>>>(value, wv, bv, Vp, 4096, 1024, 1024, 1);

    rq_kernel<<<2048, 256>>>(Qp, relk, RQp);

    cudaFuncSetAttribute(attn_kernel, cudaFuncAttributeMaxDynamicSharedMemorySize,
                         (int)sizeof(AttnSmem));
    attn_kernel<<<dim3(16, 64), 256, sizeof(AttnSmem)>>>(Qp, Kp, Vp, RQp, relv, Yp);

    sgemm_kernel<<<gg, 256>>>(Yp, wo, bo, out, 4096, 1024, 1024, 0);
}

// round 3
// speedup vs baseline: 1.3726x; 1.3726x over previous
#include <cuda_runtime.h>
#include <math.h>
#include <cstdint>

// Problem constants
#define Bn  4
#define Ln  1024
#define En  1024
#define Hn  16
#define HDn 64
#define NT  33          // 2*CLIP+1
#define CLIPV 16
#define SCALEF 0.125f   // 1/sqrt(64)

// Scratch (device globals; no allocation allowed)
__device__ float gQ[Bn*Hn*Ln*HDn];   // [b][h][l][d]
__device__ float gK[Bn*Hn*Ln*HDn];
__device__ float gV[Bn*Hn*Ln*HDn];
__device__ float gY[Bn*Ln*En];       // [b][l][e]

// ---------------------------------------------------------------------------
// helpers
// ---------------------------------------------------------------------------
__device__ __forceinline__ uint32_t f2tf32(float x) {
    uint32_t r;
    asm("cvt.rna.tf32.f32 %0, %1;" : "=r"(r) : "f"(x));
    return r;
}

__device__ __forceinline__ void cp_async16(void* dst, const void* src) {
    uint32_t d = (uint32_t)__cvta_generic_to_shared(dst);
    asm volatile("cp.async.cg.shared.global [%0], [%1], 16;\n" :: "r"(d), "l"(src));
}

// ---------------------------------------------------------------------------
// TF32 tensor-core GEMM: C = A(4096x1024) @ W(1024x1024)^T + bias
// CTA tile 128x128, BK=16, cp.async double buffer, 8 warps (4m x 2n), warp
// tile 32x64, mma.sync.m16n8k8.tf32.  Optional head-layout store.
// ---------------------------------------------------------------------------
__device__ __forceinline__ void gemm_body(
    const float* __restrict__ A, const float* __restrict__ W,
    const float* __restrict__ bias, float* __restrict__ C, int head_layout)
{
    __shared__ float As[2][128][20];
    __shared__ float Bs[2][128][20];
    const int Kd = 1024;
    const int Nd = 1024;

    int tid  = threadIdx.x;
    int warp = tid >> 5, lane = tid & 31;
    int wm = (warp >> 1) << 5;   // 0,32,64,96
    int wn = (warp & 1) << 6;    // 0,64
    int g = lane >> 2, c = lane & 3;
    int m0 = blockIdx.y << 7, n0 = blockIdx.x << 7;

    // cp.async mapping: each thread loads rows (ra, ra+64), 16B segment ks4
    int ra  = tid >> 2;          // 0..63
    int ks4 = (tid & 3) << 2;    // 0,4,8,12
    const float* Ag = A + (size_t)(m0 + ra) * Kd + ks4;
    const float* Wg = W + (size_t)(n0 + ra) * Kd + ks4;

    float acc[2][8][4];
#pragma unroll
    for (int mi = 0; mi < 2; mi++)
#pragma unroll
        for (int ni = 0; ni < 8; ni++)
#pragma unroll
            for (int q = 0; q < 4; q++) acc[mi][ni][q] = 0.f;

    // prefetch tile 0
    cp_async16(&As[0][ra][ks4],      Ag);
    cp_async16(&As[0][ra + 64][ks4], Ag + (size_t)64 * Kd);
    cp_async16(&Bs[0][ra][ks4],      Wg);
    cp_async16(&Bs[0][ra + 64][ks4], Wg + (size_t)64 * Kd);
    asm volatile("cp.async.commit_group;\n");

    const int NITER = Kd / 16;   // 64
    for (int t = 0; t < NITER; t++) {
        if (t + 1 < NITER) {
            int nb = (t + 1) & 1;
            int k0 = (t + 1) << 4;
            cp_async16(&As[nb][ra][ks4],      Ag + k0);
            cp_async16(&As[nb][ra + 64][ks4], Ag + (size_t)64 * Kd + k0);
            cp_async16(&Bs[nb][ra][ks4],      Wg + k0);
            cp_async16(&Bs[nb][ra + 64][ks4], Wg + (size_t)64 * Kd + k0);
            asm volatile("cp.async.commit_group;\n");
            asm volatile("cp.async.wait_group 1;\n");
        } else {
            asm volatile("cp.async.wait_group 0;\n");
        }
        __syncthreads();

        int buf = t & 1;
#pragma unroll
        for (int ks = 0; ks < 2; ks++) {
            int kb = ks << 3;
            uint32_t af[2][4], bf[8][2];
#pragma unroll
            for (int mi = 0; mi < 2; mi++) {
                int m = wm + (mi << 4) + g;
                int k = kb + c;
                af[mi][0] = f2tf32(As[buf][m][k]);
                af[mi][1] = f2tf32(As[buf][m + 8][k]);
                af[mi][2] = f2tf32(As[buf][m][k + 4]);
                af[mi][3] = f2tf32(As[buf][m + 8][k + 4]);
            }
#pragma unroll
            for (int ni = 0; ni < 8; ni++) {
                int n = wn + (ni << 3) + g;
                int k = kb + c;
                bf[ni][0] = f2tf32(Bs[buf][n][k]);
                bf[ni][1] = f2tf32(Bs[buf][n][k + 4]);
            }
#pragma unroll
            for (int mi = 0; mi < 2; mi++)
#pragma unroll
                for (int ni = 0; ni < 8; ni++) {
                    asm volatile(
                        "mma.sync.aligned.m16n8k8.row.col.f32.tf32.tf32.f32 "
                        "{%0,%1,%2,%3}, {%4,%5,%6,%7}, {%8,%9}, {%0,%1,%2,%3};"
                        : "+f"(acc[mi][ni][0]), "+f"(acc[mi][ni][1]),
                          "+f"(acc[mi][ni][2]), "+f"(acc[mi][ni][3])
                        : "r"(af[mi][0]), "r"(af[mi][1]),
                          "r"(af[mi][2]), "r"(af[mi][3]),
                          "r"(bf[ni][0]), "r"(bf[ni][1]));
                }
        }
        __syncthreads();
    }

    // epilogue
#pragma unroll
    for (int mi = 0; mi < 2; mi++) {
#pragma unroll
        for (int ni = 0; ni < 8; ni++) {
            int row = m0 + wm + (mi << 4) + g;
            int col = n0 + wn + (ni << 3) + (c << 1);
            float b0 = bias[col], b1 = bias[col + 1];
            float2 v0 = make_float2(acc[mi][ni][0] + b0, acc[mi][ni][1] + b1);
            float2 v1 = make_float2(acc[mi][ni][2] + b0, acc[mi][ni][3] + b1);
            if (head_layout) {
                int b = row >> 10, l = row & 1023, h = col >> 6, d = col & 63;
                size_t off = (((size_t)(b * Hn + h)) << 16) + ((size_t)l << 6) + d;
                *(float2*)(C + off) = v0;
                int row2 = row + 8;
                int b2 = row2 >> 10, l2 = row2 & 1023;
                size_t off2 = (((size_t)(b2 * Hn + h)) << 16) + ((size_t)l2 << 6) + d;
                *(float2*)(C + off2) = v1;
            } else {
                *(float2*)(C + (size_t)row * Nd + col) = v0;
                *(float2*)(C + (size_t)(row + 8) * Nd + col) = v1;
            }
        }
    }
}

__global__ __launch_bounds__(256) void qkv_gemm_kernel(
    const float* __restrict__ query, const float* __restrict__ key,
    const float* __restrict__ value,
    const float* __restrict__ wq, const float* __restrict__ wk,
    const float* __restrict__ wv,
    const float* __restrict__ bq, const float* __restrict__ bk,
    const float* __restrict__ bv,
    float* __restrict__ Q, float* __restrict__ K, float* __restrict__ V)
{
    if (blockIdx.z == 0)      gemm_body(query, wq, bq, Q, 1);
    else if (blockIdx.z == 1) gemm_body(key,   wk, bk, K, 1);
    else                      gemm_body(value, wv, bv, V, 1);
}

__global__ __launch_bounds__(256) void out_gemm_kernel(
    const float* __restrict__ Y, const float* __restrict__ wo,
    const float* __restrict__ bo, float* __restrict__ out)
{
    gemm_body(Y, wo, bo, out, 0);
}

// ---------------------------------------------------------------------------
// Fused flash attention with relative-position bias + rel_v bucket sums.
// grid: (16 q-tiles, 64 bh). 256 threads. 64 q-rows per block.
// RQ[i][t] = (SCALE*Q[i]) . rel_k[t] computed in-kernel.
// ---------------------------------------------------------------------------
struct AttnSmem {
    float QsT[64][65];    // [d][i], SCALE folded
    float KsT[64][65];    // [d][j]
    float Vs[64][68];     // [j][d]
    float Ps[64][65];     // scores -> probs
    float RQs[64][NT];
    float Wb[64][NT];     // bucket weights (unnormalized)
    float relvs[NT][68];
    float relks[NT][68];
    float mrow[64], lrow[64], alpha_s[64];
};

__global__ __launch_bounds__(256) void attn_kernel(
    const float* __restrict__ Q, const float* __restrict__ Kg,
    const float* __restrict__ Vg, const float* __restrict__ relk,
    const float* __restrict__ relv, float* __restrict__ Y)
{
    extern __shared__ char smem_raw[];
    AttnSmem& s = *reinterpret_cast<AttnSmem*>(smem_raw);
    int tid = threadIdx.x;
    int bh = blockIdx.y;
    int i0 = blockIdx.x * 64;
    const float* Qb = Q + ((size_t)bh << 16) + (size_t)i0 * 64;
    const float* Kb = Kg + ((size_t)bh << 16);
    const float* Vb = Vg + ((size_t)bh << 16);

    // init loads
    {
        int r = tid >> 2;
        int dq = (tid & 3) << 4;
#pragma unroll
        for (int c = 0; c < 16; c += 4) {
            float4 v = *(const float4*)(Qb + r * 64 + dq + c);
            s.QsT[dq + c + 0][r] = v.x * SCALEF;
            s.QsT[dq + c + 1][r] = v.y * SCALEF;
            s.QsT[dq + c + 2][r] = v.z * SCALEF;
            s.QsT[dq + c + 3][r] = v.w * SCALEF;
        }
    }
    for (int idx = tid; idx < 64 * NT; idx += 256) {
        int i = idx / NT, t = idx % NT;
        s.Wb[i][t] = 0.f;
    }
    for (int idx = tid; idx < NT * 64; idx += 256) {
        s.relvs[idx >> 6][idx & 63] = relv[idx];
        s.relks[idx >> 6][idx & 63] = relk[idx];
    }
    if (tid < 64) { s.mrow[tid] = -1e30f; s.lrow[tid] = 0.f; }
    __syncthreads();

    // compute RQs[i][t] = QsT(:,i) . relks(t,:)  (SCALE already folded in QsT)
    {
        int i = tid >> 2;
        int qq = tid & 3;
        int dr = qq << 4;
        for (int t = 0; t < NT; t++) {
            float p = 0.f;
#pragma unroll
            for (int dd = 0; dd < 16; dd++)
                p += s.QsT[dr + dd][i] * s.relks[t][dr + dd];
            p += __shfl_xor_sync(0xffffffffu, p, 1);
            p += __shfl_xor_sync(0xffffffffu, p, 2);
            if (qq == 0) s.RQs[i][t] = p;
        }
    }

    float acc[16];
#pragma unroll
    for (int r = 0; r < 16; r++) acc[r] = 0.f;

    int tx = tid & 15, ty = tid >> 4;
    int i_acc = tid >> 2;
    int dbase = (tid & 3) << 4;

    for (int jt = 0; jt < 16; jt++) {
        int j0 = jt * 64;
        __syncthreads();
        // load K (transposed), V
        {
            int r = tid >> 2;
            int dq = (tid & 3) << 4;
#pragma unroll
            for (int c = 0; c < 16; c += 4) {
                float4 kv = *(const float4*)(Kb + (size_t)(j0 + r) * 64 + dq + c);
                s.KsT[dq + c + 0][r] = kv.x;
                s.KsT[dq + c + 1][r] = kv.y;
                s.KsT[dq + c + 2][r] = kv.z;
                s.KsT[dq + c + 3][r] = kv.w;
                float4 vv = *(const float4*)(Vb + (size_t)(j0 + r) * 64 + dq + c);
                *(float4*)&s.Vs[r][dq + c] = vv;
            }
        }
        __syncthreads();
        // S = Q K^T (+ rel bias)
        float cacc[4][4];
#pragma unroll
        for (int u = 0; u < 4; u++)
#pragma unroll
            for (int v = 0; v < 4; v++) cacc[u][v] = 0.f;
#pragma unroll
        for (int d = 0; d < 64; d++) {
            float a[4], bb[4];
#pragma unroll
            for (int u = 0; u < 4; u++) a[u] = s.QsT[d][ty * 4 + u];
#pragma unroll
            for (int v = 0; v < 4; v++) bb[v] = s.KsT[d][tx * 4 + v];
#pragma unroll
            for (int u = 0; u < 4; u++)
#pragma unroll
                for (int v = 0; v < 4; v++)
                    cacc[u][v] += a[u] * bb[v];
        }
#pragma unroll
        for (int u = 0; u < 4; u++) {
            int i = ty * 4 + u;
            int ig = i0 + i;
#pragma unroll
            for (int v = 0; v < 4; v++) {
                int j = tx * 4 + v;
                int dd = (j0 + j) - ig;
                dd = dd < -CLIPV ? -CLIPV : (dd > CLIPV ? CLIPV : dd);
                s.Ps[i][j] = cacc[u][v] + s.RQs[i][dd + CLIPV];
            }
        }
        __syncthreads();
        // per-row softmax state update (threads 0..63)
        if (tid < 64) {
            int i = tid;
            int ig = i0 + i;
            float mold = s.mrow[i];
            float mt = -1e30f;
#pragma unroll 8
            for (int j = 0; j < 64; j++) mt = fmaxf(mt, s.Ps[i][j]);
            float mnew = fmaxf(mold, mt);
            float alpha = __expf(mold - mnew);
#pragma unroll
            for (int t = 0; t < NT; t++) s.Wb[i][t] *= alpha;
            float rs = 0.f;
            for (int j = 0; j < 64; j++) {
                float p = __expf(s.Ps[i][j] - mnew);
                s.Ps[i][j] = p;
                rs += p;
                int dd = (j0 + j) - ig;
                dd = dd < -CLIPV ? -CLIPV : (dd > CLIPV ? CLIPV : dd);
                s.Wb[i][dd + CLIPV] += p;
            }
            s.lrow[i] = s.lrow[i] * alpha + rs;
            s.mrow[i] = mnew;
            s.alpha_s[i] = alpha;
        }
        __syncthreads();
        // acc = acc*alpha + P @ V
        {
            float alpha = s.alpha_s[i_acc];
#pragma unroll
            for (int r = 0; r < 16; r++) acc[r] *= alpha;
            for (int j = 0; j < 64; j++) {
                float p = s.Ps[i_acc][j];
                const float4* vp = (const float4*)&s.Vs[j][dbase];
                float4 v0 = vp[0], v1 = vp[1], v2 = vp[2], v3 = vp[3];
                acc[0]  += p * v0.x; acc[1]  += p * v0.y; acc[2]  += p * v0.z; acc[3]  += p * v0.w;
                acc[4]  += p * v1.x; acc[5]  += p * v1.y; acc[6]  += p * v1.z; acc[7]  += p * v1.w;
                acc[8]  += p * v2.x; acc[9]  += p * v2.y; acc[10] += p * v2.z; acc[11] += p * v2.w;
                acc[12] += p * v3.x; acc[13] += p * v3.y; acc[14] += p * v3.z; acc[15] += p * v3.w;
            }
        }
    }
    __syncthreads();
    // epilogue: + W @ rel_v, normalize, store
    {
        float inv = 1.f / s.lrow[i_acc];
#pragma unroll
        for (int t = 0; t < NT; t++) {
            float wv = s.Wb[i_acc][t];
            const float4* rp = (const float4*)&s.relvs[t][dbase];
            float4 r0 = rp[0], r1 = rp[1], r2 = rp[2], r3 = rp[3];
            acc[0]  += wv * r0.x; acc[1]  += wv * r0.y; acc[2]  += wv * r0.z; acc[3]  += wv * r0.w;
            acc[4]  += wv * r1.x; acc[5]  += wv * r1.y; acc[6]  += wv * r1.z; acc[7]  += wv * r1.w;
            acc[8]  += wv * r2.x; acc[9]  += wv * r2.y; acc[10] += wv * r2.z; acc[11] += wv * r2.w;
            acc[12] += wv * r3.x; acc[13] += wv * r3.y; acc[14] += wv * r3.z; acc[15] += wv * r3.w;
        }
#pragma unroll
        for (int r = 0; r < 16; r++) acc[r] *= inv;
        int b = bh >> 4, h = bh & 15;
        int l = i0 + i_acc;
        float* yp = Y + ((size_t)(b * 1024 + l)) * 1024 + h * 64 + dbase;
        *(float4*)(yp + 0)  = make_float4(acc[0],  acc[1],  acc[2],  acc[3]);
        *(float4*)(yp + 4)  = make_float4(acc[4],  acc[5],  acc[6],  acc[7]);
        *(float4*)(yp + 8)  = make_float4(acc[8],  acc[9],  acc[10], acc[11]);
        *(float4*)(yp + 12) = make_float4(acc[12], acc[13], acc[14], acc[15]);
    }
}

// ---------------------------------------------------------------------------

extern "C" void kernel_launch(void* const* d_in, const int* in_sizes, int n_in,
                              void* d_out, int out_size)
{
    const float* query = (const float*)d_in[0];
    const float* key   = (const float*)d_in[1];
    const float* value = (const float*)d_in[2];
    const float* wq = (const float*)d_in[3];
    const float* bq = (const float*)d_in[4];
    const float* wk = (const float*)d_in[5];
    const float* bk = (const float*)d_in[6];
    const float* wv = (const float*)d_in[7];
    const float* bv = (const float*)d_in[8];
    const float* wo = (const float*)d_in[9];
    const float* bo = (const float*)d_in[10];
    const float* relk = (const float*)d_in[11];
    const float* relv = (const float*)d_in[12];
    float* out = (float*)d_out;

    float *Qp, *Kp, *Vp, *Yp;
    cudaGetSymbolAddress((void**)&Qp, gQ);
    cudaGetSymbolAddress((void**)&Kp, gK);
    cudaGetSymbolAddress((void**)&Vp, gV);
    cudaGetSymbolAddress((void**)&Yp, gY);

    dim3 gqkv(8, 32, 3);   // N/128, M/128, {q,k,v}
    qkv_gemm_kernel<<<gqkv, 256>>>(query, key, value, wq, wk, wv,
                                   bq, bk, bv, Qp, Kp, Vp);

    cudaFuncSetAttribute(attn_kernel, cudaFuncAttributeMaxDynamicSharedMemorySize,
                         (int)sizeof(AttnSmem));
    attn_kernel<<<dim3(16, 64), 256, sizeof(AttnSmem)>>>(Qp, Kp, Vp, relk, relv, Yp);

    out_gemm_kernel<<<dim3(8, 32), 256>>>(Yp, wo, bo, out);
}

// round 4
// speedup vs baseline: 4.2685x; 3.1098x over previous
#include <cuda_runtime.h>
#include <math.h>
#include <cstdint>

// Problem constants
#define Bn  4
#define Ln  1024
#define En  1024
#define Hn  16
#define HDn 64
#define NT  33          // 2*CLIP+1
#define CLIPV 16
#define SCALEF 0.125f   // 1/sqrt(64)

// Scratch (device globals; no allocation allowed)
__device__ float gQ[Bn*Hn*Ln*HDn];   // [b][h][l][d]
__device__ float gK[Bn*Hn*Ln*HDn];
__device__ float gV[Bn*Hn*Ln*HDn];
__device__ float gY[Bn*Ln*En];       // [b][l][e]

// ---------------------------------------------------------------------------
// helpers
// ---------------------------------------------------------------------------
__device__ __forceinline__ uint32_t f2tf32(float x) {
    uint32_t r;
    asm("cvt.rna.tf32.f32 %0, %1;" : "=r"(r) : "f"(x));
    return r;
}

__device__ __forceinline__ void cp_async16(void* dst, const void* src) {
    uint32_t d = (uint32_t)__cvta_generic_to_shared(dst);
    asm volatile("cp.async.cg.shared.global [%0], [%1], 16;\n" :: "r"(d), "l"(src));
}

__device__ __forceinline__ void mma_tf32(float* d,
    uint32_t a0, uint32_t a1, uint32_t a2, uint32_t a3,
    uint32_t b0, uint32_t b1)
{
    asm volatile(
        "mma.sync.aligned.m16n8k8.row.col.f32.tf32.tf32.f32 "
        "{%0,%1,%2,%3}, {%4,%5,%6,%7}, {%8,%9}, {%0,%1,%2,%3};"
        : "+f"(d[0]), "+f"(d[1]), "+f"(d[2]), "+f"(d[3])
        : "r"(a0), "r"(a1), "r"(a2), "r"(a3), "r"(b0), "r"(b1));
}

// ---------------------------------------------------------------------------
// TF32 tensor-core GEMM: C = A(4096x1024) @ W(1024x1024)^T + bias
// ---------------------------------------------------------------------------
__device__ __forceinline__ void gemm_body(
    const float* __restrict__ A, const float* __restrict__ W,
    const float* __restrict__ bias, float* __restrict__ C, int head_layout)
{
    __shared__ float As[2][128][20];
    __shared__ float Bs[2][128][20];
    const int Kd = 1024;
    const int Nd = 1024;

    int tid  = threadIdx.x;
    int warp = tid >> 5, lane = tid & 31;
    int wm = (warp >> 1) << 5;
    int wn = (warp & 1) << 6;
    int g = lane >> 2, c = lane & 3;
    int m0 = blockIdx.y << 7, n0 = blockIdx.x << 7;

    int ra  = tid >> 2;
    int ks4 = (tid & 3) << 2;
    const float* Ag = A + (size_t)(m0 + ra) * Kd + ks4;
    const float* Wg = W + (size_t)(n0 + ra) * Kd + ks4;

    float acc[2][8][4];
#pragma unroll
    for (int mi = 0; mi < 2; mi++)
#pragma unroll
        for (int ni = 0; ni < 8; ni++)
#pragma unroll
            for (int q = 0; q < 4; q++) acc[mi][ni][q] = 0.f;

    cp_async16(&As[0][ra][ks4],      Ag);
    cp_async16(&As[0][ra + 64][ks4], Ag + (size_t)64 * Kd);
    cp_async16(&Bs[0][ra][ks4],      Wg);
    cp_async16(&Bs[0][ra + 64][ks4], Wg + (size_t)64 * Kd);
    asm volatile("cp.async.commit_group;\n");

    const int NITER = Kd / 16;
    for (int t = 0; t < NITER; t++) {
        if (t + 1 < NITER) {
            int nb = (t + 1) & 1;
            int k0 = (t + 1) << 4;
            cp_async16(&As[nb][ra][ks4],      Ag + k0);
            cp_async16(&As[nb][ra + 64][ks4], Ag + (size_t)64 * Kd + k0);
            cp_async16(&Bs[nb][ra][ks4],      Wg + k0);
            cp_async16(&Bs[nb][ra + 64][ks4], Wg + (size_t)64 * Kd + k0);
            asm volatile("cp.async.commit_group;\n");
            asm volatile("cp.async.wait_group 1;\n");
        } else {
            asm volatile("cp.async.wait_group 0;\n");
        }
        __syncthreads();

        int buf = t & 1;
#pragma unroll
        for (int ks = 0; ks < 2; ks++) {
            int kb = ks << 3;
            uint32_t af[2][4], bf[8][2];
#pragma unroll
            for (int mi = 0; mi < 2; mi++) {
                int m = wm + (mi << 4) + g;
                int k = kb + c;
                af[mi][0] = f2tf32(As[buf][m][k]);
                af[mi][1] = f2tf32(As[buf][m + 8][k]);
                af[mi][2] = f2tf32(As[buf][m][k + 4]);
                af[mi][3] = f2tf32(As[buf][m + 8][k + 4]);
            }
#pragma unroll
            for (int ni = 0; ni < 8; ni++) {
                int n = wn + (ni << 3) + g;
                int k = kb + c;
                bf[ni][0] = f2tf32(Bs[buf][n][k]);
                bf[ni][1] = f2tf32(Bs[buf][n][k + 4]);
            }
#pragma unroll
            for (int mi = 0; mi < 2; mi++)
#pragma unroll
                for (int ni = 0; ni < 8; ni++)
                    mma_tf32(acc[mi][ni], af[mi][0], af[mi][1], af[mi][2], af[mi][3],
                             bf[ni][0], bf[ni][1]);
        }
        __syncthreads();
    }

#pragma unroll
    for (int mi = 0; mi < 2; mi++) {
#pragma unroll
        for (int ni = 0; ni < 8; ni++) {
            int row = m0 + wm + (mi << 4) + g;
            int col = n0 + wn + (ni << 3) + (c << 1);
            float b0 = bias[col], b1 = bias[col + 1];
            float2 v0 = make_float2(acc[mi][ni][0] + b0, acc[mi][ni][1] + b1);
            float2 v1 = make_float2(acc[mi][ni][2] + b0, acc[mi][ni][3] + b1);
            if (head_layout) {
                int b = row >> 10, l = row & 1023, h = col >> 6, d = col & 63;
                size_t off = (((size_t)(b * Hn + h)) << 16) + ((size_t)l << 6) + d;
                *(float2*)(C + off) = v0;
                int row2 = row + 8;
                int b2 = row2 >> 10, l2 = row2 & 1023;
                size_t off2 = (((size_t)(b2 * Hn + h)) << 16) + ((size_t)l2 << 6) + d;
                *(float2*)(C + off2) = v1;
            } else {
                *(float2*)(C + (size_t)row * Nd + col) = v0;
                *(float2*)(C + (size_t)(row + 8) * Nd + col) = v1;
            }
        }
    }
}

__global__ __launch_bounds__(256) void qkv_gemm_kernel(
    const float* __restrict__ query, const float* __restrict__ key,
    const float* __restrict__ value,
    const float* __restrict__ wq, const float* __restrict__ wk,
    const float* __restrict__ wv,
    const float* __restrict__ bq, const float* __restrict__ bk,
    const float* __restrict__ bv,
    float* __restrict__ Q, float* __restrict__ K, float* __restrict__ V)
{
    if (blockIdx.z == 0)      gemm_body(query, wq, bq, Q, 1);
    else if (blockIdx.z == 1) gemm_body(key,   wk, bk, K, 1);
    else                      gemm_body(value, wv, bv, V, 1);
}

__global__ __launch_bounds__(256) void out_gemm_kernel(
    const float* __restrict__ Y, const float* __restrict__ wo,
    const float* __restrict__ bo, float* __restrict__ out)
{
    gemm_body(Y, wo, bo, out, 0);
}

// ---------------------------------------------------------------------------
// Tensor-core flash attention with relative-position bias + rel_v buckets.
// grid: (8 q-tiles of 128 rows, 64 bh). 256 threads = 8 warps x 16 rows.
// ---------------------------------------------------------------------------
#define PADA 68
#define PADV 72

struct AttnSmem {
    float Qs[128][PADA];    // Q tile (SCALE folded); reused as rel_v scratch in epilogue
    float Ps[128][PADA];    // probabilities
    float Ks[2][64][PADA];
    float Vs[2][64][PADV];
    float RQs[128][NT];     // per-row rel-k bias
    float Wb[128][NT];      // interior bucket weights (t=1..31); 0/32 filled at epilogue
    float relvs[NT][68];
    float relks[NT][68];
    float wscale[128];
    float linv[128];
};

__device__ __forceinline__ void load_kv_tile(AttnSmem& s, int buf,
    const float* Kb, const float* Vb, int j0, int tid)
{
    int j = tid >> 2, c4 = tid & 3;
    const float* ksrc = Kb + (size_t)(j0 + j) * 64;
    const float* vsrc = Vb + (size_t)(j0 + j) * 64;
#pragma unroll
    for (int q = 0; q < 4; q++) {
        int off = (c4 + 4 * q) * 4;
        cp_async16(&s.Ks[buf][j][off], ksrc + off);
        cp_async16(&s.Vs[buf][j][off], vsrc + off);
    }
}

__global__ __launch_bounds__(256) void attn_kernel(
    const float* __restrict__ Q, const float* __restrict__ Kg,
    const float* __restrict__ Vg, const float* __restrict__ relk,
    const float* __restrict__ relv, float* __restrict__ Y)
{
    extern __shared__ char smem_raw[];
    AttnSmem& s = *reinterpret_cast<AttnSmem*>(smem_raw);
    int tid = threadIdx.x;
    int warp = tid >> 5, lane = tid & 31;
    int g = lane >> 2, c = lane & 3;
    int r0 = warp * 16 + g;
    int r1 = r0 + 8;

    int bh = blockIdx.y;
    int bx = blockIdx.x;
    int i0 = bx * 128;
    const float* Qb = Q + ((size_t)bh << 16) + (size_t)i0 * 64;
    const float* Kb = Kg + ((size_t)bh << 16);
    const float* Vb = Vg + ((size_t)bh << 16);

    // ---- prologue: Q (scaled), rel tables, Wb zero, prefetch tile 0 ----
    {
        int r = tid >> 1;
        int half = (tid & 1) * 32;
        const float* src = Qb + (size_t)r * 64 + half;
#pragma unroll
        for (int kq = 0; kq < 8; kq++) {
            float4 v = *(const float4*)(src + kq * 4);
            v.x *= SCALEF; v.y *= SCALEF; v.z *= SCALEF; v.w *= SCALEF;
            *(float4*)&s.Qs[r][half + kq * 4] = v;
        }
    }
    for (int idx = tid; idx < NT * 64; idx += 256) {
        s.relvs[idx >> 6][idx & 63] = relv[idx];
        s.relks[idx >> 6][idx & 63] = relk[idx];
    }
    for (int idx = tid; idx < 128 * NT; idx += 256)
        s.Wb[idx / NT][idx % NT] = 0.f;
    load_kv_tile(s, 0, Kb, Vb, 0, tid);
    asm volatile("cp.async.commit_group;\n");
    __syncthreads();

    // ---- RQs[i][t] = Qs(i,:) . relk(t,:)  (SCALE already folded) ----
    {
        int i = tid >> 1;
        int h = (tid & 1) * 32;
        for (int t = 0; t < NT; t++) {
            float p = 0.f;
#pragma unroll
            for (int dd = 0; dd < 32; dd++)
                p += s.Qs[i][h + dd] * s.relks[t][h + dd];
            p += __shfl_xor_sync(0xffffffffu, p, 1);
            if ((tid & 1) == 0) s.RQs[i][t] = p;
        }
    }

    // per-row state (rows r0, r1), replicated across quad
    float m0s = -1e30f, m1s = -1e30f;
    float l0 = 0.f, l1 = 0.f;
    float b0a = 0.f, b0b = 0.f, b32a = 0.f, b32b = 0.f;
    float mW0 = -1e30f, mW1 = -1e30f;
    float acc[8][4];
#pragma unroll
    for (int ni = 0; ni < 8; ni++)
#pragma unroll
        for (int q = 0; q < 4; q++) acc[ni][q] = 0.f;

    int ig0 = i0 + r0, ig1 = i0 + r1;

    for (int jt = 0; jt < 16; jt++) {
        int buf = jt & 1;
        int j0 = jt * 64;
        __syncthreads();   // prev iter consumers done before overwriting buf^1
        if (jt + 1 < 16) {
            load_kv_tile(s, buf ^ 1, Kb, Vb, (jt + 1) * 64, tid);
            asm volatile("cp.async.commit_group;\n");
            asm volatile("cp.async.wait_group 1;\n");
        } else {
            asm volatile("cp.async.wait_group 0;\n");
        }
        __syncthreads();   // K/V[buf] visible

        int dj = jt - 2 * bx;
        bool far_left  = (dj <= -2);
        bool far_right = (dj >= 3);
        bool diag = !(far_left || far_right);

        // ---- S = Q K^T ----
        float sf[8][4];
#pragma unroll
        for (int ni = 0; ni < 8; ni++)
#pragma unroll
            for (int q = 0; q < 4; q++) sf[ni][q] = 0.f;
#pragma unroll
        for (int kb8 = 0; kb8 < 8; kb8++) {
            int kb = kb8 << 3;
            uint32_t a0 = f2tf32(s.Qs[r0][kb + c]);
            uint32_t a1 = f2tf32(s.Qs[r1][kb + c]);
            uint32_t a2 = f2tf32(s.Qs[r0][kb + c + 4]);
            uint32_t a3 = f2tf32(s.Qs[r1][kb + c + 4]);
#pragma unroll
            for (int ni = 0; ni < 8; ni++) {
                uint32_t bb0 = f2tf32(s.Ks[buf][ni * 8 + g][kb + c]);
                uint32_t bb1 = f2tf32(s.Ks[buf][ni * 8 + g][kb + c + 4]);
                mma_tf32(sf[ni], a0, a1, a2, a3, bb0, bb1);
            }
        }

        // ---- bias ----
        if (!diag) {
            int tf = far_left ? 0 : 32;
            float rq0 = s.RQs[r0][tf], rq1 = s.RQs[r1][tf];
#pragma unroll
            for (int ni = 0; ni < 8; ni++) {
                sf[ni][0] += rq0; sf[ni][1] += rq0;
                sf[ni][2] += rq1; sf[ni][3] += rq1;
            }
        } else {
#pragma unroll
            for (int ni = 0; ni < 8; ni++) {
#pragma unroll
                for (int e = 0; e < 2; e++) {
                    int j = j0 + ni * 8 + 2 * c + e;
                    int d0 = j - ig0; d0 = d0 < -CLIPV ? -CLIPV : (d0 > CLIPV ? CLIPV : d0);
                    int d1 = j - ig1; d1 = d1 < -CLIPV ? -CLIPV : (d1 > CLIPV ? CLIPV : d1);
                    sf[ni][e]     += s.RQs[r0][d0 + CLIPV];
                    sf[ni][2 + e] += s.RQs[r1][d1 + CLIPV];
                }
            }
        }

        // ---- online softmax in registers ----
        float mt0 = -1e30f, mt1 = -1e30f;
#pragma unroll
        for (int ni = 0; ni < 8; ni++) {
            mt0 = fmaxf(mt0, fmaxf(sf[ni][0], sf[ni][1]));
            mt1 = fmaxf(mt1, fmaxf(sf[ni][2], sf[ni][3]));
        }
        mt0 = fmaxf(mt0, __shfl_xor_sync(0xffffffffu, mt0, 1));
        mt0 = fmaxf(mt0, __shfl_xor_sync(0xffffffffu, mt0, 2));
        mt1 = fmaxf(mt1, __shfl_xor_sync(0xffffffffu, mt1, 1));
        mt1 = fmaxf(mt1, __shfl_xor_sync(0xffffffffu, mt1, 2));
        float mn0 = fmaxf(m0s, mt0), mn1 = fmaxf(m1s, mt1);
        float al0 = __expf(m0s - mn0), al1 = __expf(m1s - mn1);

        float rs0 = 0.f, rs1 = 0.f;
#pragma unroll
        for (int ni = 0; ni < 8; ni++) {
            sf[ni][0] = __expf(sf[ni][0] - mn0);
            sf[ni][1] = __expf(sf[ni][1] - mn0);
            sf[ni][2] = __expf(sf[ni][2] - mn1);
            sf[ni][3] = __expf(sf[ni][3] - mn1);
            rs0 += sf[ni][0] + sf[ni][1];
            rs1 += sf[ni][2] + sf[ni][3];
        }
        rs0 += __shfl_xor_sync(0xffffffffu, rs0, 1);
        rs0 += __shfl_xor_sync(0xffffffffu, rs0, 2);
        rs1 += __shfl_xor_sync(0xffffffffu, rs1, 1);
        rs1 += __shfl_xor_sync(0xffffffffu, rs1, 2);
        l0 = l0 * al0 + rs0;
        l1 = l1 * al1 + rs1;

        // ---- bucket weights ----
        if (far_left) {
            b0a = b0a * al0 + rs0;  b0b = b0b * al1 + rs1;
            b32a *= al0;            b32b *= al1;
        } else if (far_right) {
            b32a = b32a * al0 + rs0; b32b = b32b * al1 + rs1;
            b0a *= al0;              b0b *= al1;
        } else {
            float c0a = 0.f, c0b = 0.f, c32a = 0.f, c32b = 0.f;
#pragma unroll
            for (int ni = 0; ni < 8; ni++) {
#pragma unroll
                for (int e = 0; e < 2; e++) {
                    int j = j0 + ni * 8 + 2 * c + e;
                    int d0 = j - ig0;
                    int d1 = j - ig1;
                    if (d0 <= -CLIPV) c0a += sf[ni][e];
                    else if (d0 >= CLIPV) c32a += sf[ni][e];
                    if (d1 <= -CLIPV) c0b += sf[ni][2 + e];
                    else if (d1 >= CLIPV) c32b += sf[ni][2 + e];
                }
            }
            c0a += __shfl_xor_sync(0xffffffffu, c0a, 1);
            c0a += __shfl_xor_sync(0xffffffffu, c0a, 2);
            c0b += __shfl_xor_sync(0xffffffffu, c0b, 1);
            c0b += __shfl_xor_sync(0xffffffffu, c0b, 2);
            c32a += __shfl_xor_sync(0xffffffffu, c32a, 1);
            c32a += __shfl_xor_sync(0xffffffffu, c32a, 2);
            c32b += __shfl_xor_sync(0xffffffffu, c32b, 1);
            c32b += __shfl_xor_sync(0xffffffffu, c32b, 2);
            b0a = b0a * al0 + c0a;   b0b = b0b * al1 + c0b;
            b32a = b32a * al0 + c32a; b32b = b32b * al1 + c32b;
        }

        // wscale for interior rescale (diag tiles only)
        if (diag && c == 0) {
            s.wscale[r0] = __expf(mW0 - mn0);
            s.wscale[r1] = __expf(mW1 - mn1);
        }
        if (diag) { mW0 = mn0; mW1 = mn1; }
        m0s = mn0; m1s = mn1;

        // write probabilities
#pragma unroll
        for (int ni = 0; ni < 8; ni++) {
            int nc = ni * 8 + 2 * c;
            *(float2*)&s.Ps[r0][nc] = make_float2(sf[ni][0], sf[ni][1]);
            *(float2*)&s.Ps[r1][nc] = make_float2(sf[ni][2], sf[ni][3]);
        }
        __syncthreads();   // Ps + wscale visible

        if (diag) {
            // rescale interior buckets to new reference max
            for (int idx = tid; idx < 128 * 31; idx += 256) {
                int i = idx / 31, t = idx % 31 + 1;
                s.Wb[i][t] *= s.wscale[i];
            }
            __syncthreads();
            // scatter interior contributions
#pragma unroll
            for (int ni = 0; ni < 8; ni++) {
#pragma unroll
                for (int e = 0; e < 2; e++) {
                    int j = j0 + ni * 8 + 2 * c + e;
                    int d0 = j - ig0;
                    int d1 = j - ig1;
                    if (d0 > -CLIPV && d0 < CLIPV)
                        atomicAdd(&s.Wb[r0][d0 + CLIPV], sf[ni][e]);
                    if (d1 > -CLIPV && d1 < CLIPV)
                        atomicAdd(&s.Wb[r1][d1 + CLIPV], sf[ni][2 + e]);
                }
            }
        }

        // ---- acc = acc*alpha + P @ V ----
#pragma unroll
        for (int ni = 0; ni < 8; ni++) {
            acc[ni][0] *= al0; acc[ni][1] *= al0;
            acc[ni][2] *= al1; acc[ni][3] *= al1;
        }
#pragma unroll
        for (int kb8 = 0; kb8 < 8; kb8++) {
            int kb = kb8 << 3;
            uint32_t a0 = f2tf32(s.Ps[r0][kb + c]);
            uint32_t a1 = f2tf32(s.Ps[r1][kb + c]);
            uint32_t a2 = f2tf32(s.Ps[r0][kb + c + 4]);
            uint32_t a3 = f2tf32(s.Ps[r1][kb + c + 4]);
#pragma unroll
            for (int ni = 0; ni < 8; ni++) {
                uint32_t bb0 = f2tf32(s.Vs[buf][kb + c][ni * 8 + g]);
                uint32_t bb1 = f2tf32(s.Vs[buf][kb + c + 4][ni * 8 + g]);
                mma_tf32(acc[ni], a0, a1, a2, a3, bb0, bb1);
            }
        }
    }

    // ---- epilogue ----
    if (c == 0) {
        s.Wb[r0][0] = b0a;  s.Wb[r0][32] = b32a;
        s.Wb[r1][0] = b0b;  s.Wb[r1][32] = b32b;
        s.wscale[r0] = __expf(mW0 - m0s);
        s.wscale[r1] = __expf(mW1 - m1s);
        s.linv[r0] = 1.f / l0;
        s.linv[r1] = 1.f / l1;
    }
    __syncthreads();

    // rel_v contribution per row into Qs scratch: scr[i][d] = sum_t W_t relv[t][d]
    {
        int i = tid >> 1;
        int h = (tid & 1) * 32;
        float ws = s.wscale[i];
        float sc[32];
#pragma unroll
        for (int d = 0; d < 32; d++) sc[d] = 0.f;
        for (int t = 0; t < NT; t++) {
            float w = s.Wb[i][t];
            if (t != 0 && t != 32) w *= ws;
#pragma unroll
            for (int d = 0; d < 32; d++)
                sc[d] += w * s.relvs[t][h + d];
        }
#pragma unroll
        for (int d = 0; d < 32; d++) s.Qs[i][h + d] = sc[d];
    }
    __syncthreads();

    {
        float li0 = s.linv[r0], li1 = s.linv[r1];
        int bb = bh >> 4, hh = bh & 15;
        float* y0 = Y + ((size_t)(bb * 1024 + i0 + r0)) * 1024 + hh * 64;
        float* y1 = Y + ((size_t)(bb * 1024 + i0 + r1)) * 1024 + hh * 64;
#pragma unroll
        for (int ni = 0; ni < 8; ni++) {
            int col = ni * 8 + 2 * c;
            float2 v0 = make_float2((acc[ni][0] + s.Qs[r0][col]) * li0,
                                    (acc[ni][1] + s.Qs[r0][col + 1]) * li0);
            float2 v1 = make_float2((acc[ni][2] + s.Qs[r1][col]) * li1,
                                    (acc[ni][3] + s.Qs[r1][col + 1]) * li1);
            *(float2*)(y0 + col) = v0;
            *(float2*)(y1 + col) = v1;
        }
    }
}

// ---------------------------------------------------------------------------

extern "C" void kernel_launch(void* const* d_in, const int* in_sizes, int n_in,
                              void* d_out, int out_size)
{
    const float* query = (const float*)d_in[0];
    const float* key   = (const float*)d_in[1];
    const float* value = (const float*)d_in[2];
    const float* wq = (const float*)d_in[3];
    const float* bq = (const float*)d_in[4];
    const float* wk = (const float*)d_in[5];
    const float* bk = (const float*)d_in[6];
    const float* wv = (const float*)d_in[7];
    const float* bv = (const float*)d_in[8];
    const float* wo = (const float*)d_in[9];
    const float* bo = (const float*)d_in[10];
    const float* relk = (const float*)d_in[11];
    const float* relv = (const float*)d_in[12];
    float* out = (float*)d_out;

    float *Qp, *Kp, *Vp, *Yp;
    cudaGetSymbolAddress((void**)&Qp, gQ);
    cudaGetSymbolAddress((void**)&Kp, gK);
    cudaGetSymbolAddress((void**)&Vp, gV);
    cudaGetSymbolAddress((void**)&Yp, gY);

    dim3 gqkv(8, 32, 3);
    qkv_gemm_kernel<<<gqkv, 256>>>(query, key, value, wq, wk, wv,
                                   bq, bk, bv, Qp, Kp, Vp);

    cudaFuncSetAttribute(attn_kernel, cudaFuncAttributeMaxDynamicSharedMemorySize,
                         (int)sizeof(AttnSmem));
    attn_kernel<<<dim3(8, 64), 256, sizeof(AttnSmem)>>>(Qp, Kp, Vp, relk, relv, Yp);

    out_gemm_kernel<<<dim3(8, 32), 256>>>(Yp, wo, bo, out);
}

// round 5
// speedup vs baseline: 4.3296x; 1.0143x over previous
#include <cuda_runtime.h>
#include <math.h>
#include <cstdint>

// Problem constants
#define Bn  4
#define Ln  1024
#define En  1024
#define Hn  16
#define HDn 64
#define NT  33          // 2*CLIP+1
#define CLIPV 16
#define SCALEF 0.125f   // 1/sqrt(64)

// Scratch (device globals; no allocation allowed)
__device__ float gQ[Bn*Hn*Ln*HDn];   // [b][h][l][d]  (tf32-rounded)
__device__ float gK[Bn*Hn*Ln*HDn];
__device__ float gV[Bn*Hn*Ln*HDn];
__device__ float gY[Bn*Ln*En];       // [b][l][e]     (tf32-rounded)
__device__ float gXq[Bn*Ln*En];      // rounded inputs
__device__ float gXk[Bn*Ln*En];
__device__ float gXv[Bn*Ln*En];
__device__ float gWq[En*En];         // rounded weights
__device__ float gWk[En*En];
__device__ float gWv[En*En];
__device__ float gWo[En*En];

// ---------------------------------------------------------------------------
// helpers
// ---------------------------------------------------------------------------
__device__ __forceinline__ uint32_t f2tf32(float x) {
    uint32_t r;
    asm("cvt.rna.tf32.f32 %0, %1;" : "=r"(r) : "f"(x));
    return r;
}
__device__ __forceinline__ float roundtf(float x) {
    return __uint_as_float(f2tf32(x));
}

__device__ __forceinline__ void cp_async16(void* dst, const void* src) {
    uint32_t d = (uint32_t)__cvta_generic_to_shared(dst);
    asm volatile("cp.async.cg.shared.global [%0], [%1], 16;\n" :: "r"(d), "l"(src));
}

__device__ __forceinline__ void mma_tf32(float* d,
    uint32_t a0, uint32_t a1, uint32_t a2, uint32_t a3,
    uint32_t b0, uint32_t b1)
{
    asm volatile(
        "mma.sync.aligned.m16n8k8.row.col.f32.tf32.tf32.f32 "
        "{%0,%1,%2,%3}, {%4,%5,%6,%7}, {%8,%9}, {%0,%1,%2,%3};"
        : "+f"(d[0]), "+f"(d[1]), "+f"(d[2]), "+f"(d[3])
        : "r"(a0), "r"(a1), "r"(a2), "r"(a3), "r"(b0), "r"(b1));
}

// ---------------------------------------------------------------------------
// Elementwise tf32 rounding of 3 inputs + 4 weights.
// ---------------------------------------------------------------------------
__global__ __launch_bounds__(256) void round7_kernel(
    const float* __restrict__ xq, const float* __restrict__ xk,
    const float* __restrict__ xv,
    const float* __restrict__ wq, const float* __restrict__ wk,
    const float* __restrict__ wv, const float* __restrict__ wo,
    float* __restrict__ oxq, float* __restrict__ oxk, float* __restrict__ oxv,
    float* __restrict__ owq, float* __restrict__ owk,
    float* __restrict__ owv, float* __restrict__ owo)
{
    int t = blockIdx.y;
    const float* src; float* dst; int n4;
    switch (t) {
        case 0: src = xq; dst = oxq; n4 = (Bn*Ln*En)/4; break;
        case 1: src = xk; dst = oxk; n4 = (Bn*Ln*En)/4; break;
        case 2: src = xv; dst = oxv; n4 = (Bn*Ln*En)/4; break;
        case 3: src = wq; dst = owq; n4 = (En*En)/4; break;
        case 4: src = wk; dst = owk; n4 = (En*En)/4; break;
        case 5: src = wv; dst = owv; n4 = (En*En)/4; break;
        default: src = wo; dst = owo; n4 = (En*En)/4; break;
    }
    int stride = gridDim.x * 256;
    for (int i = blockIdx.x * 256 + threadIdx.x; i < n4; i += stride) {
        float4 v = ((const float4*)src)[i];
        v.x = roundtf(v.x); v.y = roundtf(v.y);
        v.z = roundtf(v.z); v.w = roundtf(v.w);
        ((float4*)dst)[i] = v;
    }
}

// ---------------------------------------------------------------------------
// TF32 tensor-core GEMM: C = A(4096x1024) @ W(1024x1024)^T + bias
// Operands are pre-rounded to tf32 -> no cvt in inner loop.
// ---------------------------------------------------------------------------
__device__ __forceinline__ void gemm_body(
    const float* __restrict__ A, const float* __restrict__ W,
    const float* __restrict__ bias, float* __restrict__ C, int head_layout)
{
    __shared__ float As[2][128][20];
    __shared__ float Bs[2][128][20];
    const int Kd = 1024;
    const int Nd = 1024;

    int tid  = threadIdx.x;
    int warp = tid >> 5, lane = tid & 31;
    int wm = (warp >> 1) << 5;
    int wn = (warp & 1) << 6;
    int g = lane >> 2, c = lane & 3;
    int m0 = blockIdx.y << 7, n0 = blockIdx.x << 7;

    int ra  = tid >> 2;
    int ks4 = (tid & 3) << 2;
    const float* Ag = A + (size_t)(m0 + ra) * Kd + ks4;
    const float* Wg = W + (size_t)(n0 + ra) * Kd + ks4;

    float acc[2][8][4];
#pragma unroll
    for (int mi = 0; mi < 2; mi++)
#pragma unroll
        for (int ni = 0; ni < 8; ni++)
#pragma unroll
            for (int q = 0; q < 4; q++) acc[mi][ni][q] = 0.f;

    cp_async16(&As[0][ra][ks4],      Ag);
    cp_async16(&As[0][ra + 64][ks4], Ag + (size_t)64 * Kd);
    cp_async16(&Bs[0][ra][ks4],      Wg);
    cp_async16(&Bs[0][ra + 64][ks4], Wg + (size_t)64 * Kd);
    asm volatile("cp.async.commit_group;\n");

    const int NITER = Kd / 16;
    for (int t = 0; t < NITER; t++) {
        if (t + 1 < NITER) {
            int nb = (t + 1) & 1;
            int k0 = (t + 1) << 4;
            cp_async16(&As[nb][ra][ks4],      Ag + k0);
            cp_async16(&As[nb][ra + 64][ks4], Ag + (size_t)64 * Kd + k0);
            cp_async16(&Bs[nb][ra][ks4],      Wg + k0);
            cp_async16(&Bs[nb][ra + 64][ks4], Wg + (size_t)64 * Kd + k0);
            asm volatile("cp.async.commit_group;\n");
            asm volatile("cp.async.wait_group 1;\n");
        } else {
            asm volatile("cp.async.wait_group 0;\n");
        }
        __syncthreads();

        int buf = t & 1;
#pragma unroll
        for (int ks = 0; ks < 2; ks++) {
            int kb = ks << 3;
            uint32_t af[2][4], bf[8][2];
#pragma unroll
            for (int mi = 0; mi < 2; mi++) {
                int m = wm + (mi << 4) + g;
                int k = kb + c;
                af[mi][0] = __float_as_uint(As[buf][m][k]);
                af[mi][1] = __float_as_uint(As[buf][m + 8][k]);
                af[mi][2] = __float_as_uint(As[buf][m][k + 4]);
                af[mi][3] = __float_as_uint(As[buf][m + 8][k + 4]);
            }
#pragma unroll
            for (int ni = 0; ni < 8; ni++) {
                int n = wn + (ni << 3) + g;
                int k = kb + c;
                bf[ni][0] = __float_as_uint(Bs[buf][n][k]);
                bf[ni][1] = __float_as_uint(Bs[buf][n][k + 4]);
            }
#pragma unroll
            for (int mi = 0; mi < 2; mi++)
#pragma unroll
                for (int ni = 0; ni < 8; ni++)
                    mma_tf32(acc[mi][ni], af[mi][0], af[mi][1], af[mi][2], af[mi][3],
                             bf[ni][0], bf[ni][1]);
        }
        __syncthreads();
    }

#pragma unroll
    for (int mi = 0; mi < 2; mi++) {
#pragma unroll
        for (int ni = 0; ni < 8; ni++) {
            int row = m0 + wm + (mi << 4) + g;
            int col = n0 + wn + (ni << 3) + (c << 1);
            float b0 = bias[col], b1 = bias[col + 1];
            float2 v0 = make_float2(acc[mi][ni][0] + b0, acc[mi][ni][1] + b1);
            float2 v1 = make_float2(acc[mi][ni][2] + b0, acc[mi][ni][3] + b1);
            if (head_layout) {
                // round so downstream tf32 consumers need no cvt
                v0.x = roundtf(v0.x); v0.y = roundtf(v0.y);
                v1.x = roundtf(v1.x); v1.y = roundtf(v1.y);
                int b = row >> 10, l = row & 1023, h = col >> 6, d = col & 63;
                size_t off = (((size_t)(b * Hn + h)) << 16) + ((size_t)l << 6) + d;
                *(float2*)(C + off) = v0;
                int row2 = row + 8;
                int b2 = row2 >> 10, l2 = row2 & 1023;
                size_t off2 = (((size_t)(b2 * Hn + h)) << 16) + ((size_t)l2 << 6) + d;
                *(float2*)(C + off2) = v1;
            } else {
                *(float2*)(C + (size_t)row * Nd + col) = v0;
                *(float2*)(C + (size_t)(row + 8) * Nd + col) = v1;
            }
        }
    }
}

__global__ __launch_bounds__(256) void qkv_gemm_kernel(
    const float* __restrict__ query, const float* __restrict__ key,
    const float* __restrict__ value,
    const float* __restrict__ wq, const float* __restrict__ wk,
    const float* __restrict__ wv,
    const float* __restrict__ bq, const float* __restrict__ bk,
    const float* __restrict__ bv,
    float* __restrict__ Q, float* __restrict__ K, float* __restrict__ V)
{
    if (blockIdx.z == 0)      gemm_body(query, wq, bq, Q, 1);
    else if (blockIdx.z == 1) gemm_body(key,   wk, bk, K, 1);
    else                      gemm_body(value, wv, bv, V, 1);
}

__global__ __launch_bounds__(256) void out_gemm_kernel(
    const float* __restrict__ Y, const float* __restrict__ wo,
    const float* __restrict__ bo, float* __restrict__ out)
{
    gemm_body(Y, wo, bo, out, 0);
}

// ---------------------------------------------------------------------------
// Tensor-core flash attention with relative-position bias + rel_v buckets.
// grid: (8 q-tiles of 128 rows, 64 bh). 256 threads = 8 warps x 16 rows.
// V stored transposed in smem (VsT[d][j]) -> conflict-free B-fragment loads.
// ---------------------------------------------------------------------------
#define PADA 68

struct AttnSmem {
    float Qs[128][PADA];    // Q tile (SCALE folded); reused as rel_v scratch
    float Ps[128][PADA];    // probabilities (tf32-rounded)
    float Ks[2][64][PADA];  // K [j][d]
    float VsT[2][64][PADA]; // V transposed [d][j]
    float RQs[128][NT];
    float Wb[128][NT];
    float relvs[NT][68];
    float relks[NT][68];
    float wscale[128];
    float linv[128];
};

__device__ __forceinline__ void load_k_tile(AttnSmem& s, int buf,
    const float* Kb, int j0, int tid)
{
    int j = tid >> 2, c4 = tid & 3;
    const float* ksrc = Kb + (size_t)(j0 + j) * 64;
#pragma unroll
    for (int q = 0; q < 4; q++) {
        int off = (c4 + 4 * q) * 4;
        cp_async16(&s.Ks[buf][j][off], ksrc + off);
    }
}

__device__ __forceinline__ void ldg_v_tile(float4* vreg,
    const float* Vb, int j0, int tid)
{
    int j = tid >> 2, c4 = tid & 3;
    const float* vsrc = Vb + (size_t)(j0 + j) * 64;
#pragma unroll
    for (int q = 0; q < 4; q++)
        vreg[q] = *(const float4*)(vsrc + (c4 + 4 * q) * 4);
}

__device__ __forceinline__ void sts_v_tile(AttnSmem& s, int buf,
    const float4* vreg, int tid)
{
    int j = tid >> 2, c4 = tid & 3;
#pragma unroll
    for (int q = 0; q < 4; q++) {
        int d0 = (c4 + 4 * q) * 4;
        s.VsT[buf][d0 + 0][j] = vreg[q].x;
        s.VsT[buf][d0 + 1][j] = vreg[q].y;
        s.VsT[buf][d0 + 2][j] = vreg[q].z;
        s.VsT[buf][d0 + 3][j] = vreg[q].w;
    }
}

__global__ __launch_bounds__(256) void attn_kernel(
    const float* __restrict__ Q, const float* __restrict__ Kg,
    const float* __restrict__ Vg, const float* __restrict__ relk,
    const float* __restrict__ relv, float* __restrict__ Y)
{
    extern __shared__ char smem_raw[];
    AttnSmem& s = *reinterpret_cast<AttnSmem*>(smem_raw);
    int tid = threadIdx.x;
    int warp = tid >> 5, lane = tid & 31;
    int g = lane >> 2, c = lane & 3;
    int r0 = warp * 16 + g;
    int r1 = r0 + 8;

    int bh = blockIdx.y;
    int bx = blockIdx.x;
    int i0 = bx * 128;
    const float* Qb = Q + ((size_t)bh << 16) + (size_t)i0 * 64;
    const float* Kb = Kg + ((size_t)bh << 16);
    const float* Vb = Vg + ((size_t)bh << 16);

    // ---- prologue ----
    float4 vreg[4];
    ldg_v_tile(vreg, Vb, 0, tid);
    load_k_tile(s, 0, Kb, 0, tid);
    asm volatile("cp.async.commit_group;\n");
    {
        int r = tid >> 1;
        int half = (tid & 1) * 32;
        const float* src = Qb + (size_t)r * 64 + half;
#pragma unroll
        for (int kq = 0; kq < 8; kq++) {
            float4 v = *(const float4*)(src + kq * 4);
            v.x *= SCALEF; v.y *= SCALEF; v.z *= SCALEF; v.w *= SCALEF;
            *(float4*)&s.Qs[r][half + kq * 4] = v;
        }
    }
    for (int idx = tid; idx < NT * 64; idx += 256) {
        s.relvs[idx >> 6][idx & 63] = relv[idx];
        s.relks[idx >> 6][idx & 63] = relk[idx];
    }
    for (int idx = tid; idx < 128 * NT; idx += 256)
        s.Wb[idx / NT][idx % NT] = 0.f;
    sts_v_tile(s, 0, vreg, tid);     // V(0) -> buf 0
    ldg_v_tile(vreg, Vb, 64, tid);   // V(1) -> regs
    __syncthreads();

    // ---- RQs[i][t] = Qs(i,:) . relk(t,:) ----
    {
        int i = tid >> 1;
        int h = (tid & 1) * 32;
        for (int t = 0; t < NT; t++) {
            float p = 0.f;
#pragma unroll
            for (int dd = 0; dd < 32; dd++)
                p += s.Qs[i][h + dd] * s.relks[t][h + dd];
            p += __shfl_xor_sync(0xffffffffu, p, 1);
            if ((tid & 1) == 0) s.RQs[i][t] = p;
        }
    }

    float m0s = -1e30f, m1s = -1e30f;
    float l0 = 0.f, l1 = 0.f;
    float b0a = 0.f, b0b = 0.f, b32a = 0.f, b32b = 0.f;
    float mW0 = -1e30f, mW1 = -1e30f;
    float acc[8][4];
#pragma unroll
    for (int ni = 0; ni < 8; ni++)
#pragma unroll
        for (int q = 0; q < 4; q++) acc[ni][q] = 0.f;

    int ig0 = i0 + r0, ig1 = i0 + r1;

    for (int jt = 0; jt < 16; jt++) {
        int buf = jt & 1;
        int j0 = jt * 64;
        __syncthreads();   // consumers of buf^1 done
        if (jt + 1 < 16) {
            sts_v_tile(s, buf ^ 1, vreg, tid);        // V(jt+1)
            load_k_tile(s, buf ^ 1, Kb, j0 + 64, tid);
            asm volatile("cp.async.commit_group;\n");
            asm volatile("cp.async.wait_group 1;\n");
        } else {
            asm volatile("cp.async.wait_group 0;\n");
        }
        __syncthreads();   // K/V[buf] visible

        if (jt + 2 < 16)   // prefetch V(jt+2); latency hidden by compute
            ldg_v_tile(vreg, Vb, j0 + 128, tid);

        int dj = jt - 2 * bx;
        bool far_left  = (dj <= -2);
        bool far_right = (dj >= 3);
        bool diag = !(far_left || far_right);

        // ---- S = Q K^T ----
        float sf[8][4];
#pragma unroll
        for (int ni = 0; ni < 8; ni++)
#pragma unroll
            for (int q = 0; q < 4; q++) sf[ni][q] = 0.f;
#pragma unroll
        for (int kb8 = 0; kb8 < 8; kb8++) {
            int kb = kb8 << 3;
            uint32_t a0 = __float_as_uint(s.Qs[r0][kb + c]);
            uint32_t a1 = __float_as_uint(s.Qs[r1][kb + c]);
            uint32_t a2 = __float_as_uint(s.Qs[r0][kb + c + 4]);
            uint32_t a3 = __float_as_uint(s.Qs[r1][kb + c + 4]);
#pragma unroll
            for (int ni = 0; ni < 8; ni++) {
                uint32_t bb0 = __float_as_uint(s.Ks[buf][ni * 8 + g][kb + c]);
                uint32_t bb1 = __float_as_uint(s.Ks[buf][ni * 8 + g][kb + c + 4]);
                mma_tf32(sf[ni], a0, a1, a2, a3, bb0, bb1);
            }
        }

        // ---- bias ----
        if (!diag) {
            int tf = far_left ? 0 : 32;
            float rq0 = s.RQs[r0][tf], rq1 = s.RQs[r1][tf];
#pragma unroll
            for (int ni = 0; ni < 8; ni++) {
                sf[ni][0] += rq0; sf[ni][1] += rq0;
                sf[ni][2] += rq1; sf[ni][3] += rq1;
            }
        } else {
#pragma unroll
            for (int ni = 0; ni < 8; ni++) {
#pragma unroll
                for (int e = 0; e < 2; e++) {
                    int j = j0 + ni * 8 + 2 * c + e;
                    int d0 = j - ig0; d0 = d0 < -CLIPV ? -CLIPV : (d0 > CLIPV ? CLIPV : d0);
                    int d1 = j - ig1; d1 = d1 < -CLIPV ? -CLIPV : (d1 > CLIPV ? CLIPV : d1);
                    sf[ni][e]     += s.RQs[r0][d0 + CLIPV];
                    sf[ni][2 + e] += s.RQs[r1][d1 + CLIPV];
                }
            }
        }

        // ---- online softmax ----
        float mt0 = -1e30f, mt1 = -1e30f;
#pragma unroll
        for (int ni = 0; ni < 8; ni++) {
            mt0 = fmaxf(mt0, fmaxf(sf[ni][0], sf[ni][1]));
            mt1 = fmaxf(mt1, fmaxf(sf[ni][2], sf[ni][3]));
        }
        mt0 = fmaxf(mt0, __shfl_xor_sync(0xffffffffu, mt0, 1));
        mt0 = fmaxf(mt0, __shfl_xor_sync(0xffffffffu, mt0, 2));
        mt1 = fmaxf(mt1, __shfl_xor_sync(0xffffffffu, mt1, 1));
        mt1 = fmaxf(mt1, __shfl_xor_sync(0xffffffffu, mt1, 2));
        float mn0 = fmaxf(m0s, mt0), mn1 = fmaxf(m1s, mt1);
        float al0 = __expf(m0s - mn0), al1 = __expf(m1s - mn1);

        float rs0 = 0.f, rs1 = 0.f;
#pragma unroll
        for (int ni = 0; ni < 8; ni++) {
            sf[ni][0] = __expf(sf[ni][0] - mn0);
            sf[ni][1] = __expf(sf[ni][1] - mn0);
            sf[ni][2] = __expf(sf[ni][2] - mn1);
            sf[ni][3] = __expf(sf[ni][3] - mn1);
            rs0 += sf[ni][0] + sf[ni][1];
            rs1 += sf[ni][2] + sf[ni][3];
        }
        rs0 += __shfl_xor_sync(0xffffffffu, rs0, 1);
        rs0 += __shfl_xor_sync(0xffffffffu, rs0, 2);
        rs1 += __shfl_xor_sync(0xffffffffu, rs1, 1);
        rs1 += __shfl_xor_sync(0xffffffffu, rs1, 2);
        l0 = l0 * al0 + rs0;
        l1 = l1 * al1 + rs1;

        // ---- bucket weights ----
        if (far_left) {
            b0a = b0a * al0 + rs0;  b0b = b0b * al1 + rs1;
            b32a *= al0;            b32b *= al1;
        } else if (far_right) {
            b32a = b32a * al0 + rs0; b32b = b32b * al1 + rs1;
            b0a *= al0;              b0b *= al1;
        } else {
            float c0a = 0.f, c0b = 0.f, c32a = 0.f, c32b = 0.f;
#pragma unroll
            for (int ni = 0; ni < 8; ni++) {
#pragma unroll
                for (int e = 0; e < 2; e++) {
                    int j = j0 + ni * 8 + 2 * c + e;
                    int d0 = j - ig0;
                    int d1 = j - ig1;
                    if (d0 <= -CLIPV) c0a += sf[ni][e];
                    else if (d0 >= CLIPV) c32a += sf[ni][e];
                    if (d1 <= -CLIPV) c0b += sf[ni][2 + e];
                    else if (d1 >= CLIPV) c32b += sf[ni][2 + e];
                }
            }
            c0a += __shfl_xor_sync(0xffffffffu, c0a, 1);
            c0a += __shfl_xor_sync(0xffffffffu, c0a, 2);
            c0b += __shfl_xor_sync(0xffffffffu, c0b, 1);
            c0b += __shfl_xor_sync(0xffffffffu, c0b, 2);
            c32a += __shfl_xor_sync(0xffffffffu, c32a, 1);
            c32a += __shfl_xor_sync(0xffffffffu, c32a, 2);
            c32b += __shfl_xor_sync(0xffffffffu, c32b, 1);
            c32b += __shfl_xor_sync(0xffffffffu, c32b, 2);
            b0a = b0a * al0 + c0a;   b0b = b0b * al1 + c0b;
            b32a = b32a * al0 + c32a; b32b = b32b * al1 + c32b;
        }

        if (diag && c == 0) {
            s.wscale[r0] = __expf(mW0 - mn0);
            s.wscale[r1] = __expf(mW1 - mn1);
        }
        if (diag) { mW0 = mn0; mW1 = mn1; }
        m0s = mn0; m1s = mn1;

        // write probabilities (tf32-rounded so PV mma needs no cvt)
#pragma unroll
        for (int ni = 0; ni < 8; ni++) {
            int nc = ni * 8 + 2 * c;
            *(float2*)&s.Ps[r0][nc] = make_float2(roundtf(sf[ni][0]), roundtf(sf[ni][1]));
            *(float2*)&s.Ps[r1][nc] = make_float2(roundtf(sf[ni][2]), roundtf(sf[ni][3]));
        }
        __syncthreads();

        if (diag) {
            for (int idx = tid; idx < 128 * 31; idx += 256) {
                int i = idx / 31, t = idx % 31 + 1;
                s.Wb[i][t] *= s.wscale[i];
            }
            __syncthreads();
#pragma unroll
            for (int ni = 0; ni < 8; ni++) {
#pragma unroll
                for (int e = 0; e < 2; e++) {
                    int j = j0 + ni * 8 + 2 * c + e;
                    int d0 = j - ig0;
                    int d1 = j - ig1;
                    if (d0 > -CLIPV && d0 < CLIPV)
                        atomicAdd(&s.Wb[r0][d0 + CLIPV], sf[ni][e]);
                    if (d1 > -CLIPV && d1 < CLIPV)
                        atomicAdd(&s.Wb[r1][d1 + CLIPV], sf[ni][2 + e]);
                }
            }
        }

        // ---- acc = acc*alpha + P @ V ----
#pragma unroll
        for (int ni = 0; ni < 8; ni++) {
            acc[ni][0] *= al0; acc[ni][1] *= al0;
            acc[ni][2] *= al1; acc[ni][3] *= al1;
        }
#pragma unroll
        for (int kb8 = 0; kb8 < 8; kb8++) {
            int kb = kb8 << 3;
            uint32_t a0 = __float_as_uint(s.Ps[r0][kb + c]);
            uint32_t a1 = __float_as_uint(s.Ps[r1][kb + c]);
            uint32_t a2 = __float_as_uint(s.Ps[r0][kb + c + 4]);
            uint32_t a3 = __float_as_uint(s.Ps[r1][kb + c + 4]);
#pragma unroll
            for (int ni = 0; ni < 8; ni++) {
                uint32_t bb0 = __float_as_uint(s.VsT[buf][ni * 8 + g][kb + c]);
                uint32_t bb1 = __float_as_uint(s.VsT[buf][ni * 8 + g][kb + c + 4]);
                mma_tf32(acc[ni], a0, a1, a2, a3, bb0, bb1);
            }
        }
    }

    // ---- epilogue ----
    if (c == 0) {
        s.Wb[r0][0] = b0a;  s.Wb[r0][32] = b32a;
        s.Wb[r1][0] = b0b;  s.Wb[r1][32] = b32b;
        s.wscale[r0] = __expf(mW0 - m0s);
        s.wscale[r1] = __expf(mW1 - m1s);
        s.linv[r0] = 1.f / l0;
        s.linv[r1] = 1.f / l1;
    }
    __syncthreads();

    {
        int i = tid >> 1;
        int h = (tid & 1) * 32;
        float ws = s.wscale[i];
        float sc[32];
#pragma unroll
        for (int d = 0; d < 32; d++) sc[d] = 0.f;
        for (int t = 0; t < NT; t++) {
            float w = s.Wb[i][t];
            if (t != 0 && t != 32) w *= ws;
#pragma unroll
            for (int d = 0; d < 32; d++)
                sc[d] += w * s.relvs[t][h + d];
        }
#pragma unroll
        for (int d = 0; d < 32; d++) s.Qs[i][h + d] = sc[d];
    }
    __syncthreads();

    {
        float li0 = s.linv[r0], li1 = s.linv[r1];
        int bb = bh >> 4, hh = bh & 15;
        float* y0 = Y + ((size_t)(bb * 1024 + i0 + r0)) * 1024 + hh * 64;
        float* y1 = Y + ((size_t)(bb * 1024 + i0 + r1)) * 1024 + hh * 64;
#pragma unroll
        for (int ni = 0; ni < 8; ni++) {
            int col = ni * 8 + 2 * c;
            float2 v0 = make_float2(roundtf((acc[ni][0] + s.Qs[r0][col]) * li0),
                                    roundtf((acc[ni][1] + s.Qs[r0][col + 1]) * li0));
            float2 v1 = make_float2(roundtf((acc[ni][2] + s.Qs[r1][col]) * li1),
                                    roundtf((acc[ni][3] + s.Qs[r1][col + 1]) * li1));
            *(float2*)(y0 + col) = v0;
            *(float2*)(y1 + col) = v1;
        }
    }
}

// ---------------------------------------------------------------------------

extern "C" void kernel_launch(void* const* d_in, const int* in_sizes, int n_in,
                              void* d_out, int out_size)
{
    const float* query = (const float*)d_in[0];
    const float* key   = (const float*)d_in[1];
    const float* value = (const float*)d_in[2];
    const float* wq = (const float*)d_in[3];
    const float* bq = (const float*)d_in[4];
    const float* wk = (const float*)d_in[5];
    const float* bk = (const float*)d_in[6];
    const float* wv = (const float*)d_in[7];
    const float* bv = (const float*)d_in[8];
    const float* wo = (const float*)d_in[9];
    const float* bo = (const float*)d_in[10];
    const float* relk = (const float*)d_in[11];
    const float* relv = (const float*)d_in[12];
    float* out = (float*)d_out;

    float *Qp, *Kp, *Vp, *Yp;
    float *Xq, *Xk, *Xv, *Wq, *Wk, *Wv, *Wo;
    cudaGetSymbolAddress((void**)&Qp, gQ);
    cudaGetSymbolAddress((void**)&Kp, gK);
    cudaGetSymbolAddress((void**)&Vp, gV);
    cudaGetSymbolAddress((void**)&Yp, gY);
    cudaGetSymbolAddress((void**)&Xq, gXq);
    cudaGetSymbolAddress((void**)&Xk, gXk);
    cudaGetSymbolAddress((void**)&Xv, gXv);
    cudaGetSymbolAddress((void**)&Wq, gWq);
    cudaGetSymbolAddress((void**)&Wk, gWk);
    cudaGetSymbolAddress((void**)&Wv, gWv);
    cudaGetSymbolAddress((void**)&Wo, gWo);

    round7_kernel<<<dim3(1024, 7), 256>>>(query, key, value, wq, wk, wv, wo,
                                          Xq, Xk, Xv, Wq, Wk, Wv, Wo);

    dim3 gqkv(8, 32, 3);
    qkv_gemm_kernel<<<gqkv, 256>>>(Xq, Xk, Xv, Wq, Wk, Wv,
                                   bq, bk, bv, Qp, Kp, Vp);

    cudaFuncSetAttribute(attn_kernel, cudaFuncAttributeMaxDynamicSharedMemorySize,
                         (int)sizeof(AttnSmem));
    attn_kernel<<<dim3(8, 64), 256, sizeof(AttnSmem)>>>(Qp, Kp, Vp, relk, relv, Yp);

    out_gemm_kernel<<<dim3(8, 32), 256>>>(Yp, Wo, bo, out);
}

// round 6
// speedup vs baseline: 7.4553x; 1.7219x over previous
#include <cuda_runtime.h>
#include <cuda_fp16.h>
#include <math.h>
#include <cstdint>

// Problem constants
#define Bn  4
#define Ln  1024
#define En  1024
#define Hn  16
#define HDn 64
#define NT  33          // 2*CLIP+1
#define CLIPV 16
#define SCALEF 0.125f   // 1/sqrt(64)

// Scratch (device globals; no allocation allowed)
__device__ __half gQ[Bn*Hn*Ln*HDn];   // [b][h][l][d] fp16
__device__ __half gK[Bn*Hn*Ln*HDn];
__device__ __half gV[Bn*Hn*Ln*HDn];
__device__ __half gY[Bn*Ln*En];       // [b][l][e] fp16
__device__ __half gXq[Bn*Ln*En];      // fp16 inputs
__device__ __half gXk[Bn*Ln*En];
__device__ __half gXv[Bn*Ln*En];
__device__ __half gWq[En*En];         // fp16 weights
__device__ __half gWk[En*En];
__device__ __half gWv[En*En];
__device__ __half gWo[En*En];

// ---------------------------------------------------------------------------
// helpers
// ---------------------------------------------------------------------------
__device__ __forceinline__ uint32_t packh2(float x, float y) {
    __half2 h = __floats2half2_rn(x, y);
    return *reinterpret_cast<uint32_t*>(&h);
}

__device__ __forceinline__ void cp_async16(void* dst, const void* src) {
    uint32_t d = (uint32_t)__cvta_generic_to_shared(dst);
    asm volatile("cp.async.cg.shared.global [%0], [%1], 16;\n" :: "r"(d), "l"(src));
}

__device__ __forceinline__ void ldsm4(uint32_t& r0, uint32_t& r1,
                                      uint32_t& r2, uint32_t& r3, const void* p) {
    uint32_t a = (uint32_t)__cvta_generic_to_shared(p);
    asm volatile("ldmatrix.sync.aligned.m8n8.x4.shared.b16 {%0,%1,%2,%3}, [%4];"
                 : "=r"(r0), "=r"(r1), "=r"(r2), "=r"(r3) : "r"(a));
}

__device__ __forceinline__ void ldsm4t(uint32_t& r0, uint32_t& r1,
                                       uint32_t& r2, uint32_t& r3, const void* p) {
    uint32_t a = (uint32_t)__cvta_generic_to_shared(p);
    asm volatile("ldmatrix.sync.aligned.m8n8.x4.trans.shared.b16 {%0,%1,%2,%3}, [%4];"
                 : "=r"(r0), "=r"(r1), "=r"(r2), "=r"(r3) : "r"(a));
}

__device__ __forceinline__ void mma_f16(float* d,
    uint32_t a0, uint32_t a1, uint32_t a2, uint32_t a3,
    uint32_t b0, uint32_t b1)
{
    asm volatile(
        "mma.sync.aligned.m16n8k16.row.col.f32.f16.f16.f32 "
        "{%0,%1,%2,%3}, {%4,%5,%6,%7}, {%8,%9}, {%0,%1,%2,%3};"
        : "+f"(d[0]), "+f"(d[1]), "+f"(d[2]), "+f"(d[3])
        : "r"(a0), "r"(a1), "r"(a2), "r"(a3), "r"(b0), "r"(b1));
}

// ---------------------------------------------------------------------------
// fp32 -> fp16 conversion of 3 inputs + 4 weights.
// ---------------------------------------------------------------------------
__global__ __launch_bounds__(256) void convert7_kernel(
    const float* __restrict__ xq, const float* __restrict__ xk,
    const float* __restrict__ xv,
    const float* __restrict__ wq, const float* __restrict__ wk,
    const float* __restrict__ wv, const float* __restrict__ wo,
    __half* __restrict__ oxq, __half* __restrict__ oxk, __half* __restrict__ oxv,
    __half* __restrict__ owq, __half* __restrict__ owk,
    __half* __restrict__ owv, __half* __restrict__ owo)
{
    int t = blockIdx.y;
    const float* src; __half* dst; int n8;
    switch (t) {
        case 0: src = xq; dst = oxq; n8 = (Bn*Ln*En)/8; break;
        case 1: src = xk; dst = oxk; n8 = (Bn*Ln*En)/8; break;
        case 2: src = xv; dst = oxv; n8 = (Bn*Ln*En)/8; break;
        case 3: src = wq; dst = owq; n8 = (En*En)/8; break;
        case 4: src = wk; dst = owk; n8 = (En*En)/8; break;
        case 5: src = wv; dst = owv; n8 = (En*En)/8; break;
        default: src = wo; dst = owo; n8 = (En*En)/8; break;
    }
    int stride = gridDim.x * 256;
    for (int i = blockIdx.x * 256 + threadIdx.x; i < n8; i += stride) {
        float4 a = ((const float4*)src)[2*i];
        float4 b = ((const float4*)src)[2*i + 1];
        uint4 o;
        o.x = packh2(a.x, a.y); o.y = packh2(a.z, a.w);
        o.z = packh2(b.x, b.y); o.w = packh2(b.z, b.w);
        ((uint4*)dst)[i] = o;
    }
}

// ---------------------------------------------------------------------------
// fp16 tensor-core GEMM: C = A(4096x1024) @ W(1024x1024)^T + bias.
// CTA 128x128, BK=32, cp.async double buffer, ldmatrix fragments,
// 8 warps (4m x 2n), warp tile 32x64, mma m16n8k16 fp16 -> fp32.
// head_layout=1: write fp16 to [b][h][l][d]; else fp32 row-major.
// ---------------------------------------------------------------------------
__device__ __forceinline__ void gemm_body(
    const __half* __restrict__ A, const __half* __restrict__ W,
    const float* __restrict__ bias, void* __restrict__ Cout, int head_layout)
{
    __shared__ __half As[2][128][40];
    __shared__ __half Bs[2][128][40];
    const int Kd = 1024;

    int tid  = threadIdx.x;
    int warp = tid >> 5, lane = tid & 31;
    int wm = (warp >> 1) << 5;
    int wn = (warp & 1) << 6;
    int g = lane >> 2, c = lane & 3;
    int m0 = blockIdx.y << 7, n0 = blockIdx.x << 7;

    // ldmatrix lane addressing components
    int lrow = (lane & 7) + ((lane >> 3) & 1) * 8;
    int lcol = (lane >> 4) * 8;

    // cp.async mapping: row = tid>>1, 2x16B chunks at (tid&1)*16 halves
    int ra   = tid >> 1;
    int colh = (tid & 1) << 4;
    const __half* Ag = A + (size_t)(m0 + ra) * Kd + colh;
    const __half* Wg = W + (size_t)(n0 + ra) * Kd + colh;

    float acc[2][8][4];
#pragma unroll
    for (int mi = 0; mi < 2; mi++)
#pragma unroll
        for (int ni = 0; ni < 8; ni++)
#pragma unroll
            for (int q = 0; q < 4; q++) acc[mi][ni][q] = 0.f;

    cp_async16(&As[0][ra][colh],     Ag);
    cp_async16(&As[0][ra][colh + 8], Ag + 8);
    cp_async16(&Bs[0][ra][colh],     Wg);
    cp_async16(&Bs[0][ra][colh + 8], Wg + 8);
    asm volatile("cp.async.commit_group;\n");

    const int NITER = Kd / 32;   // 32
    for (int t = 0; t < NITER; t++) {
        if (t + 1 < NITER) {
            int nb = (t + 1) & 1;
            int k0 = (t + 1) << 5;
            cp_async16(&As[nb][ra][colh],     Ag + k0);
            cp_async16(&As[nb][ra][colh + 8], Ag + k0 + 8);
            cp_async16(&Bs[nb][ra][colh],     Wg + k0);
            cp_async16(&Bs[nb][ra][colh + 8], Wg + k0 + 8);
            asm volatile("cp.async.commit_group;\n");
            asm volatile("cp.async.wait_group 1;\n");
        } else {
            asm volatile("cp.async.wait_group 0;\n");
        }
        __syncthreads();

        int buf = t & 1;
#pragma unroll
        for (int ks = 0; ks < 2; ks++) {
            int kc = ks * 16 + lcol;
            uint32_t af[2][4], bf[4][4];
#pragma unroll
            for (int mi = 0; mi < 2; mi++)
                ldsm4(af[mi][0], af[mi][1], af[mi][2], af[mi][3],
                      &As[buf][wm + mi * 16 + lrow][kc]);
#pragma unroll
            for (int p = 0; p < 4; p++)
                ldsm4(bf[p][0], bf[p][1], bf[p][2], bf[p][3],
                      &Bs[buf][wn + p * 16 + lrow][kc]);
#pragma unroll
            for (int mi = 0; mi < 2; mi++)
#pragma unroll
                for (int ni = 0; ni < 8; ni++) {
                    int p = ni >> 1;
                    uint32_t b0 = (ni & 1) ? bf[p][1] : bf[p][0];
                    uint32_t b1 = (ni & 1) ? bf[p][3] : bf[p][2];
                    mma_f16(acc[mi][ni], af[mi][0], af[mi][1], af[mi][2], af[mi][3],
                            b0, b1);
                }
        }
        __syncthreads();
    }

#pragma unroll
    for (int mi = 0; mi < 2; mi++) {
#pragma unroll
        for (int ni = 0; ni < 8; ni++) {
            int row = m0 + wm + (mi << 4) + g;
            int col = n0 + wn + (ni << 3) + (c << 1);
            float b0 = bias[col], b1 = bias[col + 1];
            float x0 = acc[mi][ni][0] + b0, x1 = acc[mi][ni][1] + b1;
            float x2 = acc[mi][ni][2] + b0, x3 = acc[mi][ni][3] + b1;
            if (head_layout) {
                __half* C = (__half*)Cout;
                int b = row >> 10, l = row & 1023, h = col >> 6, d = col & 63;
                size_t off = (((size_t)(b * Hn + h)) << 16) + ((size_t)l << 6) + d;
                *(uint32_t*)(C + off) = packh2(x0, x1);
                int row2 = row + 8;
                int b2 = row2 >> 10, l2 = row2 & 1023;
                size_t off2 = (((size_t)(b2 * Hn + h)) << 16) + ((size_t)l2 << 6) + d;
                *(uint32_t*)(C + off2) = packh2(x2, x3);
            } else {
                float* C = (float*)Cout;
                *(float2*)(C + (size_t)row * 1024 + col) = make_float2(x0, x1);
                *(float2*)(C + (size_t)(row + 8) * 1024 + col) = make_float2(x2, x3);
            }
        }
    }
}

__global__ __launch_bounds__(256, 2) void qkv_gemm_kernel(
    const __half* __restrict__ xq, const __half* __restrict__ xk,
    const __half* __restrict__ xv,
    const __half* __restrict__ wq, const __half* __restrict__ wk,
    const __half* __restrict__ wv,
    const float* __restrict__ bq, const float* __restrict__ bk,
    const float* __restrict__ bv,
    __half* __restrict__ Q, __half* __restrict__ K, __half* __restrict__ V)
{
    if (blockIdx.z == 0)      gemm_body(xq, wq, bq, Q, 1);
    else if (blockIdx.z == 1) gemm_body(xk, wk, bk, K, 1);
    else                      gemm_body(xv, wv, bv, V, 1);
}

__global__ __launch_bounds__(256, 2) void out_gemm_kernel(
    const __half* __restrict__ Y, const __half* __restrict__ wo,
    const float* __restrict__ bo, float* __restrict__ out)
{
    gemm_body(Y, wo, bo, out, 0);
}

// ---------------------------------------------------------------------------
// fp16 tensor-core flash attention with relative-position bias + rel_v buckets.
// grid: (8 q-tiles of 128 rows, 64 bh). 256 threads = 8 warps x 16 rows.
// P stays in registers (S-accumulator fragment == PV A-operand fragment).
// V consumed via ldmatrix.trans (no transpose staging).
// ---------------------------------------------------------------------------
#define QPAD 72

struct __align__(16) AttnSmem {
    __half Qs[128][QPAD];     // SCALE folded
    __half Ks[2][64][QPAD];   // [j][d]   } reused as fp32 scratch [128][68]
    __half Vs[2][64][QPAD];   // [j][d]   } in the epilogue
    float RQs[128][NT];
    float Wb[128][NT];
    float relvs[NT][68];
    float relks[NT][68];
    float wscale[128];
    float linv[128];
};

__device__ __forceinline__ void load_kv_tile(AttnSmem& s, int buf,
    const __half* Kb, const __half* Vb, int j0, int tid)
{
    int j = tid >> 2;
    int ch = (tid & 3) << 4;   // half offset: 0,16,32,48
    const __half* ks = Kb + (size_t)(j0 + j) * 64 + ch;
    const __half* vs = Vb + (size_t)(j0 + j) * 64 + ch;
    cp_async16(&s.Ks[buf][j][ch],     ks);
    cp_async16(&s.Ks[buf][j][ch + 8], ks + 8);
    cp_async16(&s.Vs[buf][j][ch],     vs);
    cp_async16(&s.Vs[buf][j][ch + 8], vs + 8);
}

__global__ __launch_bounds__(256, 2) void attn_kernel(
    const __half* __restrict__ Q, const __half* __restrict__ Kg,
    const __half* __restrict__ Vg, const float* __restrict__ relk,
    const float* __restrict__ relv, __half* __restrict__ Y)
{
    extern __shared__ char smem_raw[];
    AttnSmem& s = *reinterpret_cast<AttnSmem*>(smem_raw);
    int tid = threadIdx.x;
    int warp = tid >> 5, lane = tid & 31;
    int g = lane >> 2, c = lane & 3;
    int r0 = warp * 16 + g;
    int r1 = r0 + 8;
    int lrow = (lane & 7) + ((lane >> 3) & 1) * 8;
    int lcol = (lane >> 4) * 8;
    // trans-ldmatrix (V): row j advances with bit4, col d with bit3
    int vrow = (lane & 7) + (lane >> 4) * 8;
    int vcol = ((lane >> 3) & 1) * 8;

    int bh = blockIdx.y;
    int bx = blockIdx.x;
    int i0 = bx * 128;
    const __half* Qb = Q + ((size_t)bh << 16) + (size_t)i0 * 64;
    const __half* Kb = Kg + ((size_t)bh << 16);
    const __half* Vb = Vg + ((size_t)bh << 16);

    // ---- prologue ----
    load_kv_tile(s, 0, Kb, Vb, 0, tid);
    asm volatile("cp.async.commit_group;\n");
    {
        int r = tid >> 1;
        int seg = (tid & 1) * 32;
        const __half* src = Qb + (size_t)r * 64 + seg;
        __half2 hs = __float2half2_rn(SCALEF);
#pragma unroll
        for (int q = 0; q < 4; q++) {
            uint4 v = *(const uint4*)(src + q * 8);
            __half2* hv = (__half2*)&v;
#pragma unroll
            for (int e = 0; e < 4; e++) hv[e] = __hmul2(hv[e], hs);
            *(uint4*)&s.Qs[r][seg + q * 8] = v;
        }
    }
    for (int idx = tid; idx < NT * 64; idx += 256) {
        s.relvs[idx >> 6][idx & 63] = relv[idx];
        s.relks[idx >> 6][idx & 63] = relk[idx];
    }
    for (int idx = tid; idx < 128 * NT; idx += 256)
        s.Wb[idx / NT][idx % NT] = 0.f;
    __syncthreads();

    // ---- RQs[i][t] = Qs(i,:) . relk(t,:) ----
    {
        int i = tid >> 1;
        int h = (tid & 1) * 32;
        float qf[32];
#pragma unroll
        for (int dd = 0; dd < 32; dd++) qf[dd] = __half2float(s.Qs[i][h + dd]);
        for (int t = 0; t < NT; t++) {
            float p = 0.f;
#pragma unroll
            for (int dd = 0; dd < 32; dd++) p += qf[dd] * s.relks[t][h + dd];
            p += __shfl_xor_sync(0xffffffffu, p, 1);
            if ((tid & 1) == 0) s.RQs[i][t] = p;
        }
    }

    float m0s = -1e30f, m1s = -1e30f;
    float l0 = 0.f, l1 = 0.f;
    float b0a = 0.f, b0b = 0.f, b32a = 0.f, b32b = 0.f;
    float mW0 = -1e30f, mW1 = -1e30f;
    float acc[8][4];
#pragma unroll
    for (int ni = 0; ni < 8; ni++)
#pragma unroll
        for (int q = 0; q < 4; q++) acc[ni][q] = 0.f;

    int ig0 = i0 + r0, ig1 = i0 + r1;

    for (int jt = 0; jt < 16; jt++) {
        int buf = jt & 1;
        int j0 = jt * 64;
        __syncthreads();   // consumers of buf^1 done
        if (jt + 1 < 16) {
            load_kv_tile(s, buf ^ 1, Kb, Vb, j0 + 64, tid);
            asm volatile("cp.async.commit_group;\n");
            asm volatile("cp.async.wait_group 1;\n");
        } else {
            asm volatile("cp.async.wait_group 0;\n");
        }
        __syncthreads();   // K/V[buf] visible

        int dj = jt - 2 * bx;
        bool far_left  = (dj <= -2);
        bool far_right = (dj >= 3);
        bool diag = !(far_left || far_right);

        // ---- S = Q K^T ----
        float sf[8][4];
#pragma unroll
        for (int ni = 0; ni < 8; ni++)
#pragma unroll
            for (int q = 0; q < 4; q++) sf[ni][q] = 0.f;
#pragma unroll
        for (int ks = 0; ks < 4; ks++) {
            int kc = ks * 16 + lcol;
            uint32_t a0, a1, a2, a3;
            ldsm4(a0, a1, a2, a3, &s.Qs[warp * 16 + lrow][kc]);
#pragma unroll
            for (int p = 0; p < 4; p++) {
                uint32_t b0, b1, b2, b3;
                ldsm4(b0, b1, b2, b3, &s.Ks[buf][p * 16 + lrow][kc]);
                mma_f16(sf[2 * p],     a0, a1, a2, a3, b0, b2);
                mma_f16(sf[2 * p + 1], a0, a1, a2, a3, b1, b3);
            }
        }

        // ---- bias ----
        if (!diag) {
            int tf = far_left ? 0 : 32;
            float rq0 = s.RQs[r0][tf], rq1 = s.RQs[r1][tf];
#pragma unroll
            for (int ni = 0; ni < 8; ni++) {
                sf[ni][0] += rq0; sf[ni][1] += rq0;
                sf[ni][2] += rq1; sf[ni][3] += rq1;
            }
        } else {
#pragma unroll
            for (int ni = 0; ni < 8; ni++) {
#pragma unroll
                for (int e = 0; e < 2; e++) {
                    int j = j0 + ni * 8 + 2 * c + e;
                    int d0 = j - ig0; d0 = d0 < -CLIPV ? -CLIPV : (d0 > CLIPV ? CLIPV : d0);
                    int d1 = j - ig1; d1 = d1 < -CLIPV ? -CLIPV : (d1 > CLIPV ? CLIPV : d1);
                    sf[ni][e]     += s.RQs[r0][d0 + CLIPV];
                    sf[ni][2 + e] += s.RQs[r1][d1 + CLIPV];
                }
            }
        }

        // ---- online softmax ----
        float mt0 = -1e30f, mt1 = -1e30f;
#pragma unroll
        for (int ni = 0; ni < 8; ni++) {
            mt0 = fmaxf(mt0, fmaxf(sf[ni][0], sf[ni][1]));
            mt1 = fmaxf(mt1, fmaxf(sf[ni][2], sf[ni][3]));
        }
        mt0 = fmaxf(mt0, __shfl_xor_sync(0xffffffffu, mt0, 1));
        mt0 = fmaxf(mt0, __shfl_xor_sync(0xffffffffu, mt0, 2));
        mt1 = fmaxf(mt1, __shfl_xor_sync(0xffffffffu, mt1, 1));
        mt1 = fmaxf(mt1, __shfl_xor_sync(0xffffffffu, mt1, 2));
        float mn0 = fmaxf(m0s, mt0), mn1 = fmaxf(m1s, mt1);
        float al0 = __expf(m0s - mn0), al1 = __expf(m1s - mn1);

        float rs0 = 0.f, rs1 = 0.f;
#pragma unroll
        for (int ni = 0; ni < 8; ni++) {
            sf[ni][0] = __expf(sf[ni][0] - mn0);
            sf[ni][1] = __expf(sf[ni][1] - mn0);
            sf[ni][2] = __expf(sf[ni][2] - mn1);
            sf[ni][3] = __expf(sf[ni][3] - mn1);
            rs0 += sf[ni][0] + sf[ni][1];
            rs1 += sf[ni][2] + sf[ni][3];
        }
        rs0 += __shfl_xor_sync(0xffffffffu, rs0, 1);
        rs0 += __shfl_xor_sync(0xffffffffu, rs0, 2);
        rs1 += __shfl_xor_sync(0xffffffffu, rs1, 1);
        rs1 += __shfl_xor_sync(0xffffffffu, rs1, 2);
        l0 = l0 * al0 + rs0;
        l1 = l1 * al1 + rs1;

        // ---- bucket weights ----
        if (far_left) {
            b0a = b0a * al0 + rs0;  b0b = b0b * al1 + rs1;
            b32a *= al0;            b32b *= al1;
        } else if (far_right) {
            b32a = b32a * al0 + rs0; b32b = b32b * al1 + rs1;
            b0a *= al0;              b0b *= al1;
        } else {
            float c0a = 0.f, c0b = 0.f, c32a = 0.f, c32b = 0.f;
#pragma unroll
            for (int ni = 0; ni < 8; ni++) {
#pragma unroll
                for (int e = 0; e < 2; e++) {
                    int j = j0 + ni * 8 + 2 * c + e;
                    int d0 = j - ig0;
                    int d1 = j - ig1;
                    if (d0 <= -CLIPV) c0a += sf[ni][e];
                    else if (d0 >= CLIPV) c32a += sf[ni][e];
                    if (d1 <= -CLIPV) c0b += sf[ni][2 + e];
                    else if (d1 >= CLIPV) c32b += sf[ni][2 + e];
                }
            }
            c0a += __shfl_xor_sync(0xffffffffu, c0a, 1);
            c0a += __shfl_xor_sync(0xffffffffu, c0a, 2);
            c0b += __shfl_xor_sync(0xffffffffu, c0b, 1);
            c0b += __shfl_xor_sync(0xffffffffu, c0b, 2);
            c32a += __shfl_xor_sync(0xffffffffu, c32a, 1);
            c32a += __shfl_xor_sync(0xffffffffu, c32a, 2);
            c32b += __shfl_xor_sync(0xffffffffu, c32b, 1);
            c32b += __shfl_xor_sync(0xffffffffu, c32b, 2);
            b0a = b0a * al0 + c0a;   b0b = b0b * al1 + c0b;
            b32a = b32a * al0 + c32a; b32b = b32b * al1 + c32b;
        }

        if (diag && c == 0) {
            s.wscale[r0] = __expf(mW0 - mn0);
            s.wscale[r1] = __expf(mW1 - mn1);
        }
        if (diag) { mW0 = mn0; mW1 = mn1; }
        m0s = mn0; m1s = mn1;

        // ---- pack P into PV A-fragments (registers; no smem round-trip) ----
        uint32_t ap[4][4];
#pragma unroll
        for (int kk = 0; kk < 4; kk++) {
            ap[kk][0] = packh2(sf[2 * kk][0],     sf[2 * kk][1]);
            ap[kk][1] = packh2(sf[2 * kk][2],     sf[2 * kk][3]);
            ap[kk][2] = packh2(sf[2 * kk + 1][0], sf[2 * kk + 1][1]);
            ap[kk][3] = packh2(sf[2 * kk + 1][2], sf[2 * kk + 1][3]);
        }

        if (diag) {
            __syncthreads();   // wscale visible; prior atomics done
            for (int idx = tid; idx < 128 * 31; idx += 256) {
                int i = idx / 31, t = idx % 31 + 1;
                s.Wb[i][t] *= s.wscale[i];
            }
            __syncthreads();
#pragma unroll
            for (int ni = 0; ni < 8; ni++) {
#pragma unroll
                for (int e = 0; e < 2; e++) {
                    int j = j0 + ni * 8 + 2 * c + e;
                    int d0 = j - ig0;
                    int d1 = j - ig1;
                    if (d0 > -CLIPV && d0 < CLIPV)
                        atomicAdd(&s.Wb[r0][d0 + CLIPV], sf[ni][e]);
                    if (d1 > -CLIPV && d1 < CLIPV)
                        atomicAdd(&s.Wb[r1][d1 + CLIPV], sf[ni][2 + e]);
                }
            }
        }

        // ---- acc = acc*alpha + P @ V  (V via ldmatrix.trans) ----
#pragma unroll
        for (int ni = 0; ni < 8; ni++) {
            acc[ni][0] *= al0; acc[ni][1] *= al0;
            acc[ni][2] *= al1; acc[ni][3] *= al1;
        }
#pragma unroll
        for (int kk = 0; kk < 4; kk++) {
#pragma unroll
            for (int p = 0; p < 4; p++) {
                uint32_t b0, b1, b2, b3;
                ldsm4t(b0, b1, b2, b3, &s.Vs[buf][kk * 16 + vrow][p * 16 + vcol]);
                mma_f16(acc[2 * p],     ap[kk][0], ap[kk][1], ap[kk][2], ap[kk][3], b0, b2);
                mma_f16(acc[2 * p + 1], ap[kk][0], ap[kk][1], ap[kk][2], ap[kk][3], b1, b3);
            }
        }
    }

    // ---- epilogue ----
    if (c == 0) {
        s.Wb[r0][0] = b0a;  s.Wb[r0][32] = b32a;
        s.Wb[r1][0] = b0b;  s.Wb[r1][32] = b32b;
        s.wscale[r0] = __expf(mW0 - m0s);
        s.wscale[r1] = __expf(mW1 - m1s);
        s.linv[r0] = 1.f / l0;
        s.linv[r1] = 1.f / l1;
    }
    __syncthreads();

    // rel_v contribution: scr[i][d] = sum_t W'[i][t] * relv[t][d]
    float* scr = (float*)&s.Ks[0][0][0];   // 128*68 floats, overlays Ks+Vs
    {
        int i = tid >> 1;
        int h = (tid & 1) * 32;
        float ws = s.wscale[i];
        float sc[32];
#pragma unroll
        for (int d = 0; d < 32; d++) sc[d] = 0.f;
        for (int t = 0; t < NT; t++) {
            float w = s.Wb[i][t];
            if (t != 0 && t != 32) w *= ws;
#pragma unroll
            for (int d = 0; d < 32; d++)
                sc[d] += w * s.relvs[t][h + d];
        }
#pragma unroll
        for (int d = 0; d < 32; d++) scr[i * 68 + h + d] = sc[d];
    }
    __syncthreads();

    {
        float li0 = s.linv[r0], li1 = s.linv[r1];
        int bb = bh >> 4, hh = bh & 15;
        __half* y0 = Y + ((size_t)(bb * 1024 + i0 + r0)) * 1024 + hh * 64;
        __half* y1 = Y + ((size_t)(bb * 1024 + i0 + r1)) * 1024 + hh * 64;
#pragma unroll
        for (int ni = 0; ni < 8; ni++) {
            int col = ni * 8 + 2 * c;
            *(uint32_t*)(y0 + col) = packh2((acc[ni][0] + scr[r0 * 68 + col]) * li0,
                                            (acc[ni][1] + scr[r0 * 68 + col + 1]) * li0);
            *(uint32_t*)(y1 + col) = packh2((acc[ni][2] + scr[r1 * 68 + col]) * li1,
                                            (acc[ni][3] + scr[r1 * 68 + col + 1]) * li1);
        }
    }
}

// ---------------------------------------------------------------------------

extern "C" void kernel_launch(void* const* d_in, const int* in_sizes, int n_in,
                              void* d_out, int out_size)
{
    const float* query = (const float*)d_in[0];
    const float* key   = (const float*)d_in[1];
    const float* value = (const float*)d_in[2];
    const float* wq = (const float*)d_in[3];
    const float* bq = (const float*)d_in[4];
    const float* wk = (const float*)d_in[5];
    const float* bk = (const float*)d_in[6];
    const float* wv = (const float*)d_in[7];
    const float* bv = (const float*)d_in[8];
    const float* wo = (const float*)d_in[9];
    const float* bo = (const float*)d_in[10];
    const float* relk = (const float*)d_in[11];
    const float* relv = (const float*)d_in[12];
    float* out = (float*)d_out;

    __half *Qp, *Kp, *Vp, *Yp, *Xq, *Xk, *Xv, *Wq, *Wk, *Wv, *Wo;
    cudaGetSymbolAddress((void**)&Qp, gQ);
    cudaGetSymbolAddress((void**)&Kp, gK);
    cudaGetSymbolAddress((void**)&Vp, gV);
    cudaGetSymbolAddress((void**)&Yp, gY);
    cudaGetSymbolAddress((void**)&Xq, gXq);
    cudaGetSymbolAddress((void**)&Xk, gXk);
    cudaGetSymbolAddress((void**)&Xv, gXv);
    cudaGetSymbolAddress((void**)&Wq, gWq);
    cudaGetSymbolAddress((void**)&Wk, gWk);
    cudaGetSymbolAddress((void**)&Wv, gWv);
    cudaGetSymbolAddress((void**)&Wo, gWo);

    convert7_kernel<<<dim3(512, 7), 256>>>(query, key, value, wq, wk, wv, wo,
                                           Xq, Xk, Xv, Wq, Wk, Wv, Wo);

    dim3 gqkv(8, 32, 3);
    qkv_gemm_kernel<<<gqkv, 256>>>(Xq, Xk, Xv, Wq, Wk, Wv,
                                   bq, bk, bv, Qp, Kp, Vp);

    cudaFuncSetAttribute(attn_kernel, cudaFuncAttributeMaxDynamicSharedMemorySize,
                         (int)sizeof(AttnSmem));
    attn_kernel<<<dim3(8, 64), 256, sizeof(AttnSmem)>>>(Qp, Kp, Vp, relk, relv, Yp);

    out_gemm_kernel<<<dim3(8, 32), 256>>>(Yp, Wo, bo, out);
}

// round 7
// speedup vs baseline: 7.8022x; 1.0465x over previous
#include <cuda_runtime.h>
#include <cuda_fp16.h>
#include <math.h>
#include <cstdint>

// Problem constants
#define Bn  4
#define Ln  1024
#define En  1024
#define Hn  16
#define HDn 64
#define NT  33          // 2*CLIP+1
#define CLIPV 16
#define SCALEF 0.125f   // 1/sqrt(64)

// Scratch (device globals; no allocation allowed)
__device__ __half gQ[Bn*Hn*Ln*HDn];   // [b][h][l][d] fp16
__device__ __half gK[Bn*Hn*Ln*HDn];
__device__ __half gV[Bn*Hn*Ln*HDn];
__device__ __half gY[Bn*Ln*En];       // [b][l][e] fp16
__device__ __half gXq[Bn*Ln*En];      // fp16 inputs
__device__ __half gXk[Bn*Ln*En];
__device__ __half gXv[Bn*Ln*En];
__device__ __half gWq[En*En];         // fp16 weights
__device__ __half gWk[En*En];
__device__ __half gWv[En*En];
__device__ __half gWo[En*En];

// ---------------------------------------------------------------------------
// helpers
// ---------------------------------------------------------------------------
__device__ __forceinline__ uint32_t packh2(float x, float y) {
    __half2 h = __floats2half2_rn(x, y);
    return *reinterpret_cast<uint32_t*>(&h);
}

__device__ __forceinline__ void cp_async16(void* dst, const void* src) {
    uint32_t d = (uint32_t)__cvta_generic_to_shared(dst);
    asm volatile("cp.async.cg.shared.global [%0], [%1], 16;\n" :: "r"(d), "l"(src));
}

__device__ __forceinline__ void ldsm4(uint32_t& r0, uint32_t& r1,
                                      uint32_t& r2, uint32_t& r3, const void* p) {
    uint32_t a = (uint32_t)__cvta_generic_to_shared(p);
    asm volatile("ldmatrix.sync.aligned.m8n8.x4.shared.b16 {%0,%1,%2,%3}, [%4];"
                 : "=r"(r0), "=r"(r1), "=r"(r2), "=r"(r3) : "r"(a));
}

__device__ __forceinline__ void ldsm4t(uint32_t& r0, uint32_t& r1,
                                       uint32_t& r2, uint32_t& r3, const void* p) {
    uint32_t a = (uint32_t)__cvta_generic_to_shared(p);
    asm volatile("ldmatrix.sync.aligned.m8n8.x4.trans.shared.b16 {%0,%1,%2,%3}, [%4];"
                 : "=r"(r0), "=r"(r1), "=r"(r2), "=r"(r3) : "r"(a));
}

__device__ __forceinline__ void mma_f16(float* d,
    uint32_t a0, uint32_t a1, uint32_t a2, uint32_t a3,
    uint32_t b0, uint32_t b1)
{
    asm volatile(
        "mma.sync.aligned.m16n8k16.row.col.f32.f16.f16.f32 "
        "{%0,%1,%2,%3}, {%4,%5,%6,%7}, {%8,%9}, {%0,%1,%2,%3};"
        : "+f"(d[0]), "+f"(d[1]), "+f"(d[2]), "+f"(d[3])
        : "r"(a0), "r"(a1), "r"(a2), "r"(a3), "r"(b0), "r"(b1));
}

// ---------------------------------------------------------------------------
// fp32 -> fp16 conversion of 3 inputs + 4 weights.
// ---------------------------------------------------------------------------
__global__ __launch_bounds__(256) void convert7_kernel(
    const float* __restrict__ xq, const float* __restrict__ xk,
    const float* __restrict__ xv,
    const float* __restrict__ wq, const float* __restrict__ wk,
    const float* __restrict__ wv, const float* __restrict__ wo,
    __half* __restrict__ oxq, __half* __restrict__ oxk, __half* __restrict__ oxv,
    __half* __restrict__ owq, __half* __restrict__ owk,
    __half* __restrict__ owv, __half* __restrict__ owo)
{
    int t = blockIdx.y;
    const float* src; __half* dst; int n8;
    switch (t) {
        case 0: src = xq; dst = oxq; n8 = (Bn*Ln*En)/8; break;
        case 1: src = xk; dst = oxk; n8 = (Bn*Ln*En)/8; break;
        case 2: src = xv; dst = oxv; n8 = (Bn*Ln*En)/8; break;
        case 3: src = wq; dst = owq; n8 = (En*En)/8; break;
        case 4: src = wk; dst = owk; n8 = (En*En)/8; break;
        case 5: src = wv; dst = owv; n8 = (En*En)/8; break;
        default: src = wo; dst = owo; n8 = (En*En)/8; break;
    }
    int stride = gridDim.x * 256;
    for (int i = blockIdx.x * 256 + threadIdx.x; i < n8; i += stride) {
        float4 a = ((const float4*)src)[2*i];
        float4 b = ((const float4*)src)[2*i + 1];
        uint4 o;
        o.x = packh2(a.x, a.y); o.y = packh2(a.z, a.w);
        o.z = packh2(b.x, b.y); o.w = packh2(b.z, b.w);
        ((uint4*)dst)[i] = o;
    }
}

// ---------------------------------------------------------------------------
// fp16 tensor-core GEMM: C = A(4096x1024) @ W(1024x1024)^T + bias.
// CTA 128x128, BK=32, 3-stage cp.async pipeline, ONE syncthreads per k-iter.
// 8 warps (4m x 2n), warp tile 32x64, mma m16n8k16 fp16 -> fp32.
// ---------------------------------------------------------------------------
struct __align__(16) GemmSmem {
    __half As[3][128][40];
    __half Bs[3][128][40];
};

__device__ __forceinline__ void gemm_body(
    const __half* __restrict__ A, const __half* __restrict__ W,
    const float* __restrict__ bias, void* __restrict__ Cout, int head_layout)
{
    extern __shared__ char smem_raw[];
    GemmSmem& s = *reinterpret_cast<GemmSmem*>(smem_raw);
    const int Kd = 1024;

    int tid  = threadIdx.x;
    int warp = tid >> 5, lane = tid & 31;
    int wm = (warp >> 1) << 5;
    int wn = (warp & 1) << 6;
    int g = lane >> 2, c = lane & 3;
    int m0 = blockIdx.y << 7, n0 = blockIdx.x << 7;

    int lrow = (lane & 7) + ((lane >> 3) & 1) * 8;
    int lcol = (lane >> 4) * 8;

    int ra   = tid >> 1;
    int colh = (tid & 1) << 4;
    const __half* Ag = A + (size_t)(m0 + ra) * Kd + colh;
    const __half* Wg = W + (size_t)(n0 + ra) * Kd + colh;

    float acc[2][8][4];
#pragma unroll
    for (int mi = 0; mi < 2; mi++)
#pragma unroll
        for (int ni = 0; ni < 8; ni++)
#pragma unroll
            for (int q = 0; q < 4; q++) acc[mi][ni][q] = 0.f;

    // prologue: stages 0 and 1 in flight
#pragma unroll
    for (int pt = 0; pt < 2; pt++) {
        int k0 = pt << 5;
        cp_async16(&s.As[pt][ra][colh],     Ag + k0);
        cp_async16(&s.As[pt][ra][colh + 8], Ag + k0 + 8);
        cp_async16(&s.Bs[pt][ra][colh],     Wg + k0);
        cp_async16(&s.Bs[pt][ra][colh + 8], Wg + k0 + 8);
        asm volatile("cp.async.commit_group;\n");
    }

    const int NITER = Kd / 32;   // 32
    int buf = 0, nbuf = 2;
    for (int t = 0; t < NITER; t++) {
        asm volatile("cp.async.wait_group 1;\n");   // group t complete
        __syncthreads();                             // data visible; compute t-1 done
        if (t + 2 < NITER) {
            int k0 = (t + 2) << 5;
            cp_async16(&s.As[nbuf][ra][colh],     Ag + k0);
            cp_async16(&s.As[nbuf][ra][colh + 8], Ag + k0 + 8);
            cp_async16(&s.Bs[nbuf][ra][colh],     Wg + k0);
            cp_async16(&s.Bs[nbuf][ra][colh + 8], Wg + k0 + 8);
        }
        asm volatile("cp.async.commit_group;\n");

#pragma unroll
        for (int ks = 0; ks < 2; ks++) {
            int kc = ks * 16 + lcol;
            uint32_t af[2][4], bf[4][4];
#pragma unroll
            for (int mi = 0; mi < 2; mi++)
                ldsm4(af[mi][0], af[mi][1], af[mi][2], af[mi][3],
                      &s.As[buf][wm + mi * 16 + lrow][kc]);
#pragma unroll
            for (int p = 0; p < 4; p++)
                ldsm4(bf[p][0], bf[p][1], bf[p][2], bf[p][3],
                      &s.Bs[buf][wn + p * 16 + lrow][kc]);
#pragma unroll
            for (int mi = 0; mi < 2; mi++)
#pragma unroll
                for (int ni = 0; ni < 8; ni++) {
                    int p = ni >> 1;
                    uint32_t b0 = (ni & 1) ? bf[p][1] : bf[p][0];
                    uint32_t b1 = (ni & 1) ? bf[p][3] : bf[p][2];
                    mma_f16(acc[mi][ni], af[mi][0], af[mi][1], af[mi][2], af[mi][3],
                            b0, b1);
                }
        }
        buf = buf == 2 ? 0 : buf + 1;
        nbuf = nbuf == 2 ? 0 : nbuf + 1;
    }

#pragma unroll
    for (int mi = 0; mi < 2; mi++) {
#pragma unroll
        for (int ni = 0; ni < 8; ni++) {
            int row = m0 + wm + (mi << 4) + g;
            int col = n0 + wn + (ni << 3) + (c << 1);
            float b0 = bias[col], b1 = bias[col + 1];
            float x0 = acc[mi][ni][0] + b0, x1 = acc[mi][ni][1] + b1;
            float x2 = acc[mi][ni][2] + b0, x3 = acc[mi][ni][3] + b1;
            if (head_layout) {
                __half* C = (__half*)Cout;
                int b = row >> 10, l = row & 1023, h = col >> 6, d = col & 63;
                size_t off = (((size_t)(b * Hn + h)) << 16) + ((size_t)l << 6) + d;
                *(uint32_t*)(C + off) = packh2(x0, x1);
                int row2 = row + 8;
                int b2 = row2 >> 10, l2 = row2 & 1023;
                size_t off2 = (((size_t)(b2 * Hn + h)) << 16) + ((size_t)l2 << 6) + d;
                *(uint32_t*)(C + off2) = packh2(x2, x3);
            } else {
                float* C = (float*)Cout;
                *(float2*)(C + (size_t)row * 1024 + col) = make_float2(x0, x1);
                *(float2*)(C + (size_t)(row + 8) * 1024 + col) = make_float2(x2, x3);
            }
        }
    }
}

__global__ __launch_bounds__(256, 2) void qkv_gemm_kernel(
    const __half* __restrict__ xq, const __half* __restrict__ xk,
    const __half* __restrict__ xv,
    const __half* __restrict__ wq, const __half* __restrict__ wk,
    const __half* __restrict__ wv,
    const float* __restrict__ bq, const float* __restrict__ bk,
    const float* __restrict__ bv,
    __half* __restrict__ Q, __half* __restrict__ K, __half* __restrict__ V)
{
    if (blockIdx.z == 0)      gemm_body(xq, wq, bq, Q, 1);
    else if (blockIdx.z == 1) gemm_body(xk, wk, bk, K, 1);
    else                      gemm_body(xv, wv, bv, V, 1);
}

__global__ __launch_bounds__(256, 2) void out_gemm_kernel(
    const __half* __restrict__ Y, const __half* __restrict__ wo,
    const float* __restrict__ bo, float* __restrict__ out)
{
    gemm_body(Y, wo, bo, out, 0);
}

// ---------------------------------------------------------------------------
// fp16 tensor-core flash attention with relative-position bias + rel_v buckets.
// grid: (8 q-tiles of 128 rows, 64 bh). 256 threads = 8 warps x 16 rows.
// One syncthreads per j-tile (2-stage cp.async, issue-after-sync).
// ---------------------------------------------------------------------------
#define QPAD 72

struct __align__(16) AttnSmem {
    __half Qs[128][QPAD];     // SCALE folded
    __half Ks[2][64][QPAD];   // [j][d]   } reused as fp32 scratch [128][68]
    __half Vs[2][64][QPAD];   // [j][d]   } in the epilogue
    float RQs[128][NT];
    float Wb[128][NT];
    float relvs[NT][68];
    float relks[NT][68];
    float wscale[128];
    float linv[128];
};

__device__ __forceinline__ void load_kv_tile(AttnSmem& s, int buf,
    const __half* Kb, const __half* Vb, int j0, int tid)
{
    int j = tid >> 2;
    int ch = (tid & 3) << 4;   // half offset: 0,16,32,48
    const __half* ks = Kb + (size_t)(j0 + j) * 64 + ch;
    const __half* vs = Vb + (size_t)(j0 + j) * 64 + ch;
    cp_async16(&s.Ks[buf][j][ch],     ks);
    cp_async16(&s.Ks[buf][j][ch + 8], ks + 8);
    cp_async16(&s.Vs[buf][j][ch],     vs);
    cp_async16(&s.Vs[buf][j][ch + 8], vs + 8);
}

__global__ __launch_bounds__(256, 2) void attn_kernel(
    const __half* __restrict__ Q, const __half* __restrict__ Kg,
    const __half* __restrict__ Vg, const float* __restrict__ relk,
    const float* __restrict__ relv, __half* __restrict__ Y)
{
    extern __shared__ char smem_raw[];
    AttnSmem& s = *reinterpret_cast<AttnSmem*>(smem_raw);
    int tid = threadIdx.x;
    int warp = tid >> 5, lane = tid & 31;
    int g = lane >> 2, c = lane & 3;
    int r0 = warp * 16 + g;
    int r1 = r0 + 8;
    int lrow = (lane & 7) + ((lane >> 3) & 1) * 8;
    int lcol = (lane >> 4) * 8;
    int vrow = (lane & 7) + (lane >> 4) * 8;
    int vcol = ((lane >> 3) & 1) * 8;

    int bh = blockIdx.y;
    int bx = blockIdx.x;
    int i0 = bx * 128;
    const __half* Qb = Q + ((size_t)bh << 16) + (size_t)i0 * 64;
    const __half* Kb = Kg + ((size_t)bh << 16);
    const __half* Vb = Vg + ((size_t)bh << 16);

    // ---- prologue ----
    load_kv_tile(s, 0, Kb, Vb, 0, tid);
    asm volatile("cp.async.commit_group;\n");
    {
        int r = tid >> 1;
        int seg = (tid & 1) * 32;
        const __half* src = Qb + (size_t)r * 64 + seg;
        __half2 hs = __float2half2_rn(SCALEF);
#pragma unroll
        for (int q = 0; q < 4; q++) {
            uint4 v = *(const uint4*)(src + q * 8);
            __half2* hv = (__half2*)&v;
#pragma unroll
            for (int e = 0; e < 4; e++) hv[e] = __hmul2(hv[e], hs);
            *(uint4*)&s.Qs[r][seg + q * 8] = v;
        }
    }
    for (int idx = tid; idx < NT * 64; idx += 256) {
        s.relvs[idx >> 6][idx & 63] = relv[idx];
        s.relks[idx >> 6][idx & 63] = relk[idx];
    }
    for (int idx = tid; idx < 128 * NT; idx += 256)
        s.Wb[idx / NT][idx % NT] = 0.f;
    __syncthreads();

    // ---- RQs[i][t] = Qs(i,:) . relk(t,:) ----
    {
        int i = tid >> 1;
        int h = (tid & 1) * 32;
        float qf[32];
#pragma unroll
        for (int dd = 0; dd < 32; dd++) qf[dd] = __half2float(s.Qs[i][h + dd]);
        for (int t = 0; t < NT; t++) {
            float p = 0.f;
#pragma unroll
            for (int dd = 0; dd < 32; dd++) p += qf[dd] * s.relks[t][h + dd];
            p += __shfl_xor_sync(0xffffffffu, p, 1);
            if ((tid & 1) == 0) s.RQs[i][t] = p;
        }
    }

    float m0s = -1e30f, m1s = -1e30f;
    float l0 = 0.f, l1 = 0.f;
    float b0a = 0.f, b0b = 0.f, b32a = 0.f, b32b = 0.f;
    float mW0 = -1e30f, mW1 = -1e30f;
    float acc[8][4];
#pragma unroll
    for (int ni = 0; ni < 8; ni++)
#pragma unroll
        for (int q = 0; q < 4; q++) acc[ni][q] = 0.f;

    int ig0 = i0 + r0, ig1 = i0 + r1;

    for (int jt = 0; jt < 16; jt++) {
        int buf = jt & 1;
        int j0 = jt * 64;
        asm volatile("cp.async.wait_group 0;\n");   // tile jt loaded
        __syncthreads();                             // visible; compute jt-1 done
        if (jt + 1 < 16)
            load_kv_tile(s, buf ^ 1, Kb, Vb, j0 + 64, tid);
        asm volatile("cp.async.commit_group;\n");

        int dj = jt - 2 * bx;
        bool far_left  = (dj <= -2);
        bool far_right = (dj >= 3);
        bool diag = !(far_left || far_right);

        // ---- S = Q K^T ----
        float sf[8][4];
#pragma unroll
        for (int ni = 0; ni < 8; ni++)
#pragma unroll
            for (int q = 0; q < 4; q++) sf[ni][q] = 0.f;
#pragma unroll
        for (int ks = 0; ks < 4; ks++) {
            int kc = ks * 16 + lcol;
            uint32_t a0, a1, a2, a3;
            ldsm4(a0, a1, a2, a3, &s.Qs[warp * 16 + lrow][kc]);
#pragma unroll
            for (int p = 0; p < 4; p++) {
                uint32_t b0, b1, b2, b3;
                ldsm4(b0, b1, b2, b3, &s.Ks[buf][p * 16 + lrow][kc]);
                mma_f16(sf[2 * p],     a0, a1, a2, a3, b0, b2);
                mma_f16(sf[2 * p + 1], a0, a1, a2, a3, b1, b3);
            }
        }

        // ---- bias ----
        if (!diag) {
            int tf = far_left ? 0 : 32;
            float rq0 = s.RQs[r0][tf], rq1 = s.RQs[r1][tf];
#pragma unroll
            for (int ni = 0; ni < 8; ni++) {
                sf[ni][0] += rq0; sf[ni][1] += rq0;
                sf[ni][2] += rq1; sf[ni][3] += rq1;
            }
        } else {
#pragma unroll
            for (int ni = 0; ni < 8; ni++) {
#pragma unroll
                for (int e = 0; e < 2; e++) {
                    int j = j0 + ni * 8 + 2 * c + e;
                    int d0 = j - ig0; d0 = d0 < -CLIPV ? -CLIPV : (d0 > CLIPV ? CLIPV : d0);
                    int d1 = j - ig1; d1 = d1 < -CLIPV ? -CLIPV : (d1 > CLIPV ? CLIPV : d1);
                    sf[ni][e]     += s.RQs[r0][d0 + CLIPV];
                    sf[ni][2 + e] += s.RQs[r1][d1 + CLIPV];
                }
            }
        }

        // ---- online softmax ----
        float mt0 = -1e30f, mt1 = -1e30f;
#pragma unroll
        for (int ni = 0; ni < 8; ni++) {
            mt0 = fmaxf(mt0, fmaxf(sf[ni][0], sf[ni][1]));
            mt1 = fmaxf(mt1, fmaxf(sf[ni][2], sf[ni][3]));
        }
        mt0 = fmaxf(mt0, __shfl_xor_sync(0xffffffffu, mt0, 1));
        mt0 = fmaxf(mt0, __shfl_xor_sync(0xffffffffu, mt0, 2));
        mt1 = fmaxf(mt1, __shfl_xor_sync(0xffffffffu, mt1, 1));
        mt1 = fmaxf(mt1, __shfl_xor_sync(0xffffffffu, mt1, 2));
        float mn0 = fmaxf(m0s, mt0), mn1 = fmaxf(m1s, mt1);
        float al0 = __expf(m0s - mn0), al1 = __expf(m1s - mn1);

        float rs0 = 0.f, rs1 = 0.f;
#pragma unroll
        for (int ni = 0; ni < 8; ni++) {
            sf[ni][0] = __expf(sf[ni][0] - mn0);
            sf[ni][1] = __expf(sf[ni][1] - mn0);
            sf[ni][2] = __expf(sf[ni][2] - mn1);
            sf[ni][3] = __expf(sf[ni][3] - mn1);
            rs0 += sf[ni][0] + sf[ni][1];
            rs1 += sf[ni][2] + sf[ni][3];
        }
        rs0 += __shfl_xor_sync(0xffffffffu, rs0, 1);
        rs0 += __shfl_xor_sync(0xffffffffu, rs0, 2);
        rs1 += __shfl_xor_sync(0xffffffffu, rs1, 1);
        rs1 += __shfl_xor_sync(0xffffffffu, rs1, 2);
        l0 = l0 * al0 + rs0;
        l1 = l1 * al1 + rs1;

        // ---- bucket weights ----
        if (far_left) {
            b0a = b0a * al0 + rs0;  b0b = b0b * al1 + rs1;
            b32a *= al0;            b32b *= al1;
        } else if (far_right) {
            b32a = b32a * al0 + rs0; b32b = b32b * al1 + rs1;
            b0a *= al0;              b0b *= al1;
        } else {
            float c0a = 0.f, c0b = 0.f, c32a = 0.f, c32b = 0.f;
#pragma unroll
            for (int ni = 0; ni < 8; ni++) {
#pragma unroll
                for (int e = 0; e < 2; e++) {
                    int j = j0 + ni * 8 + 2 * c + e;
                    int d0 = j - ig0;
                    int d1 = j - ig1;
                    if (d0 <= -CLIPV) c0a += sf[ni][e];
                    else if (d0 >= CLIPV) c32a += sf[ni][e];
                    if (d1 <= -CLIPV) c0b += sf[ni][2 + e];
                    else if (d1 >= CLIPV) c32b += sf[ni][2 + e];
                }
            }
            c0a += __shfl_xor_sync(0xffffffffu, c0a, 1);
            c0a += __shfl_xor_sync(0xffffffffu, c0a, 2);
            c0b += __shfl_xor_sync(0xffffffffu, c0b, 1);
            c0b += __shfl_xor_sync(0xffffffffu, c0b, 2);
            c32a += __shfl_xor_sync(0xffffffffu, c32a, 1);
            c32a += __shfl_xor_sync(0xffffffffu, c32a, 2);
            c32b += __shfl_xor_sync(0xffffffffu, c32b, 1);
            c32b += __shfl_xor_sync(0xffffffffu, c32b, 2);
            b0a = b0a * al0 + c0a;   b0b = b0b * al1 + c0b;
            b32a = b32a * al0 + c32a; b32b = b32b * al1 + c32b;
        }

        if (diag && c == 0) {
            s.wscale[r0] = __expf(mW0 - mn0);
            s.wscale[r1] = __expf(mW1 - mn1);
        }
        if (diag) { mW0 = mn0; mW1 = mn1; }
        m0s = mn0; m1s = mn1;

        // ---- pack P into PV A-fragments (registers) ----
        uint32_t ap[4][4];
#pragma unroll
        for (int kk = 0; kk < 4; kk++) {
            ap[kk][0] = packh2(sf[2 * kk][0],     sf[2 * kk][1]);
            ap[kk][1] = packh2(sf[2 * kk][2],     sf[2 * kk][3]);
            ap[kk][2] = packh2(sf[2 * kk + 1][0], sf[2 * kk + 1][1]);
            ap[kk][3] = packh2(sf[2 * kk + 1][2], sf[2 * kk + 1][3]);
        }

        if (diag) {
            __syncthreads();   // wscale visible; prior atomics done
            for (int idx = tid; idx < 128 * 31; idx += 256) {
                int i = idx / 31, t = idx % 31 + 1;
                s.Wb[i][t] *= s.wscale[i];
            }
            __syncthreads();
#pragma unroll
            for (int ni = 0; ni < 8; ni++) {
#pragma unroll
                for (int e = 0; e < 2; e++) {
                    int j = j0 + ni * 8 + 2 * c + e;
                    int d0 = j - ig0;
                    int d1 = j - ig1;
                    if (d0 > -CLIPV && d0 < CLIPV)
                        atomicAdd(&s.Wb[r0][d0 + CLIPV], sf[ni][e]);
                    if (d1 > -CLIPV && d1 < CLIPV)
                        atomicAdd(&s.Wb[r1][d1 + CLIPV], sf[ni][2 + e]);
                }
            }
        }

        // ---- acc = acc*alpha + P @ V  (V via ldmatrix.trans) ----
#pragma unroll
        for (int ni = 0; ni < 8; ni++) {
            acc[ni][0] *= al0; acc[ni][1] *= al0;
            acc[ni][2] *= al1; acc[ni][3] *= al1;
        }
#pragma unroll
        for (int kk = 0; kk < 4; kk++) {
#pragma unroll
            for (int p = 0; p < 4; p++) {
                uint32_t b0, b1, b2, b3;
                ldsm4t(b0, b1, b2, b3, &s.Vs[buf][kk * 16 + vrow][p * 16 + vcol]);
                mma_f16(acc[2 * p],     ap[kk][0], ap[kk][1], ap[kk][2], ap[kk][3], b0, b2);
                mma_f16(acc[2 * p + 1], ap[kk][0], ap[kk][1], ap[kk][2], ap[kk][3], b1, b3);
            }
        }
    }

    // ---- epilogue ----
    if (c == 0) {
        s.Wb[r0][0] = b0a;  s.Wb[r0][32] = b32a;
        s.Wb[r1][0] = b0b;  s.Wb[r1][32] = b32b;
        s.wscale[r0] = __expf(mW0 - m0s);
        s.wscale[r1] = __expf(mW1 - m1s);
        s.linv[r0] = 1.f / l0;
        s.linv[r1] = 1.f / l1;
    }
    __syncthreads();

    // rel_v contribution: scr[i][d] = sum_t W'[i][t] * relv[t][d]
    float* scr = (float*)&s.Ks[0][0][0];   // overlays Ks+Vs
    {
        int i = tid >> 1;
        int h = (tid & 1) * 32;
        float ws = s.wscale[i];
        float sc[32];
#pragma unroll
        for (int d = 0; d < 32; d++) sc[d] = 0.f;
        for (int t = 0; t < NT; t++) {
            float w = s.Wb[i][t];
            if (t != 0 && t != 32) w *= ws;
#pragma unroll
            for (int d = 0; d < 32; d++)
                sc[d] += w * s.relvs[t][h + d];
        }
#pragma unroll
        for (int d = 0; d < 32; d++) scr[i * 68 + h + d] = sc[d];
    }
    __syncthreads();

    {
        float li0 = s.linv[r0], li1 = s.linv[r1];
        int bb = bh >> 4, hh = bh & 15;
        __half* y0 = Y + ((size_t)(bb * 1024 + i0 + r0)) * 1024 + hh * 64;
        __half* y1 = Y + ((size_t)(bb * 1024 + i0 + r1)) * 1024 + hh * 64;
#pragma unroll
        for (int ni = 0; ni < 8; ni++) {
            int col = ni * 8 + 2 * c;
            *(uint32_t*)(y0 + col) = packh2((acc[ni][0] + scr[r0 * 68 + col]) * li0,
                                            (acc[ni][1] + scr[r0 * 68 + col + 1]) * li0);
            *(uint32_t*)(y1 + col) = packh2((acc[ni][2] + scr[r1 * 68 + col]) * li1,
                                            (acc[ni][3] + scr[r1 * 68 + col + 1]) * li1);
        }
    }
}

// ---------------------------------------------------------------------------

extern "C" void kernel_launch(void* const* d_in, const int* in_sizes, int n_in,
                              void* d_out, int out_size)
{
    const float* query = (const float*)d_in[0];
    const float* key   = (const float*)d_in[1];
    const float* value = (const float*)d_in[2];
    const float* wq = (const float*)d_in[3];
    const float* bq = (const float*)d_in[4];
    const float* wk = (const float*)d_in[5];
    const float* bk = (const float*)d_in[6];
    const float* wv = (const float*)d_in[7];
    const float* bv = (const float*)d_in[8];
    const float* wo = (const float*)d_in[9];
    const float* bo = (const float*)d_in[10];
    const float* relk = (const float*)d_in[11];
    const float* relv = (const float*)d_in[12];
    float* out = (float*)d_out;

    __half *Qp, *Kp, *Vp, *Yp, *Xq, *Xk, *Xv, *Wq, *Wk, *Wv, *Wo;
    cudaGetSymbolAddress((void**)&Qp, gQ);
    cudaGetSymbolAddress((void**)&Kp, gK);
    cudaGetSymbolAddress((void**)&Vp, gV);
    cudaGetSymbolAddress((void**)&Yp, gY);
    cudaGetSymbolAddress((void**)&Xq, gXq);
    cudaGetSymbolAddress((void**)&Xk, gXk);
    cudaGetSymbolAddress((void**)&Xv, gXv);
    cudaGetSymbolAddress((void**)&Wq, gWq);
    cudaGetSymbolAddress((void**)&Wk, gWk);
    cudaGetSymbolAddress((void**)&Wv, gWv);
    cudaGetSymbolAddress((void**)&Wo, gWo);

    convert7_kernel<<<dim3(512, 7), 256>>>(query, key, value, wq, wk, wv, wo,
                                           Xq, Xk, Xv, Wq, Wk, Wv, Wo);

    cudaFuncSetAttribute(qkv_gemm_kernel, cudaFuncAttributeMaxDynamicSharedMemorySize,
                         (int)sizeof(GemmSmem));
    cudaFuncSetAttribute(out_gemm_kernel, cudaFuncAttributeMaxDynamicSharedMemorySize,
                         (int)sizeof(GemmSmem));
    cudaFuncSetAttribute(attn_kernel, cudaFuncAttributeMaxDynamicSharedMemorySize,
                         (int)sizeof(AttnSmem));

    dim3 gqkv(8, 32, 3);
    qkv_gemm_kernel<<<gqkv, 256, sizeof(GemmSmem)>>>(Xq, Xk, Xv, Wq, Wk, Wv,
                                                     bq, bk, bv, Qp, Kp, Vp);

    attn_kernel<<<dim3(8, 64), 256, sizeof(AttnSmem)>>>(Qp, Kp, Vp, relk, relv, Yp);

    out_gemm_kernel<<<dim3(8, 32), 256, sizeof(GemmSmem)>>>(Yp, Wo, bo, out);
}

// round 9
// speedup vs baseline: 7.8250x; 1.0029x over previous
#include <cuda_runtime.h>
#include <cuda_fp16.h>
#include <math.h>
#include <cstdint>

// Problem constants
#define Bn  4
#define Ln  1024
#define En  1024
#define Hn  16
#define HDn 64
#define NT  33          // 2*CLIP+1
#define CLIPV 16
#define SCALEF 0.125f   // 1/sqrt(64)
#define LOG2E 1.4426950408889634f

// Scratch (device globals; no allocation allowed)
__device__ __half gQ[Bn*Hn*Ln*HDn];   // [b][h][l][d] fp16
__device__ __half gK[Bn*Hn*Ln*HDn];
__device__ __half gV[Bn*Hn*Ln*HDn];
__device__ __half gY[Bn*Ln*En];       // [b][l][e] fp16
__device__ __half gXq[Bn*Ln*En];      // fp16 inputs
__device__ __half gXk[Bn*Ln*En];
__device__ __half gXv[Bn*Ln*En];
__device__ __half gWq[En*En];         // fp16 weights
__device__ __half gWk[En*En];
__device__ __half gWv[En*En];
__device__ __half gWo[En*En];

// ---------------------------------------------------------------------------
// helpers
// ---------------------------------------------------------------------------
__device__ __forceinline__ uint32_t packh2(float x, float y) {
    __half2 h = __floats2half2_rn(x, y);
    return *reinterpret_cast<uint32_t*>(&h);
}

__device__ __forceinline__ void cp_async16(void* dst, const void* src) {
    uint32_t d = (uint32_t)__cvta_generic_to_shared(dst);
    asm volatile("cp.async.cg.shared.global [%0], [%1], 16;\n" :: "r"(d), "l"(src));
}

__device__ __forceinline__ void cp_async16_s(uint32_t dst, const void* src) {
    asm volatile("cp.async.cg.shared.global [%0], [%1], 16;\n" :: "r"(dst), "l"(src));
}

__device__ __forceinline__ void ldsm4(uint32_t& r0, uint32_t& r1,
                                      uint32_t& r2, uint32_t& r3, const void* p) {
    uint32_t a = (uint32_t)__cvta_generic_to_shared(p);
    asm volatile("ldmatrix.sync.aligned.m8n8.x4.shared.b16 {%0,%1,%2,%3}, [%4];"
                 : "=r"(r0), "=r"(r1), "=r"(r2), "=r"(r3) : "r"(a));
}

__device__ __forceinline__ void ldsm4_s(uint32_t& r0, uint32_t& r1,
                                        uint32_t& r2, uint32_t& r3, uint32_t a) {
    asm volatile("ldmatrix.sync.aligned.m8n8.x4.shared.b16 {%0,%1,%2,%3}, [%4];"
                 : "=r"(r0), "=r"(r1), "=r"(r2), "=r"(r3) : "r"(a));
}

__device__ __forceinline__ void ldsm4t(uint32_t& r0, uint32_t& r1,
                                       uint32_t& r2, uint32_t& r3, const void* p) {
    uint32_t a = (uint32_t)__cvta_generic_to_shared(p);
    asm volatile("ldmatrix.sync.aligned.m8n8.x4.trans.shared.b16 {%0,%1,%2,%3}, [%4];"
                 : "=r"(r0), "=r"(r1), "=r"(r2), "=r"(r3) : "r"(a));
}

__device__ __forceinline__ void mma_f16(float* d,
    uint32_t a0, uint32_t a1, uint32_t a2, uint32_t a3,
    uint32_t b0, uint32_t b1)
{
    asm volatile(
        "mma.sync.aligned.m16n8k16.row.col.f32.f16.f16.f32 "
        "{%0,%1,%2,%3}, {%4,%5,%6,%7}, {%8,%9}, {%0,%1,%2,%3};"
        : "+f"(d[0]), "+f"(d[1]), "+f"(d[2]), "+f"(d[3])
        : "r"(a0), "r"(a1), "r"(a2), "r"(a3), "r"(b0), "r"(b1));
}

__device__ __forceinline__ uint32_t sw128(uint32_t off) {
    return off ^ ((off >> 3) & 0x70);
}

// ---------------------------------------------------------------------------
// fp32 -> fp16 conversion of 3 inputs + 4 weights.
// ---------------------------------------------------------------------------
__global__ __launch_bounds__(256) void convert7_kernel(
    const float* __restrict__ xq, const float* __restrict__ xk,
    const float* __restrict__ xv,
    const float* __restrict__ wq, const float* __restrict__ wk,
    const float* __restrict__ wv, const float* __restrict__ wo,
    __half* __restrict__ oxq, __half* __restrict__ oxk, __half* __restrict__ oxv,
    __half* __restrict__ owq, __half* __restrict__ owk,
    __half* __restrict__ owv, __half* __restrict__ owo)
{
    int t = blockIdx.y;
    const float* src; __half* dst; int n8;
    switch (t) {
        case 0: src = xq; dst = oxq; n8 = (Bn*Ln*En)/8; break;
        case 1: src = xk; dst = oxk; n8 = (Bn*Ln*En)/8; break;
        case 2: src = xv; dst = oxv; n8 = (Bn*Ln*En)/8; break;
        case 3: src = wq; dst = owq; n8 = (En*En)/8; break;
        case 4: src = wk; dst = owk; n8 = (En*En)/8; break;
        case 5: src = wv; dst = owv; n8 = (En*En)/8; break;
        default: src = wo; dst = owo; n8 = (En*En)/8; break;
    }
    int stride = gridDim.x * 256;
    for (int i = blockIdx.x * 256 + threadIdx.x; i < n8; i += stride) {
        float4 a = ((const float4*)src)[2*i];
        float4 b = ((const float4*)src)[2*i + 1];
        uint4 o;
        o.x = packh2(a.x, a.y); o.y = packh2(a.z, a.w);
        o.z = packh2(b.x, b.y); o.w = packh2(b.z, b.w);
        ((uint4*)dst)[i] = o;
    }
}

// ---------------------------------------------------------------------------
// fp16 tensor-core GEMM: C = A(4096x1024) @ W(1024x1024)^T + bias.
// CTA 128x128, BK=64 (128B SW128-swizzled rows), 3-stage cp.async,
// ONE syncthreads per k-iter (16 iters). 8 warps, warp tile 32x64.
// ---------------------------------------------------------------------------
#define GTILE 16384                       // 128 rows * 128 bytes
#define GS_TOTAL (6 * GTILE)              // 3 stages * (A + B) = 96 KB

__device__ __forceinline__ void gemm_body(
    const __half* __restrict__ A, const __half* __restrict__ W,
    const float* __restrict__ bias, void* __restrict__ Cout, int head_layout)
{
    extern __shared__ char sm[];
    uint32_t smem = (uint32_t)__cvta_generic_to_shared(sm);
    uint32_t smA = smem, smB = smem + 3 * GTILE;
    const int Kd = 1024;

    int tid  = threadIdx.x;
    int warp = tid >> 5, lane = tid & 31;
    int wm = (warp >> 1) << 5;
    int wn = (warp & 1) << 6;
    int g = lane >> 2, c = lane & 3;
    int m0 = blockIdx.y << 7, n0 = blockIdx.x << 7;

    int lrow = (lane & 7) + ((lane >> 3) & 1) * 8;
    int lcol = (lane >> 4) * 8;

    // stage-load mapping: 2 threads per row, 4 x 16B chunks each
    int r = tid >> 1;
    int chbase = (tid & 1) * 4;
    const __half* Ag = A + (size_t)(m0 + r) * Kd;
    const __half* Wg = W + (size_t)(n0 + r) * Kd;

    float acc[2][8][4];
#pragma unroll
    for (int mi = 0; mi < 2; mi++)
#pragma unroll
        for (int ni = 0; ni < 8; ni++)
#pragma unroll
            for (int q = 0; q < 4; q++) acc[mi][ni][q] = 0.f;

    auto load_stage = [&](int s, int k0) {
#pragma unroll
        for (int q = 0; q < 4; q++) {
            int ch = chbase + q;
            uint32_t d = sw128((uint32_t)(r * 128 + ch * 16));
            cp_async16_s(smA + s * GTILE + d, Ag + k0 + ch * 8);
            cp_async16_s(smB + s * GTILE + d, Wg + k0 + ch * 8);
        }
    };

    load_stage(0, 0);
    asm volatile("cp.async.commit_group;\n");
    load_stage(1, 64);
    asm volatile("cp.async.commit_group;\n");

    const int NITER = Kd / 64;   // 16
    for (int t = 0; t < NITER; t++) {
        asm volatile("cp.async.wait_group 1;\n");   // stage t resident
        __syncthreads();                             // visible; compute t-1 done
        if (t + 2 < NITER) {
            int s = (t + 2) % 3;
            load_stage(s, (t + 2) * 64);
        }
        asm volatile("cp.async.commit_group;\n");

        int s = t % 3;
#pragma unroll
        for (int ks = 0; ks < 4; ks++) {
            int kc = ks * 16 + lcol;    // halves within 64-half row
            uint32_t af[2][4], bf[4][4];
#pragma unroll
            for (int mi = 0; mi < 2; mi++) {
                uint32_t addr = smA + s * GTILE +
                    sw128((uint32_t)((wm + mi * 16 + lrow) * 128 + kc * 2));
                ldsm4_s(af[mi][0], af[mi][1], af[mi][2], af[mi][3], addr);
            }
#pragma unroll
            for (int p = 0; p < 4; p++) {
                uint32_t addr = smB + s * GTILE +
                    sw128((uint32_t)((wn + p * 16 + lrow) * 128 + kc * 2));
                ldsm4_s(bf[p][0], bf[p][1], bf[p][2], bf[p][3], addr);
            }
#pragma unroll
            for (int mi = 0; mi < 2; mi++)
#pragma unroll
                for (int ni = 0; ni < 8; ni++) {
                    int p = ni >> 1;
                    uint32_t b0 = (ni & 1) ? bf[p][1] : bf[p][0];
                    uint32_t b1 = (ni & 1) ? bf[p][3] : bf[p][2];
                    mma_f16(acc[mi][ni], af[mi][0], af[mi][1], af[mi][2], af[mi][3],
                            b0, b1);
                }
        }
    }

#pragma unroll
    for (int mi = 0; mi < 2; mi++) {
#pragma unroll
        for (int ni = 0; ni < 8; ni++) {
            int row = m0 + wm + (mi << 4) + g;
            int col = n0 + wn + (ni << 3) + (c << 1);
            float b0 = bias[col], b1 = bias[col + 1];
            float x0 = acc[mi][ni][0] + b0, x1 = acc[mi][ni][1] + b1;
            float x2 = acc[mi][ni][2] + b0, x3 = acc[mi][ni][3] + b1;
            if (head_layout) {
                __half* C = (__half*)Cout;
                int b = row >> 10, l = row & 1023, h = col >> 6, d = col & 63;
                size_t off = (((size_t)(b * Hn + h)) << 16) + ((size_t)l << 6) + d;
                *(uint32_t*)(C + off) = packh2(x0, x1);
                int row2 = row + 8;
                int b2 = row2 >> 10, l2 = row2 & 1023;
                size_t off2 = (((size_t)(b2 * Hn + h)) << 16) + ((size_t)l2 << 6) + d;
                *(uint32_t*)(C + off2) = packh2(x2, x3);
            } else {
                float* C = (float*)Cout;
                *(float2*)(C + (size_t)row * 1024 + col) = make_float2(x0, x1);
                *(float2*)(C + (size_t)(row + 8) * 1024 + col) = make_float2(x2, x3);
            }
        }
    }
}

__global__ __launch_bounds__(256, 2) void qkv_gemm_kernel(
    const __half* __restrict__ xq, const __half* __restrict__ xk,
    const __half* __restrict__ xv,
    const __half* __restrict__ wq, const __half* __restrict__ wk,
    const __half* __restrict__ wv,
    const float* __restrict__ bq, const float* __restrict__ bk,
    const float* __restrict__ bv,
    __half* __restrict__ Q, __half* __restrict__ K, __half* __restrict__ V)
{
    if (blockIdx.z == 0)      gemm_body(xq, wq, bq, Q, 1);
    else if (blockIdx.z == 1) gemm_body(xk, wk, bk, K, 1);
    else                      gemm_body(xv, wv, bv, V, 1);
}

__global__ __launch_bounds__(256, 2) void out_gemm_kernel(
    const __half* __restrict__ Y, const __half* __restrict__ wo,
    const float* __restrict__ bo, float* __restrict__ out)
{
    gemm_body(Y, wo, bo, out, 0);
}

// ---------------------------------------------------------------------------
// fp16 tensor-core flash attention; softmax in log2 domain (exp2f only).
// grid: (8 q-tiles of 128 rows, 64 bh). 256 threads = 8 warps x 16 rows.
// ---------------------------------------------------------------------------
#define QPAD 72

struct __align__(16) AttnSmem {
    __half Qs[128][QPAD];     // SCALE*LOG2E folded
    __half Ks[2][64][QPAD];   // [j][d]   } reused as fp32 scratch in epilogue
    __half Vs[2][64][QPAD];   // [j][d]   }
    float RQs[128][NT];       // log2-domain bias
    float Wb[128][NT];
    float relvs[NT][68];
    float relks[NT][68];
    float wscale[128];
    float linv[128];
};

__device__ __forceinline__ void load_kv_tile(AttnSmem& s, int buf,
    const __half* Kb, const __half* Vb, int j0, int tid)
{
    int j = tid >> 2;
    int ch = (tid & 3) << 4;
    const __half* ks = Kb + (size_t)(j0 + j) * 64 + ch;
    const __half* vs = Vb + (size_t)(j0 + j) * 64 + ch;
    cp_async16(&s.Ks[buf][j][ch],     ks);
    cp_async16(&s.Ks[buf][j][ch + 8], ks + 8);
    cp_async16(&s.Vs[buf][j][ch],     vs);
    cp_async16(&s.Vs[buf][j][ch + 8], vs + 8);
}

__global__ __launch_bounds__(256, 2) void attn_kernel(
    const __half* __restrict__ Q, const __half* __restrict__ Kg,
    const __half* __restrict__ Vg, const float* __restrict__ relk,
    const float* __restrict__ relv, __half* __restrict__ Y)
{
    extern __shared__ char smem_raw[];
    AttnSmem& s = *reinterpret_cast<AttnSmem*>(smem_raw);
    int tid = threadIdx.x;
    int warp = tid >> 5, lane = tid & 31;
    int g = lane >> 2, c = lane & 3;
    int r0 = warp * 16 + g;
    int r1 = r0 + 8;
    int lrow = (lane & 7) + ((lane >> 3) & 1) * 8;
    int lcol = (lane >> 4) * 8;
    int vrow = (lane & 7) + (lane >> 4) * 8;
    int vcol = ((lane >> 3) & 1) * 8;

    int bh = blockIdx.y;
    int bx = blockIdx.x;
    int i0 = bx * 128;
    const __half* Qb = Q + ((size_t)bh << 16) + (size_t)i0 * 64;
    const __half* Kb = Kg + ((size_t)bh << 16);
    const __half* Vb = Vg + ((size_t)bh << 16);

    load_kv_tile(s, 0, Kb, Vb, 0, tid);
    asm volatile("cp.async.commit_group;\n");
    {
        int r = tid >> 1;
        int seg = (tid & 1) * 32;
        const __half* src = Qb + (size_t)r * 64 + seg;
        __half2 hs = __float2half2_rn(SCALEF * LOG2E);   // log2 domain
#pragma unroll
        for (int q = 0; q < 4; q++) {
            uint4 v = *(const uint4*)(src + q * 8);
            __half2* hv = (__half2*)&v;
#pragma unroll
            for (int e = 0; e < 4; e++) hv[e] = __hmul2(hv[e], hs);
            *(uint4*)&s.Qs[r][seg + q * 8] = v;
        }
    }
    for (int idx = tid; idx < NT * 64; idx += 256) {
        s.relvs[idx >> 6][idx & 63] = relv[idx];
        s.relks[idx >> 6][idx & 63] = relk[idx];
    }
    for (int idx = tid; idx < 128 * NT; idx += 256)
        s.Wb[idx / NT][idx % NT] = 0.f;
    __syncthreads();

    // RQs[i][t] = Qs(i,:) . relk(t,:)  (log2e & scale already folded via Qs)
    {
        int i = tid >> 1;
        int h = (tid & 1) * 32;
        float qf[32];
#pragma unroll
        for (int dd = 0; dd < 32; dd++) qf[dd] = __half2float(s.Qs[i][h + dd]);
        for (int t = 0; t < NT; t++) {
            float p = 0.f;
#pragma unroll
            for (int dd = 0; dd < 32; dd++) p += qf[dd] * s.relks[t][h + dd];
            p += __shfl_xor_sync(0xffffffffu, p, 1);
            if ((tid & 1) == 0) s.RQs[i][t] = p;
        }
    }

    float m0s = -1e30f, m1s = -1e30f;
    float l0 = 0.f, l1 = 0.f;
    float b0a = 0.f, b0b = 0.f, b32a = 0.f, b32b = 0.f;
    float mW0 = -1e30f, mW1 = -1e30f;
    float acc[8][4];
#pragma unroll
    for (int ni = 0; ni < 8; ni++)
#pragma unroll
        for (int q = 0; q < 4; q++) acc[ni][q] = 0.f;

    int ig0 = i0 + r0, ig1 = i0 + r1;

    for (int jt = 0; jt < 16; jt++) {
        int buf = jt & 1;
        int j0 = jt * 64;
        asm volatile("cp.async.wait_group 0;\n");
        __syncthreads();
        if (jt + 1 < 16)
            load_kv_tile(s, buf ^ 1, Kb, Vb, j0 + 64, tid);
        asm volatile("cp.async.commit_group;\n");

        int dj = jt - 2 * bx;
        bool far_left  = (dj <= -2);
        bool far_right = (dj >= 3);
        bool diag = !(far_left || far_right);

        float sf[8][4];
#pragma unroll
        for (int ni = 0; ni < 8; ni++)
#pragma unroll
            for (int q = 0; q < 4; q++) sf[ni][q] = 0.f;
#pragma unroll
        for (int ks = 0; ks < 4; ks++) {
            int kc = ks * 16 + lcol;
            uint32_t a0, a1, a2, a3;
            ldsm4(a0, a1, a2, a3, &s.Qs[warp * 16 + lrow][kc]);
#pragma unroll
            for (int p = 0; p < 4; p++) {
                uint32_t b0, b1, b2, b3;
                ldsm4(b0, b1, b2, b3, &s.Ks[buf][p * 16 + lrow][kc]);
                mma_f16(sf[2 * p],     a0, a1, a2, a3, b0, b2);
                mma_f16(sf[2 * p + 1], a0, a1, a2, a3, b1, b3);
            }
        }

        if (!diag) {
            int tf = far_left ? 0 : 32;
            float rq0 = s.RQs[r0][tf], rq1 = s.RQs[r1][tf];
#pragma unroll
            for (int ni = 0; ni < 8; ni++) {
                sf[ni][0] += rq0; sf[ni][1] += rq0;
                sf[ni][2] += rq1; sf[ni][3] += rq1;
            }
        } else {
#pragma unroll
            for (int ni = 0; ni < 8; ni++) {
#pragma unroll
                for (int e = 0; e < 2; e++) {
                    int j = j0 + ni * 8 + 2 * c + e;
                    int d0 = j - ig0; d0 = d0 < -CLIPV ? -CLIPV : (d0 > CLIPV ? CLIPV : d0);
                    int d1 = j - ig1; d1 = d1 < -CLIPV ? -CLIPV : (d1 > CLIPV ? CLIPV : d1);
                    sf[ni][e]     += s.RQs[r0][d0 + CLIPV];
                    sf[ni][2 + e] += s.RQs[r1][d1 + CLIPV];
                }
            }
        }

        float mt0 = -1e30f, mt1 = -1e30f;
#pragma unroll
        for (int ni = 0; ni < 8; ni++) {
            mt0 = fmaxf(mt0, fmaxf(sf[ni][0], sf[ni][1]));
            mt1 = fmaxf(mt1, fmaxf(sf[ni][2], sf[ni][3]));
        }
        mt0 = fmaxf(mt0, __shfl_xor_sync(0xffffffffu, mt0, 1));
        mt0 = fmaxf(mt0, __shfl_xor_sync(0xffffffffu, mt0, 2));
        mt1 = fmaxf(mt1, __shfl_xor_sync(0xffffffffu, mt1, 1));
        mt1 = fmaxf(mt1, __shfl_xor_sync(0xffffffffu, mt1, 2));
        float mn0 = fmaxf(m0s, mt0), mn1 = fmaxf(m1s, mt1);
        float al0 = exp2f(m0s - mn0), al1 = exp2f(m1s - mn1);

        float rs0 = 0.f, rs1 = 0.f;
#pragma unroll
        for (int ni = 0; ni < 8; ni++) {
            sf[ni][0] = exp2f(sf[ni][0] - mn0);
            sf[ni][1] = exp2f(sf[ni][1] - mn0);
            sf[ni][2] = exp2f(sf[ni][2] - mn1);
            sf[ni][3] = exp2f(sf[ni][3] - mn1);
            rs0 += sf[ni][0] + sf[ni][1];
            rs1 += sf[ni][2] + sf[ni][3];
        }
        rs0 += __shfl_xor_sync(0xffffffffu, rs0, 1);
        rs0 += __shfl_xor_sync(0xffffffffu, rs0, 2);
        rs1 += __shfl_xor_sync(0xffffffffu, rs1, 1);
        rs1 += __shfl_xor_sync(0xffffffffu, rs1, 2);
        l0 = l0 * al0 + rs0;
        l1 = l1 * al1 + rs1;

        if (far_left) {
            b0a = b0a * al0 + rs0;  b0b = b0b * al1 + rs1;
            b32a *= al0;            b32b *= al1;
        } else if (far_right) {
            b32a = b32a * al0 + rs0; b32b = b32b * al1 + rs1;
            b0a *= al0;              b0b *= al1;
        } else {
            float c0a = 0.f, c0b = 0.f, c32a = 0.f, c32b = 0.f;
#pragma unroll
            for (int ni = 0; ni < 8; ni++) {
#pragma unroll
                for (int e = 0; e < 2; e++) {
                    int j = j0 + ni * 8 + 2 * c + e;
                    int d0 = j - ig0;
                    int d1 = j - ig1;
                    if (d0 <= -CLIPV) c0a += sf[ni][e];
                    else if (d0 >= CLIPV) c32a += sf[ni][e];
                    if (d1 <= -CLIPV) c0b += sf[ni][2 + e];
                    else if (d1 >= CLIPV) c32b += sf[ni][2 + e];
                }
            }
            c0a += __shfl_xor_sync(0xffffffffu, c0a, 1);
            c0a += __shfl_xor_sync(0xffffffffu, c0a, 2);
            c0b += __shfl_xor_sync(0xffffffffu, c0b, 1);
            c0b += __shfl_xor_sync(0xffffffffu, c0b, 2);
            c32a += __shfl_xor_sync(0xffffffffu, c32a, 1);
            c32a += __shfl_xor_sync(0xffffffffu, c32a, 2);
            c32b += __shfl_xor_sync(0xffffffffu, c32b, 1);
            c32b += __shfl_xor_sync(0xffffffffu, c32b, 2);
            b0a = b0a * al0 + c0a;   b0b = b0b * al1 + c0b;
            b32a = b32a * al0 + c32a; b32b = b32b * al1 + c32b;
        }

        if (diag && c == 0) {
            s.wscale[r0] = exp2f(mW0 - mn0);
            s.wscale[r1] = exp2f(mW1 - mn1);
        }
        if (diag) { mW0 = mn0; mW1 = mn1; }
        m0s = mn0; m1s = mn1;

        uint32_t ap[4][4];
#pragma unroll
        for (int kk = 0; kk < 4; kk++) {
            ap[kk][0] = packh2(sf[2 * kk][0],     sf[2 * kk][1]);
            ap[kk][1] = packh2(sf[2 * kk][2],     sf[2 * kk][3]);
            ap[kk][2] = packh2(sf[2 * kk + 1][0], sf[2 * kk + 1][1]);
            ap[kk][3] = packh2(sf[2 * kk + 1][2], sf[2 * kk + 1][3]);
        }

        if (diag) {
            __syncthreads();
            for (int idx = tid; idx < 128 * 31; idx += 256) {
                int i = idx / 31, t = idx % 31 + 1;
                s.Wb[i][t] *= s.wscale[i];
            }
            __syncthreads();
#pragma unroll
            for (int ni = 0; ni < 8; ni++) {
#pragma unroll
                for (int e = 0; e < 2; e++) {
                    int j = j0 + ni * 8 + 2 * c + e;
                    int d0 = j - ig0;
                    int d1 = j - ig1;
                    if (d0 > -CLIPV && d0 < CLIPV)
                        atomicAdd(&s.Wb[r0][d0 + CLIPV], sf[ni][e]);
                    if (d1 > -CLIPV && d1 < CLIPV)
                        atomicAdd(&s.Wb[r1][d1 + CLIPV], sf[ni][2 + e]);
                }
            }
        }

#pragma unroll
        for (int ni = 0; ni < 8; ni++) {
            acc[ni][0] *= al0; acc[ni][1] *= al0;
            acc[ni][2] *= al1; acc[ni][3] *= al1;
        }
#pragma unroll
        for (int kk = 0; kk < 4; kk++) {
#pragma unroll
            for (int p = 0; p < 4; p++) {
                uint32_t b0, b1, b2, b3;
                ldsm4t(b0, b1, b2, b3, &s.Vs[buf][kk * 16 + vrow][p * 16 + vcol]);
                mma_f16(acc[2 * p],     ap[kk][0], ap[kk][1], ap[kk][2], ap[kk][3], b0, b2);
                mma_f16(acc[2 * p + 1], ap[kk][0], ap[kk][1], ap[kk][2], ap[kk][3], b1, b3);
            }
        }
    }

    if (c == 0) {
        s.Wb[r0][0] = b0a;  s.Wb[r0][32] = b32a;
        s.Wb[r1][0] = b0b;  s.Wb[r1][32] = b32b;
        s.wscale[r0] = exp2f(mW0 - m0s);
        s.wscale[r1] = exp2f(mW1 - m1s);
        s.linv[r0] = 1.f / l0;
        s.linv[r1] = 1.f / l1;
    }
    __syncthreads();

    float* scr = (float*)&s.Ks[0][0][0];
    {
        int i = tid >> 1;
        int h = (tid & 1) * 32;
        float ws = s.wscale[i];
        float sc[32];
#pragma unroll
        for (int d = 0; d < 32; d++) sc[d] = 0.f;
        for (int t = 0; t < NT; t++) {
            float w = s.Wb[i][t];
            if (t != 0 && t != 32) w *= ws;
#pragma unroll
            for (int d = 0; d < 32; d++)
                sc[d] += w * s.relvs[t][h + d];
        }
#pragma unroll
        for (int d = 0; d < 32; d++) scr[i * 68 + h + d] = sc[d];
    }
    __syncthreads();

    {
        float li0 = s.linv[r0], li1 = s.linv[r1];
        int bb = bh >> 4, hh = bh & 15;
        __half* y0 = Y + ((size_t)(bb * 1024 + i0 + r0)) * 1024 + hh * 64;
        __half* y1 = Y + ((size_t)(bb * 1024 + i0 + r1)) * 1024 + hh * 64;
#pragma unroll
        for (int ni = 0; ni < 8; ni++) {
            int col = ni * 8 + 2 * c;
            *(uint32_t*)(y0 + col) = packh2((acc[ni][0] + scr[r0 * 68 + col]) * li0,
                                            (acc[ni][1] + scr[r0 * 68 + col + 1]) * li0);
            *(uint32_t*)(y1 + col) = packh2((acc[ni][2] + scr[r1 * 68 + col]) * li1,
                                            (acc[ni][3] + scr[r1 * 68 + col + 1]) * li1);
        }
    }
}

// ---------------------------------------------------------------------------

extern "C" void kernel_launch(void* const* d_in, const int* in_sizes, int n_in,
                              void* d_out, int out_size)
{
    const float* query = (const float*)d_in[0];
    const float* key   = (const float*)d_in[1];
    const float* value = (const float*)d_in[2];
    const float* wq = (const float*)d_in[3];
    const float* bq = (const float*)d_in[4];
    const float* wk = (const float*)d_in[5];
    const float* bk = (const float*)d_in[6];
    const float* wv = (const float*)d_in[7];
    const float* bv = (const float*)d_in[8];
    const float* wo = (const float*)d_in[9];
    const float* bo = (const float*)d_in[10];
    const float* relk = (const float*)d_in[11];
    const float* relv = (const float*)d_in[12];
    float* out = (float*)d_out;

    __half *Qp, *Kp, *Vp, *Yp, *Xq, *Xk, *Xv, *Wq, *Wk, *Wv, *Wo;
    cudaGetSymbolAddress((void**)&Qp, gQ);
    cudaGetSymbolAddress((void**)&Kp, gK);
    cudaGetSymbolAddress((void**)&Vp, gV);
    cudaGetSymbolAddress((void**)&Yp, gY);
    cudaGetSymbolAddress((void**)&Xq, gXq);
    cudaGetSymbolAddress((void**)&Xk, gXk);
    cudaGetSymbolAddress((void**)&Xv, gXv);
    cudaGetSymbolAddress((void**)&Wq, gWq);
    cudaGetSymbolAddress((void**)&Wk, gWk);
    cudaGetSymbolAddress((void**)&Wv, gWv);
    cudaGetSymbolAddress((void**)&Wo, gWo);

    convert7_kernel<<<dim3(512, 7), 256>>>(query, key, value, wq, wk, wv, wo,
                                           Xq, Xk, Xv, Wq, Wk, Wv, Wo);

    cudaFuncSetAttribute(qkv_gemm_kernel, cudaFuncAttributeMaxDynamicSharedMemorySize,
                         GS_TOTAL);
    cudaFuncSetAttribute(out_gemm_kernel, cudaFuncAttributeMaxDynamicSharedMemorySize,
                         GS_TOTAL);
    cudaFuncSetAttribute(attn_kernel, cudaFuncAttributeMaxDynamicSharedMemorySize,
                         (int)sizeof(AttnSmem));

    qkv_gemm_kernel<<<dim3(8, 32, 3), 256, GS_TOTAL>>>(Xq, Xk, Xv, Wq, Wk, Wv,
                                                       bq, bk, bv, Qp, Kp, Vp);

    attn_kernel<<<dim3(8, 64), 256, sizeof(AttnSmem)>>>(Qp, Kp, Vp, relk, relv, Yp);

    out_gemm_kernel<<<dim3(8, 32), 256, GS_TOTAL>>>(Yp, Wo, bo, out);
}

// round 10
// speedup vs baseline: 7.8639x; 1.0050x over previous
#include <cuda_runtime.h>
#include <cuda_fp16.h>
#include <math.h>
#include <cstdint>

// Problem constants
#define Bn  4
#define Ln  1024
#define En  1024
#define Hn  16
#define HDn 64
#define NT  33          // 2*CLIP+1
#define CLIPV 16
#define SCALEF 0.125f   // 1/sqrt(64)
#define LOG2E 1.4426950408889634f

// Scratch (device globals; no allocation allowed)
__device__ __half gQ[Bn*Hn*Ln*HDn];   // [b][h][l][d] fp16
__device__ __half gK[Bn*Hn*Ln*HDn];
__device__ __half gV[Bn*Hn*Ln*HDn];
__device__ __half gY[Bn*Ln*En];       // [b][l][e] fp16
__device__ __half gXq[Bn*Ln*En];      // fp16 inputs
__device__ __half gXk[Bn*Ln*En];
__device__ __half gXv[Bn*Ln*En];
__device__ __half gWq[En*En];         // fp16 weights
__device__ __half gWk[En*En];
__device__ __half gWv[En*En];
__device__ __half gWo[En*En];

// ---------------------------------------------------------------------------
// helpers
// ---------------------------------------------------------------------------
__device__ __forceinline__ uint32_t packh2(float x, float y) {
    __half2 h = __floats2half2_rn(x, y);
    return *reinterpret_cast<uint32_t*>(&h);
}

__device__ __forceinline__ void cp_async16(void* dst, const void* src) {
    uint32_t d = (uint32_t)__cvta_generic_to_shared(dst);
    asm volatile("cp.async.cg.shared.global [%0], [%1], 16;\n" :: "r"(d), "l"(src));
}

__device__ __forceinline__ void cp_async16_s(uint32_t dst, const void* src) {
    asm volatile("cp.async.cg.shared.global [%0], [%1], 16;\n" :: "r"(dst), "l"(src));
}

__device__ __forceinline__ void ldsm4(uint32_t& r0, uint32_t& r1,
                                      uint32_t& r2, uint32_t& r3, const void* p) {
    uint32_t a = (uint32_t)__cvta_generic_to_shared(p);
    asm volatile("ldmatrix.sync.aligned.m8n8.x4.shared.b16 {%0,%1,%2,%3}, [%4];"
                 : "=r"(r0), "=r"(r1), "=r"(r2), "=r"(r3) : "r"(a));
}

__device__ __forceinline__ void ldsm4_s(uint32_t& r0, uint32_t& r1,
                                        uint32_t& r2, uint32_t& r3, uint32_t a) {
    asm volatile("ldmatrix.sync.aligned.m8n8.x4.shared.b16 {%0,%1,%2,%3}, [%4];"
                 : "=r"(r0), "=r"(r1), "=r"(r2), "=r"(r3) : "r"(a));
}

__device__ __forceinline__ void ldsm4t(uint32_t& r0, uint32_t& r1,
                                       uint32_t& r2, uint32_t& r3, const void* p) {
    uint32_t a = (uint32_t)__cvta_generic_to_shared(p);
    asm volatile("ldmatrix.sync.aligned.m8n8.x4.trans.shared.b16 {%0,%1,%2,%3}, [%4];"
                 : "=r"(r0), "=r"(r1), "=r"(r2), "=r"(r3) : "r"(a));
}

__device__ __forceinline__ void mma_f16(float* d,
    uint32_t a0, uint32_t a1, uint32_t a2, uint32_t a3,
    uint32_t b0, uint32_t b1)
{
    asm volatile(
        "mma.sync.aligned.m16n8k16.row.col.f32.f16.f16.f32 "
        "{%0,%1,%2,%3}, {%4,%5,%6,%7}, {%8,%9}, {%0,%1,%2,%3};"
        : "+f"(d[0]), "+f"(d[1]), "+f"(d[2]), "+f"(d[3])
        : "r"(a0), "r"(a1), "r"(a2), "r"(a3), "r"(b0), "r"(b1));
}

__device__ __forceinline__ uint32_t sw128(uint32_t off) {
    return off ^ ((off >> 3) & 0x70);
}

// ---------------------------------------------------------------------------
// fp32 -> fp16 conversion of 3 inputs + 4 weights.
// ---------------------------------------------------------------------------
__global__ __launch_bounds__(256) void convert7_kernel(
    const float* __restrict__ xq, const float* __restrict__ xk,
    const float* __restrict__ xv,
    const float* __restrict__ wq, const float* __restrict__ wk,
    const float* __restrict__ wv, const float* __restrict__ wo,
    __half* __restrict__ oxq, __half* __restrict__ oxk, __half* __restrict__ oxv,
    __half* __restrict__ owq, __half* __restrict__ owk,
    __half* __restrict__ owv, __half* __restrict__ owo)
{
    int t = blockIdx.y;
    const float* src; __half* dst; int n8;
    switch (t) {
        case 0: src = xq; dst = oxq; n8 = (Bn*Ln*En)/8; break;
        case 1: src = xk; dst = oxk; n8 = (Bn*Ln*En)/8; break;
        case 2: src = xv; dst = oxv; n8 = (Bn*Ln*En)/8; break;
        case 3: src = wq; dst = owq; n8 = (En*En)/8; break;
        case 4: src = wk; dst = owk; n8 = (En*En)/8; break;
        case 5: src = wv; dst = owv; n8 = (En*En)/8; break;
        default: src = wo; dst = owo; n8 = (En*En)/8; break;
    }
    int stride = gridDim.x * 256;
    for (int i = blockIdx.x * 256 + threadIdx.x; i < n8; i += stride) {
        float4 a = ((const float4*)src)[2*i];
        float4 b = ((const float4*)src)[2*i + 1];
        uint4 o;
        o.x = packh2(a.x, a.y); o.y = packh2(a.z, a.w);
        o.z = packh2(b.x, b.y); o.w = packh2(b.z, b.w);
        ((uint4*)dst)[i] = o;
    }
}

// ---------------------------------------------------------------------------
// fp16 tensor-core GEMM (unchanged from round 9).
// ---------------------------------------------------------------------------
#define GTILE 16384                       // 128 rows * 128 bytes
#define GS_TOTAL (6 * GTILE)              // 3 stages * (A + B) = 96 KB

__device__ __forceinline__ void gemm_body(
    const __half* __restrict__ A, const __half* __restrict__ W,
    const float* __restrict__ bias, void* __restrict__ Cout, int head_layout)
{
    extern __shared__ char sm[];
    uint32_t smem = (uint32_t)__cvta_generic_to_shared(sm);
    uint32_t smA = smem, smB = smem + 3 * GTILE;
    const int Kd = 1024;

    int tid  = threadIdx.x;
    int warp = tid >> 5, lane = tid & 31;
    int wm = (warp >> 1) << 5;
    int wn = (warp & 1) << 6;
    int g = lane >> 2, c = lane & 3;
    int m0 = blockIdx.y << 7, n0 = blockIdx.x << 7;

    int lrow = (lane & 7) + ((lane >> 3) & 1) * 8;
    int lcol = (lane >> 4) * 8;

    int r = tid >> 1;
    int chbase = (tid & 1) * 4;
    const __half* Ag = A + (size_t)(m0 + r) * Kd;
    const __half* Wg = W + (size_t)(n0 + r) * Kd;

    float acc[2][8][4];
#pragma unroll
    for (int mi = 0; mi < 2; mi++)
#pragma unroll
        for (int ni = 0; ni < 8; ni++)
#pragma unroll
            for (int q = 0; q < 4; q++) acc[mi][ni][q] = 0.f;

    auto load_stage = [&](int s, int k0) {
#pragma unroll
        for (int q = 0; q < 4; q++) {
            int ch = chbase + q;
            uint32_t d = sw128((uint32_t)(r * 128 + ch * 16));
            cp_async16_s(smA + s * GTILE + d, Ag + k0 + ch * 8);
            cp_async16_s(smB + s * GTILE + d, Wg + k0 + ch * 8);
        }
    };

    load_stage(0, 0);
    asm volatile("cp.async.commit_group;\n");
    load_stage(1, 64);
    asm volatile("cp.async.commit_group;\n");

    const int NITER = Kd / 64;   // 16
    for (int t = 0; t < NITER; t++) {
        asm volatile("cp.async.wait_group 1;\n");
        __syncthreads();
        if (t + 2 < NITER) {
            int s = (t + 2) % 3;
            load_stage(s, (t + 2) * 64);
        }
        asm volatile("cp.async.commit_group;\n");

        int s = t % 3;
#pragma unroll
        for (int ks = 0; ks < 4; ks++) {
            int kc = ks * 16 + lcol;
            uint32_t af[2][4], bf[4][4];
#pragma unroll
            for (int mi = 0; mi < 2; mi++) {
                uint32_t addr = smA + s * GTILE +
                    sw128((uint32_t)((wm + mi * 16 + lrow) * 128 + kc * 2));
                ldsm4_s(af[mi][0], af[mi][1], af[mi][2], af[mi][3], addr);
            }
#pragma unroll
            for (int p = 0; p < 4; p++) {
                uint32_t addr = smB + s * GTILE +
                    sw128((uint32_t)((wn + p * 16 + lrow) * 128 + kc * 2));
                ldsm4_s(bf[p][0], bf[p][1], bf[p][2], bf[p][3], addr);
            }
#pragma unroll
            for (int mi = 0; mi < 2; mi++)
#pragma unroll
                for (int ni = 0; ni < 8; ni++) {
                    int p = ni >> 1;
                    uint32_t b0 = (ni & 1) ? bf[p][1] : bf[p][0];
                    uint32_t b1 = (ni & 1) ? bf[p][3] : bf[p][2];
                    mma_f16(acc[mi][ni], af[mi][0], af[mi][1], af[mi][2], af[mi][3],
                            b0, b1);
                }
        }
    }

#pragma unroll
    for (int mi = 0; mi < 2; mi++) {
#pragma unroll
        for (int ni = 0; ni < 8; ni++) {
            int row = m0 + wm + (mi << 4) + g;
            int col = n0 + wn + (ni << 3) + (c << 1);
            float b0 = bias[col], b1 = bias[col + 1];
            float x0 = acc[mi][ni][0] + b0, x1 = acc[mi][ni][1] + b1;
            float x2 = acc[mi][ni][2] + b0, x3 = acc[mi][ni][3] + b1;
            if (head_layout) {
                __half* C = (__half*)Cout;
                int b = row >> 10, l = row & 1023, h = col >> 6, d = col & 63;
                size_t off = (((size_t)(b * Hn + h)) << 16) + ((size_t)l << 6) + d;
                *(uint32_t*)(C + off) = packh2(x0, x1);
                int row2 = row + 8;
                int b2 = row2 >> 10, l2 = row2 & 1023;
                size_t off2 = (((size_t)(b2 * Hn + h)) << 16) + ((size_t)l2 << 6) + d;
                *(uint32_t*)(C + off2) = packh2(x2, x3);
            } else {
                float* C = (float*)Cout;
                *(float2*)(C + (size_t)row * 1024 + col) = make_float2(x0, x1);
                *(float2*)(C + (size_t)(row + 8) * 1024 + col) = make_float2(x2, x3);
            }
        }
    }
}

__global__ __launch_bounds__(256, 2) void qkv_gemm_kernel(
    const __half* __restrict__ xq, const __half* __restrict__ xk,
    const __half* __restrict__ xv,
    const __half* __restrict__ wq, const __half* __restrict__ wk,
    const __half* __restrict__ wv,
    const float* __restrict__ bq, const float* __restrict__ bk,
    const float* __restrict__ bv,
    __half* __restrict__ Q, __half* __restrict__ K, __half* __restrict__ V)
{
    if (blockIdx.z == 0)      gemm_body(xq, wq, bq, Q, 1);
    else if (blockIdx.z == 1) gemm_body(xk, wk, bk, K, 1);
    else                      gemm_body(xv, wv, bv, V, 1);
}

__global__ __launch_bounds__(256, 2) void out_gemm_kernel(
    const __half* __restrict__ Y, const __half* __restrict__ wo,
    const float* __restrict__ bo, float* __restrict__ out)
{
    gemm_body(Y, wo, bo, out, 0);
}

// ---------------------------------------------------------------------------
// fp16 tensor-core flash attention; log2-domain softmax.
// Bucket weights: atomic-free. Within a tile, (row, bucket) writers are
// unique (bucket t = j-i+16; thread c owns t = 2c+e-i mod 8), so each thread
// rescales and scatters ONLY its own residue classes -> no atomics, no
// barriers in the diag path.
// ---------------------------------------------------------------------------
#define QPAD 72

struct __align__(16) AttnSmem {
    __half Qs[128][QPAD];     // SCALE*LOG2E folded
    __half Ks[2][64][QPAD];   // [j][d]   } reused as fp32 scratch in epilogue
    __half Vs[2][64][QPAD];   // [j][d]   }
    float RQs[128][NT];       // log2-domain bias
    float Wb[128][NT];
    float relvs[NT][68];
    float relks[NT][68];
    float wscale[128];
    float linv[128];
};

__device__ __forceinline__ void load_kv_tile(AttnSmem& s, int buf,
    const __half* Kb, const __half* Vb, int j0, int tid)
{
    int j = tid >> 2;
    int ch = (tid & 3) << 4;
    const __half* ks = Kb + (size_t)(j0 + j) * 64 + ch;
    const __half* vs = Vb + (size_t)(j0 + j) * 64 + ch;
    cp_async16(&s.Ks[buf][j][ch],     ks);
    cp_async16(&s.Ks[buf][j][ch + 8], ks + 8);
    cp_async16(&s.Vs[buf][j][ch],     vs);
    cp_async16(&s.Vs[buf][j][ch + 8], vs + 8);
}

__global__ __launch_bounds__(256, 2) void attn_kernel(
    const __half* __restrict__ Q, const __half* __restrict__ Kg,
    const __half* __restrict__ Vg, const float* __restrict__ relk,
    const float* __restrict__ relv, __half* __restrict__ Y)
{
    extern __shared__ char smem_raw[];
    AttnSmem& s = *reinterpret_cast<AttnSmem*>(smem_raw);
    int tid = threadIdx.x;
    int warp = tid >> 5, lane = tid & 31;
    int g = lane >> 2, c = lane & 3;
    int r0 = warp * 16 + g;
    int r1 = r0 + 8;
    int lrow = (lane & 7) + ((lane >> 3) & 1) * 8;
    int lcol = (lane >> 4) * 8;
    int vrow = (lane & 7) + (lane >> 4) * 8;
    int vcol = ((lane >> 3) & 1) * 8;

    int bh = blockIdx.y;
    int bx = blockIdx.x;
    int i0 = bx * 128;
    const __half* Qb = Q + ((size_t)bh << 16) + (size_t)i0 * 64;
    const __half* Kb = Kg + ((size_t)bh << 16);
    const __half* Vb = Vg + ((size_t)bh << 16);

    load_kv_tile(s, 0, Kb, Vb, 0, tid);
    asm volatile("cp.async.commit_group;\n");
    {
        int r = tid >> 1;
        int seg = (tid & 1) * 32;
        const __half* src = Qb + (size_t)r * 64 + seg;
        __half2 hs = __float2half2_rn(SCALEF * LOG2E);   // log2 domain
#pragma unroll
        for (int q = 0; q < 4; q++) {
            uint4 v = *(const uint4*)(src + q * 8);
            __half2* hv = (__half2*)&v;
#pragma unroll
            for (int e = 0; e < 4; e++) hv[e] = __hmul2(hv[e], hs);
            *(uint4*)&s.Qs[r][seg + q * 8] = v;
        }
    }
    for (int idx = tid; idx < NT * 64; idx += 256) {
        s.relvs[idx >> 6][idx & 63] = relv[idx];
        s.relks[idx >> 6][idx & 63] = relk[idx];
    }
    for (int idx = tid; idx < 128 * NT; idx += 256)
        s.Wb[idx / NT][idx % NT] = 0.f;
    __syncthreads();

    // RQs[i][t] = Qs(i,:) . relk(t,:)  (log2e & scale folded via Qs)
    {
        int i = tid >> 1;
        int h = (tid & 1) * 32;
        float qf[32];
#pragma unroll
        for (int dd = 0; dd < 32; dd++) qf[dd] = __half2float(s.Qs[i][h + dd]);
        for (int t = 0; t < NT; t++) {
            float p = 0.f;
#pragma unroll
            for (int dd = 0; dd < 32; dd++) p += qf[dd] * s.relks[t][h + dd];
            p += __shfl_xor_sync(0xffffffffu, p, 1);
            if ((tid & 1) == 0) s.RQs[i][t] = p;
        }
    }

    float m0s = -1e30f, m1s = -1e30f;
    float l0 = 0.f, l1 = 0.f;
    float b0a = 0.f, b0b = 0.f, b32a = 0.f, b32b = 0.f;
    float mW0 = -1e30f, mW1 = -1e30f;
    float acc[8][4];
#pragma unroll
    for (int ni = 0; ni < 8; ni++)
#pragma unroll
        for (int q = 0; q < 4; q++) acc[ni][q] = 0.f;

    int ig0 = i0 + r0, ig1 = i0 + r1;

    for (int jt = 0; jt < 16; jt++) {
        int buf = jt & 1;
        int j0 = jt * 64;
        asm volatile("cp.async.wait_group 0;\n");
        __syncthreads();
        if (jt + 1 < 16)
            load_kv_tile(s, buf ^ 1, Kb, Vb, j0 + 64, tid);
        asm volatile("cp.async.commit_group;\n");

        int dj = jt - 2 * bx;
        bool far_left  = (dj <= -2);
        bool far_right = (dj >= 3);
        bool diag = !(far_left || far_right);

        float sf[8][4];
#pragma unroll
        for (int ni = 0; ni < 8; ni++)
#pragma unroll
            for (int q = 0; q < 4; q++) sf[ni][q] = 0.f;
#pragma unroll
        for (int ks = 0; ks < 4; ks++) {
            int kc = ks * 16 + lcol;
            uint32_t a0, a1, a2, a3;
            ldsm4(a0, a1, a2, a3, &s.Qs[warp * 16 + lrow][kc]);
#pragma unroll
            for (int p = 0; p < 4; p++) {
                uint32_t b0, b1, b2, b3;
                ldsm4(b0, b1, b2, b3, &s.Ks[buf][p * 16 + lrow][kc]);
                mma_f16(sf[2 * p],     a0, a1, a2, a3, b0, b2);
                mma_f16(sf[2 * p + 1], a0, a1, a2, a3, b1, b3);
            }
        }

        if (!diag) {
            int tf = far_left ? 0 : 32;
            float rq0 = s.RQs[r0][tf], rq1 = s.RQs[r1][tf];
#pragma unroll
            for (int ni = 0; ni < 8; ni++) {
                sf[ni][0] += rq0; sf[ni][1] += rq0;
                sf[ni][2] += rq1; sf[ni][3] += rq1;
            }
        } else {
#pragma unroll
            for (int ni = 0; ni < 8; ni++) {
#pragma unroll
                for (int e = 0; e < 2; e++) {
                    int j = j0 + ni * 8 + 2 * c + e;
                    int d0 = j - ig0; d0 = d0 < -CLIPV ? -CLIPV : (d0 > CLIPV ? CLIPV : d0);
                    int d1 = j - ig1; d1 = d1 < -CLIPV ? -CLIPV : (d1 > CLIPV ? CLIPV : d1);
                    sf[ni][e]     += s.RQs[r0][d0 + CLIPV];
                    sf[ni][2 + e] += s.RQs[r1][d1 + CLIPV];
                }
            }
        }

        float mt0 = -1e30f, mt1 = -1e30f;
#pragma unroll
        for (int ni = 0; ni < 8; ni++) {
            mt0 = fmaxf(mt0, fmaxf(sf[ni][0], sf[ni][1]));
            mt1 = fmaxf(mt1, fmaxf(sf[ni][2], sf[ni][3]));
        }
        mt0 = fmaxf(mt0, __shfl_xor_sync(0xffffffffu, mt0, 1));
        mt0 = fmaxf(mt0, __shfl_xor_sync(0xffffffffu, mt0, 2));
        mt1 = fmaxf(mt1, __shfl_xor_sync(0xffffffffu, mt1, 1));
        mt1 = fmaxf(mt1, __shfl_xor_sync(0xffffffffu, mt1, 2));
        float mn0 = fmaxf(m0s, mt0), mn1 = fmaxf(m1s, mt1);
        float al0 = exp2f(m0s - mn0), al1 = exp2f(m1s - mn1);

        float rs0 = 0.f, rs1 = 0.f;
#pragma unroll
        for (int ni = 0; ni < 8; ni++) {
            sf[ni][0] = exp2f(sf[ni][0] - mn0);
            sf[ni][1] = exp2f(sf[ni][1] - mn0);
            sf[ni][2] = exp2f(sf[ni][2] - mn1);
            sf[ni][3] = exp2f(sf[ni][3] - mn1);
            rs0 += sf[ni][0] + sf[ni][1];
            rs1 += sf[ni][2] + sf[ni][3];
        }
        rs0 += __shfl_xor_sync(0xffffffffu, rs0, 1);
        rs0 += __shfl_xor_sync(0xffffffffu, rs0, 2);
        rs1 += __shfl_xor_sync(0xffffffffu, rs1, 1);
        rs1 += __shfl_xor_sync(0xffffffffu, rs1, 2);
        l0 = l0 * al0 + rs0;
        l1 = l1 * al1 + rs1;

        if (far_left) {
            b0a = b0a * al0 + rs0;  b0b = b0b * al1 + rs1;
            b32a *= al0;            b32b *= al1;
        } else if (far_right) {
            b32a = b32a * al0 + rs0; b32b = b32b * al1 + rs1;
            b0a *= al0;              b0b *= al1;
        } else {
            float c0a = 0.f, c0b = 0.f, c32a = 0.f, c32b = 0.f;
#pragma unroll
            for (int ni = 0; ni < 8; ni++) {
#pragma unroll
                for (int e = 0; e < 2; e++) {
                    int j = j0 + ni * 8 + 2 * c + e;
                    int d0 = j - ig0;
                    int d1 = j - ig1;
                    if (d0 <= -CLIPV) c0a += sf[ni][e];
                    else if (d0 >= CLIPV) c32a += sf[ni][e];
                    if (d1 <= -CLIPV) c0b += sf[ni][2 + e];
                    else if (d1 >= CLIPV) c32b += sf[ni][2 + e];
                }
            }
            c0a += __shfl_xor_sync(0xffffffffu, c0a, 1);
            c0a += __shfl_xor_sync(0xffffffffu, c0a, 2);
            c0b += __shfl_xor_sync(0xffffffffu, c0b, 1);
            c0b += __shfl_xor_sync(0xffffffffu, c0b, 2);
            c32a += __shfl_xor_sync(0xffffffffu, c32a, 1);
            c32a += __shfl_xor_sync(0xffffffffu, c32a, 2);
            c32b += __shfl_xor_sync(0xffffffffu, c32b, 1);
            c32b += __shfl_xor_sync(0xffffffffu, c32b, 2);
            b0a = b0a * al0 + c0a;   b0b = b0b * al1 + c0b;
            b32a = b32a * al0 + c32a; b32b = b32b * al1 + c32b;

            // ---- atomic-free interior-bucket update (residue-partitioned) ----
            float wsc0 = exp2f(mW0 - mn0);
            float wsc1 = exp2f(mW1 - mn1);
#pragma unroll
            for (int e = 0; e < 2; e++) {
                int rr0 = (2 * c + e - ig0) & 7;
                int rr1 = (2 * c + e - ig1) & 7;
#pragma unroll
                for (int tt = 0; tt < 4; tt++) {
                    int t0 = rr0 + 8 * tt;
                    int t1 = rr1 + 8 * tt;
                    if (t0 >= 1) s.Wb[r0][t0] *= wsc0;   // t0 <= 31 always
                    if (t1 >= 1) s.Wb[r1][t1] *= wsc1;
                }
            }
#pragma unroll
            for (int ni = 0; ni < 8; ni++) {
#pragma unroll
                for (int e = 0; e < 2; e++) {
                    int j = j0 + ni * 8 + 2 * c + e;
                    int d0 = j - ig0;
                    int d1 = j - ig1;
                    if (d0 > -CLIPV && d0 < CLIPV)
                        s.Wb[r0][d0 + CLIPV] += sf[ni][e];
                    if (d1 > -CLIPV && d1 < CLIPV)
                        s.Wb[r1][d1 + CLIPV] += sf[ni][2 + e];
                }
            }
            mW0 = mn0; mW1 = mn1;
        }
        m0s = mn0; m1s = mn1;

        uint32_t ap[4][4];
#pragma unroll
        for (int kk = 0; kk < 4; kk++) {
            ap[kk][0] = packh2(sf[2 * kk][0],     sf[2 * kk][1]);
            ap[kk][1] = packh2(sf[2 * kk][2],     sf[2 * kk][3]);
            ap[kk][2] = packh2(sf[2 * kk + 1][0], sf[2 * kk + 1][1]);
            ap[kk][3] = packh2(sf[2 * kk + 1][2], sf[2 * kk + 1][3]);
        }

#pragma unroll
        for (int ni = 0; ni < 8; ni++) {
            acc[ni][0] *= al0; acc[ni][1] *= al0;
            acc[ni][2] *= al1; acc[ni][3] *= al1;
        }
#pragma unroll
        for (int kk = 0; kk < 4; kk++) {
#pragma unroll
            for (int p = 0; p < 4; p++) {
                uint32_t b0, b1, b2, b3;
                ldsm4t(b0, b1, b2, b3, &s.Vs[buf][kk * 16 + vrow][p * 16 + vcol]);
                mma_f16(acc[2 * p],     ap[kk][0], ap[kk][1], ap[kk][2], ap[kk][3], b0, b2);
                mma_f16(acc[2 * p + 1], ap[kk][0], ap[kk][1], ap[kk][2], ap[kk][3], b1, b3);
            }
        }
    }

    if (c == 0) {
        s.Wb[r0][0] = b0a;  s.Wb[r0][32] = b32a;
        s.Wb[r1][0] = b0b;  s.Wb[r1][32] = b32b;
        s.wscale[r0] = exp2f(mW0 - m0s);
        s.wscale[r1] = exp2f(mW1 - m1s);
        s.linv[r0] = 1.f / l0;
        s.linv[r1] = 1.f / l1;
    }
    __syncthreads();

    float* scr = (float*)&s.Ks[0][0][0];
    {
        int i = tid >> 1;
        int h = (tid & 1) * 32;
        float ws = s.wscale[i];
        float sc[32];
#pragma unroll
        for (int d = 0; d < 32; d++) sc[d] = 0.f;
        for (int t = 0; t < NT; t++) {
            float w = s.Wb[i][t];
            if (t != 0 && t != 32) w *= ws;
#pragma unroll
            for (int d = 0; d < 32; d++)
                sc[d] += w * s.relvs[t][h + d];
        }
#pragma unroll
        for (int d = 0; d < 32; d++) scr[i * 68 + h + d] = sc[d];
    }
    __syncthreads();

    {
        float li0 = s.linv[r0], li1 = s.linv[r1];
        int bb = bh >> 4, hh = bh & 15;
        __half* y0 = Y + ((size_t)(bb * 1024 + i0 + r0)) * 1024 + hh * 64;
        __half* y1 = Y + ((size_t)(bb * 1024 + i0 + r1)) * 1024 + hh * 64;
#pragma unroll
        for (int ni = 0; ni < 8; ni++) {
            int col = ni * 8 + 2 * c;
            *(uint32_t*)(y0 + col) = packh2((acc[ni][0] + scr[r0 * 68 + col]) * li0,
                                            (acc[ni][1] + scr[r0 * 68 + col + 1]) * li0);
            *(uint32_t*)(y1 + col) = packh2((acc[ni][2] + scr[r1 * 68 + col]) * li1,
                                            (acc[ni][3] + scr[r1 * 68 + col + 1]) * li1);
        }
    }
}

// ---------------------------------------------------------------------------

extern "C" void kernel_launch(void* const* d_in, const int* in_sizes, int n_in,
                              void* d_out, int out_size)
{
    const float* query = (const float*)d_in[0];
    const float* key   = (const float*)d_in[1];
    const float* value = (const float*)d_in[2];
    const float* wq = (const float*)d_in[3];
    const float* bq = (const float*)d_in[4];
    const float* wk = (const float*)d_in[5];
    const float* bk = (const float*)d_in[6];
    const float* wv = (const float*)d_in[7];
    const float* bv = (const float*)d_in[8];
    const float* wo = (const float*)d_in[9];
    const float* bo = (const float*)d_in[10];
    const float* relk = (const float*)d_in[11];
    const float* relv = (const float*)d_in[12];
    float* out = (float*)d_out;

    __half *Qp, *Kp, *Vp, *Yp, *Xq, *Xk, *Xv, *Wq, *Wk, *Wv, *Wo;
    cudaGetSymbolAddress((void**)&Qp, gQ);
    cudaGetSymbolAddress((void**)&Kp, gK);
    cudaGetSymbolAddress((void**)&Vp, gV);
    cudaGetSymbolAddress((void**)&Yp, gY);
    cudaGetSymbolAddress((void**)&Xq, gXq);
    cudaGetSymbolAddress((void**)&Xk, gXk);
    cudaGetSymbolAddress((void**)&Xv, gXv);
    cudaGetSymbolAddress((void**)&Wq, gWq);
    cudaGetSymbolAddress((void**)&Wk, gWk);
    cudaGetSymbolAddress((void**)&Wv, gWv);
    cudaGetSymbolAddress((void**)&Wo, gWo);

    convert7_kernel<<<dim3(512, 7), 256>>>(query, key, value, wq, wk, wv, wo,
                                           Xq, Xk, Xv, Wq, Wk, Wv, Wo);

    cudaFuncSetAttribute(qkv_gemm_kernel, cudaFuncAttributeMaxDynamicSharedMemorySize,
                         GS_TOTAL);
    cudaFuncSetAttribute(out_gemm_kernel, cudaFuncAttributeMaxDynamicSharedMemorySize,
                         GS_TOTAL);
    cudaFuncSetAttribute(attn_kernel, cudaFuncAttributeMaxDynamicSharedMemorySize,
                         (int)sizeof(AttnSmem));

    qkv_gemm_kernel<<<dim3(8, 32, 3), 256, GS_TOTAL>>>(Xq, Xk, Xv, Wq, Wk, Wv,
                                                       bq, bk, bv, Qp, Kp, Vp);

    attn_kernel<<<dim3(8, 64), 256, sizeof(AttnSmem)>>>(Qp, Kp, Vp, relk, relv, Yp);

    out_gemm_kernel<<<dim3(8, 32), 256, GS_TOTAL>>>(Yp, Wo, bo, out);
}

// round 11
// speedup vs baseline: 8.0227x; 1.0202x over previous
#include <cuda_runtime.h>
#include <cuda_fp16.h>
#include <math.h>
#include <cstdint>

// Problem constants
#define Bn  4
#define Ln  1024
#define En  1024
#define Hn  16
#define HDn 64
#define NT  33          // 2*CLIP+1
#define CLIPV 16
#define SCALEF 0.125f   // 1/sqrt(64)
#define LOG2E 1.4426950408889634f

// Scratch (device globals; no allocation allowed)
__device__ __half gQ[Bn*Hn*Ln*HDn];   // [b][h][l][d] fp16
__device__ __half gK[Bn*Hn*Ln*HDn];
__device__ __half gV[Bn*Hn*Ln*HDn];
__device__ __half gY[Bn*Ln*En];       // [b][l][e] fp16
__device__ __half gXq[Bn*Ln*En];      // fp16 inputs
__device__ __half gXk[Bn*Ln*En];
__device__ __half gXv[Bn*Ln*En];
__device__ __half gWq[En*En];         // fp16 weights
__device__ __half gWk[En*En];
__device__ __half gWv[En*En];
__device__ __half gWo[En*En];

// ---------------------------------------------------------------------------
// helpers
// ---------------------------------------------------------------------------
__device__ __forceinline__ uint32_t packh2(float x, float y) {
    __half2 h = __floats2half2_rn(x, y);
    return *reinterpret_cast<uint32_t*>(&h);
}

__device__ __forceinline__ uint32_t h2exp2(uint32_t x) {
    uint32_t r;
    asm("ex2.approx.f16x2 %0, %1;" : "=r"(r) : "r"(x));
    return r;
}

__device__ __forceinline__ float2 h2unpack(uint32_t x) {
    __half2 h = *reinterpret_cast<__half2*>(&x);
    return __half22float2(h);
}

__device__ __forceinline__ void cp_async16(void* dst, const void* src) {
    uint32_t d = (uint32_t)__cvta_generic_to_shared(dst);
    asm volatile("cp.async.cg.shared.global [%0], [%1], 16;\n" :: "r"(d), "l"(src));
}

__device__ __forceinline__ void cp_async16_s(uint32_t dst, const void* src) {
    asm volatile("cp.async.cg.shared.global [%0], [%1], 16;\n" :: "r"(dst), "l"(src));
}

__device__ __forceinline__ void ldsm4(uint32_t& r0, uint32_t& r1,
                                      uint32_t& r2, uint32_t& r3, const void* p) {
    uint32_t a = (uint32_t)__cvta_generic_to_shared(p);
    asm volatile("ldmatrix.sync.aligned.m8n8.x4.shared.b16 {%0,%1,%2,%3}, [%4];"
                 : "=r"(r0), "=r"(r1), "=r"(r2), "=r"(r3) : "r"(a));
}

__device__ __forceinline__ void ldsm4_s(uint32_t& r0, uint32_t& r1,
                                        uint32_t& r2, uint32_t& r3, uint32_t a) {
    asm volatile("ldmatrix.sync.aligned.m8n8.x4.shared.b16 {%0,%1,%2,%3}, [%4];"
                 : "=r"(r0), "=r"(r1), "=r"(r2), "=r"(r3) : "r"(a));
}

__device__ __forceinline__ void ldsm4t(uint32_t& r0, uint32_t& r1,
                                       uint32_t& r2, uint32_t& r3, const void* p) {
    uint32_t a = (uint32_t)__cvta_generic_to_shared(p);
    asm volatile("ldmatrix.sync.aligned.m8n8.x4.trans.shared.b16 {%0,%1,%2,%3}, [%4];"
                 : "=r"(r0), "=r"(r1), "=r"(r2), "=r"(r3) : "r"(a));
}

__device__ __forceinline__ void ldsm2t(uint32_t& r0, uint32_t& r1, const void* p) {
    uint32_t a = (uint32_t)__cvta_generic_to_shared(p);
    asm volatile("ldmatrix.sync.aligned.m8n8.x2.trans.shared.b16 {%0,%1}, [%2];"
                 : "=r"(r0), "=r"(r1) : "r"(a));
}

__device__ __forceinline__ void mma_f16(float* d,
    uint32_t a0, uint32_t a1, uint32_t a2, uint32_t a3,
    uint32_t b0, uint32_t b1)
{
    asm volatile(
        "mma.sync.aligned.m16n8k16.row.col.f32.f16.f16.f32 "
        "{%0,%1,%2,%3}, {%4,%5,%6,%7}, {%8,%9}, {%0,%1,%2,%3};"
        : "+f"(d[0]), "+f"(d[1]), "+f"(d[2]), "+f"(d[3])
        : "r"(a0), "r"(a1), "r"(a2), "r"(a3), "r"(b0), "r"(b1));
}

__device__ __forceinline__ uint32_t sw128(uint32_t off) {
    return off ^ ((off >> 3) & 0x70);
}

// ---------------------------------------------------------------------------
// fp32 -> fp16 conversion of 3 inputs + 4 weights.
// ---------------------------------------------------------------------------
__global__ __launch_bounds__(256) void convert7_kernel(
    const float* __restrict__ xq, const float* __restrict__ xk,
    const float* __restrict__ xv,
    const float* __restrict__ wq, const float* __restrict__ wk,
    const float* __restrict__ wv, const float* __restrict__ wo,
    __half* __restrict__ oxq, __half* __restrict__ oxk, __half* __restrict__ oxv,
    __half* __restrict__ owq, __half* __restrict__ owk,
    __half* __restrict__ owv, __half* __restrict__ owo)
{
    int t = blockIdx.y;
    const float* src; __half* dst; int n8;
    switch (t) {
        case 0: src = xq; dst = oxq; n8 = (Bn*Ln*En)/8; break;
        case 1: src = xk; dst = oxk; n8 = (Bn*Ln*En)/8; break;
        case 2: src = xv; dst = oxv; n8 = (Bn*Ln*En)/8; break;
        case 3: src = wq; dst = owq; n8 = (En*En)/8; break;
        case 4: src = wk; dst = owk; n8 = (En*En)/8; break;
        case 5: src = wv; dst = owv; n8 = (En*En)/8; break;
        default: src = wo; dst = owo; n8 = (En*En)/8; break;
    }
    int stride = gridDim.x * 256;
    for (int i = blockIdx.x * 256 + threadIdx.x; i < n8; i += stride) {
        float4 a = ((const float4*)src)[2*i];
        float4 b = ((const float4*)src)[2*i + 1];
        uint4 o;
        o.x = packh2(a.x, a.y); o.y = packh2(a.z, a.w);
        o.z = packh2(b.x, b.y); o.w = packh2(b.z, b.w);
        ((uint4*)dst)[i] = o;
    }
}

// ---------------------------------------------------------------------------
// fp16 tensor-core GEMM (unchanged).
// ---------------------------------------------------------------------------
#define GTILE 16384                       // 128 rows * 128 bytes
#define GS_TOTAL (6 * GTILE)              // 3 stages * (A + B) = 96 KB

__device__ __forceinline__ void gemm_body(
    const __half* __restrict__ A, const __half* __restrict__ W,
    const float* __restrict__ bias, void* __restrict__ Cout, int head_layout)
{
    extern __shared__ char sm[];
    uint32_t smem = (uint32_t)__cvta_generic_to_shared(sm);
    uint32_t smA = smem, smB = smem + 3 * GTILE;
    const int Kd = 1024;

    int tid  = threadIdx.x;
    int warp = tid >> 5, lane = tid & 31;
    int wm = (warp >> 1) << 5;
    int wn = (warp & 1) << 6;
    int g = lane >> 2, c = lane & 3;
    int m0 = blockIdx.y << 7, n0 = blockIdx.x << 7;

    int lrow = (lane & 7) + ((lane >> 3) & 1) * 8;
    int lcol = (lane >> 4) * 8;

    int r = tid >> 1;
    int chbase = (tid & 1) * 4;
    const __half* Ag = A + (size_t)(m0 + r) * Kd;
    const __half* Wg = W + (size_t)(n0 + r) * Kd;

    float acc[2][8][4];
#pragma unroll
    for (int mi = 0; mi < 2; mi++)
#pragma unroll
        for (int ni = 0; ni < 8; ni++)
#pragma unroll
            for (int q = 0; q < 4; q++) acc[mi][ni][q] = 0.f;

    auto load_stage = [&](int s, int k0) {
#pragma unroll
        for (int q = 0; q < 4; q++) {
            int ch = chbase + q;
            uint32_t d = sw128((uint32_t)(r * 128 + ch * 16));
            cp_async16_s(smA + s * GTILE + d, Ag + k0 + ch * 8);
            cp_async16_s(smB + s * GTILE + d, Wg + k0 + ch * 8);
        }
    };

    load_stage(0, 0);
    asm volatile("cp.async.commit_group;\n");
    load_stage(1, 64);
    asm volatile("cp.async.commit_group;\n");

    const int NITER = Kd / 64;   // 16
    for (int t = 0; t < NITER; t++) {
        asm volatile("cp.async.wait_group 1;\n");
        __syncthreads();
        if (t + 2 < NITER) {
            int s = (t + 2) % 3;
            load_stage(s, (t + 2) * 64);
        }
        asm volatile("cp.async.commit_group;\n");

        int s = t % 3;
#pragma unroll
        for (int ks = 0; ks < 4; ks++) {
            int kc = ks * 16 + lcol;
            uint32_t af[2][4], bf[4][4];
#pragma unroll
            for (int mi = 0; mi < 2; mi++) {
                uint32_t addr = smA + s * GTILE +
                    sw128((uint32_t)((wm + mi * 16 + lrow) * 128 + kc * 2));
                ldsm4_s(af[mi][0], af[mi][1], af[mi][2], af[mi][3], addr);
            }
#pragma unroll
            for (int p = 0; p < 4; p++) {
                uint32_t addr = smB + s * GTILE +
                    sw128((uint32_t)((wn + p * 16 + lrow) * 128 + kc * 2));
                ldsm4_s(bf[p][0], bf[p][1], bf[p][2], bf[p][3], addr);
            }
#pragma unroll
            for (int mi = 0; mi < 2; mi++)
#pragma unroll
                for (int ni = 0; ni < 8; ni++) {
                    int p = ni >> 1;
                    uint32_t b0 = (ni & 1) ? bf[p][1] : bf[p][0];
                    uint32_t b1 = (ni & 1) ? bf[p][3] : bf[p][2];
                    mma_f16(acc[mi][ni], af[mi][0], af[mi][1], af[mi][2], af[mi][3],
                            b0, b1);
                }
        }
    }

#pragma unroll
    for (int mi = 0; mi < 2; mi++) {
#pragma unroll
        for (int ni = 0; ni < 8; ni++) {
            int row = m0 + wm + (mi << 4) + g;
            int col = n0 + wn + (ni << 3) + (c << 1);
            float b0 = bias[col], b1 = bias[col + 1];
            float x0 = acc[mi][ni][0] + b0, x1 = acc[mi][ni][1] + b1;
            float x2 = acc[mi][ni][2] + b0, x3 = acc[mi][ni][3] + b1;
            if (head_layout) {
                __half* C = (__half*)Cout;
                int b = row >> 10, l = row & 1023, h = col >> 6, d = col & 63;
                size_t off = (((size_t)(b * Hn + h)) << 16) + ((size_t)l << 6) + d;
                *(uint32_t*)(C + off) = packh2(x0, x1);
                int row2 = row + 8;
                int b2 = row2 >> 10, l2 = row2 & 1023;
                size_t off2 = (((size_t)(b2 * Hn + h)) << 16) + ((size_t)l2 << 6) + d;
                *(uint32_t*)(C + off2) = packh2(x2, x3);
            } else {
                float* C = (float*)Cout;
                *(float2*)(C + (size_t)row * 1024 + col) = make_float2(x0, x1);
                *(float2*)(C + (size_t)(row + 8) * 1024 + col) = make_float2(x2, x3);
            }
        }
    }
}

__global__ __launch_bounds__(256, 2) void qkv_gemm_kernel(
    const __half* __restrict__ xq, const __half* __restrict__ xk,
    const __half* __restrict__ xv,
    const __half* __restrict__ wq, const __half* __restrict__ wk,
    const __half* __restrict__ wv,
    const float* __restrict__ bq, const float* __restrict__ bk,
    const float* __restrict__ bv,
    __half* __restrict__ Q, __half* __restrict__ K, __half* __restrict__ V)
{
    if (blockIdx.z == 0)      gemm_body(xq, wq, bq, Q, 1);
    else if (blockIdx.z == 1) gemm_body(xk, wk, bk, K, 1);
    else                      gemm_body(xv, wv, bv, V, 1);
}

__global__ __launch_bounds__(256, 2) void out_gemm_kernel(
    const __half* __restrict__ Y, const __half* __restrict__ wo,
    const float* __restrict__ bo, float* __restrict__ out)
{
    gemm_body(Y, wo, bo, out, 0);
}

// ---------------------------------------------------------------------------
// fp16 tensor-core flash attention; log2-domain softmax with ex2.approx.f16x2
// (P computed directly as fp16 fragments), row sums via ones-column MMA
// (Vs padding col 64 = 1.0), atomic-free residue-partitioned bucket weights.
// ---------------------------------------------------------------------------
#define QPAD 72

struct __align__(16) AttnSmem {
    __half Qs[128][QPAD];     // SCALE*LOG2E folded
    __half Ks[2][64][QPAD];   // [j][d]   } reused as fp32 scratch in epilogue
    __half Vs[2][64][QPAD];   // [j][d]; col 64 = 1.0 (ones col), 65..71 = 0
    float RQs[128][NT];       // log2-domain bias
    float Wb[128][NT];
    float relvs[NT][68];
    float relks[NT][68];
    float wscale[128];
    float linv[128];
};

__device__ __forceinline__ void load_kv_tile(AttnSmem& s, int buf,
    const __half* Kb, const __half* Vb, int j0, int tid)
{
    int j = tid >> 2;
    int ch = (tid & 3) << 4;
    const __half* ks = Kb + (size_t)(j0 + j) * 64 + ch;
    const __half* vs = Vb + (size_t)(j0 + j) * 64 + ch;
    cp_async16(&s.Ks[buf][j][ch],     ks);
    cp_async16(&s.Ks[buf][j][ch + 8], ks + 8);
    cp_async16(&s.Vs[buf][j][ch],     vs);
    cp_async16(&s.Vs[buf][j][ch + 8], vs + 8);
}

__global__ __launch_bounds__(256, 2) void attn_kernel(
    const __half* __restrict__ Q, const __half* __restrict__ Kg,
    const __half* __restrict__ Vg, const float* __restrict__ relk,
    const float* __restrict__ relv, __half* __restrict__ Y)
{
    extern __shared__ char smem_raw[];
    AttnSmem& s = *reinterpret_cast<AttnSmem*>(smem_raw);
    int tid = threadIdx.x;
    int warp = tid >> 5, lane = tid & 31;
    int g = lane >> 2, c = lane & 3;
    int r0 = warp * 16 + g;
    int r1 = r0 + 8;
    int lrow = (lane & 7) + ((lane >> 3) & 1) * 8;
    int lcol = (lane >> 4) * 8;
    int vrow = (lane & 7) + (lane >> 4) * 8;
    int vcol = ((lane >> 3) & 1) * 8;
    int l16 = lane & 15;

    int bh = blockIdx.y;
    int bx = blockIdx.x;
    int i0 = bx * 128;
    const __half* Qb = Q + ((size_t)bh << 16) + (size_t)i0 * 64;
    const __half* Kb = Kg + ((size_t)bh << 16);
    const __half* Vb = Vg + ((size_t)bh << 16);

    load_kv_tile(s, 0, Kb, Vb, 0, tid);
    asm volatile("cp.async.commit_group;\n");
    {
        int r = tid >> 1;
        int seg = (tid & 1) * 32;
        const __half* src = Qb + (size_t)r * 64 + seg;
        __half2 hs = __float2half2_rn(SCALEF * LOG2E);   // log2 domain
#pragma unroll
        for (int q = 0; q < 4; q++) {
            uint4 v = *(const uint4*)(src + q * 8);
            __half2* hv = (__half2*)&v;
#pragma unroll
            for (int e = 0; e < 4; e++) hv[e] = __hmul2(hv[e], hs);
            *(uint4*)&s.Qs[r][seg + q * 8] = v;
        }
    }
    for (int idx = tid; idx < NT * 64; idx += 256) {
        s.relvs[idx >> 6][idx & 63] = relv[idx];
        s.relks[idx >> 6][idx & 63] = relk[idx];
    }
    for (int idx = tid; idx < 128 * NT; idx += 256)
        s.Wb[idx / NT][idx % NT] = 0.f;
    // ones column in V padding (cp.async never writes cols >= 64)
    if (tid < 128) {
        int b = tid >> 6, j = tid & 63;
        s.Vs[b][j][64] = __float2half(1.f);
#pragma unroll
        for (int d = 65; d < QPAD; d++) s.Vs[b][j][d] = __float2half(0.f);
    }
    __syncthreads();

    // RQs[i][t] = Qs(i,:) . relk(t,:)  (log2e & scale folded via Qs)
    {
        int i = tid >> 1;
        int h = (tid & 1) * 32;
        float qf[32];
#pragma unroll
        for (int dd = 0; dd < 32; dd++) qf[dd] = __half2float(s.Qs[i][h + dd]);
        for (int t = 0; t < NT; t++) {
            float p = 0.f;
#pragma unroll
            for (int dd = 0; dd < 32; dd++) p += qf[dd] * s.relks[t][h + dd];
            p += __shfl_xor_sync(0xffffffffu, p, 1);
            if ((tid & 1) == 0) s.RQs[i][t] = p;
        }
    }

    float m0s = -1e30f, m1s = -1e30f;
    float l0 = 0.f, l1 = 0.f;
    float b0a = 0.f, b0b = 0.f, b32a = 0.f, b32b = 0.f;
    float mW0 = -1e30f, mW1 = -1e30f;
    float acc[8][4];
#pragma unroll
    for (int ni = 0; ni < 8; ni++)
#pragma unroll
        for (int q = 0; q < 4; q++) acc[ni][q] = 0.f;

    int ig0 = i0 + r0, ig1 = i0 + r1;

    for (int jt = 0; jt < 16; jt++) {
        int buf = jt & 1;
        int j0 = jt * 64;
        asm volatile("cp.async.wait_group 0;\n");
        __syncthreads();
        if (jt + 1 < 16)
            load_kv_tile(s, buf ^ 1, Kb, Vb, j0 + 64, tid);
        asm volatile("cp.async.commit_group;\n");

        int dj = jt - 2 * bx;
        bool far_left  = (dj <= -2);
        bool far_right = (dj >= 3);
        bool diag = !(far_left || far_right);

        // ---- S = Q K^T ----
        float sf[8][4];
#pragma unroll
        for (int ni = 0; ni < 8; ni++)
#pragma unroll
            for (int q = 0; q < 4; q++) sf[ni][q] = 0.f;
#pragma unroll
        for (int ks = 0; ks < 4; ks++) {
            int kc = ks * 16 + lcol;
            uint32_t a0, a1, a2, a3;
            ldsm4(a0, a1, a2, a3, &s.Qs[warp * 16 + lrow][kc]);
#pragma unroll
            for (int p = 0; p < 4; p++) {
                uint32_t b0, b1, b2, b3;
                ldsm4(b0, b1, b2, b3, &s.Ks[buf][p * 16 + lrow][kc]);
                mma_f16(sf[2 * p],     a0, a1, a2, a3, b0, b2);
                mma_f16(sf[2 * p + 1], a0, a1, a2, a3, b1, b3);
            }
        }

        // ---- bias ----
        if (!diag) {
            int tf = far_left ? 0 : 32;
            float rq0 = s.RQs[r0][tf], rq1 = s.RQs[r1][tf];
#pragma unroll
            for (int ni = 0; ni < 8; ni++) {
                sf[ni][0] += rq0; sf[ni][1] += rq0;
                sf[ni][2] += rq1; sf[ni][3] += rq1;
            }
        } else {
#pragma unroll
            for (int ni = 0; ni < 8; ni++) {
#pragma unroll
                for (int e = 0; e < 2; e++) {
                    int j = j0 + ni * 8 + 2 * c + e;
                    int d0 = j - ig0; d0 = d0 < -CLIPV ? -CLIPV : (d0 > CLIPV ? CLIPV : d0);
                    int d1 = j - ig1; d1 = d1 < -CLIPV ? -CLIPV : (d1 > CLIPV ? CLIPV : d1);
                    sf[ni][e]     += s.RQs[r0][d0 + CLIPV];
                    sf[ni][2 + e] += s.RQs[r1][d1 + CLIPV];
                }
            }
        }

        // ---- max reduction ----
        float mt0 = -1e30f, mt1 = -1e30f;
#pragma unroll
        for (int ni = 0; ni < 8; ni++) {
            mt0 = fmaxf(mt0, fmaxf(sf[ni][0], sf[ni][1]));
            mt1 = fmaxf(mt1, fmaxf(sf[ni][2], sf[ni][3]));
        }
        mt0 = fmaxf(mt0, __shfl_xor_sync(0xffffffffu, mt0, 1));
        mt0 = fmaxf(mt0, __shfl_xor_sync(0xffffffffu, mt0, 2));
        mt1 = fmaxf(mt1, __shfl_xor_sync(0xffffffffu, mt1, 1));
        mt1 = fmaxf(mt1, __shfl_xor_sync(0xffffffffu, mt1, 2));
        float mn0 = fmaxf(m0s, mt0), mn1 = fmaxf(m1s, mt1);
        float al0 = exp2f(m0s - mn0), al1 = exp2f(m1s - mn1);

        // ---- P = exp2(S - m) directly in fp16 fragments ----
        uint32_t ap[4][4];
#pragma unroll
        for (int kk = 0; kk < 4; kk++) {
            ap[kk][0] = h2exp2(packh2(sf[2 * kk][0] - mn0,     sf[2 * kk][1] - mn0));
            ap[kk][1] = h2exp2(packh2(sf[2 * kk][2] - mn1,     sf[2 * kk][3] - mn1));
            ap[kk][2] = h2exp2(packh2(sf[2 * kk + 1][0] - mn0, sf[2 * kk + 1][1] - mn0));
            ap[kk][3] = h2exp2(packh2(sf[2 * kk + 1][2] - mn1, sf[2 * kk + 1][3] - mn1));
        }

        // ---- acc = acc*alpha + P @ V ; row sums via ones column ----
#pragma unroll
        for (int ni = 0; ni < 8; ni++) {
            acc[ni][0] *= al0; acc[ni][1] *= al0;
            acc[ni][2] *= al1; acc[ni][3] *= al1;
        }
        float accS[4] = {0.f, 0.f, 0.f, 0.f};
#pragma unroll
        for (int kk = 0; kk < 4; kk++) {
#pragma unroll
            for (int p = 0; p < 4; p++) {
                uint32_t b0, b1, b2, b3;
                ldsm4t(b0, b1, b2, b3, &s.Vs[buf][kk * 16 + vrow][p * 16 + vcol]);
                mma_f16(acc[2 * p],     ap[kk][0], ap[kk][1], ap[kk][2], ap[kk][3], b0, b2);
                mma_f16(acc[2 * p + 1], ap[kk][0], ap[kk][1], ap[kk][2], ap[kk][3], b1, b3);
            }
            uint32_t o0, o1;
            ldsm2t(o0, o1, &s.Vs[buf][kk * 16 + l16][64]);
            mma_f16(accS, ap[kk][0], ap[kk][1], ap[kk][2], ap[kk][3], o0, o1);
        }
        float rs0 = __shfl_sync(0xffffffffu, accS[0], lane & ~3);
        float rs1 = __shfl_sync(0xffffffffu, accS[2], lane & ~3);
        l0 = l0 * al0 + rs0;
        l1 = l1 * al1 + rs1;

        // ---- bucket weights ----
        if (far_left) {
            b0a = b0a * al0 + rs0;  b0b = b0b * al1 + rs1;
            b32a *= al0;            b32b *= al1;
        } else if (far_right) {
            b32a = b32a * al0 + rs0; b32b = b32b * al1 + rs1;
            b0a *= al0;              b0b *= al1;
        } else {
            // residue-partitioned interior rescale (atomic-free)
            float wsc0 = exp2f(mW0 - mn0);
            float wsc1 = exp2f(mW1 - mn1);
#pragma unroll
            for (int e = 0; e < 2; e++) {
                int rr0 = (2 * c + e - ig0) & 7;
                int rr1 = (2 * c + e - ig1) & 7;
#pragma unroll
                for (int tt = 0; tt < 4; tt++) {
                    int t0 = rr0 + 8 * tt;
                    int t1 = rr1 + 8 * tt;
                    if (t0 >= 1) s.Wb[r0][t0] *= wsc0;
                    if (t1 >= 1) s.Wb[r1][t1] *= wsc1;
                }
            }
            // unpack fp16 P and scatter / boundary-sum
            float c0a = 0.f, c0b = 0.f, c32a = 0.f, c32b = 0.f;
#pragma unroll
            for (int kk = 0; kk < 4; kk++) {
#pragma unroll
                for (int sub = 0; sub < 2; sub++) {   // ni = 2kk+sub
                    int ni = 2 * kk + sub;
                    float2 p0 = h2unpack(ap[kk][2 * sub]);       // row r0
                    float2 p1 = h2unpack(ap[kk][2 * sub + 1]);   // row r1
                    int jb = j0 + ni * 8 + 2 * c;
                    int d0 = jb - ig0;
                    int d1 = jb - ig1;
                    if (d0 <= -CLIPV) c0a += p0.x;
                    else if (d0 >= CLIPV) c32a += p0.x;
                    else s.Wb[r0][d0 + CLIPV] += p0.x;
                    if (d0 + 1 <= -CLIPV) c0a += p0.y;
                    else if (d0 + 1 >= CLIPV) c32a += p0.y;
                    else s.Wb[r0][d0 + 1 + CLIPV] += p0.y;
                    if (d1 <= -CLIPV) c0b += p1.x;
                    else if (d1 >= CLIPV) c32b += p1.x;
                    else s.Wb[r1][d1 + CLIPV] += p1.x;
                    if (d1 + 1 <= -CLIPV) c0b += p1.y;
                    else if (d1 + 1 >= CLIPV) c32b += p1.y;
                    else s.Wb[r1][d1 + 1 + CLIPV] += p1.y;
                }
            }
            c0a += __shfl_xor_sync(0xffffffffu, c0a, 1);
            c0a += __shfl_xor_sync(0xffffffffu, c0a, 2);
            c0b += __shfl_xor_sync(0xffffffffu, c0b, 1);
            c0b += __shfl_xor_sync(0xffffffffu, c0b, 2);
            c32a += __shfl_xor_sync(0xffffffffu, c32a, 1);
            c32a += __shfl_xor_sync(0xffffffffu, c32a, 2);
            c32b += __shfl_xor_sync(0xffffffffu, c32b, 1);
            c32b += __shfl_xor_sync(0xffffffffu, c32b, 2);
            b0a = b0a * al0 + c0a;   b0b = b0b * al1 + c0b;
            b32a = b32a * al0 + c32a; b32b = b32b * al1 + c32b;
            mW0 = mn0; mW1 = mn1;
        }
        m0s = mn0; m1s = mn1;
    }

    if (c == 0) {
        s.Wb[r0][0] = b0a;  s.Wb[r0][32] = b32a;
        s.Wb[r1][0] = b0b;  s.Wb[r1][32] = b32b;
        s.wscale[r0] = exp2f(mW0 - m0s);
        s.wscale[r1] = exp2f(mW1 - m1s);
        s.linv[r0] = 1.f / l0;
        s.linv[r1] = 1.f / l1;
    }
    __syncthreads();

    float* scr = (float*)&s.Ks[0][0][0];
    {
        int i = tid >> 1;
        int h = (tid & 1) * 32;
        float ws = s.wscale[i];
        float sc[32];
#pragma unroll
        for (int d = 0; d < 32; d++) sc[d] = 0.f;
        for (int t = 0; t < NT; t++) {
            float w = s.Wb[i][t];
            if (t != 0 && t != 32) w *= ws;
#pragma unroll
            for (int d = 0; d < 32; d++)
                sc[d] += w * s.relvs[t][h + d];
        }
#pragma unroll
        for (int d = 0; d < 32; d++) scr[i * 68 + h + d] = sc[d];
    }
    __syncthreads();

    {
        float li0 = s.linv[r0], li1 = s.linv[r1];
        int bb = bh >> 4, hh = bh & 15;
        __half* y0 = Y + ((size_t)(bb * 1024 + i0 + r0)) * 1024 + hh * 64;
        __half* y1 = Y + ((size_t)(bb * 1024 + i0 + r1)) * 1024 + hh * 64;
#pragma unroll
        for (int ni = 0; ni < 8; ni++) {
            int col = ni * 8 + 2 * c;
            *(uint32_t*)(y0 + col) = packh2((acc[ni][0] + scr[r0 * 68 + col]) * li0,
                                            (acc[ni][1] + scr[r0 * 68 + col + 1]) * li0);
            *(uint32_t*)(y1 + col) = packh2((acc[ni][2] + scr[r1 * 68 + col]) * li1,
                                            (acc[ni][3] + scr[r1 * 68 + col + 1]) * li1);
        }
    }
}

// ---------------------------------------------------------------------------

extern "C" void kernel_launch(void* const* d_in, const int* in_sizes, int n_in,
                              void* d_out, int out_size)
{
    const float* query = (const float*)d_in[0];
    const float* key   = (const float*)d_in[1];
    const float* value = (const float*)d_in[2];
    const float* wq = (const float*)d_in[3];
    const float* bq = (const float*)d_in[4];
    const float* wk = (const float*)d_in[5];
    const float* bk = (const float*)d_in[6];
    const float* wv = (const float*)d_in[7];
    const float* bv = (const float*)d_in[8];
    const float* wo = (const float*)d_in[9];
    const float* bo = (const float*)d_in[10];
    const float* relk = (const float*)d_in[11];
    const float* relv = (const float*)d_in[12];
    float* out = (float*)d_out;

    __half *Qp, *Kp, *Vp, *Yp, *Xq, *Xk, *Xv, *Wq, *Wk, *Wv, *Wo;
    cudaGetSymbolAddress((void**)&Qp, gQ);
    cudaGetSymbolAddress((void**)&Kp, gK);
    cudaGetSymbolAddress((void**)&Vp, gV);
    cudaGetSymbolAddress((void**)&Yp, gY);
    cudaGetSymbolAddress((void**)&Xq, gXq);
    cudaGetSymbolAddress((void**)&Xk, gXk);
    cudaGetSymbolAddress((void**)&Xv, gXv);
    cudaGetSymbolAddress((void**)&Wq, gWq);
    cudaGetSymbolAddress((void**)&Wk, gWk);
    cudaGetSymbolAddress((void**)&Wv, gWv);
    cudaGetSymbolAddress((void**)&Wo, gWo);

    convert7_kernel<<<dim3(512, 7), 256>>>(query, key, value, wq, wk, wv, wo,
                                           Xq, Xk, Xv, Wq, Wk, Wv, Wo);

    cudaFuncSetAttribute(qkv_gemm_kernel, cudaFuncAttributeMaxDynamicSharedMemorySize,
                         GS_TOTAL);
    cudaFuncSetAttribute(out_gemm_kernel, cudaFuncAttributeMaxDynamicSharedMemorySize,
                         GS_TOTAL);
    cudaFuncSetAttribute(attn_kernel, cudaFuncAttributeMaxDynamicSharedMemorySize,
                         (int)sizeof(AttnSmem));

    qkv_gemm_kernel<<<dim3(8, 32, 3), 256, GS_TOTAL>>>(Xq, Xk, Xv, Wq, Wk, Wv,
                                                       bq, bk, bv, Qp, Kp, Vp);

    attn_kernel<<<dim3(8, 64), 256, sizeof(AttnSmem)>>>(Qp, Kp, Vp, relk, relv, Yp);

    out_gemm_kernel<<<dim3(8, 32), 256, GS_TOTAL>>>(Yp, Wo, bo, out);
}

// round 12
// speedup vs baseline: 8.5655x; 1.0677x over previous
#include <cuda_runtime.h>
#include <cuda_fp16.h>
#include <math.h>
#include <cstdint>

// Problem constants
#define Bn  4
#define Ln  1024
#define En  1024
#define Hn  16
#define HDn 64
#define NT  33          // 2*CLIP+1
#define CLIPV 16
#define SCALEF 0.125f   // 1/sqrt(64)
#define LOG2E 1.4426950408889634f

// Scratch (device globals; no allocation allowed)
__device__ __half gQ[Bn*Hn*Ln*HDn];   // [b][h][l][d] fp16
__device__ __half gK[Bn*Hn*Ln*HDn];
__device__ __half gV[Bn*Hn*Ln*HDn];
__device__ __half gY[Bn*Ln*En];       // [b][l][e] fp16
__device__ __half gXq[Bn*Ln*En];      // fp16 inputs
__device__ __half gXk[Bn*Ln*En];
__device__ __half gXv[Bn*Ln*En];
__device__ __half gWq[En*En];         // fp16 weights
__device__ __half gWk[En*En];
__device__ __half gWv[En*En];
__device__ __half gWo[En*En];

// ---------------------------------------------------------------------------
// helpers
// ---------------------------------------------------------------------------
__device__ __forceinline__ uint32_t packh2(float x, float y) {
    __half2 h = __floats2half2_rn(x, y);
    return *reinterpret_cast<uint32_t*>(&h);
}

__device__ __forceinline__ uint32_t h2exp2(uint32_t x) {
    uint32_t r;
    asm("ex2.approx.f16x2 %0, %1;" : "=r"(r) : "r"(x));
    return r;
}

__device__ __forceinline__ float2 h2unpack(uint32_t x) {
    __half2 h = *reinterpret_cast<__half2*>(&x);
    return __half22float2(h);
}

__device__ __forceinline__ void cp_async16(void* dst, const void* src) {
    uint32_t d = (uint32_t)__cvta_generic_to_shared(dst);
    asm volatile("cp.async.cg.shared.global [%0], [%1], 16;\n" :: "r"(d), "l"(src));
}

__device__ __forceinline__ void cp_async16_s(uint32_t dst, const void* src) {
    asm volatile("cp.async.cg.shared.global [%0], [%1], 16;\n" :: "r"(dst), "l"(src));
}

__device__ __forceinline__ void ldsm4(uint32_t& r0, uint32_t& r1,
                                      uint32_t& r2, uint32_t& r3, const void* p) {
    uint32_t a = (uint32_t)__cvta_generic_to_shared(p);
    asm volatile("ldmatrix.sync.aligned.m8n8.x4.shared.b16 {%0,%1,%2,%3}, [%4];"
                 : "=r"(r0), "=r"(r1), "=r"(r2), "=r"(r3) : "r"(a));
}

__device__ __forceinline__ void ldsm4_s(uint32_t& r0, uint32_t& r1,
                                        uint32_t& r2, uint32_t& r3, uint32_t a) {
    asm volatile("ldmatrix.sync.aligned.m8n8.x4.shared.b16 {%0,%1,%2,%3}, [%4];"
                 : "=r"(r0), "=r"(r1), "=r"(r2), "=r"(r3) : "r"(a));
}

__device__ __forceinline__ void ldsm4t(uint32_t& r0, uint32_t& r1,
                                       uint32_t& r2, uint32_t& r3, const void* p) {
    uint32_t a = (uint32_t)__cvta_generic_to_shared(p);
    asm volatile("ldmatrix.sync.aligned.m8n8.x4.trans.shared.b16 {%0,%1,%2,%3}, [%4];"
                 : "=r"(r0), "=r"(r1), "=r"(r2), "=r"(r3) : "r"(a));
}

__device__ __forceinline__ void mma_f16(float* d,
    uint32_t a0, uint32_t a1, uint32_t a2, uint32_t a3,
    uint32_t b0, uint32_t b1)
{
    asm volatile(
        "mma.sync.aligned.m16n8k16.row.col.f32.f16.f16.f32 "
        "{%0,%1,%2,%3}, {%4,%5,%6,%7}, {%8,%9}, {%0,%1,%2,%3};"
        : "+f"(d[0]), "+f"(d[1]), "+f"(d[2]), "+f"(d[3])
        : "r"(a0), "r"(a1), "r"(a2), "r"(a3), "r"(b0), "r"(b1));
}

__device__ __forceinline__ uint32_t sw128(uint32_t off) {
    return off ^ ((off >> 3) & 0x70);
}

// ---------------------------------------------------------------------------
// fp32 -> fp16 conversion of 3 inputs + 4 weights.
// ---------------------------------------------------------------------------
__global__ __launch_bounds__(256) void convert7_kernel(
    const float* __restrict__ xq, const float* __restrict__ xk,
    const float* __restrict__ xv,
    const float* __restrict__ wq, const float* __restrict__ wk,
    const float* __restrict__ wv, const float* __restrict__ wo,
    __half* __restrict__ oxq, __half* __restrict__ oxk, __half* __restrict__ oxv,
    __half* __restrict__ owq, __half* __restrict__ owk,
    __half* __restrict__ owv, __half* __restrict__ owo)
{
    int t = blockIdx.y;
    const float* src; __half* dst; int n8;
    switch (t) {
        case 0: src = xq; dst = oxq; n8 = (Bn*Ln*En)/8; break;
        case 1: src = xk; dst = oxk; n8 = (Bn*Ln*En)/8; break;
        case 2: src = xv; dst = oxv; n8 = (Bn*Ln*En)/8; break;
        case 3: src = wq; dst = owq; n8 = (En*En)/8; break;
        case 4: src = wk; dst = owk; n8 = (En*En)/8; break;
        case 5: src = wv; dst = owv; n8 = (En*En)/8; break;
        default: src = wo; dst = owo; n8 = (En*En)/8; break;
    }
    int stride = gridDim.x * 256;
    for (int i = blockIdx.x * 256 + threadIdx.x; i < n8; i += stride) {
        float4 a = ((const float4*)src)[2*i];
        float4 b = ((const float4*)src)[2*i + 1];
        uint4 o;
        o.x = packh2(a.x, a.y); o.y = packh2(a.z, a.w);
        o.z = packh2(b.x, b.y); o.w = packh2(b.z, b.w);
        ((uint4*)dst)[i] = o;
    }
}

// ---------------------------------------------------------------------------
// fp16 tensor-core GEMM: k-loop fully unrolled -> literal stage indices and
// swizzled addresses (kills the per-LDSM IMAD/XOR chains).
// ---------------------------------------------------------------------------
#define GTILE 16384                       // 128 rows * 128 bytes
#define GS_TOTAL (6 * GTILE)              // 3 stages * (A + B) = 96 KB

__device__ __forceinline__ void gemm_body(
    const __half* __restrict__ A, const __half* __restrict__ W,
    const float* __restrict__ bias, void* __restrict__ Cout, int head_layout)
{
    extern __shared__ char sm[];
    uint32_t smem = (uint32_t)__cvta_generic_to_shared(sm);
    uint32_t smA = smem, smB = smem + 3 * GTILE;
    const int Kd = 1024;

    int tid  = threadIdx.x;
    int warp = tid >> 5, lane = tid & 31;
    int wm = (warp >> 1) << 5;
    int wn = (warp & 1) << 6;
    int g = lane >> 2, c = lane & 3;
    int m0 = blockIdx.y << 7, n0 = blockIdx.x << 7;

    int lrow = (lane & 7) + ((lane >> 3) & 1) * 8;
    int lcol = (lane >> 4) * 8;

    int r = tid >> 1;
    int chbase = (tid & 1) * 4;
    const __half* Ag = A + (size_t)(m0 + r) * Kd;
    const __half* Wg = W + (size_t)(n0 + r) * Kd;

    float acc[2][8][4];
#pragma unroll
    for (int mi = 0; mi < 2; mi++)
#pragma unroll
        for (int ni = 0; ni < 8; ni++)
#pragma unroll
            for (int q = 0; q < 4; q++) acc[mi][ni][q] = 0.f;

    auto load_stage = [&](int s, int k0) {
#pragma unroll
        for (int q = 0; q < 4; q++) {
            int ch = chbase + q;
            uint32_t d = sw128((uint32_t)(r * 128 + ch * 16));
            cp_async16_s(smA + s * GTILE + d, Ag + k0 + ch * 8);
            cp_async16_s(smB + s * GTILE + d, Wg + k0 + ch * 8);
        }
    };

    load_stage(0, 0);
    asm volatile("cp.async.commit_group;\n");
    load_stage(1, 64);
    asm volatile("cp.async.commit_group;\n");

    const int NITER = Kd / 64;   // 16
#pragma unroll
    for (int t = 0; t < NITER; t++) {
        asm volatile("cp.async.wait_group 1;\n");
        __syncthreads();
        if (t + 2 < NITER) {
            load_stage((t + 2) % 3, (t + 2) * 64);
        }
        asm volatile("cp.async.commit_group;\n");

        const int s = t % 3;
#pragma unroll
        for (int ks = 0; ks < 4; ks++) {
            int kc = ks * 16 + lcol;
            uint32_t af[2][4], bf[4][4];
#pragma unroll
            for (int mi = 0; mi < 2; mi++) {
                uint32_t addr = smA + s * GTILE +
                    sw128((uint32_t)((wm + mi * 16 + lrow) * 128 + kc * 2));
                ldsm4_s(af[mi][0], af[mi][1], af[mi][2], af[mi][3], addr);
            }
#pragma unroll
            for (int p = 0; p < 4; p++) {
                uint32_t addr = smB + s * GTILE +
                    sw128((uint32_t)((wn + p * 16 + lrow) * 128 + kc * 2));
                ldsm4_s(bf[p][0], bf[p][1], bf[p][2], bf[p][3], addr);
            }
#pragma unroll
            for (int mi = 0; mi < 2; mi++)
#pragma unroll
                for (int ni = 0; ni < 8; ni++) {
                    int p = ni >> 1;
                    uint32_t b0 = (ni & 1) ? bf[p][1] : bf[p][0];
                    uint32_t b1 = (ni & 1) ? bf[p][3] : bf[p][2];
                    mma_f16(acc[mi][ni], af[mi][0], af[mi][1], af[mi][2], af[mi][3],
                            b0, b1);
                }
        }
    }

#pragma unroll
    for (int mi = 0; mi < 2; mi++) {
#pragma unroll
        for (int ni = 0; ni < 8; ni++) {
            int row = m0 + wm + (mi << 4) + g;
            int col = n0 + wn + (ni << 3) + (c << 1);
            float b0 = bias[col], b1 = bias[col + 1];
            float x0 = acc[mi][ni][0] + b0, x1 = acc[mi][ni][1] + b1;
            float x2 = acc[mi][ni][2] + b0, x3 = acc[mi][ni][3] + b1;
            if (head_layout) {
                __half* C = (__half*)Cout;
                int b = row >> 10, l = row & 1023, h = col >> 6, d = col & 63;
                size_t off = (((size_t)(b * Hn + h)) << 16) + ((size_t)l << 6) + d;
                *(uint32_t*)(C + off) = packh2(x0, x1);
                int row2 = row + 8;
                int b2 = row2 >> 10, l2 = row2 & 1023;
                size_t off2 = (((size_t)(b2 * Hn + h)) << 16) + ((size_t)l2 << 6) + d;
                *(uint32_t*)(C + off2) = packh2(x2, x3);
            } else {
                float* C = (float*)Cout;
                *(float2*)(C + (size_t)row * 1024 + col) = make_float2(x0, x1);
                *(float2*)(C + (size_t)(row + 8) * 1024 + col) = make_float2(x2, x3);
            }
        }
    }
}

__global__ __launch_bounds__(256, 2) void qkv_gemm_kernel(
    const __half* __restrict__ xq, const __half* __restrict__ xk,
    const __half* __restrict__ xv,
    const __half* __restrict__ wq, const __half* __restrict__ wk,
    const __half* __restrict__ wv,
    const float* __restrict__ bq, const float* __restrict__ bk,
    const float* __restrict__ bv,
    __half* __restrict__ Q, __half* __restrict__ K, __half* __restrict__ V)
{
    if (blockIdx.z == 0)      gemm_body(xq, wq, bq, Q, 1);
    else if (blockIdx.z == 1) gemm_body(xk, wk, bk, K, 1);
    else                      gemm_body(xv, wv, bv, V, 1);
}

__global__ __launch_bounds__(256, 2) void out_gemm_kernel(
    const __half* __restrict__ Y, const __half* __restrict__ wo,
    const float* __restrict__ bo, float* __restrict__ out)
{
    gemm_body(Y, wo, bo, out, 0);
}

// ---------------------------------------------------------------------------
// fp16 tensor-core flash attention; log2-domain softmax, f16x2 exp,
// Q fragments hoisted into registers, row sums on ALU pipe (MMA pipe is the
// binding resource), atomic-free residue-partitioned bucket weights.
// ---------------------------------------------------------------------------
#define QPAD 72

struct __align__(16) AttnSmem {
    __half Qs[128][QPAD];     // SCALE*LOG2E folded
    __half Ks[2][64][QPAD];   // [j][d]   } reused as fp32 scratch in epilogue
    __half Vs[2][64][QPAD];   // [j][d]
    float RQs[128][NT];       // log2-domain bias
    float Wb[128][NT];
    float relvs[NT][68];
    float relks[NT][68];
    float wscale[128];
    float linv[128];
};

__device__ __forceinline__ void load_kv_tile(AttnSmem& s, int buf,
    const __half* Kb, const __half* Vb, int j0, int tid)
{
    int j = tid >> 2;
    int ch = (tid & 3) << 4;
    const __half* ks = Kb + (size_t)(j0 + j) * 64 + ch;
    const __half* vs = Vb + (size_t)(j0 + j) * 64 + ch;
    cp_async16(&s.Ks[buf][j][ch],     ks);
    cp_async16(&s.Ks[buf][j][ch + 8], ks + 8);
    cp_async16(&s.Vs[buf][j][ch],     vs);
    cp_async16(&s.Vs[buf][j][ch + 8], vs + 8);
}

__global__ __launch_bounds__(256, 2) void attn_kernel(
    const __half* __restrict__ Q, const __half* __restrict__ Kg,
    const __half* __restrict__ Vg, const float* __restrict__ relk,
    const float* __restrict__ relv, __half* __restrict__ Y)
{
    extern __shared__ char smem_raw[];
    AttnSmem& s = *reinterpret_cast<AttnSmem*>(smem_raw);
    int tid = threadIdx.x;
    int warp = tid >> 5, lane = tid & 31;
    int g = lane >> 2, c = lane & 3;
    int r0 = warp * 16 + g;
    int r1 = r0 + 8;
    int lrow = (lane & 7) + ((lane >> 3) & 1) * 8;
    int lcol = (lane >> 4) * 8;
    int vrow = (lane & 7) + (lane >> 4) * 8;
    int vcol = ((lane >> 3) & 1) * 8;

    int bh = blockIdx.y;
    int bx = blockIdx.x;
    int i0 = bx * 128;
    const __half* Qb = Q + ((size_t)bh << 16) + (size_t)i0 * 64;
    const __half* Kb = Kg + ((size_t)bh << 16);
    const __half* Vb = Vg + ((size_t)bh << 16);

    load_kv_tile(s, 0, Kb, Vb, 0, tid);
    asm volatile("cp.async.commit_group;\n");
    {
        int r = tid >> 1;
        int seg = (tid & 1) * 32;
        const __half* src = Qb + (size_t)r * 64 + seg;
        __half2 hs = __float2half2_rn(SCALEF * LOG2E);   // log2 domain
#pragma unroll
        for (int q = 0; q < 4; q++) {
            uint4 v = *(const uint4*)(src + q * 8);
            __half2* hv = (__half2*)&v;
#pragma unroll
            for (int e = 0; e < 4; e++) hv[e] = __hmul2(hv[e], hs);
            *(uint4*)&s.Qs[r][seg + q * 8] = v;
        }
    }
    for (int idx = tid; idx < NT * 64; idx += 256) {
        s.relvs[idx >> 6][idx & 63] = relv[idx];
        s.relks[idx >> 6][idx & 63] = relk[idx];
    }
    for (int idx = tid; idx < 128 * NT; idx += 256)
        s.Wb[idx / NT][idx % NT] = 0.f;
    __syncthreads();

    // RQs[i][t] = Qs(i,:) . relk(t,:)  (log2e & scale folded via Qs)
    {
        int i = tid >> 1;
        int h = (tid & 1) * 32;
        float qf[32];
#pragma unroll
        for (int dd = 0; dd < 32; dd++) qf[dd] = __half2float(s.Qs[i][h + dd]);
        for (int t = 0; t < NT; t++) {
            float p = 0.f;
#pragma unroll
            for (int dd = 0; dd < 32; dd++) p += qf[dd] * s.relks[t][h + dd];
            p += __shfl_xor_sync(0xffffffffu, p, 1);
            if ((tid & 1) == 0) s.RQs[i][t] = p;
        }
    }

    // hoist Q fragments (loop-invariant across j-tiles)
    uint32_t aq[4][4];
#pragma unroll
    for (int ks = 0; ks < 4; ks++)
        ldsm4(aq[ks][0], aq[ks][1], aq[ks][2], aq[ks][3],
              &s.Qs[warp * 16 + lrow][ks * 16 + lcol]);

    float m0s = -1e30f, m1s = -1e30f;
    float l0 = 0.f, l1 = 0.f;
    float b0a = 0.f, b0b = 0.f, b32a = 0.f, b32b = 0.f;
    float mW0 = -1e30f, mW1 = -1e30f;
    float acc[8][4];
#pragma unroll
    for (int ni = 0; ni < 8; ni++)
#pragma unroll
        for (int q = 0; q < 4; q++) acc[ni][q] = 0.f;

    int ig0 = i0 + r0, ig1 = i0 + r1;

#pragma unroll 2
    for (int jt = 0; jt < 16; jt++) {
        int buf = jt & 1;
        int j0 = jt * 64;
        asm volatile("cp.async.wait_group 0;\n");
        __syncthreads();
        if (jt + 1 < 16)
            load_kv_tile(s, buf ^ 1, Kb, Vb, j0 + 64, tid);
        asm volatile("cp.async.commit_group;\n");

        int dj = jt - 2 * bx;
        bool far_left  = (dj <= -2);
        bool far_right = (dj >= 3);
        bool diag = !(far_left || far_right);

        // ---- S = Q K^T ----
        float sf[8][4];
#pragma unroll
        for (int ni = 0; ni < 8; ni++)
#pragma unroll
            for (int q = 0; q < 4; q++) sf[ni][q] = 0.f;
#pragma unroll
        for (int ks = 0; ks < 4; ks++) {
            int kc = ks * 16 + lcol;
#pragma unroll
            for (int p = 0; p < 4; p++) {
                uint32_t b0, b1, b2, b3;
                ldsm4(b0, b1, b2, b3, &s.Ks[buf][p * 16 + lrow][kc]);
                mma_f16(sf[2 * p],     aq[ks][0], aq[ks][1], aq[ks][2], aq[ks][3], b0, b2);
                mma_f16(sf[2 * p + 1], aq[ks][0], aq[ks][1], aq[ks][2], aq[ks][3], b1, b3);
            }
        }

        // ---- bias ----
        if (!diag) {
            int tf = far_left ? 0 : 32;
            float rq0 = s.RQs[r0][tf], rq1 = s.RQs[r1][tf];
#pragma unroll
            for (int ni = 0; ni < 8; ni++) {
                sf[ni][0] += rq0; sf[ni][1] += rq0;
                sf[ni][2] += rq1; sf[ni][3] += rq1;
            }
        } else {
#pragma unroll
            for (int ni = 0; ni < 8; ni++) {
#pragma unroll
                for (int e = 0; e < 2; e++) {
                    int j = j0 + ni * 8 + 2 * c + e;
                    int d0 = j - ig0; d0 = d0 < -CLIPV ? -CLIPV : (d0 > CLIPV ? CLIPV : d0);
                    int d1 = j - ig1; d1 = d1 < -CLIPV ? -CLIPV : (d1 > CLIPV ? CLIPV : d1);
                    sf[ni][e]     += s.RQs[r0][d0 + CLIPV];
                    sf[ni][2 + e] += s.RQs[r1][d1 + CLIPV];
                }
            }
        }

        // ---- max reduction ----
        float mt0 = -1e30f, mt1 = -1e30f;
#pragma unroll
        for (int ni = 0; ni < 8; ni++) {
            mt0 = fmaxf(mt0, fmaxf(sf[ni][0], sf[ni][1]));
            mt1 = fmaxf(mt1, fmaxf(sf[ni][2], sf[ni][3]));
        }
        mt0 = fmaxf(mt0, __shfl_xor_sync(0xffffffffu, mt0, 1));
        mt0 = fmaxf(mt0, __shfl_xor_sync(0xffffffffu, mt0, 2));
        mt1 = fmaxf(mt1, __shfl_xor_sync(0xffffffffu, mt1, 1));
        mt1 = fmaxf(mt1, __shfl_xor_sync(0xffffffffu, mt1, 2));
        float mn0 = fmaxf(m0s, mt0), mn1 = fmaxf(m1s, mt1);
        float al0 = exp2f(m0s - mn0), al1 = exp2f(m1s - mn1);

        // ---- P = exp2(S - m) directly in fp16 fragments ----
        uint32_t ap[4][4];
#pragma unroll
        for (int kk = 0; kk < 4; kk++) {
            ap[kk][0] = h2exp2(packh2(sf[2 * kk][0] - mn0,     sf[2 * kk][1] - mn0));
            ap[kk][1] = h2exp2(packh2(sf[2 * kk][2] - mn1,     sf[2 * kk][3] - mn1));
            ap[kk][2] = h2exp2(packh2(sf[2 * kk + 1][0] - mn0, sf[2 * kk + 1][1] - mn0));
            ap[kk][3] = h2exp2(packh2(sf[2 * kk + 1][2] - mn1, sf[2 * kk + 1][3] - mn1));
        }

        // ---- row sums on ALU pipe (fp32) ----
        float rs0 = 0.f, rs1 = 0.f;
#pragma unroll
        for (int kk = 0; kk < 4; kk++) {
            float2 u0 = h2unpack(ap[kk][0]);
            float2 u1 = h2unpack(ap[kk][2]);
            rs0 += (u0.x + u0.y) + (u1.x + u1.y);
            float2 v0 = h2unpack(ap[kk][1]);
            float2 v1 = h2unpack(ap[kk][3]);
            rs1 += (v0.x + v0.y) + (v1.x + v1.y);
        }
        rs0 += __shfl_xor_sync(0xffffffffu, rs0, 1);
        rs0 += __shfl_xor_sync(0xffffffffu, rs0, 2);
        rs1 += __shfl_xor_sync(0xffffffffu, rs1, 1);
        rs1 += __shfl_xor_sync(0xffffffffu, rs1, 2);
        l0 = l0 * al0 + rs0;
        l1 = l1 * al1 + rs1;

        // ---- bucket weights ----
        if (far_left) {
            b0a = b0a * al0 + rs0;  b0b = b0b * al1 + rs1;
            b32a *= al0;            b32b *= al1;
        } else if (far_right) {
            b32a = b32a * al0 + rs0; b32b = b32b * al1 + rs1;
            b0a *= al0;              b0b *= al1;
        } else {
            // residue-partitioned interior rescale (atomic-free)
            float wsc0 = exp2f(mW0 - mn0);
            float wsc1 = exp2f(mW1 - mn1);
#pragma unroll
            for (int e = 0; e < 2; e++) {
                int rr0 = (2 * c + e - ig0) & 7;
                int rr1 = (2 * c + e - ig1) & 7;
#pragma unroll
                for (int tt = 0; tt < 4; tt++) {
                    int t0 = rr0 + 8 * tt;
                    int t1 = rr1 + 8 * tt;
                    if (t0 >= 1) s.Wb[r0][t0] *= wsc0;
                    if (t1 >= 1) s.Wb[r1][t1] *= wsc1;
                }
            }
            float c0a = 0.f, c0b = 0.f, c32a = 0.f, c32b = 0.f;
#pragma unroll
            for (int kk = 0; kk < 4; kk++) {
#pragma unroll
                for (int sub = 0; sub < 2; sub++) {   // ni = 2kk+sub
                    int ni = 2 * kk + sub;
                    float2 p0 = h2unpack(ap[kk][2 * sub]);       // row r0
                    float2 p1 = h2unpack(ap[kk][2 * sub + 1]);   // row r1
                    int jb = j0 + ni * 8 + 2 * c;
                    int d0 = jb - ig0;
                    int d1 = jb - ig1;
                    if (d0 <= -CLIPV) c0a += p0.x;
                    else if (d0 >= CLIPV) c32a += p0.x;
                    else s.Wb[r0][d0 + CLIPV] += p0.x;
                    if (d0 + 1 <= -CLIPV) c0a += p0.y;
                    else if (d0 + 1 >= CLIPV) c32a += p0.y;
                    else s.Wb[r0][d0 + 1 + CLIPV] += p0.y;
                    if (d1 <= -CLIPV) c0b += p1.x;
                    else if (d1 >= CLIPV) c32b += p1.x;
                    else s.Wb[r1][d1 + CLIPV] += p1.x;
                    if (d1 + 1 <= -CLIPV) c0b += p1.y;
                    else if (d1 + 1 >= CLIPV) c32b += p1.y;
                    else s.Wb[r1][d1 + 1 + CLIPV] += p1.y;
                }
            }
            c0a += __shfl_xor_sync(0xffffffffu, c0a, 1);
            c0a += __shfl_xor_sync(0xffffffffu, c0a, 2);
            c0b += __shfl_xor_sync(0xffffffffu, c0b, 1);
            c0b += __shfl_xor_sync(0xffffffffu, c0b, 2);
            c32a += __shfl_xor_sync(0xffffffffu, c32a, 1);
            c32a += __shfl_xor_sync(0xffffffffu, c32a, 2);
            c32b += __shfl_xor_sync(0xffffffffu, c32b, 1);
            c32b += __shfl_xor_sync(0xffffffffu, c32b, 2);
            b0a = b0a * al0 + c0a;   b0b = b0b * al1 + c0b;
            b32a = b32a * al0 + c32a; b32b = b32b * al1 + c32b;
            mW0 = mn0; mW1 = mn1;
        }
        m0s = mn0; m1s = mn1;

        // ---- acc = acc*alpha + P @ V ----
#pragma unroll
        for (int ni = 0; ni < 8; ni++) {
            acc[ni][0] *= al0; acc[ni][1] *= al0;
            acc[ni][2] *= al1; acc[ni][3] *= al1;
        }
#pragma unroll
        for (int kk = 0; kk < 4; kk++) {
#pragma unroll
            for (int p = 0; p < 4; p++) {
                uint32_t b0, b1, b2, b3;
                ldsm4t(b0, b1, b2, b3, &s.Vs[buf][kk * 16 + vrow][p * 16 + vcol]);
                mma_f16(acc[2 * p],     ap[kk][0], ap[kk][1], ap[kk][2], ap[kk][3], b0, b2);
                mma_f16(acc[2 * p + 1], ap[kk][0], ap[kk][1], ap[kk][2], ap[kk][3], b1, b3);
            }
        }
    }

    if (c == 0) {
        s.Wb[r0][0] = b0a;  s.Wb[r0][32] = b32a;
        s.Wb[r1][0] = b0b;  s.Wb[r1][32] = b32b;
        s.wscale[r0] = exp2f(mW0 - m0s);
        s.wscale[r1] = exp2f(mW1 - m1s);
        s.linv[r0] = 1.f / l0;
        s.linv[r1] = 1.f / l1;
    }
    __syncthreads();

    float* scr = (float*)&s.Ks[0][0][0];
    {
        int i = tid >> 1;
        int h = (tid & 1) * 32;
        float ws = s.wscale[i];
        float sc[32];
#pragma unroll
        for (int d = 0; d < 32; d++) sc[d] = 0.f;
        for (int t = 0; t < NT; t++) {
            float w = s.Wb[i][t];
            if (t != 0 && t != 32) w *= ws;
#pragma unroll
            for (int d = 0; d < 32; d++)
                sc[d] += w * s.relvs[t][h + d];
        }
#pragma unroll
        for (int d = 0; d < 32; d++) scr[i * 68 + h + d] = sc[d];
    }
    __syncthreads();

    {
        float li0 = s.linv[r0], li1 = s.linv[r1];
        int bb = bh >> 4, hh = bh & 15;
        __half* y0 = Y + ((size_t)(bb * 1024 + i0 + r0)) * 1024 + hh * 64;
        __half* y1 = Y + ((size_t)(bb * 1024 + i0 + r1)) * 1024 + hh * 64;
#pragma unroll
        for (int ni = 0; ni < 8; ni++) {
            int col = ni * 8 + 2 * c;
            *(uint32_t*)(y0 + col) = packh2((acc[ni][0] + scr[r0 * 68 + col]) * li0,
                                            (acc[ni][1] + scr[r0 * 68 + col + 1]) * li0);
            *(uint32_t*)(y1 + col) = packh2((acc[ni][2] + scr[r1 * 68 + col]) * li1,
                                            (acc[ni][3] + scr[r1 * 68 + col + 1]) * li1);
        }
    }
}

// ---------------------------------------------------------------------------

extern "C" void kernel_launch(void* const* d_in, const int* in_sizes, int n_in,
                              void* d_out, int out_size)
{
    const float* query = (const float*)d_in[0];
    const float* key   = (const float*)d_in[1];
    const float* value = (const float*)d_in[2];
    const float* wq = (const float*)d_in[3];
    const float* bq = (const float*)d_in[4];
    const float* wk = (const float*)d_in[5];
    const float* bk = (const float*)d_in[6];
    const float* wv = (const float*)d_in[7];
    const float* bv = (const float*)d_in[8];
    const float* wo = (const float*)d_in[9];
    const float* bo = (const float*)d_in[10];
    const float* relk = (const float*)d_in[11];
    const float* relv = (const float*)d_in[12];
    float* out = (float*)d_out;

    __half *Qp, *Kp, *Vp, *Yp, *Xq, *Xk, *Xv, *Wq, *Wk, *Wv, *Wo;
    cudaGetSymbolAddress((void**)&Qp, gQ);
    cudaGetSymbolAddress((void**)&Kp, gK);
    cudaGetSymbolAddress((void**)&Vp, gV);
    cudaGetSymbolAddress((void**)&Yp, gY);
    cudaGetSymbolAddress((void**)&Xq, gXq);
    cudaGetSymbolAddress((void**)&Xk, gXk);
    cudaGetSymbolAddress((void**)&Xv, gXv);
    cudaGetSymbolAddress((void**)&Wq, gWq);
    cudaGetSymbolAddress((void**)&Wk, gWk);
    cudaGetSymbolAddress((void**)&Wv, gWv);
    cudaGetSymbolAddress((void**)&Wo, gWo);

    convert7_kernel<<<dim3(512, 7), 256>>>(query, key, value, wq, wk, wv, wo,
                                           Xq, Xk, Xv, Wq, Wk, Wv, Wo);

    cudaFuncSetAttribute(qkv_gemm_kernel, cudaFuncAttributeMaxDynamicSharedMemorySize,
                         GS_TOTAL);
    cudaFuncSetAttribute(out_gemm_kernel, cudaFuncAttributeMaxDynamicSharedMemorySize,
                         GS_TOTAL);
    cudaFuncSetAttribute(attn_kernel, cudaFuncAttributeMaxDynamicSharedMemorySize,
                         (int)sizeof(AttnSmem));

    qkv_gemm_kernel<<<dim3(8, 32, 3), 256, GS_TOTAL>>>(Xq, Xk, Xv, Wq, Wk, Wv,
                                                       bq, bk, bv, Qp, Kp, Vp);

    attn_kernel<<<dim3(8, 64), 256, sizeof(AttnSmem)>>>(Qp, Kp, Vp, relk, relv, Yp);

    out_gemm_kernel<<<dim3(8, 32), 256, GS_TOTAL>>>(Yp, Wo, bo, out);
}

// round 13
// speedup vs baseline: 8.6269x; 1.0072x over previous
#include <cuda_runtime.h>
#include <cuda_fp16.h>
#include <math.h>
#include <cstdint>

// Problem constants
#define Bn  4
#define Ln  1024
#define En  1024
#define Hn  16
#define HDn 64
#define NT  33          // 2*CLIP+1
#define CLIPV 16
#define SCALEF 0.125f   // 1/sqrt(64)
#define LOG2E 1.4426950408889634f

// Scratch (device globals; no allocation allowed)
__device__ __half gQ[Bn*Hn*Ln*HDn];   // [b][h][l][d] fp16
__device__ __half gK[Bn*Hn*Ln*HDn];
__device__ __half gV[Bn*Hn*Ln*HDn];
__device__ __half gY[Bn*Ln*En];       // [b][l][e] fp16
__device__ __half gXq[Bn*Ln*En];      // fp16 inputs
__device__ __half gXk[Bn*Ln*En];
__device__ __half gXv[Bn*Ln*En];
__device__ __half gWq[En*En];         // fp16 weights
__device__ __half gWk[En*En];
__device__ __half gWv[En*En];
__device__ __half gWo[En*En];

// ---------------------------------------------------------------------------
// helpers
// ---------------------------------------------------------------------------
__device__ __forceinline__ uint32_t packh2(float x, float y) {
    __half2 h = __floats2half2_rn(x, y);
    return *reinterpret_cast<uint32_t*>(&h);
}

__device__ __forceinline__ uint32_t h2exp2(uint32_t x) {
    uint32_t r;
    asm("ex2.approx.f16x2 %0, %1;" : "=r"(r) : "r"(x));
    return r;
}

__device__ __forceinline__ float2 h2unpack(uint32_t x) {
    __half2 h = *reinterpret_cast<__half2*>(&x);
    return __half22float2(h);
}

__device__ __forceinline__ void cp_async16(void* dst, const void* src) {
    uint32_t d = (uint32_t)__cvta_generic_to_shared(dst);
    asm volatile("cp.async.cg.shared.global [%0], [%1], 16;\n" :: "r"(d), "l"(src));
}

__device__ __forceinline__ void cp_async16_s(uint32_t dst, const void* src) {
    asm volatile("cp.async.cg.shared.global [%0], [%1], 16;\n" :: "r"(dst), "l"(src));
}

__device__ __forceinline__ void ldsm4(uint32_t& r0, uint32_t& r1,
                                      uint32_t& r2, uint32_t& r3, const void* p) {
    uint32_t a = (uint32_t)__cvta_generic_to_shared(p);
    asm volatile("ldmatrix.sync.aligned.m8n8.x4.shared.b16 {%0,%1,%2,%3}, [%4];"
                 : "=r"(r0), "=r"(r1), "=r"(r2), "=r"(r3) : "r"(a));
}

__device__ __forceinline__ void ldsm4_s(uint32_t& r0, uint32_t& r1,
                                        uint32_t& r2, uint32_t& r3, uint32_t a) {
    asm volatile("ldmatrix.sync.aligned.m8n8.x4.shared.b16 {%0,%1,%2,%3}, [%4];"
                 : "=r"(r0), "=r"(r1), "=r"(r2), "=r"(r3) : "r"(a));
}

__device__ __forceinline__ void ldsm4t(uint32_t& r0, uint32_t& r1,
                                       uint32_t& r2, uint32_t& r3, const void* p) {
    uint32_t a = (uint32_t)__cvta_generic_to_shared(p);
    asm volatile("ldmatrix.sync.aligned.m8n8.x4.trans.shared.b16 {%0,%1,%2,%3}, [%4];"
                 : "=r"(r0), "=r"(r1), "=r"(r2), "=r"(r3) : "r"(a));
}

__device__ __forceinline__ void mma_f16(float* d,
    uint32_t a0, uint32_t a1, uint32_t a2, uint32_t a3,
    uint32_t b0, uint32_t b1)
{
    asm volatile(
        "mma.sync.aligned.m16n8k16.row.col.f32.f16.f16.f32 "
        "{%0,%1,%2,%3}, {%4,%5,%6,%7}, {%8,%9}, {%0,%1,%2,%3};"
        : "+f"(d[0]), "+f"(d[1]), "+f"(d[2]), "+f"(d[3])
        : "r"(a0), "r"(a1), "r"(a2), "r"(a3), "r"(b0), "r"(b1));
}

__device__ __forceinline__ uint32_t sw128(uint32_t off) {
    return off ^ ((off >> 3) & 0x70);
}

// ---------------------------------------------------------------------------
// fp32 -> fp16 conversion of 3 inputs + 4 weights.
// ---------------------------------------------------------------------------
__global__ __launch_bounds__(256) void convert7_kernel(
    const float* __restrict__ xq, const float* __restrict__ xk,
    const float* __restrict__ xv,
    const float* __restrict__ wq, const float* __restrict__ wk,
    const float* __restrict__ wv, const float* __restrict__ wo,
    __half* __restrict__ oxq, __half* __restrict__ oxk, __half* __restrict__ oxv,
    __half* __restrict__ owq, __half* __restrict__ owk,
    __half* __restrict__ owv, __half* __restrict__ owo)
{
    int t = blockIdx.y;
    const float* src; __half* dst; int n8;
    switch (t) {
        case 0: src = xq; dst = oxq; n8 = (Bn*Ln*En)/8; break;
        case 1: src = xk; dst = oxk; n8 = (Bn*Ln*En)/8; break;
        case 2: src = xv; dst = oxv; n8 = (Bn*Ln*En)/8; break;
        case 3: src = wq; dst = owq; n8 = (En*En)/8; break;
        case 4: src = wk; dst = owk; n8 = (En*En)/8; break;
        case 5: src = wv; dst = owv; n8 = (En*En)/8; break;
        default: src = wo; dst = owo; n8 = (En*En)/8; break;
    }
    int stride = gridDim.x * 256;
    for (int i = blockIdx.x * 256 + threadIdx.x; i < n8; i += stride) {
        float4 a = ((const float4*)src)[2*i];
        float4 b = ((const float4*)src)[2*i + 1];
        uint4 o;
        o.x = packh2(a.x, a.y); o.y = packh2(a.z, a.w);
        o.z = packh2(b.x, b.y); o.w = packh2(b.z, b.w);
        ((uint4*)dst)[i] = o;
    }
}

// ---------------------------------------------------------------------------
// fp16 tensor-core GEMM (unchanged from round 12 — fully unrolled k-loop).
// ---------------------------------------------------------------------------
#define GTILE 16384                       // 128 rows * 128 bytes
#define GS_TOTAL (6 * GTILE)              // 3 stages * (A + B) = 96 KB

__device__ __forceinline__ void gemm_body(
    const __half* __restrict__ A, const __half* __restrict__ W,
    const float* __restrict__ bias, void* __restrict__ Cout, int head_layout)
{
    extern __shared__ char sm[];
    uint32_t smem = (uint32_t)__cvta_generic_to_shared(sm);
    uint32_t smA = smem, smB = smem + 3 * GTILE;
    const int Kd = 1024;

    int tid  = threadIdx.x;
    int warp = tid >> 5, lane = tid & 31;
    int wm = (warp >> 1) << 5;
    int wn = (warp & 1) << 6;
    int g = lane >> 2, c = lane & 3;
    int m0 = blockIdx.y << 7, n0 = blockIdx.x << 7;

    int lrow = (lane & 7) + ((lane >> 3) & 1) * 8;
    int lcol = (lane >> 4) * 8;

    int r = tid >> 1;
    int chbase = (tid & 1) * 4;
    const __half* Ag = A + (size_t)(m0 + r) * Kd;
    const __half* Wg = W + (size_t)(n0 + r) * Kd;

    float acc[2][8][4];
#pragma unroll
    for (int mi = 0; mi < 2; mi++)
#pragma unroll
        for (int ni = 0; ni < 8; ni++)
#pragma unroll
            for (int q = 0; q < 4; q++) acc[mi][ni][q] = 0.f;

    auto load_stage = [&](int s, int k0) {
#pragma unroll
        for (int q = 0; q < 4; q++) {
            int ch = chbase + q;
            uint32_t d = sw128((uint32_t)(r * 128 + ch * 16));
            cp_async16_s(smA + s * GTILE + d, Ag + k0 + ch * 8);
            cp_async16_s(smB + s * GTILE + d, Wg + k0 + ch * 8);
        }
    };

    load_stage(0, 0);
    asm volatile("cp.async.commit_group;\n");
    load_stage(1, 64);
    asm volatile("cp.async.commit_group;\n");

    const int NITER = Kd / 64;   // 16
#pragma unroll
    for (int t = 0; t < NITER; t++) {
        asm volatile("cp.async.wait_group 1;\n");
        __syncthreads();
        if (t + 2 < NITER) {
            load_stage((t + 2) % 3, (t + 2) * 64);
        }
        asm volatile("cp.async.commit_group;\n");

        const int s = t % 3;
#pragma unroll
        for (int ks = 0; ks < 4; ks++) {
            int kc = ks * 16 + lcol;
            uint32_t af[2][4], bf[4][4];
#pragma unroll
            for (int mi = 0; mi < 2; mi++) {
                uint32_t addr = smA + s * GTILE +
                    sw128((uint32_t)((wm + mi * 16 + lrow) * 128 + kc * 2));
                ldsm4_s(af[mi][0], af[mi][1], af[mi][2], af[mi][3], addr);
            }
#pragma unroll
            for (int p = 0; p < 4; p++) {
                uint32_t addr = smB + s * GTILE +
                    sw128((uint32_t)((wn + p * 16 + lrow) * 128 + kc * 2));
                ldsm4_s(bf[p][0], bf[p][1], bf[p][2], bf[p][3], addr);
            }
#pragma unroll
            for (int mi = 0; mi < 2; mi++)
#pragma unroll
                for (int ni = 0; ni < 8; ni++) {
                    int p = ni >> 1;
                    uint32_t b0 = (ni & 1) ? bf[p][1] : bf[p][0];
                    uint32_t b1 = (ni & 1) ? bf[p][3] : bf[p][2];
                    mma_f16(acc[mi][ni], af[mi][0], af[mi][1], af[mi][2], af[mi][3],
                            b0, b1);
                }
        }
    }

#pragma unroll
    for (int mi = 0; mi < 2; mi++) {
#pragma unroll
        for (int ni = 0; ni < 8; ni++) {
            int row = m0 + wm + (mi << 4) + g;
            int col = n0 + wn + (ni << 3) + (c << 1);
            float b0 = bias[col], b1 = bias[col + 1];
            float x0 = acc[mi][ni][0] + b0, x1 = acc[mi][ni][1] + b1;
            float x2 = acc[mi][ni][2] + b0, x3 = acc[mi][ni][3] + b1;
            if (head_layout) {
                __half* C = (__half*)Cout;
                int b = row >> 10, l = row & 1023, h = col >> 6, d = col & 63;
                size_t off = (((size_t)(b * Hn + h)) << 16) + ((size_t)l << 6) + d;
                *(uint32_t*)(C + off) = packh2(x0, x1);
                int row2 = row + 8;
                int b2 = row2 >> 10, l2 = row2 & 1023;
                size_t off2 = (((size_t)(b2 * Hn + h)) << 16) + ((size_t)l2 << 6) + d;
                *(uint32_t*)(C + off2) = packh2(x2, x3);
            } else {
                float* C = (float*)Cout;
                *(float2*)(C + (size_t)row * 1024 + col) = make_float2(x0, x1);
                *(float2*)(C + (size_t)(row + 8) * 1024 + col) = make_float2(x2, x3);
            }
        }
    }
}

__global__ __launch_bounds__(256, 2) void qkv_gemm_kernel(
    const __half* __restrict__ xq, const __half* __restrict__ xk,
    const __half* __restrict__ xv,
    const __half* __restrict__ wq, const __half* __restrict__ wk,
    const __half* __restrict__ wv,
    const float* __restrict__ bq, const float* __restrict__ bk,
    const float* __restrict__ bv,
    __half* __restrict__ Q, __half* __restrict__ K, __half* __restrict__ V)
{
    if (blockIdx.z == 0)      gemm_body(xq, wq, bq, Q, 1);
    else if (blockIdx.z == 1) gemm_body(xk, wk, bk, K, 1);
    else                      gemm_body(xv, wv, bv, V, 1);
}

__global__ __launch_bounds__(256, 2) void out_gemm_kernel(
    const __half* __restrict__ Y, const __half* __restrict__ wo,
    const float* __restrict__ bo, float* __restrict__ out)
{
    gemm_body(Y, wo, bo, out, 0);
}

// ---------------------------------------------------------------------------
// fp16 tensor-core flash attention; log2-domain softmax, f16x2 exp, hoisted
// Q fragments, warp-vote alpha skip, bias folded into exp offset (far tiles),
// atomic-free residue-partitioned bucket weights.
// ---------------------------------------------------------------------------
#define QPAD 72

struct __align__(16) AttnSmem {
    __half Qs[128][QPAD];     // SCALE*LOG2E folded
    __half Ks[2][64][QPAD];   // [j][d]   } reused as fp32 scratch in epilogue
    __half Vs[2][64][QPAD];   // [j][d]
    float RQs[128][NT];       // log2-domain bias
    float Wb[128][NT];
    float relvs[NT][68];
    float relks[NT][68];
    float wscale[128];
    float linv[128];
};

__device__ __forceinline__ void load_kv_tile(AttnSmem& s, int buf,
    const __half* Kb, const __half* Vb, int j0, int tid)
{
    int j = tid >> 2;
    int ch = (tid & 3) << 4;
    const __half* ks = Kb + (size_t)(j0 + j) * 64 + ch;
    const __half* vs = Vb + (size_t)(j0 + j) * 64 + ch;
    cp_async16(&s.Ks[buf][j][ch],     ks);
    cp_async16(&s.Ks[buf][j][ch + 8], ks + 8);
    cp_async16(&s.Vs[buf][j][ch],     vs);
    cp_async16(&s.Vs[buf][j][ch + 8], vs + 8);
}

__global__ __launch_bounds__(256, 2) void attn_kernel(
    const __half* __restrict__ Q, const __half* __restrict__ Kg,
    const __half* __restrict__ Vg, const float* __restrict__ relk,
    const float* __restrict__ relv, __half* __restrict__ Y)
{
    extern __shared__ char smem_raw[];
    AttnSmem& s = *reinterpret_cast<AttnSmem*>(smem_raw);
    int tid = threadIdx.x;
    int warp = tid >> 5, lane = tid & 31;
    int g = lane >> 2, c = lane & 3;
    int r0 = warp * 16 + g;
    int r1 = r0 + 8;
    int lrow = (lane & 7) + ((lane >> 3) & 1) * 8;
    int lcol = (lane >> 4) * 8;
    int vrow = (lane & 7) + (lane >> 4) * 8;
    int vcol = ((lane >> 3) & 1) * 8;

    int bh = blockIdx.y;
    int bx = blockIdx.x;
    int i0 = bx * 128;
    const __half* Qb = Q + ((size_t)bh << 16) + (size_t)i0 * 64;
    const __half* Kb = Kg + ((size_t)bh << 16);
    const __half* Vb = Vg + ((size_t)bh << 16);

    load_kv_tile(s, 0, Kb, Vb, 0, tid);
    asm volatile("cp.async.commit_group;\n");
    {
        int r = tid >> 1;
        int seg = (tid & 1) * 32;
        const __half* src = Qb + (size_t)r * 64 + seg;
        __half2 hs = __float2half2_rn(SCALEF * LOG2E);   // log2 domain
#pragma unroll
        for (int q = 0; q < 4; q++) {
            uint4 v = *(const uint4*)(src + q * 8);
            __half2* hv = (__half2*)&v;
#pragma unroll
            for (int e = 0; e < 4; e++) hv[e] = __hmul2(hv[e], hs);
            *(uint4*)&s.Qs[r][seg + q * 8] = v;
        }
    }
    for (int idx = tid; idx < NT * 64; idx += 256) {
        s.relvs[idx >> 6][idx & 63] = relv[idx];
        s.relks[idx >> 6][idx & 63] = relk[idx];
    }
    for (int idx = tid; idx < 128 * NT; idx += 256)
        s.Wb[idx / NT][idx % NT] = 0.f;
    __syncthreads();

    // RQs[i][t] = Qs(i,:) . relk(t,:)  (log2e & scale folded via Qs)
    {
        int i = tid >> 1;
        int h = (tid & 1) * 32;
        float qf[32];
#pragma unroll
        for (int dd = 0; dd < 32; dd++) qf[dd] = __half2float(s.Qs[i][h + dd]);
        for (int t = 0; t < NT; t++) {
            float p = 0.f;
#pragma unroll
            for (int dd = 0; dd < 32; dd++) p += qf[dd] * s.relks[t][h + dd];
            p += __shfl_xor_sync(0xffffffffu, p, 1);
            if ((tid & 1) == 0) s.RQs[i][t] = p;
        }
    }

    // hoist Q fragments (loop-invariant across j-tiles)
    uint32_t aq[4][4];
#pragma unroll
    for (int ks = 0; ks < 4; ks++)
        ldsm4(aq[ks][0], aq[ks][1], aq[ks][2], aq[ks][3],
              &s.Qs[warp * 16 + lrow][ks * 16 + lcol]);

    float m0s = -1e30f, m1s = -1e30f;
    float l0 = 0.f, l1 = 0.f;
    float b0a = 0.f, b0b = 0.f, b32a = 0.f, b32b = 0.f;
    float mW0 = -1e30f, mW1 = -1e30f;
    float acc[8][4];
#pragma unroll
    for (int ni = 0; ni < 8; ni++)
#pragma unroll
        for (int q = 0; q < 4; q++) acc[ni][q] = 0.f;

    int ig0 = i0 + r0, ig1 = i0 + r1;

#pragma unroll 2
    for (int jt = 0; jt < 16; jt++) {
        int buf = jt & 1;
        int j0 = jt * 64;
        asm volatile("cp.async.wait_group 0;\n");
        __syncthreads();
        if (jt + 1 < 16)
            load_kv_tile(s, buf ^ 1, Kb, Vb, j0 + 64, tid);
        asm volatile("cp.async.commit_group;\n");

        int dj = jt - 2 * bx;
        bool far_left  = (dj <= -2);
        bool far_right = (dj >= 3);
        bool diag = !(far_left || far_right);

        // ---- S = Q K^T ----
        float sf[8][4];
#pragma unroll
        for (int ni = 0; ni < 8; ni++)
#pragma unroll
            for (int q = 0; q < 4; q++) sf[ni][q] = 0.f;
#pragma unroll
        for (int ks = 0; ks < 4; ks++) {
            int kc = ks * 16 + lcol;
#pragma unroll
            for (int p = 0; p < 4; p++) {
                uint32_t b0, b1, b2, b3;
                ldsm4(b0, b1, b2, b3, &s.Ks[buf][p * 16 + lrow][kc]);
                mma_f16(sf[2 * p],     aq[ks][0], aq[ks][1], aq[ks][2], aq[ks][3], b0, b2);
                mma_f16(sf[2 * p + 1], aq[ks][0], aq[ks][1], aq[ks][2], aq[ks][3], b1, b3);
            }
        }

        // ---- diag tiles: per-element bias before max ----
        if (diag) {
#pragma unroll
            for (int ni = 0; ni < 8; ni++) {
#pragma unroll
                for (int e = 0; e < 2; e++) {
                    int j = j0 + ni * 8 + 2 * c + e;
                    int d0 = j - ig0; d0 = d0 < -CLIPV ? -CLIPV : (d0 > CLIPV ? CLIPV : d0);
                    int d1 = j - ig1; d1 = d1 < -CLIPV ? -CLIPV : (d1 > CLIPV ? CLIPV : d1);
                    sf[ni][e]     += s.RQs[r0][d0 + CLIPV];
                    sf[ni][2 + e] += s.RQs[r1][d1 + CLIPV];
                }
            }
        }

        // ---- max reduction (raw for far tiles; bias folded as offset) ----
        float mt0 = -1e30f, mt1 = -1e30f;
#pragma unroll
        for (int ni = 0; ni < 8; ni++) {
            mt0 = fmaxf(mt0, fmaxf(sf[ni][0], sf[ni][1]));
            mt1 = fmaxf(mt1, fmaxf(sf[ni][2], sf[ni][3]));
        }
        mt0 = fmaxf(mt0, __shfl_xor_sync(0xffffffffu, mt0, 1));
        mt0 = fmaxf(mt0, __shfl_xor_sync(0xffffffffu, mt0, 2));
        mt1 = fmaxf(mt1, __shfl_xor_sync(0xffffffffu, mt1, 1));
        mt1 = fmaxf(mt1, __shfl_xor_sync(0xffffffffu, mt1, 2));

        float mn0, mn1, off0, off1;
        if (!diag) {
            int tf = far_left ? 0 : 32;
            float rq0 = s.RQs[r0][tf], rq1 = s.RQs[r1][tf];
            mn0 = fmaxf(m0s, mt0 + rq0);
            mn1 = fmaxf(m1s, mt1 + rq1);
            off0 = mn0 - rq0; off1 = mn1 - rq1;
        } else {
            mn0 = fmaxf(m0s, mt0);
            mn1 = fmaxf(m1s, mt1);
            off0 = mn0; off1 = mn1;
        }

        // ---- warp-vote alpha skip ----
        bool nochg = (mn0 == m0s) && (mn1 == m1s);
        bool skip = __all_sync(0xffffffffu, nochg);
        float al0 = 1.f, al1 = 1.f;
        if (!skip) {
            al0 = exp2f(m0s - mn0);
            al1 = exp2f(m1s - mn1);
        }

        // ---- P = exp2(S - off) directly in fp16 fragments ----
        uint32_t ap[4][4];
#pragma unroll
        for (int kk = 0; kk < 4; kk++) {
            ap[kk][0] = h2exp2(packh2(sf[2 * kk][0] - off0,     sf[2 * kk][1] - off0));
            ap[kk][1] = h2exp2(packh2(sf[2 * kk][2] - off1,     sf[2 * kk][3] - off1));
            ap[kk][2] = h2exp2(packh2(sf[2 * kk + 1][0] - off0, sf[2 * kk + 1][1] - off0));
            ap[kk][3] = h2exp2(packh2(sf[2 * kk + 1][2] - off1, sf[2 * kk + 1][3] - off1));
        }

        // ---- row sums on ALU pipe (fp32) ----
        float rs0 = 0.f, rs1 = 0.f;
#pragma unroll
        for (int kk = 0; kk < 4; kk++) {
            float2 u0 = h2unpack(ap[kk][0]);
            float2 u1 = h2unpack(ap[kk][2]);
            rs0 += (u0.x + u0.y) + (u1.x + u1.y);
            float2 v0 = h2unpack(ap[kk][1]);
            float2 v1 = h2unpack(ap[kk][3]);
            rs1 += (v0.x + v0.y) + (v1.x + v1.y);
        }
        rs0 += __shfl_xor_sync(0xffffffffu, rs0, 1);
        rs0 += __shfl_xor_sync(0xffffffffu, rs0, 2);
        rs1 += __shfl_xor_sync(0xffffffffu, rs1, 1);
        rs1 += __shfl_xor_sync(0xffffffffu, rs1, 2);
        l0 = l0 * al0 + rs0;
        l1 = l1 * al1 + rs1;

        // ---- bucket weights ----
        if (far_left) {
            b0a = b0a * al0 + rs0;  b0b = b0b * al1 + rs1;
            b32a *= al0;            b32b *= al1;
        } else if (far_right) {
            b32a = b32a * al0 + rs0; b32b = b32b * al1 + rs1;
            b0a *= al0;              b0b *= al1;
        } else {
            // interior rescale to new reference max (independent of vote —
            // reference is the LAST DIAG tile's max, not the previous tile's)
            float wsc0 = exp2f(mW0 - mn0);
            float wsc1 = exp2f(mW1 - mn1);
#pragma unroll
            for (int e = 0; e < 2; e++) {
                int rr0 = (2 * c + e - ig0) & 7;
                int rr1 = (2 * c + e - ig1) & 7;
#pragma unroll
                for (int tt = 0; tt < 4; tt++) {
                    int t0 = rr0 + 8 * tt;
                    int t1 = rr1 + 8 * tt;
                    if (t0 >= 1) s.Wb[r0][t0] *= wsc0;
                    if (t1 >= 1) s.Wb[r1][t1] *= wsc1;
                }
            }
            float c0a = 0.f, c0b = 0.f, c32a = 0.f, c32b = 0.f;
#pragma unroll
            for (int kk = 0; kk < 4; kk++) {
#pragma unroll
                for (int sub = 0; sub < 2; sub++) {   // ni = 2kk+sub
                    int ni = 2 * kk + sub;
                    float2 p0 = h2unpack(ap[kk][2 * sub]);       // row r0
                    float2 p1 = h2unpack(ap[kk][2 * sub + 1]);   // row r1
                    int jb = j0 + ni * 8 + 2 * c;
                    int d0 = jb - ig0;
                    int d1 = jb - ig1;
                    if (d0 <= -CLIPV) c0a += p0.x;
                    else if (d0 >= CLIPV) c32a += p0.x;
                    else s.Wb[r0][d0 + CLIPV] += p0.x;
                    if (d0 + 1 <= -CLIPV) c0a += p0.y;
                    else if (d0 + 1 >= CLIPV) c32a += p0.y;
                    else s.Wb[r0][d0 + 1 + CLIPV] += p0.y;
                    if (d1 <= -CLIPV) c0b += p1.x;
                    else if (d1 >= CLIPV) c32b += p1.x;
                    else s.Wb[r1][d1 + CLIPV] += p1.x;
                    if (d1 + 1 <= -CLIPV) c0b += p1.y;
                    else if (d1 + 1 >= CLIPV) c32b += p1.y;
                    else s.Wb[r1][d1 + 1 + CLIPV] += p1.y;
                }
            }
            c0a += __shfl_xor_sync(0xffffffffu, c0a, 1);
            c0a += __shfl_xor_sync(0xffffffffu, c0a, 2);
            c0b += __shfl_xor_sync(0xffffffffu, c0b, 1);
            c0b += __shfl_xor_sync(0xffffffffu, c0b, 2);
            c32a += __shfl_xor_sync(0xffffffffu, c32a, 1);
            c32a += __shfl_xor_sync(0xffffffffu, c32a, 2);
            c32b += __shfl_xor_sync(0xffffffffu, c32b, 1);
            c32b += __shfl_xor_sync(0xffffffffu, c32b, 2);
            b0a = b0a * al0 + c0a;   b0b = b0b * al1 + c0b;
            b32a = b32a * al0 + c32a; b32b = b32b * al1 + c32b;
            mW0 = mn0; mW1 = mn1;
        }
        m0s = mn0; m1s = mn1;

        // ---- acc = acc*alpha (skipped when max unchanged) + P @ V ----
        if (!skip) {
#pragma unroll
            for (int ni = 0; ni < 8; ni++) {
                acc[ni][0] *= al0; acc[ni][1] *= al0;
                acc[ni][2] *= al1; acc[ni][3] *= al1;
            }
        }
#pragma unroll
        for (int kk = 0; kk < 4; kk++) {
#pragma unroll
            for (int p = 0; p < 4; p++) {
                uint32_t b0, b1, b2, b3;
                ldsm4t(b0, b1, b2, b3, &s.Vs[buf][kk * 16 + vrow][p * 16 + vcol]);
                mma_f16(acc[2 * p],     ap[kk][0], ap[kk][1], ap[kk][2], ap[kk][3], b0, b2);
                mma_f16(acc[2 * p + 1], ap[kk][0], ap[kk][1], ap[kk][2], ap[kk][3], b1, b3);
            }
        }
    }

    if (c == 0) {
        s.Wb[r0][0] = b0a;  s.Wb[r0][32] = b32a;
        s.Wb[r1][0] = b0b;  s.Wb[r1][32] = b32b;
        s.wscale[r0] = exp2f(mW0 - m0s);
        s.wscale[r1] = exp2f(mW1 - m1s);
        s.linv[r0] = 1.f / l0;
        s.linv[r1] = 1.f / l1;
    }
    __syncthreads();

    float* scr = (float*)&s.Ks[0][0][0];
    {
        int i = tid >> 1;
        int h = (tid & 1) * 32;
        float ws = s.wscale[i];
        float sc[32];
#pragma unroll
        for (int d = 0; d < 32; d++) sc[d] = 0.f;
        for (int t = 0; t < NT; t++) {
            float w = s.Wb[i][t];
            if (t != 0 && t != 32) w *= ws;
#pragma unroll
            for (int d = 0; d < 32; d++)
                sc[d] += w * s.relvs[t][h + d];
        }
#pragma unroll
        for (int d = 0; d < 32; d++) scr[i * 68 + h + d] = sc[d];
    }
    __syncthreads();

    {
        float li0 = s.linv[r0], li1 = s.linv[r1];
        int bb = bh >> 4, hh = bh & 15;
        __half* y0 = Y + ((size_t)(bb * 1024 + i0 + r0)) * 1024 + hh * 64;
        __half* y1 = Y + ((size_t)(bb * 1024 + i0 + r1)) * 1024 + hh * 64;
#pragma unroll
        for (int ni = 0; ni < 8; ni++) {
            int col = ni * 8 + 2 * c;
            *(uint32_t*)(y0 + col) = packh2((acc[ni][0] + scr[r0 * 68 + col]) * li0,
                                            (acc[ni][1] + scr[r0 * 68 + col + 1]) * li0);
            *(uint32_t*)(y1 + col) = packh2((acc[ni][2] + scr[r1 * 68 + col]) * li1,
                                            (acc[ni][3] + scr[r1 * 68 + col + 1]) * li1);
        }
    }
}

// ---------------------------------------------------------------------------

extern "C" void kernel_launch(void* const* d_in, const int* in_sizes, int n_in,
                              void* d_out, int out_size)
{
    const float* query = (const float*)d_in[0];
    const float* key   = (const float*)d_in[1];
    const float* value = (const float*)d_in[2];
    const float* wq = (const float*)d_in[3];
    const float* bq = (const float*)d_in[4];
    const float* wk = (const float*)d_in[5];
    const float* bk = (const float*)d_in[6];
    const float* wv = (const float*)d_in[7];
    const float* bv = (const float*)d_in[8];
    const float* wo = (const float*)d_in[9];
    const float* bo = (const float*)d_in[10];
    const float* relk = (const float*)d_in[11];
    const float* relv = (const float*)d_in[12];
    float* out = (float*)d_out;

    __half *Qp, *Kp, *Vp, *Yp, *Xq, *Xk, *Xv, *Wq, *Wk, *Wv, *Wo;
    cudaGetSymbolAddress((void**)&Qp, gQ);
    cudaGetSymbolAddress((void**)&Kp, gK);
    cudaGetSymbolAddress((void**)&Vp, gV);
    cudaGetSymbolAddress((void**)&Yp, gY);
    cudaGetSymbolAddress((void**)&Xq, gXq);
    cudaGetSymbolAddress((void**)&Xk, gXk);
    cudaGetSymbolAddress((void**)&Xv, gXv);
    cudaGetSymbolAddress((void**)&Wq, gWq);
    cudaGetSymbolAddress((void**)&Wk, gWk);
    cudaGetSymbolAddress((void**)&Wv, gWv);
    cudaGetSymbolAddress((void**)&Wo, gWo);

    convert7_kernel<<<dim3(512, 7), 256>>>(query, key, value, wq, wk, wv, wo,
                                           Xq, Xk, Xv, Wq, Wk, Wv, Wo);

    cudaFuncSetAttribute(qkv_gemm_kernel, cudaFuncAttributeMaxDynamicSharedMemorySize,
                         GS_TOTAL);
    cudaFuncSetAttribute(out_gemm_kernel, cudaFuncAttributeMaxDynamicSharedMemorySize,
                         GS_TOTAL);
    cudaFuncSetAttribute(attn_kernel, cudaFuncAttributeMaxDynamicSharedMemorySize,
                         (int)sizeof(AttnSmem));

    qkv_gemm_kernel<<<dim3(8, 32, 3), 256, GS_TOTAL>>>(Xq, Xk, Xv, Wq, Wk, Wv,
                                                       bq, bk, bv, Qp, Kp, Vp);

    attn_kernel<<<dim3(8, 64), 256, sizeof(AttnSmem)>>>(Qp, Kp, Vp, relk, relv, Yp);

    out_gemm_kernel<<<dim3(8, 32), 256, GS_TOTAL>>>(Yp, Wo, bo, out);
}

// round 14
// speedup vs baseline: 9.0621x; 1.0505x over previous
#include <cuda_runtime.h>
#include <cuda_fp16.h>
#include <math.h>
#include <cstdint>

// Problem constants
#define Bn  4
#define Ln  1024
#define En  1024
#define Hn  16
#define HDn 64
#define NT  33          // 2*CLIP+1
#define CLIPV 16
#define SCALEF 0.125f   // 1/sqrt(64)
#define LOG2E 1.4426950408889634f

// Scratch (device globals; no allocation allowed)
__device__ __half gQ[Bn*Hn*Ln*HDn];   // [b][h][l][d] fp16
__device__ __half gK[Bn*Hn*Ln*HDn];
__device__ __half gV[Bn*Hn*Ln*HDn];
__device__ __half gY[Bn*Ln*En];       // [b][l][e] fp16
__device__ __half gXq[Bn*Ln*En];      // fp16 inputs
__device__ __half gXk[Bn*Ln*En];
__device__ __half gXv[Bn*Ln*En];
__device__ __half gWq[En*En];         // fp16 weights
__device__ __half gWk[En*En];
__device__ __half gWv[En*En];
__device__ __half gWo[En*En];

// ---------------------------------------------------------------------------
// helpers
// ---------------------------------------------------------------------------
__device__ __forceinline__ uint32_t packh2(float x, float y) {
    __half2 h = __floats2half2_rn(x, y);
    return *reinterpret_cast<uint32_t*>(&h);
}

__device__ __forceinline__ uint32_t h2exp2(uint32_t x) {
    uint32_t r;
    asm("ex2.approx.f16x2 %0, %1;" : "=r"(r) : "r"(x));
    return r;
}

__device__ __forceinline__ float2 h2unpack(uint32_t x) {
    __half2 h = *reinterpret_cast<__half2*>(&x);
    return __half22float2(h);
}

__device__ __forceinline__ uint32_t h2add(uint32_t a, uint32_t b) {
    __half2 ha = *reinterpret_cast<__half2*>(&a);
    __half2 hb = *reinterpret_cast<__half2*>(&b);
    __half2 hc = __hadd2(ha, hb);
    return *reinterpret_cast<uint32_t*>(&hc);
}

__device__ __forceinline__ void cp_async16(void* dst, const void* src) {
    uint32_t d = (uint32_t)__cvta_generic_to_shared(dst);
    asm volatile("cp.async.cg.shared.global [%0], [%1], 16;\n" :: "r"(d), "l"(src));
}

__device__ __forceinline__ void cp_async16_s(uint32_t dst, const void* src) {
    asm volatile("cp.async.cg.shared.global [%0], [%1], 16;\n" :: "r"(dst), "l"(src));
}

__device__ __forceinline__ void ldsm4(uint32_t& r0, uint32_t& r1,
                                      uint32_t& r2, uint32_t& r3, const void* p) {
    uint32_t a = (uint32_t)__cvta_generic_to_shared(p);
    asm volatile("ldmatrix.sync.aligned.m8n8.x4.shared.b16 {%0,%1,%2,%3}, [%4];"
                 : "=r"(r0), "=r"(r1), "=r"(r2), "=r"(r3) : "r"(a));
}

__device__ __forceinline__ void ldsm4_s(uint32_t& r0, uint32_t& r1,
                                        uint32_t& r2, uint32_t& r3, uint32_t a) {
    asm volatile("ldmatrix.sync.aligned.m8n8.x4.shared.b16 {%0,%1,%2,%3}, [%4];"
                 : "=r"(r0), "=r"(r1), "=r"(r2), "=r"(r3) : "r"(a));
}

__device__ __forceinline__ void ldsm4t(uint32_t& r0, uint32_t& r1,
                                       uint32_t& r2, uint32_t& r3, const void* p) {
    uint32_t a = (uint32_t)__cvta_generic_to_shared(p);
    asm volatile("ldmatrix.sync.aligned.m8n8.x4.trans.shared.b16 {%0,%1,%2,%3}, [%4];"
                 : "=r"(r0), "=r"(r1), "=r"(r2), "=r"(r3) : "r"(a));
}

__device__ __forceinline__ void mma_f16(float* d,
    uint32_t a0, uint32_t a1, uint32_t a2, uint32_t a3,
    uint32_t b0, uint32_t b1)
{
    asm volatile(
        "mma.sync.aligned.m16n8k16.row.col.f32.f16.f16.f32 "
        "{%0,%1,%2,%3}, {%4,%5,%6,%7}, {%8,%9}, {%0,%1,%2,%3};"
        : "+f"(d[0]), "+f"(d[1]), "+f"(d[2]), "+f"(d[3])
        : "r"(a0), "r"(a1), "r"(a2), "r"(a3), "r"(b0), "r"(b1));
}

__device__ __forceinline__ uint32_t sw128(uint32_t off) {
    return off ^ ((off >> 3) & 0x70);
}

// ---------------------------------------------------------------------------
// fp32 -> fp16 conversion of 3 inputs + 4 weights.
// ---------------------------------------------------------------------------
__global__ __launch_bounds__(256) void convert7_kernel(
    const float* __restrict__ xq, const float* __restrict__ xk,
    const float* __restrict__ xv,
    const float* __restrict__ wq, const float* __restrict__ wk,
    const float* __restrict__ wv, const float* __restrict__ wo,
    __half* __restrict__ oxq, __half* __restrict__ oxk, __half* __restrict__ oxv,
    __half* __restrict__ owq, __half* __restrict__ owk,
    __half* __restrict__ owv, __half* __restrict__ owo)
{
    int t = blockIdx.y;
    const float* src; __half* dst; int n8;
    switch (t) {
        case 0: src = xq; dst = oxq; n8 = (Bn*Ln*En)/8; break;
        case 1: src = xk; dst = oxk; n8 = (Bn*Ln*En)/8; break;
        case 2: src = xv; dst = oxv; n8 = (Bn*Ln*En)/8; break;
        case 3: src = wq; dst = owq; n8 = (En*En)/8; break;
        case 4: src = wk; dst = owk; n8 = (En*En)/8; break;
        case 5: src = wv; dst = owv; n8 = (En*En)/8; break;
        default: src = wo; dst = owo; n8 = (En*En)/8; break;
    }
    int stride = gridDim.x * 256;
    for (int i = blockIdx.x * 256 + threadIdx.x; i < n8; i += stride) {
        float4 a = ((const float4*)src)[2*i];
        float4 b = ((const float4*)src)[2*i + 1];
        uint4 o;
        o.x = packh2(a.x, a.y); o.y = packh2(a.z, a.w);
        o.z = packh2(b.x, b.y); o.w = packh2(b.z, b.w);
        ((uint4*)dst)[i] = o;
    }
}

// ---------------------------------------------------------------------------
// fp16 tensor-core GEMM (unchanged — fully unrolled k-loop).
// ---------------------------------------------------------------------------
#define GTILE 16384                       // 128 rows * 128 bytes
#define GS_TOTAL (6 * GTILE)              // 3 stages * (A + B) = 96 KB

__device__ __forceinline__ void gemm_body(
    const __half* __restrict__ A, const __half* __restrict__ W,
    const float* __restrict__ bias, void* __restrict__ Cout, int head_layout)
{
    extern __shared__ char sm[];
    uint32_t smem = (uint32_t)__cvta_generic_to_shared(sm);
    uint32_t smA = smem, smB = smem + 3 * GTILE;
    const int Kd = 1024;

    int tid  = threadIdx.x;
    int warp = tid >> 5, lane = tid & 31;
    int wm = (warp >> 1) << 5;
    int wn = (warp & 1) << 6;
    int g = lane >> 2, c = lane & 3;
    int m0 = blockIdx.y << 7, n0 = blockIdx.x << 7;

    int lrow = (lane & 7) + ((lane >> 3) & 1) * 8;
    int lcol = (lane >> 4) * 8;

    int r = tid >> 1;
    int chbase = (tid & 1) * 4;
    const __half* Ag = A + (size_t)(m0 + r) * Kd;
    const __half* Wg = W + (size_t)(n0 + r) * Kd;

    float acc[2][8][4];
#pragma unroll
    for (int mi = 0; mi < 2; mi++)
#pragma unroll
        for (int ni = 0; ni < 8; ni++)
#pragma unroll
            for (int q = 0; q < 4; q++) acc[mi][ni][q] = 0.f;

    auto load_stage = [&](int s, int k0) {
#pragma unroll
        for (int q = 0; q < 4; q++) {
            int ch = chbase + q;
            uint32_t d = sw128((uint32_t)(r * 128 + ch * 16));
            cp_async16_s(smA + s * GTILE + d, Ag + k0 + ch * 8);
            cp_async16_s(smB + s * GTILE + d, Wg + k0 + ch * 8);
        }
    };

    load_stage(0, 0);
    asm volatile("cp.async.commit_group;\n");
    load_stage(1, 64);
    asm volatile("cp.async.commit_group;\n");

    const int NITER = Kd / 64;   // 16
#pragma unroll
    for (int t = 0; t < NITER; t++) {
        asm volatile("cp.async.wait_group 1;\n");
        __syncthreads();
        if (t + 2 < NITER) {
            load_stage((t + 2) % 3, (t + 2) * 64);
        }
        asm volatile("cp.async.commit_group;\n");

        const int s = t % 3;
#pragma unroll
        for (int ks = 0; ks < 4; ks++) {
            int kc = ks * 16 + lcol;
            uint32_t af[2][4], bf[4][4];
#pragma unroll
            for (int mi = 0; mi < 2; mi++) {
                uint32_t addr = smA + s * GTILE +
                    sw128((uint32_t)((wm + mi * 16 + lrow) * 128 + kc * 2));
                ldsm4_s(af[mi][0], af[mi][1], af[mi][2], af[mi][3], addr);
            }
#pragma unroll
            for (int p = 0; p < 4; p++) {
                uint32_t addr = smB + s * GTILE +
                    sw128((uint32_t)((wn + p * 16 + lrow) * 128 + kc * 2));
                ldsm4_s(bf[p][0], bf[p][1], bf[p][2], bf[p][3], addr);
            }
#pragma unroll
            for (int mi = 0; mi < 2; mi++)
#pragma unroll
                for (int ni = 0; ni < 8; ni++) {
                    int p = ni >> 1;
                    uint32_t b0 = (ni & 1) ? bf[p][1] : bf[p][0];
                    uint32_t b1 = (ni & 1) ? bf[p][3] : bf[p][2];
                    mma_f16(acc[mi][ni], af[mi][0], af[mi][1], af[mi][2], af[mi][3],
                            b0, b1);
                }
        }
    }

#pragma unroll
    for (int mi = 0; mi < 2; mi++) {
#pragma unroll
        for (int ni = 0; ni < 8; ni++) {
            int row = m0 + wm + (mi << 4) + g;
            int col = n0 + wn + (ni << 3) + (c << 1);
            float b0 = bias[col], b1 = bias[col + 1];
            float x0 = acc[mi][ni][0] + b0, x1 = acc[mi][ni][1] + b1;
            float x2 = acc[mi][ni][2] + b0, x3 = acc[mi][ni][3] + b1;
            if (head_layout) {
                __half* C = (__half*)Cout;
                int b = row >> 10, l = row & 1023, h = col >> 6, d = col & 63;
                size_t off = (((size_t)(b * Hn + h)) << 16) + ((size_t)l << 6) + d;
                *(uint32_t*)(C + off) = packh2(x0, x1);
                int row2 = row + 8;
                int b2 = row2 >> 10, l2 = row2 & 1023;
                size_t off2 = (((size_t)(b2 * Hn + h)) << 16) + ((size_t)l2 << 6) + d;
                *(uint32_t*)(C + off2) = packh2(x2, x3);
            } else {
                float* C = (float*)Cout;
                *(float2*)(C + (size_t)row * 1024 + col) = make_float2(x0, x1);
                *(float2*)(C + (size_t)(row + 8) * 1024 + col) = make_float2(x2, x3);
            }
        }
    }
}

__global__ __launch_bounds__(256, 2) void qkv_gemm_kernel(
    const __half* __restrict__ xq, const __half* __restrict__ xk,
    const __half* __restrict__ xv,
    const __half* __restrict__ wq, const __half* __restrict__ wk,
    const __half* __restrict__ wv,
    const float* __restrict__ bq, const float* __restrict__ bk,
    const float* __restrict__ bv,
    __half* __restrict__ Q, __half* __restrict__ K, __half* __restrict__ V)
{
    if (blockIdx.z == 0)      gemm_body(xq, wq, bq, Q, 1);
    else if (blockIdx.z == 1) gemm_body(xk, wk, bk, K, 1);
    else                      gemm_body(xv, wv, bv, V, 1);
}

__global__ __launch_bounds__(256, 2) void out_gemm_kernel(
    const __half* __restrict__ Y, const __half* __restrict__ wo,
    const float* __restrict__ bo, float* __restrict__ out)
{
    gemm_body(Y, wo, bo, out, 0);
}

// ---------------------------------------------------------------------------
// fp16 tensor-core flash attention; log2-domain softmax, f16x2 exp, hoisted
// Q fragments, RQ bias via tensor-core MMA (relk fp16 + zero padding),
// hadd2-paired row sums, warp-vote alpha skip, folded far-tile bias,
// atomic-free residue-partitioned bucket weights.
// ---------------------------------------------------------------------------
#define QPAD 72

struct __align__(16) AttnSmem {
    __half Qs[128][QPAD];     // SCALE*LOG2E folded
    __half Ks[2][64][QPAD];   // [j][d]   } reused as fp32 scratch in epilogue
    __half Vs[2][64][QPAD];   // [j][d]
    float RQs[128][NT];       // log2-domain bias
    float Wb[128][NT];
    float relvs[NT][68];
    __half relkh[48][QPAD];   // fp16 relk, rows 33..47 zero (MMA B operand)
    float wscale[128];
    float linv[128];
};

__device__ __forceinline__ void load_kv_tile(AttnSmem& s, int buf,
    const __half* Kb, const __half* Vb, int j0, int tid)
{
    int j = tid >> 2;
    int ch = (tid & 3) << 4;
    const __half* ks = Kb + (size_t)(j0 + j) * 64 + ch;
    const __half* vs = Vb + (size_t)(j0 + j) * 64 + ch;
    cp_async16(&s.Ks[buf][j][ch],     ks);
    cp_async16(&s.Ks[buf][j][ch + 8], ks + 8);
    cp_async16(&s.Vs[buf][j][ch],     vs);
    cp_async16(&s.Vs[buf][j][ch + 8], vs + 8);
}

__global__ __launch_bounds__(256, 2) void attn_kernel(
    const __half* __restrict__ Q, const __half* __restrict__ Kg,
    const __half* __restrict__ Vg, const float* __restrict__ relk,
    const float* __restrict__ relv, __half* __restrict__ Y)
{
    extern __shared__ char smem_raw[];
    AttnSmem& s = *reinterpret_cast<AttnSmem*>(smem_raw);
    int tid = threadIdx.x;
    int warp = tid >> 5, lane = tid & 31;
    int g = lane >> 2, c = lane & 3;
    int r0 = warp * 16 + g;
    int r1 = r0 + 8;
    int lrow = (lane & 7) + ((lane >> 3) & 1) * 8;
    int lcol = (lane >> 4) * 8;
    int vrow = (lane & 7) + (lane >> 4) * 8;
    int vcol = ((lane >> 3) & 1) * 8;

    int bh = blockIdx.y;
    int bx = blockIdx.x;
    int i0 = bx * 128;
    const __half* Qb = Q + ((size_t)bh << 16) + (size_t)i0 * 64;
    const __half* Kb = Kg + ((size_t)bh << 16);
    const __half* Vb = Vg + ((size_t)bh << 16);

    load_kv_tile(s, 0, Kb, Vb, 0, tid);
    asm volatile("cp.async.commit_group;\n");
    {
        int r = tid >> 1;
        int seg = (tid & 1) * 32;
        const __half* src = Qb + (size_t)r * 64 + seg;
        __half2 hs = __float2half2_rn(SCALEF * LOG2E);   // log2 domain
#pragma unroll
        for (int q = 0; q < 4; q++) {
            uint4 v = *(const uint4*)(src + q * 8);
            __half2* hv = (__half2*)&v;
#pragma unroll
            for (int e = 0; e < 4; e++) hv[e] = __hmul2(hv[e], hs);
            *(uint4*)&s.Qs[r][seg + q * 8] = v;
        }
    }
    for (int idx = tid; idx < NT * 64; idx += 256)
        s.relvs[idx >> 6][idx & 63] = relv[idx];
    for (int idx = tid; idx < 48 * 64; idx += 256) {
        int row = idx >> 6, col = idx & 63;
        s.relkh[row][col] = (row < NT) ? __float2half(relk[row * 64 + col])
                                       : __float2half(0.f);
    }
    for (int idx = tid; idx < 128 * NT; idx += 256)
        s.Wb[idx / NT][idx % NT] = 0.f;
    __syncthreads();

    // hoist Q fragments (loop-invariant across j-tiles)
    uint32_t aq[4][4];
#pragma unroll
    for (int ks = 0; ks < 4; ks++)
        ldsm4(aq[ks][0], aq[ks][1], aq[ks][2], aq[ks][3],
              &s.Qs[warp * 16 + lrow][ks * 16 + lcol]);

    // ---- RQ = Q @ relk^T via tensor cores (N padded to 48) ----
    {
        float rqf[6][4];
#pragma unroll
        for (int u = 0; u < 6; u++)
#pragma unroll
            for (int q = 0; q < 4; q++) rqf[u][q] = 0.f;
#pragma unroll
        for (int ks = 0; ks < 4; ks++) {
            int kc = ks * 16 + lcol;
#pragma unroll
            for (int p = 0; p < 3; p++) {
                uint32_t b0, b1, b2, b3;
                ldsm4(b0, b1, b2, b3, &s.relkh[p * 16 + lrow][kc]);
                mma_f16(rqf[2 * p],     aq[ks][0], aq[ks][1], aq[ks][2], aq[ks][3], b0, b2);
                mma_f16(rqf[2 * p + 1], aq[ks][0], aq[ks][1], aq[ks][2], aq[ks][3], b1, b3);
            }
        }
#pragma unroll
        for (int p = 0; p < 3; p++)
#pragma unroll
            for (int sub = 0; sub < 2; sub++)
#pragma unroll
                for (int e = 0; e < 2; e++) {
                    int t = p * 16 + sub * 8 + 2 * c + e;
                    if (t < NT) {
                        s.RQs[r0][t] = rqf[2 * p + sub][e];
                        s.RQs[r1][t] = rqf[2 * p + sub][2 + e];
                    }
                }
    }

    float m0s = -1e30f, m1s = -1e30f;
    float l0 = 0.f, l1 = 0.f;
    float b0a = 0.f, b0b = 0.f, b32a = 0.f, b32b = 0.f;
    float mW0 = -1e30f, mW1 = -1e30f;
    float acc[8][4];
#pragma unroll
    for (int ni = 0; ni < 8; ni++)
#pragma unroll
        for (int q = 0; q < 4; q++) acc[ni][q] = 0.f;

    int ig0 = i0 + r0, ig1 = i0 + r1;

#pragma unroll 2
    for (int jt = 0; jt < 16; jt++) {
        int buf = jt & 1;
        int j0 = jt * 64;
        asm volatile("cp.async.wait_group 0;\n");
        __syncthreads();      // KV[buf] visible; RQs scatter (first iter) visible
        if (jt + 1 < 16)
            load_kv_tile(s, buf ^ 1, Kb, Vb, j0 + 64, tid);
        asm volatile("cp.async.commit_group;\n");

        int dj = jt - 2 * bx;
        bool far_left  = (dj <= -2);
        bool far_right = (dj >= 3);
        bool diag = !(far_left || far_right);

        // ---- S = Q K^T ----
        float sf[8][4];
#pragma unroll
        for (int ni = 0; ni < 8; ni++)
#pragma unroll
            for (int q = 0; q < 4; q++) sf[ni][q] = 0.f;
#pragma unroll
        for (int ks = 0; ks < 4; ks++) {
            int kc = ks * 16 + lcol;
#pragma unroll
            for (int p = 0; p < 4; p++) {
                uint32_t b0, b1, b2, b3;
                ldsm4(b0, b1, b2, b3, &s.Ks[buf][p * 16 + lrow][kc]);
                mma_f16(sf[2 * p],     aq[ks][0], aq[ks][1], aq[ks][2], aq[ks][3], b0, b2);
                mma_f16(sf[2 * p + 1], aq[ks][0], aq[ks][1], aq[ks][2], aq[ks][3], b1, b3);
            }
        }

        // ---- diag tiles: per-element bias before max ----
        if (diag) {
#pragma unroll
            for (int ni = 0; ni < 8; ni++) {
#pragma unroll
                for (int e = 0; e < 2; e++) {
                    int j = j0 + ni * 8 + 2 * c + e;
                    int d0 = j - ig0; d0 = d0 < -CLIPV ? -CLIPV : (d0 > CLIPV ? CLIPV : d0);
                    int d1 = j - ig1; d1 = d1 < -CLIPV ? -CLIPV : (d1 > CLIPV ? CLIPV : d1);
                    sf[ni][e]     += s.RQs[r0][d0 + CLIPV];
                    sf[ni][2 + e] += s.RQs[r1][d1 + CLIPV];
                }
            }
        }

        // ---- max reduction (raw for far tiles; bias folded as offset) ----
        float mt0 = -1e30f, mt1 = -1e30f;
#pragma unroll
        for (int ni = 0; ni < 8; ni++) {
            mt0 = fmaxf(mt0, fmaxf(sf[ni][0], sf[ni][1]));
            mt1 = fmaxf(mt1, fmaxf(sf[ni][2], sf[ni][3]));
        }
        mt0 = fmaxf(mt0, __shfl_xor_sync(0xffffffffu, mt0, 1));
        mt0 = fmaxf(mt0, __shfl_xor_sync(0xffffffffu, mt0, 2));
        mt1 = fmaxf(mt1, __shfl_xor_sync(0xffffffffu, mt1, 1));
        mt1 = fmaxf(mt1, __shfl_xor_sync(0xffffffffu, mt1, 2));

        float mn0, mn1, off0, off1;
        if (!diag) {
            int tf = far_left ? 0 : 32;
            float rq0 = s.RQs[r0][tf], rq1 = s.RQs[r1][tf];
            mn0 = fmaxf(m0s, mt0 + rq0);
            mn1 = fmaxf(m1s, mt1 + rq1);
            off0 = mn0 - rq0; off1 = mn1 - rq1;
        } else {
            mn0 = fmaxf(m0s, mt0);
            mn1 = fmaxf(m1s, mt1);
            off0 = mn0; off1 = mn1;
        }

        // ---- warp-vote alpha skip ----
        bool nochg = (mn0 == m0s) && (mn1 == m1s);
        bool skip = __all_sync(0xffffffffu, nochg);
        float al0 = 1.f, al1 = 1.f;
        if (!skip) {
            al0 = exp2f(m0s - mn0);
            al1 = exp2f(m1s - mn1);
        }

        // ---- P = exp2(S - off) directly in fp16 fragments ----
        uint32_t ap[4][4];
#pragma unroll
        for (int kk = 0; kk < 4; kk++) {
            ap[kk][0] = h2exp2(packh2(sf[2 * kk][0] - off0,     sf[2 * kk][1] - off0));
            ap[kk][1] = h2exp2(packh2(sf[2 * kk][2] - off1,     sf[2 * kk][3] - off1));
            ap[kk][2] = h2exp2(packh2(sf[2 * kk + 1][0] - off0, sf[2 * kk + 1][1] - off0));
            ap[kk][3] = h2exp2(packh2(sf[2 * kk + 1][2] - off1, sf[2 * kk + 1][3] - off1));
        }

        // ---- row sums: one-level hadd2 pairing, then fp32 ----
        float rs0, rs1;
        {
            uint32_t h0 = h2add(ap[0][0], ap[0][2]);
            uint32_t h1 = h2add(ap[1][0], ap[1][2]);
            uint32_t h2 = h2add(ap[2][0], ap[2][2]);
            uint32_t h3 = h2add(ap[3][0], ap[3][2]);
            float2 f0 = h2unpack(h0), f1 = h2unpack(h1);
            float2 f2 = h2unpack(h2), f3 = h2unpack(h3);
            rs0 = ((f0.x + f0.y) + (f1.x + f1.y)) + ((f2.x + f2.y) + (f3.x + f3.y));
            uint32_t k0 = h2add(ap[0][1], ap[0][3]);
            uint32_t k1 = h2add(ap[1][1], ap[1][3]);
            uint32_t k2 = h2add(ap[2][1], ap[2][3]);
            uint32_t k3 = h2add(ap[3][1], ap[3][3]);
            float2 e0 = h2unpack(k0), e1 = h2unpack(k1);
            float2 e2 = h2unpack(k2), e3 = h2unpack(k3);
            rs1 = ((e0.x + e0.y) + (e1.x + e1.y)) + ((e2.x + e2.y) + (e3.x + e3.y));
        }
        rs0 += __shfl_xor_sync(0xffffffffu, rs0, 1);
        rs0 += __shfl_xor_sync(0xffffffffu, rs0, 2);
        rs1 += __shfl_xor_sync(0xffffffffu, rs1, 1);
        rs1 += __shfl_xor_sync(0xffffffffu, rs1, 2);
        l0 = l0 * al0 + rs0;
        l1 = l1 * al1 + rs1;

        // ---- bucket weights ----
        if (far_left) {
            b0a = b0a * al0 + rs0;  b0b = b0b * al1 + rs1;
            b32a *= al0;            b32b *= al1;
        } else if (far_right) {
            b32a = b32a * al0 + rs0; b32b = b32b * al1 + rs1;
            b0a *= al0;              b0b *= al1;
        } else {
            float wsc0 = exp2f(mW0 - mn0);
            float wsc1 = exp2f(mW1 - mn1);
#pragma unroll
            for (int e = 0; e < 2; e++) {
                int rr0 = (2 * c + e - ig0) & 7;
                int rr1 = (2 * c + e - ig1) & 7;
#pragma unroll
                for (int tt = 0; tt < 4; tt++) {
                    int t0 = rr0 + 8 * tt;
                    int t1 = rr1 + 8 * tt;
                    if (t0 >= 1) s.Wb[r0][t0] *= wsc0;
                    if (t1 >= 1) s.Wb[r1][t1] *= wsc1;
                }
            }
            float c0a = 0.f, c0b = 0.f, c32a = 0.f, c32b = 0.f;
#pragma unroll
            for (int kk = 0; kk < 4; kk++) {
#pragma unroll
                for (int sub = 0; sub < 2; sub++) {   // ni = 2kk+sub
                    int ni = 2 * kk + sub;
                    float2 p0 = h2unpack(ap[kk][2 * sub]);       // row r0
                    float2 p1 = h2unpack(ap[kk][2 * sub + 1]);   // row r1
                    int jb = j0 + ni * 8 + 2 * c;
                    int d0 = jb - ig0;
                    int d1 = jb - ig1;
                    if (d0 <= -CLIPV) c0a += p0.x;
                    else if (d0 >= CLIPV) c32a += p0.x;
                    else s.Wb[r0][d0 + CLIPV] += p0.x;
                    if (d0 + 1 <= -CLIPV) c0a += p0.y;
                    else if (d0 + 1 >= CLIPV) c32a += p0.y;
                    else s.Wb[r0][d0 + 1 + CLIPV] += p0.y;
                    if (d1 <= -CLIPV) c0b += p1.x;
                    else if (d1 >= CLIPV) c32b += p1.x;
                    else s.Wb[r1][d1 + CLIPV] += p1.x;
                    if (d1 + 1 <= -CLIPV) c0b += p1.y;
                    else if (d1 + 1 >= CLIPV) c32b += p1.y;
                    else s.Wb[r1][d1 + 1 + CLIPV] += p1.y;
                }
            }
            c0a += __shfl_xor_sync(0xffffffffu, c0a, 1);
            c0a += __shfl_xor_sync(0xffffffffu, c0a, 2);
            c0b += __shfl_xor_sync(0xffffffffu, c0b, 1);
            c0b += __shfl_xor_sync(0xffffffffu, c0b, 2);
            c32a += __shfl_xor_sync(0xffffffffu, c32a, 1);
            c32a += __shfl_xor_sync(0xffffffffu, c32a, 2);
            c32b += __shfl_xor_sync(0xffffffffu, c32b, 1);
            c32b += __shfl_xor_sync(0xffffffffu, c32b, 2);
            b0a = b0a * al0 + c0a;   b0b = b0b * al1 + c0b;
            b32a = b32a * al0 + c32a; b32b = b32b * al1 + c32b;
            mW0 = mn0; mW1 = mn1;
        }
        m0s = mn0; m1s = mn1;

        // ---- acc = acc*alpha (skipped when max unchanged) + P @ V ----
        if (!skip) {
#pragma unroll
            for (int ni = 0; ni < 8; ni++) {
                acc[ni][0] *= al0; acc[ni][1] *= al0;
                acc[ni][2] *= al1; acc[ni][3] *= al1;
            }
        }
#pragma unroll
        for (int kk = 0; kk < 4; kk++) {
#pragma unroll
            for (int p = 0; p < 4; p++) {
                uint32_t b0, b1, b2, b3;
                ldsm4t(b0, b1, b2, b3, &s.Vs[buf][kk * 16 + vrow][p * 16 + vcol]);
                mma_f16(acc[2 * p],     ap[kk][0], ap[kk][1], ap[kk][2], ap[kk][3], b0, b2);
                mma_f16(acc[2 * p + 1], ap[kk][0], ap[kk][1], ap[kk][2], ap[kk][3], b1, b3);
            }
        }
    }

    if (c == 0) {
        s.Wb[r0][0] = b0a;  s.Wb[r0][32] = b32a;
        s.Wb[r1][0] = b0b;  s.Wb[r1][32] = b32b;
        s.wscale[r0] = exp2f(mW0 - m0s);
        s.wscale[r1] = exp2f(mW1 - m1s);
        s.linv[r0] = 1.f / l0;
        s.linv[r1] = 1.f / l1;
    }
    __syncthreads();

    float* scr = (float*)&s.Ks[0][0][0];
    {
        int i = tid >> 1;
        int h = (tid & 1) * 32;
        float ws = s.wscale[i];
        float sc[32];
#pragma unroll
        for (int d = 0; d < 32; d++) sc[d] = 0.f;
        for (int t = 0; t < NT; t++) {
            float w = s.Wb[i][t];
            if (t != 0 && t != 32) w *= ws;
#pragma unroll
            for (int d = 0; d < 32; d++)
                sc[d] += w * s.relvs[t][h + d];
        }
#pragma unroll
        for (int d = 0; d < 32; d++) scr[i * 68 + h + d] = sc[d];
    }
    __syncthreads();

    {
        float li0 = s.linv[r0], li1 = s.linv[r1];
        int bb = bh >> 4, hh = bh & 15;
        __half* y0 = Y + ((size_t)(bb * 1024 + i0 + r0)) * 1024 + hh * 64;
        __half* y1 = Y + ((size_t)(bb * 1024 + i0 + r1)) * 1024 + hh * 64;
#pragma unroll
        for (int ni = 0; ni < 8; ni++) {
            int col = ni * 8 + 2 * c;
            *(uint32_t*)(y0 + col) = packh2((acc[ni][0] + scr[r0 * 68 + col]) * li0,
                                            (acc[ni][1] + scr[r0 * 68 + col + 1]) * li0);
            *(uint32_t*)(y1 + col) = packh2((acc[ni][2] + scr[r1 * 68 + col]) * li1,
                                            (acc[ni][3] + scr[r1 * 68 + col + 1]) * li1);
        }
    }
}

// ---------------------------------------------------------------------------

extern "C" void kernel_launch(void* const* d_in, const int* in_sizes, int n_in,
                              void* d_out, int out_size)
{
    const float* query = (const float*)d_in[0];
    const float* key   = (const float*)d_in[1];
    const float* value = (const float*)d_in[2];
    const float* wq = (const float*)d_in[3];
    const float* bq = (const float*)d_in[4];
    const float* wk = (const float*)d_in[5];
    const float* bk = (const float*)d_in[6];
    const float* wv = (const float*)d_in[7];
    const float* bv = (const float*)d_in[8];
    const float* wo = (const float*)d_in[9];
    const float* bo = (const float*)d_in[10];
    const float* relk = (const float*)d_in[11];
    const float* relv = (const float*)d_in[12];
    float* out = (float*)d_out;

    __half *Qp, *Kp, *Vp, *Yp, *Xq, *Xk, *Xv, *Wq, *Wk, *Wv, *Wo;
    cudaGetSymbolAddress((void**)&Qp, gQ);
    cudaGetSymbolAddress((void**)&Kp, gK);
    cudaGetSymbolAddress((void**)&Vp, gV);
    cudaGetSymbolAddress((void**)&Yp, gY);
    cudaGetSymbolAddress((void**)&Xq, gXq);
    cudaGetSymbolAddress((void**)&Xk, gXk);
    cudaGetSymbolAddress((void**)&Xv, gXv);
    cudaGetSymbolAddress((void**)&Wq, gWq);
    cudaGetSymbolAddress((void**)&Wk, gWk);
    cudaGetSymbolAddress((void**)&Wv, gWv);
    cudaGetSymbolAddress((void**)&Wo, gWo);

    convert7_kernel<<<dim3(512, 7), 256>>>(query, key, value, wq, wk, wv, wo,
                                           Xq, Xk, Xv, Wq, Wk, Wv, Wo);

    cudaFuncSetAttribute(qkv_gemm_kernel, cudaFuncAttributeMaxDynamicSharedMemorySize,
                         GS_TOTAL);
    cudaFuncSetAttribute(out_gemm_kernel, cudaFuncAttributeMaxDynamicSharedMemorySize,
                         GS_TOTAL);
    cudaFuncSetAttribute(attn_kernel, cudaFuncAttributeMaxDynamicSharedMemorySize,
                         (int)sizeof(AttnSmem));

    qkv_gemm_kernel<<<dim3(8, 32, 3), 256, GS_TOTAL>>>(Xq, Xk, Xv, Wq, Wk, Wv,
                                                       bq, bk, bv, Qp, Kp, Vp);

    attn_kernel<<<dim3(8, 64), 256, sizeof(AttnSmem)>>>(Qp, Kp, Vp, relk, relv, Yp);

    out_gemm_kernel<<<dim3(8, 32), 256, GS_TOTAL>>>(Yp, Wo, bo, out);
}

// round 15
// speedup vs baseline: 9.1154x; 1.0059x over previous
#include <cuda_runtime.h>
#include <cuda_fp16.h>
#include <math.h>
#include <cstdint>

// Problem constants
#define Bn  4
#define Ln  1024
#define En  1024
#define Hn  16
#define HDn 64
#define NT  33          // 2*CLIP+1
#define CLIPV 16
#define SCALEF 0.125f   // 1/sqrt(64)
#define LOG2E 1.4426950408889634f

// Scratch (device globals; no allocation allowed)
__device__ __half gQ[Bn*Hn*Ln*HDn];   // [b][h][l][d] fp16
__device__ __half gK[Bn*Hn*Ln*HDn];
__device__ __half gV[Bn*Hn*Ln*HDn];
__device__ __half gY[Bn*Ln*En];       // [b][l][e] fp16
__device__ __half gXq[Bn*Ln*En];      // fp16 inputs
__device__ __half gXk[Bn*Ln*En];
__device__ __half gXv[Bn*Ln*En];
__device__ __half gWq[En*En];         // fp16 weights
__device__ __half gWk[En*En];
__device__ __half gWv[En*En];
__device__ __half gWo[En*En];

// ---------------------------------------------------------------------------
// helpers
// ---------------------------------------------------------------------------
__device__ __forceinline__ uint32_t packh2(float x, float y) {
    __half2 h = __floats2half2_rn(x, y);
    return *reinterpret_cast<uint32_t*>(&h);
}

__device__ __forceinline__ uint32_t h2exp2(uint32_t x) {
    uint32_t r;
    asm("ex2.approx.f16x2 %0, %1;" : "=r"(r) : "r"(x));
    return r;
}

__device__ __forceinline__ float2 h2unpack(uint32_t x) {
    __half2 h = *reinterpret_cast<__half2*>(&x);
    return __half22float2(h);
}

__device__ __forceinline__ uint32_t h2add(uint32_t a, uint32_t b) {
    __half2 ha = *reinterpret_cast<__half2*>(&a);
    __half2 hb = *reinterpret_cast<__half2*>(&b);
    __half2 hc = __hadd2(ha, hb);
    return *reinterpret_cast<uint32_t*>(&hc);
}

__device__ __forceinline__ void cp_async16(void* dst, const void* src) {
    uint32_t d = (uint32_t)__cvta_generic_to_shared(dst);
    asm volatile("cp.async.cg.shared.global [%0], [%1], 16;\n" :: "r"(d), "l"(src));
}

__device__ __forceinline__ void cp_async16_s(uint32_t dst, const void* src) {
    asm volatile("cp.async.cg.shared.global [%0], [%1], 16;\n" :: "r"(dst), "l"(src));
}

__device__ __forceinline__ void ldsm4(uint32_t& r0, uint32_t& r1,
                                      uint32_t& r2, uint32_t& r3, const void* p) {
    uint32_t a = (uint32_t)__cvta_generic_to_shared(p);
    asm volatile("ldmatrix.sync.aligned.m8n8.x4.shared.b16 {%0,%1,%2,%3}, [%4];"
                 : "=r"(r0), "=r"(r1), "=r"(r2), "=r"(r3) : "r"(a));
}

__device__ __forceinline__ void ldsm4_s(uint32_t& r0, uint32_t& r1,
                                        uint32_t& r2, uint32_t& r3, uint32_t a) {
    asm volatile("ldmatrix.sync.aligned.m8n8.x4.shared.b16 {%0,%1,%2,%3}, [%4];"
                 : "=r"(r0), "=r"(r1), "=r"(r2), "=r"(r3) : "r"(a));
}

__device__ __forceinline__ void ldsm4t(uint32_t& r0, uint32_t& r1,
                                       uint32_t& r2, uint32_t& r3, const void* p) {
    uint32_t a = (uint32_t)__cvta_generic_to_shared(p);
    asm volatile("ldmatrix.sync.aligned.m8n8.x4.trans.shared.b16 {%0,%1,%2,%3}, [%4];"
                 : "=r"(r0), "=r"(r1), "=r"(r2), "=r"(r3) : "r"(a));
}

__device__ __forceinline__ void mma_f16(float* d,
    uint32_t a0, uint32_t a1, uint32_t a2, uint32_t a3,
    uint32_t b0, uint32_t b1)
{
    asm volatile(
        "mma.sync.aligned.m16n8k16.row.col.f32.f16.f16.f32 "
        "{%0,%1,%2,%3}, {%4,%5,%6,%7}, {%8,%9}, {%0,%1,%2,%3};"
        : "+f"(d[0]), "+f"(d[1]), "+f"(d[2]), "+f"(d[3])
        : "r"(a0), "r"(a1), "r"(a2), "r"(a3), "r"(b0), "r"(b1));
}

__device__ __forceinline__ uint32_t sw128(uint32_t off) {
    return off ^ ((off >> 3) & 0x70);
}

// ---------------------------------------------------------------------------
// fp32 -> fp16 conversion of 3 inputs + 4 weights.
// ---------------------------------------------------------------------------
__global__ __launch_bounds__(256) void convert7_kernel(
    const float* __restrict__ xq, const float* __restrict__ xk,
    const float* __restrict__ xv,
    const float* __restrict__ wq, const float* __restrict__ wk,
    const float* __restrict__ wv, const float* __restrict__ wo,
    __half* __restrict__ oxq, __half* __restrict__ oxk, __half* __restrict__ oxv,
    __half* __restrict__ owq, __half* __restrict__ owk,
    __half* __restrict__ owv, __half* __restrict__ owo)
{
    int t = blockIdx.y;
    const float* src; __half* dst; int n8;
    switch (t) {
        case 0: src = xq; dst = oxq; n8 = (Bn*Ln*En)/8; break;
        case 1: src = xk; dst = oxk; n8 = (Bn*Ln*En)/8; break;
        case 2: src = xv; dst = oxv; n8 = (Bn*Ln*En)/8; break;
        case 3: src = wq; dst = owq; n8 = (En*En)/8; break;
        case 4: src = wk; dst = owk; n8 = (En*En)/8; break;
        case 5: src = wv; dst = owv; n8 = (En*En)/8; break;
        default: src = wo; dst = owo; n8 = (En*En)/8; break;
    }
    int stride = gridDim.x * 256;
    for (int i = blockIdx.x * 256 + threadIdx.x; i < n8; i += stride) {
        float4 a = ((const float4*)src)[2*i];
        float4 b = ((const float4*)src)[2*i + 1];
        uint4 o;
        o.x = packh2(a.x, a.y); o.y = packh2(a.z, a.w);
        o.z = packh2(b.x, b.y); o.w = packh2(b.z, b.w);
        ((uint4*)dst)[i] = o;
    }
}

// ---------------------------------------------------------------------------
// fp16 tensor-core GEMM (unchanged — fully unrolled k-loop).
// ---------------------------------------------------------------------------
#define GTILE 16384                       // 128 rows * 128 bytes
#define GS_TOTAL (6 * GTILE)              // 3 stages * (A + B) = 96 KB

__device__ __forceinline__ void gemm_body(
    const __half* __restrict__ A, const __half* __restrict__ W,
    const float* __restrict__ bias, void* __restrict__ Cout, int head_layout)
{
    extern __shared__ char sm[];
    uint32_t smem = (uint32_t)__cvta_generic_to_shared(sm);
    uint32_t smA = smem, smB = smem + 3 * GTILE;
    const int Kd = 1024;

    int tid  = threadIdx.x;
    int warp = tid >> 5, lane = tid & 31;
    int wm = (warp >> 1) << 5;
    int wn = (warp & 1) << 6;
    int g = lane >> 2, c = lane & 3;
    int m0 = blockIdx.y << 7, n0 = blockIdx.x << 7;

    int lrow = (lane & 7) + ((lane >> 3) & 1) * 8;
    int lcol = (lane >> 4) * 8;

    int r = tid >> 1;
    int chbase = (tid & 1) * 4;
    const __half* Ag = A + (size_t)(m0 + r) * Kd;
    const __half* Wg = W + (size_t)(n0 + r) * Kd;

    float acc[2][8][4];
#pragma unroll
    for (int mi = 0; mi < 2; mi++)
#pragma unroll
        for (int ni = 0; ni < 8; ni++)
#pragma unroll
            for (int q = 0; q < 4; q++) acc[mi][ni][q] = 0.f;

    auto load_stage = [&](int s, int k0) {
#pragma unroll
        for (int q = 0; q < 4; q++) {
            int ch = chbase + q;
            uint32_t d = sw128((uint32_t)(r * 128 + ch * 16));
            cp_async16_s(smA + s * GTILE + d, Ag + k0 + ch * 8);
            cp_async16_s(smB + s * GTILE + d, Wg + k0 + ch * 8);
        }
    };

    load_stage(0, 0);
    asm volatile("cp.async.commit_group;\n");
    load_stage(1, 64);
    asm volatile("cp.async.commit_group;\n");

    const int NITER = Kd / 64;   // 16
#pragma unroll
    for (int t = 0; t < NITER; t++) {
        asm volatile("cp.async.wait_group 1;\n");
        __syncthreads();
        if (t + 2 < NITER) {
            load_stage((t + 2) % 3, (t + 2) * 64);
        }
        asm volatile("cp.async.commit_group;\n");

        const int s = t % 3;
#pragma unroll
        for (int ks = 0; ks < 4; ks++) {
            int kc = ks * 16 + lcol;
            uint32_t af[2][4], bf[4][4];
#pragma unroll
            for (int mi = 0; mi < 2; mi++) {
                uint32_t addr = smA + s * GTILE +
                    sw128((uint32_t)((wm + mi * 16 + lrow) * 128 + kc * 2));
                ldsm4_s(af[mi][0], af[mi][1], af[mi][2], af[mi][3], addr);
            }
#pragma unroll
            for (int p = 0; p < 4; p++) {
                uint32_t addr = smB + s * GTILE +
                    sw128((uint32_t)((wn + p * 16 + lrow) * 128 + kc * 2));
                ldsm4_s(bf[p][0], bf[p][1], bf[p][2], bf[p][3], addr);
            }
#pragma unroll
            for (int mi = 0; mi < 2; mi++)
#pragma unroll
                for (int ni = 0; ni < 8; ni++) {
                    int p = ni >> 1;
                    uint32_t b0 = (ni & 1) ? bf[p][1] : bf[p][0];
                    uint32_t b1 = (ni & 1) ? bf[p][3] : bf[p][2];
                    mma_f16(acc[mi][ni], af[mi][0], af[mi][1], af[mi][2], af[mi][3],
                            b0, b1);
                }
        }
    }

#pragma unroll
    for (int mi = 0; mi < 2; mi++) {
#pragma unroll
        for (int ni = 0; ni < 8; ni++) {
            int row = m0 + wm + (mi << 4) + g;
            int col = n0 + wn + (ni << 3) + (c << 1);
            float b0 = bias[col], b1 = bias[col + 1];
            float x0 = acc[mi][ni][0] + b0, x1 = acc[mi][ni][1] + b1;
            float x2 = acc[mi][ni][2] + b0, x3 = acc[mi][ni][3] + b1;
            if (head_layout) {
                __half* C = (__half*)Cout;
                int b = row >> 10, l = row & 1023, h = col >> 6, d = col & 63;
                size_t off = (((size_t)(b * Hn + h)) << 16) + ((size_t)l << 6) + d;
                *(uint32_t*)(C + off) = packh2(x0, x1);
                int row2 = row + 8;
                int b2 = row2 >> 10, l2 = row2 & 1023;
                size_t off2 = (((size_t)(b2 * Hn + h)) << 16) + ((size_t)l2 << 6) + d;
                *(uint32_t*)(C + off2) = packh2(x2, x3);
            } else {
                float* C = (float*)Cout;
                *(float2*)(C + (size_t)row * 1024 + col) = make_float2(x0, x1);
                *(float2*)(C + (size_t)(row + 8) * 1024 + col) = make_float2(x2, x3);
            }
        }
    }
}

__global__ __launch_bounds__(256, 2) void qkv_gemm_kernel(
    const __half* __restrict__ xq, const __half* __restrict__ xk,
    const __half* __restrict__ xv,
    const __half* __restrict__ wq, const __half* __restrict__ wk,
    const __half* __restrict__ wv,
    const float* __restrict__ bq, const float* __restrict__ bk,
    const float* __restrict__ bv,
    __half* __restrict__ Q, __half* __restrict__ K, __half* __restrict__ V)
{
    if (blockIdx.z == 0)      gemm_body(xq, wq, bq, Q, 1);
    else if (blockIdx.z == 1) gemm_body(xk, wk, bk, K, 1);
    else                      gemm_body(xv, wv, bv, V, 1);
}

__global__ __launch_bounds__(256, 2) void out_gemm_kernel(
    const __half* __restrict__ Y, const __half* __restrict__ wo,
    const float* __restrict__ bo, float* __restrict__ out)
{
    gemm_body(Y, wo, bo, out, 0);
}

// ---------------------------------------------------------------------------
// fp16 tensor-core flash attention; log2-domain softmax, f16x2 exp, hoisted
// Q fragments + far-tile RQ biases, RQ via tensor-core MMA, hadd2-paired
// row sums, warp-vote alpha skip + rescale skip, skip-aware state updates,
// atomic-free residue-partitioned bucket weights.
// ---------------------------------------------------------------------------
#define QPAD 72

struct __align__(16) AttnSmem {
    __half Qs[128][QPAD];     // SCALE*LOG2E folded
    __half Ks[2][64][QPAD];   // [j][d]   } reused as fp32 scratch in epilogue
    __half Vs[2][64][QPAD];   // [j][d]
    float RQs[128][NT];       // log2-domain bias
    float Wb[128][NT];
    float relvs[NT][68];
    __half relkh[48][QPAD];   // fp16 relk, rows 33..47 zero (MMA B operand)
    float wscale[128];
    float linv[128];
};

__device__ __forceinline__ void load_kv_tile(AttnSmem& s, int buf,
    const __half* Kb, const __half* Vb, int j0, int tid)
{
    int j = tid >> 2;
    int ch = (tid & 3) << 4;
    const __half* ks = Kb + (size_t)(j0 + j) * 64 + ch;
    const __half* vs = Vb + (size_t)(j0 + j) * 64 + ch;
    cp_async16(&s.Ks[buf][j][ch],     ks);
    cp_async16(&s.Ks[buf][j][ch + 8], ks + 8);
    cp_async16(&s.Vs[buf][j][ch],     vs);
    cp_async16(&s.Vs[buf][j][ch + 8], vs + 8);
}

__global__ __launch_bounds__(256, 2) void attn_kernel(
    const __half* __restrict__ Q, const __half* __restrict__ Kg,
    const __half* __restrict__ Vg, const float* __restrict__ relk,
    const float* __restrict__ relv, __half* __restrict__ Y)
{
    extern __shared__ char smem_raw[];
    AttnSmem& s = *reinterpret_cast<AttnSmem*>(smem_raw);
    int tid = threadIdx.x;
    int warp = tid >> 5, lane = tid & 31;
    int g = lane >> 2, c = lane & 3;
    int r0 = warp * 16 + g;
    int r1 = r0 + 8;
    int lrow = (lane & 7) + ((lane >> 3) & 1) * 8;
    int lcol = (lane >> 4) * 8;
    int vrow = (lane & 7) + (lane >> 4) * 8;
    int vcol = ((lane >> 3) & 1) * 8;

    int bh = blockIdx.y;
    int bx = blockIdx.x;
    int i0 = bx * 128;
    const __half* Qb = Q + ((size_t)bh << 16) + (size_t)i0 * 64;
    const __half* Kb = Kg + ((size_t)bh << 16);
    const __half* Vb = Vg + ((size_t)bh << 16);

    load_kv_tile(s, 0, Kb, Vb, 0, tid);
    asm volatile("cp.async.commit_group;\n");
    {
        int r = tid >> 1;
        int seg = (tid & 1) * 32;
        const __half* src = Qb + (size_t)r * 64 + seg;
        __half2 hs = __float2half2_rn(SCALEF * LOG2E);   // log2 domain
#pragma unroll
        for (int q = 0; q < 4; q++) {
            uint4 v = *(const uint4*)(src + q * 8);
            __half2* hv = (__half2*)&v;
#pragma unroll
            for (int e = 0; e < 4; e++) hv[e] = __hmul2(hv[e], hs);
            *(uint4*)&s.Qs[r][seg + q * 8] = v;
        }
    }
    for (int idx = tid; idx < NT * 64; idx += 256)
        s.relvs[idx >> 6][idx & 63] = relv[idx];
    for (int idx = tid; idx < 48 * 64; idx += 256) {
        int row = idx >> 6, col = idx & 63;
        s.relkh[row][col] = (row < NT) ? __float2half(relk[row * 64 + col])
                                       : __float2half(0.f);
    }
    for (int idx = tid; idx < 128 * NT; idx += 256)
        s.Wb[idx / NT][idx % NT] = 0.f;
    __syncthreads();

    // hoist Q fragments (loop-invariant across j-tiles)
    uint32_t aq[4][4];
#pragma unroll
    for (int ks = 0; ks < 4; ks++)
        ldsm4(aq[ks][0], aq[ks][1], aq[ks][2], aq[ks][3],
              &s.Qs[warp * 16 + lrow][ks * 16 + lcol]);

    // ---- RQ = Q @ relk^T via tensor cores (N padded to 48) ----
    {
        float rqf[6][4];
#pragma unroll
        for (int u = 0; u < 6; u++)
#pragma unroll
            for (int q = 0; q < 4; q++) rqf[u][q] = 0.f;
#pragma unroll
        for (int ks = 0; ks < 4; ks++) {
            int kc = ks * 16 + lcol;
#pragma unroll
            for (int p = 0; p < 3; p++) {
                uint32_t b0, b1, b2, b3;
                ldsm4(b0, b1, b2, b3, &s.relkh[p * 16 + lrow][kc]);
                mma_f16(rqf[2 * p],     aq[ks][0], aq[ks][1], aq[ks][2], aq[ks][3], b0, b2);
                mma_f16(rqf[2 * p + 1], aq[ks][0], aq[ks][1], aq[ks][2], aq[ks][3], b1, b3);
            }
        }
#pragma unroll
        for (int p = 0; p < 3; p++)
#pragma unroll
            for (int sub = 0; sub < 2; sub++)
#pragma unroll
                for (int e = 0; e < 2; e++) {
                    int t = p * 16 + sub * 8 + 2 * c + e;
                    if (t < NT) {
                        s.RQs[r0][t] = rqf[2 * p + sub][e];
                        s.RQs[r1][t] = rqf[2 * p + sub][2 + e];
                    }
                }
    }
    __syncthreads();   // RQs scatter visible to all threads
    // hoist far-tile biases (buckets 0 and 32) into registers
    float rqA0 = s.RQs[r0][0], rqA32 = s.RQs[r0][32];
    float rqB0 = s.RQs[r1][0], rqB32 = s.RQs[r1][32];

    float m0s = -1e30f, m1s = -1e30f;
    float l0 = 0.f, l1 = 0.f;
    float b0a = 0.f, b0b = 0.f, b32a = 0.f, b32b = 0.f;
    float mW0 = -1e30f, mW1 = -1e30f;
    float acc[8][4];
#pragma unroll
    for (int ni = 0; ni < 8; ni++)
#pragma unroll
        for (int q = 0; q < 4; q++) acc[ni][q] = 0.f;

    int ig0 = i0 + r0, ig1 = i0 + r1;

#pragma unroll 2
    for (int jt = 0; jt < 16; jt++) {
        int buf = jt & 1;
        int j0 = jt * 64;
        asm volatile("cp.async.wait_group 0;\n");
        __syncthreads();      // KV[buf] visible
        if (jt + 1 < 16)
            load_kv_tile(s, buf ^ 1, Kb, Vb, j0 + 64, tid);
        asm volatile("cp.async.commit_group;\n");

        int dj = jt - 2 * bx;
        bool far_left  = (dj <= -2);
        bool far_right = (dj >= 3);
        bool diag = !(far_left || far_right);

        // ---- S = Q K^T ----
        float sf[8][4];
#pragma unroll
        for (int ni = 0; ni < 8; ni++)
#pragma unroll
            for (int q = 0; q < 4; q++) sf[ni][q] = 0.f;
#pragma unroll
        for (int ks = 0; ks < 4; ks++) {
            int kc = ks * 16 + lcol;
#pragma unroll
            for (int p = 0; p < 4; p++) {
                uint32_t b0, b1, b2, b3;
                ldsm4(b0, b1, b2, b3, &s.Ks[buf][p * 16 + lrow][kc]);
                mma_f16(sf[2 * p],     aq[ks][0], aq[ks][1], aq[ks][2], aq[ks][3], b0, b2);
                mma_f16(sf[2 * p + 1], aq[ks][0], aq[ks][1], aq[ks][2], aq[ks][3], b1, b3);
            }
        }

        // ---- diag tiles: per-element bias before max ----
        if (diag) {
#pragma unroll
            for (int ni = 0; ni < 8; ni++) {
#pragma unroll
                for (int e = 0; e < 2; e++) {
                    int j = j0 + ni * 8 + 2 * c + e;
                    int d0 = j - ig0; d0 = d0 < -CLIPV ? -CLIPV : (d0 > CLIPV ? CLIPV : d0);
                    int d1 = j - ig1; d1 = d1 < -CLIPV ? -CLIPV : (d1 > CLIPV ? CLIPV : d1);
                    sf[ni][e]     += s.RQs[r0][d0 + CLIPV];
                    sf[ni][2 + e] += s.RQs[r1][d1 + CLIPV];
                }
            }
        }

        // ---- max reduction (raw for far tiles; bias folded as offset) ----
        float mt0 = -1e30f, mt1 = -1e30f;
#pragma unroll
        for (int ni = 0; ni < 8; ni++) {
            mt0 = fmaxf(mt0, fmaxf(sf[ni][0], sf[ni][1]));
            mt1 = fmaxf(mt1, fmaxf(sf[ni][2], sf[ni][3]));
        }
        mt0 = fmaxf(mt0, __shfl_xor_sync(0xffffffffu, mt0, 1));
        mt0 = fmaxf(mt0, __shfl_xor_sync(0xffffffffu, mt0, 2));
        mt1 = fmaxf(mt1, __shfl_xor_sync(0xffffffffu, mt1, 1));
        mt1 = fmaxf(mt1, __shfl_xor_sync(0xffffffffu, mt1, 2));

        float mn0, mn1, off0, off1;
        if (!diag) {
            float rq0 = far_left ? rqA0 : rqA32;
            float rq1 = far_left ? rqB0 : rqB32;
            mn0 = fmaxf(m0s, mt0 + rq0);
            mn1 = fmaxf(m1s, mt1 + rq1);
            off0 = mn0 - rq0; off1 = mn1 - rq1;
        } else {
            mn0 = fmaxf(m0s, mt0);
            mn1 = fmaxf(m1s, mt1);
            off0 = mn0; off1 = mn1;
        }

        // ---- warp-vote alpha skip ----
        bool nochg = (mn0 == m0s) && (mn1 == m1s);
        bool skip = __all_sync(0xffffffffu, nochg);
        float al0 = 1.f, al1 = 1.f;
        if (!skip) {
            al0 = exp2f(m0s - mn0);
            al1 = exp2f(m1s - mn1);
        }

        // ---- P = exp2(S - off) directly in fp16 fragments ----
        uint32_t ap[4][4];
#pragma unroll
        for (int kk = 0; kk < 4; kk++) {
            ap[kk][0] = h2exp2(packh2(sf[2 * kk][0] - off0,     sf[2 * kk][1] - off0));
            ap[kk][1] = h2exp2(packh2(sf[2 * kk][2] - off1,     sf[2 * kk][3] - off1));
            ap[kk][2] = h2exp2(packh2(sf[2 * kk + 1][0] - off0, sf[2 * kk + 1][1] - off0));
            ap[kk][3] = h2exp2(packh2(sf[2 * kk + 1][2] - off1, sf[2 * kk + 1][3] - off1));
        }

        // ---- row sums: one-level hadd2 pairing, then fp32 ----
        float rs0, rs1;
        {
            uint32_t h0 = h2add(ap[0][0], ap[0][2]);
            uint32_t h1 = h2add(ap[1][0], ap[1][2]);
            uint32_t h2 = h2add(ap[2][0], ap[2][2]);
            uint32_t h3 = h2add(ap[3][0], ap[3][2]);
            float2 f0 = h2unpack(h0), f1 = h2unpack(h1);
            float2 f2 = h2unpack(h2), f3 = h2unpack(h3);
            rs0 = ((f0.x + f0.y) + (f1.x + f1.y)) + ((f2.x + f2.y) + (f3.x + f3.y));
            uint32_t k0 = h2add(ap[0][1], ap[0][3]);
            uint32_t k1 = h2add(ap[1][1], ap[1][3]);
            uint32_t k2 = h2add(ap[2][1], ap[2][3]);
            uint32_t k3 = h2add(ap[3][1], ap[3][3]);
            float2 e0 = h2unpack(k0), e1 = h2unpack(k1);
            float2 e2 = h2unpack(k2), e3 = h2unpack(k3);
            rs1 = ((e0.x + e0.y) + (e1.x + e1.y)) + ((e2.x + e2.y) + (e3.x + e3.y));
        }
        rs0 += __shfl_xor_sync(0xffffffffu, rs0, 1);
        rs0 += __shfl_xor_sync(0xffffffffu, rs0, 2);
        rs1 += __shfl_xor_sync(0xffffffffu, rs1, 1);
        rs1 += __shfl_xor_sync(0xffffffffu, rs1, 2);
        if (skip) { l0 += rs0; l1 += rs1; }
        else      { l0 = l0 * al0 + rs0; l1 = l1 * al1 + rs1; }

        // ---- bucket weights ----
        if (far_left) {
            if (skip) { b0a += rs0; b0b += rs1; }
            else {
                b0a = b0a * al0 + rs0;  b0b = b0b * al1 + rs1;
                b32a *= al0;            b32b *= al1;
            }
        } else if (far_right) {
            if (skip) { b32a += rs0; b32b += rs1; }
            else {
                b32a = b32a * al0 + rs0; b32b = b32b * al1 + rs1;
                b0a *= al0;              b0b *= al1;
            }
        } else {
            // interior rescale — skipped when no row's diag reference changed
            bool wno = (mW0 == mn0) && (mW1 == mn1);
            if (!__all_sync(0xffffffffu, wno)) {
                float wsc0 = exp2f(mW0 - mn0);
                float wsc1 = exp2f(mW1 - mn1);
#pragma unroll
                for (int e = 0; e < 2; e++) {
                    int rr0 = (2 * c + e - ig0) & 7;
                    int rr1 = (2 * c + e - ig1) & 7;
#pragma unroll
                    for (int tt = 0; tt < 4; tt++) {
                        int t0 = rr0 + 8 * tt;
                        int t1 = rr1 + 8 * tt;
                        if (t0 >= 1) s.Wb[r0][t0] *= wsc0;
                        if (t1 >= 1) s.Wb[r1][t1] *= wsc1;
                    }
                }
            }
            float c0a = 0.f, c0b = 0.f, c32a = 0.f, c32b = 0.f;
#pragma unroll
            for (int kk = 0; kk < 4; kk++) {
#pragma unroll
                for (int sub = 0; sub < 2; sub++) {   // ni = 2kk+sub
                    int ni = 2 * kk + sub;
                    float2 p0 = h2unpack(ap[kk][2 * sub]);       // row r0
                    float2 p1 = h2unpack(ap[kk][2 * sub + 1]);   // row r1
                    int jb = j0 + ni * 8 + 2 * c;
                    int d0 = jb - ig0;
                    int d1 = jb - ig1;
                    if (d0 <= -CLIPV) c0a += p0.x;
                    else if (d0 >= CLIPV) c32a += p0.x;
                    else s.Wb[r0][d0 + CLIPV] += p0.x;
                    if (d0 + 1 <= -CLIPV) c0a += p0.y;
                    else if (d0 + 1 >= CLIPV) c32a += p0.y;
                    else s.Wb[r0][d0 + 1 + CLIPV] += p0.y;
                    if (d1 <= -CLIPV) c0b += p1.x;
                    else if (d1 >= CLIPV) c32b += p1.x;
                    else s.Wb[r1][d1 + CLIPV] += p1.x;
                    if (d1 + 1 <= -CLIPV) c0b += p1.y;
                    else if (d1 + 1 >= CLIPV) c32b += p1.y;
                    else s.Wb[r1][d1 + 1 + CLIPV] += p1.y;
                }
            }
            c0a += __shfl_xor_sync(0xffffffffu, c0a, 1);
            c0a += __shfl_xor_sync(0xffffffffu, c0a, 2);
            c0b += __shfl_xor_sync(0xffffffffu, c0b, 1);
            c0b += __shfl_xor_sync(0xffffffffu, c0b, 2);
            c32a += __shfl_xor_sync(0xffffffffu, c32a, 1);
            c32a += __shfl_xor_sync(0xffffffffu, c32a, 2);
            c32b += __shfl_xor_sync(0xffffffffu, c32b, 1);
            c32b += __shfl_xor_sync(0xffffffffu, c32b, 2);
            if (skip) {
                b0a += c0a;   b0b += c0b;
                b32a += c32a; b32b += c32b;
            } else {
                b0a = b0a * al0 + c0a;   b0b = b0b * al1 + c0b;
                b32a = b32a * al0 + c32a; b32b = b32b * al1 + c32b;
            }
            mW0 = mn0; mW1 = mn1;
        }
        m0s = mn0; m1s = mn1;

        // ---- acc = acc*alpha (skipped when max unchanged) + P @ V ----
        if (!skip) {
#pragma unroll
            for (int ni = 0; ni < 8; ni++) {
                acc[ni][0] *= al0; acc[ni][1] *= al0;
                acc[ni][2] *= al1; acc[ni][3] *= al1;
            }
        }
#pragma unroll
        for (int kk = 0; kk < 4; kk++) {
#pragma unroll
            for (int p = 0; p < 4; p++) {
                uint32_t b0, b1, b2, b3;
                ldsm4t(b0, b1, b2, b3, &s.Vs[buf][kk * 16 + vrow][p * 16 + vcol]);
                mma_f16(acc[2 * p],     ap[kk][0], ap[kk][1], ap[kk][2], ap[kk][3], b0, b2);
                mma_f16(acc[2 * p + 1], ap[kk][0], ap[kk][1], ap[kk][2], ap[kk][3], b1, b3);
            }
        }
    }

    if (c == 0) {
        s.Wb[r0][0] = b0a;  s.Wb[r0][32] = b32a;
        s.Wb[r1][0] = b0b;  s.Wb[r1][32] = b32b;
        s.wscale[r0] = exp2f(mW0 - m0s);
        s.wscale[r1] = exp2f(mW1 - m1s);
        s.linv[r0] = 1.f / l0;
        s.linv[r1] = 1.f / l1;
    }
    __syncthreads();

    float* scr = (float*)&s.Ks[0][0][0];
    {
        int i = tid >> 1;
        int h = (tid & 1) * 32;
        float ws = s.wscale[i];
        float sc[32];
#pragma unroll
        for (int d = 0; d < 32; d++) sc[d] = 0.f;
        for (int t = 0; t < NT; t++) {
            float w = s.Wb[i][t];
            if (t != 0 && t != 32) w *= ws;
#pragma unroll
            for (int d = 0; d < 32; d++)
                sc[d] += w * s.relvs[t][h + d];
        }
#pragma unroll
        for (int d = 0; d < 32; d++) scr[i * 68 + h + d] = sc[d];
    }
    __syncthreads();

    {
        float li0 = s.linv[r0], li1 = s.linv[r1];
        int bb = bh >> 4, hh = bh & 15;
        __half* y0 = Y + ((size_t)(bb * 1024 + i0 + r0)) * 1024 + hh * 64;
        __half* y1 = Y + ((size_t)(bb * 1024 + i0 + r1)) * 1024 + hh * 64;
#pragma unroll
        for (int ni = 0; ni < 8; ni++) {
            int col = ni * 8 + 2 * c;
            *(uint32_t*)(y0 + col) = packh2((acc[ni][0] + scr[r0 * 68 + col]) * li0,
                                            (acc[ni][1] + scr[r0 * 68 + col + 1]) * li0);
            *(uint32_t*)(y1 + col) = packh2((acc[ni][2] + scr[r1 * 68 + col]) * li1,
                                            (acc[ni][3] + scr[r1 * 68 + col + 1]) * li1);
        }
    }
}

// ---------------------------------------------------------------------------

extern "C" void kernel_launch(void* const* d_in, const int* in_sizes, int n_in,
                              void* d_out, int out_size)
{
    const float* query = (const float*)d_in[0];
    const float* key   = (const float*)d_in[1];
    const float* value = (const float*)d_in[2];
    const float* wq = (const float*)d_in[3];
    const float* bq = (const float*)d_in[4];
    const float* wk = (const float*)d_in[5];
    const float* bk = (const float*)d_in[6];
    const float* wv = (const float*)d_in[7];
    const float* bv = (const float*)d_in[8];
    const float* wo = (const float*)d_in[9];
    const float* bo = (const float*)d_in[10];
    const float* relk = (const float*)d_in[11];
    const float* relv = (const float*)d_in[12];
    float* out = (float*)d_out;

    __half *Qp, *Kp, *Vp, *Yp, *Xq, *Xk, *Xv, *Wq, *Wk, *Wv, *Wo;
    cudaGetSymbolAddress((void**)&Qp, gQ);
    cudaGetSymbolAddress((void**)&Kp, gK);
    cudaGetSymbolAddress((void**)&Vp, gV);
    cudaGetSymbolAddress((void**)&Yp, gY);
    cudaGetSymbolAddress((void**)&Xq, gXq);
    cudaGetSymbolAddress((void**)&Xk, gXk);
    cudaGetSymbolAddress((void**)&Xv, gXv);
    cudaGetSymbolAddress((void**)&Wq, gWq);
    cudaGetSymbolAddress((void**)&Wk, gWk);
    cudaGetSymbolAddress((void**)&Wv, gWv);
    cudaGetSymbolAddress((void**)&Wo, gWo);

    convert7_kernel<<<dim3(512, 7), 256>>>(query, key, value, wq, wk, wv, wo,
                                           Xq, Xk, Xv, Wq, Wk, Wv, Wo);

    cudaFuncSetAttribute(qkv_gemm_kernel, cudaFuncAttributeMaxDynamicSharedMemorySize,
                         GS_TOTAL);
    cudaFuncSetAttribute(out_gemm_kernel, cudaFuncAttributeMaxDynamicSharedMemorySize,
                         GS_TOTAL);
    cudaFuncSetAttribute(attn_kernel, cudaFuncAttributeMaxDynamicSharedMemorySize,
                         (int)sizeof(AttnSmem));

    qkv_gemm_kernel<<<dim3(8, 32, 3), 256, GS_TOTAL>>>(Xq, Xk, Xv, Wq, Wk, Wv,
                                                       bq, bk, bv, Qp, Kp, Vp);

    attn_kernel<<<dim3(8, 64), 256, sizeof(AttnSmem)>>>(Qp, Kp, Vp, relk, relv, Yp);

    out_gemm_kernel<<<dim3(8, 32), 256, GS_TOTAL>>>(Yp, Wo, bo, out);
}

// round 16
// speedup vs baseline: 9.8346x; 1.0789x over previous
#include <cuda_runtime.h>
#include <cuda_fp16.h>
#include <math.h>
#include <cstdint>

// Problem constants
#define Bn  4
#define Ln  1024
#define En  1024
#define Hn  16
#define HDn 64
#define NT  33          // 2*CLIP+1
#define CLIPV 16
#define SCALEF 0.125f   // 1/sqrt(64)
#define LOG2E 1.4426950408889634f

// Scratch (device globals; no allocation allowed)
__device__ __half gQ[Bn*Hn*Ln*HDn];   // [b][h][l][d] fp16
__device__ __half gK[Bn*Hn*Ln*HDn];
__device__ __half gV[Bn*Hn*Ln*HDn];
__device__ __half gY[Bn*Ln*En];       // [b][l][e] fp16
__device__ __half gXq[Bn*Ln*En];      // fp16 inputs
__device__ __half gXk[Bn*Ln*En];
__device__ __half gXv[Bn*Ln*En];
__device__ __half gWq[En*En];         // fp16 weights
__device__ __half gWk[En*En];
__device__ __half gWv[En*En];
__device__ __half gWo[En*En];

// ---------------------------------------------------------------------------
// helpers
// ---------------------------------------------------------------------------
__device__ __forceinline__ uint32_t packh2(float x, float y) {
    __half2 h = __floats2half2_rn(x, y);
    return *reinterpret_cast<uint32_t*>(&h);
}

__device__ __forceinline__ uint32_t h2exp2(uint32_t x) {
    uint32_t r;
    asm("ex2.approx.f16x2 %0, %1;" : "=r"(r) : "r"(x));
    return r;
}

__device__ __forceinline__ float2 h2unpack(uint32_t x) {
    __half2 h = *reinterpret_cast<__half2*>(&x);
    return __half22float2(h);
}

__device__ __forceinline__ uint32_t h2add(uint32_t a, uint32_t b) {
    __half2 ha = *reinterpret_cast<__half2*>(&a);
    __half2 hb = *reinterpret_cast<__half2*>(&b);
    __half2 hc = __hadd2(ha, hb);
    return *reinterpret_cast<uint32_t*>(&hc);
}

__device__ __forceinline__ void cp_async16(void* dst, const void* src) {
    uint32_t d = (uint32_t)__cvta_generic_to_shared(dst);
    asm volatile("cp.async.cg.shared.global [%0], [%1], 16;\n" :: "r"(d), "l"(src));
}

__device__ __forceinline__ void cp_async16_s(uint32_t dst, const void* src) {
    asm volatile("cp.async.cg.shared.global [%0], [%1], 16;\n" :: "r"(dst), "l"(src));
}

__device__ __forceinline__ void ldsm4(uint32_t& r0, uint32_t& r1,
                                      uint32_t& r2, uint32_t& r3, const void* p) {
    uint32_t a = (uint32_t)__cvta_generic_to_shared(p);
    asm volatile("ldmatrix.sync.aligned.m8n8.x4.shared.b16 {%0,%1,%2,%3}, [%4];"
                 : "=r"(r0), "=r"(r1), "=r"(r2), "=r"(r3) : "r"(a));
}

__device__ __forceinline__ void ldsm4_s(uint32_t& r0, uint32_t& r1,
                                        uint32_t& r2, uint32_t& r3, uint32_t a) {
    asm volatile("ldmatrix.sync.aligned.m8n8.x4.shared.b16 {%0,%1,%2,%3}, [%4];"
                 : "=r"(r0), "=r"(r1), "=r"(r2), "=r"(r3) : "r"(a));
}

__device__ __forceinline__ void ldsm4t(uint32_t& r0, uint32_t& r1,
                                       uint32_t& r2, uint32_t& r3, const void* p) {
    uint32_t a = (uint32_t)__cvta_generic_to_shared(p);
    asm volatile("ldmatrix.sync.aligned.m8n8.x4.trans.shared.b16 {%0,%1,%2,%3}, [%4];"
                 : "=r"(r0), "=r"(r1), "=r"(r2), "=r"(r3) : "r"(a));
}

__device__ __forceinline__ void mma_f16(float* d,
    uint32_t a0, uint32_t a1, uint32_t a2, uint32_t a3,
    uint32_t b0, uint32_t b1)
{
    asm volatile(
        "mma.sync.aligned.m16n8k16.row.col.f32.f16.f16.f32 "
        "{%0,%1,%2,%3}, {%4,%5,%6,%7}, {%8,%9}, {%0,%1,%2,%3};"
        : "+f"(d[0]), "+f"(d[1]), "+f"(d[2]), "+f"(d[3])
        : "r"(a0), "r"(a1), "r"(a2), "r"(a3), "r"(b0), "r"(b1));
}

__device__ __forceinline__ uint32_t sw128(uint32_t off) {
    return off ^ ((off >> 3) & 0x70);
}

// ---------------------------------------------------------------------------
// fp32 -> fp16 conversion of 3 inputs + 4 weights.
// ---------------------------------------------------------------------------
__global__ __launch_bounds__(256) void convert7_kernel(
    const float* __restrict__ xq, const float* __restrict__ xk,
    const float* __restrict__ xv,
    const float* __restrict__ wq, const float* __restrict__ wk,
    const float* __restrict__ wv, const float* __restrict__ wo,
    __half* __restrict__ oxq, __half* __restrict__ oxk, __half* __restrict__ oxv,
    __half* __restrict__ owq, __half* __restrict__ owk,
    __half* __restrict__ owv, __half* __restrict__ owo)
{
    int t = blockIdx.y;
    const float* src; __half* dst; int n8;
    switch (t) {
        case 0: src = xq; dst = oxq; n8 = (Bn*Ln*En)/8; break;
        case 1: src = xk; dst = oxk; n8 = (Bn*Ln*En)/8; break;
        case 2: src = xv; dst = oxv; n8 = (Bn*Ln*En)/8; break;
        case 3: src = wq; dst = owq; n8 = (En*En)/8; break;
        case 4: src = wk; dst = owk; n8 = (En*En)/8; break;
        case 5: src = wv; dst = owv; n8 = (En*En)/8; break;
        default: src = wo; dst = owo; n8 = (En*En)/8; break;
    }
    int stride = gridDim.x * 256;
    for (int i = blockIdx.x * 256 + threadIdx.x; i < n8; i += stride) {
        float4 a = ((const float4*)src)[2*i];
        float4 b = ((const float4*)src)[2*i + 1];
        uint4 o;
        o.x = packh2(a.x, a.y); o.y = packh2(a.z, a.w);
        o.z = packh2(b.x, b.y); o.w = packh2(b.z, b.w);
        ((uint4*)dst)[i] = o;
    }
}

// ---------------------------------------------------------------------------
// fp16 tensor-core GEMM (unchanged — fully unrolled k-loop).
// ---------------------------------------------------------------------------
#define GTILE 16384                       // 128 rows * 128 bytes
#define GS_TOTAL (6 * GTILE)              // 3 stages * (A + B) = 96 KB

__device__ __forceinline__ void gemm_body(
    const __half* __restrict__ A, const __half* __restrict__ W,
    const float* __restrict__ bias, void* __restrict__ Cout, int head_layout)
{
    extern __shared__ char sm[];
    uint32_t smem = (uint32_t)__cvta_generic_to_shared(sm);
    uint32_t smA = smem, smB = smem + 3 * GTILE;
    const int Kd = 1024;

    int tid  = threadIdx.x;
    int warp = tid >> 5, lane = tid & 31;
    int wm = (warp >> 1) << 5;
    int wn = (warp & 1) << 6;
    int g = lane >> 2, c = lane & 3;
    int m0 = blockIdx.y << 7, n0 = blockIdx.x << 7;

    int lrow = (lane & 7) + ((lane >> 3) & 1) * 8;
    int lcol = (lane >> 4) * 8;

    int r = tid >> 1;
    int chbase = (tid & 1) * 4;
    const __half* Ag = A + (size_t)(m0 + r) * Kd;
    const __half* Wg = W + (size_t)(n0 + r) * Kd;

    float acc[2][8][4];
#pragma unroll
    for (int mi = 0; mi < 2; mi++)
#pragma unroll
        for (int ni = 0; ni < 8; ni++)
#pragma unroll
            for (int q = 0; q < 4; q++) acc[mi][ni][q] = 0.f;

    auto load_stage = [&](int s, int k0) {
#pragma unroll
        for (int q = 0; q < 4; q++) {
            int ch = chbase + q;
            uint32_t d = sw128((uint32_t)(r * 128 + ch * 16));
            cp_async16_s(smA + s * GTILE + d, Ag + k0 + ch * 8);
            cp_async16_s(smB + s * GTILE + d, Wg + k0 + ch * 8);
        }
    };

    load_stage(0, 0);
    asm volatile("cp.async.commit_group;\n");
    load_stage(1, 64);
    asm volatile("cp.async.commit_group;\n");

    const int NITER = Kd / 64;   // 16
#pragma unroll
    for (int t = 0; t < NITER; t++) {
        asm volatile("cp.async.wait_group 1;\n");
        __syncthreads();
        if (t + 2 < NITER) {
            load_stage((t + 2) % 3, (t + 2) * 64);
        }
        asm volatile("cp.async.commit_group;\n");

        const int s = t % 3;
#pragma unroll
        for (int ks = 0; ks < 4; ks++) {
            int kc = ks * 16 + lcol;
            uint32_t af[2][4], bf[4][4];
#pragma unroll
            for (int mi = 0; mi < 2; mi++) {
                uint32_t addr = smA + s * GTILE +
                    sw128((uint32_t)((wm + mi * 16 + lrow) * 128 + kc * 2));
                ldsm4_s(af[mi][0], af[mi][1], af[mi][2], af[mi][3], addr);
            }
#pragma unroll
            for (int p = 0; p < 4; p++) {
                uint32_t addr = smB + s * GTILE +
                    sw128((uint32_t)((wn + p * 16 + lrow) * 128 + kc * 2));
                ldsm4_s(bf[p][0], bf[p][1], bf[p][2], bf[p][3], addr);
            }
#pragma unroll
            for (int mi = 0; mi < 2; mi++)
#pragma unroll
                for (int ni = 0; ni < 8; ni++) {
                    int p = ni >> 1;
                    uint32_t b0 = (ni & 1) ? bf[p][1] : bf[p][0];
                    uint32_t b1 = (ni & 1) ? bf[p][3] : bf[p][2];
                    mma_f16(acc[mi][ni], af[mi][0], af[mi][1], af[mi][2], af[mi][3],
                            b0, b1);
                }
        }
    }

#pragma unroll
    for (int mi = 0; mi < 2; mi++) {
#pragma unroll
        for (int ni = 0; ni < 8; ni++) {
            int row = m0 + wm + (mi << 4) + g;
            int col = n0 + wn + (ni << 3) + (c << 1);
            float b0 = bias[col], b1 = bias[col + 1];
            float x0 = acc[mi][ni][0] + b0, x1 = acc[mi][ni][1] + b1;
            float x2 = acc[mi][ni][2] + b0, x3 = acc[mi][ni][3] + b1;
            if (head_layout) {
                __half* C = (__half*)Cout;
                int b = row >> 10, l = row & 1023, h = col >> 6, d = col & 63;
                size_t off = (((size_t)(b * Hn + h)) << 16) + ((size_t)l << 6) + d;
                *(uint32_t*)(C + off) = packh2(x0, x1);
                int row2 = row + 8;
                int b2 = row2 >> 10, l2 = row2 & 1023;
                size_t off2 = (((size_t)(b2 * Hn + h)) << 16) + ((size_t)l2 << 6) + d;
                *(uint32_t*)(C + off2) = packh2(x2, x3);
            } else {
                float* C = (float*)Cout;
                *(float2*)(C + (size_t)row * 1024 + col) = make_float2(x0, x1);
                *(float2*)(C + (size_t)(row + 8) * 1024 + col) = make_float2(x2, x3);
            }
        }
    }
}

__global__ __launch_bounds__(256, 2) void qkv_gemm_kernel(
    const __half* __restrict__ xq, const __half* __restrict__ xk,
    const __half* __restrict__ xv,
    const __half* __restrict__ wq, const __half* __restrict__ wk,
    const __half* __restrict__ wv,
    const float* __restrict__ bq, const float* __restrict__ bk,
    const float* __restrict__ bv,
    __half* __restrict__ Q, __half* __restrict__ K, __half* __restrict__ V)
{
    if (blockIdx.z == 0)      gemm_body(xq, wq, bq, Q, 1);
    else if (blockIdx.z == 1) gemm_body(xk, wk, bk, K, 1);
    else                      gemm_body(xv, wv, bv, V, 1);
}

__global__ __launch_bounds__(256, 2) void out_gemm_kernel(
    const __half* __restrict__ Y, const __half* __restrict__ wo,
    const float* __restrict__ bo, float* __restrict__ out)
{
    gemm_body(Y, wo, bo, out, 0);
}

// ---------------------------------------------------------------------------
// fp16 tensor-core flash attention; log2-domain softmax, f16x2 exp, hoisted
// Q fragments + far-tile RQ biases, RQ via MMA, hadd2-paired row sums,
// warp-vote alpha/rescale skips, atomic-free residue-partitioned buckets,
// rel_v epilogue via MMA (W' fp16 A-fragments x relv fp16 B, K padded to 48).
// ---------------------------------------------------------------------------
#define QPAD 72

struct __align__(16) AttnSmem {
    __half Qs[128][QPAD];     // SCALE*LOG2E folded
    __half Ks[2][64][QPAD];   // [j][d]
    __half Vs[2][64][QPAD];   // [j][d]
    float RQs[128][NT];       // log2-domain bias
    float Wb[128][NT];
    __half relkh[48][QPAD];   // fp16 relk, rows 33..47 zero (MMA B operand)
    __half relvh[48][QPAD];   // fp16 relv, rows 33..47 zero (MMA B operand)
};

__device__ __forceinline__ void load_kv_tile(AttnSmem& s, int buf,
    const __half* Kb, const __half* Vb, int j0, int tid)
{
    int j = tid >> 2;
    int ch = (tid & 3) << 4;
    const __half* ks = Kb + (size_t)(j0 + j) * 64 + ch;
    const __half* vs = Vb + (size_t)(j0 + j) * 64 + ch;
    cp_async16(&s.Ks[buf][j][ch],     ks);
    cp_async16(&s.Ks[buf][j][ch + 8], ks + 8);
    cp_async16(&s.Vs[buf][j][ch],     vs);
    cp_async16(&s.Vs[buf][j][ch + 8], vs + 8);
}

__global__ __launch_bounds__(256, 2) void attn_kernel(
    const __half* __restrict__ Q, const __half* __restrict__ Kg,
    const __half* __restrict__ Vg, const float* __restrict__ relk,
    const float* __restrict__ relv, __half* __restrict__ Y)
{
    extern __shared__ char smem_raw[];
    AttnSmem& s = *reinterpret_cast<AttnSmem*>(smem_raw);
    int tid = threadIdx.x;
    int warp = tid >> 5, lane = tid & 31;
    int g = lane >> 2, c = lane & 3;
    int r0 = warp * 16 + g;
    int r1 = r0 + 8;
    int lrow = (lane & 7) + ((lane >> 3) & 1) * 8;
    int lcol = (lane >> 4) * 8;
    int vrow = (lane & 7) + (lane >> 4) * 8;
    int vcol = ((lane >> 3) & 1) * 8;

    int bh = blockIdx.y;
    int bx = blockIdx.x;
    int i0 = bx * 128;
    const __half* Qb = Q + ((size_t)bh << 16) + (size_t)i0 * 64;
    const __half* Kb = Kg + ((size_t)bh << 16);
    const __half* Vb = Vg + ((size_t)bh << 16);

    load_kv_tile(s, 0, Kb, Vb, 0, tid);
    asm volatile("cp.async.commit_group;\n");
    {
        int r = tid >> 1;
        int seg = (tid & 1) * 32;
        const __half* src = Qb + (size_t)r * 64 + seg;
        __half2 hs = __float2half2_rn(SCALEF * LOG2E);   // log2 domain
#pragma unroll
        for (int q = 0; q < 4; q++) {
            uint4 v = *(const uint4*)(src + q * 8);
            __half2* hv = (__half2*)&v;
#pragma unroll
            for (int e = 0; e < 4; e++) hv[e] = __hmul2(hv[e], hs);
            *(uint4*)&s.Qs[r][seg + q * 8] = v;
        }
    }
    for (int idx = tid; idx < 48 * 64; idx += 256) {
        int row = idx >> 6, col = idx & 63;
        bool valid = (row < NT);
        s.relkh[row][col] = valid ? __float2half(relk[row * 64 + col]) : __float2half(0.f);
        s.relvh[row][col] = valid ? __float2half(relv[row * 64 + col]) : __float2half(0.f);
    }
    for (int idx = tid; idx < 128 * NT; idx += 256)
        s.Wb[idx / NT][idx % NT] = 0.f;
    __syncthreads();

    // hoist Q fragments (loop-invariant across j-tiles)
    uint32_t aq[4][4];
#pragma unroll
    for (int ks = 0; ks < 4; ks++)
        ldsm4(aq[ks][0], aq[ks][1], aq[ks][2], aq[ks][3],
              &s.Qs[warp * 16 + lrow][ks * 16 + lcol]);

    // ---- RQ = Q @ relk^T via tensor cores (N padded to 48) ----
    {
        float rqf[6][4];
#pragma unroll
        for (int u = 0; u < 6; u++)
#pragma unroll
            for (int q = 0; q < 4; q++) rqf[u][q] = 0.f;
#pragma unroll
        for (int ks = 0; ks < 4; ks++) {
            int kc = ks * 16 + lcol;
#pragma unroll
            for (int p = 0; p < 3; p++) {
                uint32_t b0, b1, b2, b3;
                ldsm4(b0, b1, b2, b3, &s.relkh[p * 16 + lrow][kc]);
                mma_f16(rqf[2 * p],     aq[ks][0], aq[ks][1], aq[ks][2], aq[ks][3], b0, b2);
                mma_f16(rqf[2 * p + 1], aq[ks][0], aq[ks][1], aq[ks][2], aq[ks][3], b1, b3);
            }
        }
#pragma unroll
        for (int p = 0; p < 3; p++)
#pragma unroll
            for (int sub = 0; sub < 2; sub++)
#pragma unroll
                for (int e = 0; e < 2; e++) {
                    int t = p * 16 + sub * 8 + 2 * c + e;
                    if (t < NT) {
                        s.RQs[r0][t] = rqf[2 * p + sub][e];
                        s.RQs[r1][t] = rqf[2 * p + sub][2 + e];
                    }
                }
    }
    __syncthreads();   // RQs scatter visible to all threads
    // hoist far-tile biases (buckets 0 and 32) into registers
    float rqA0 = s.RQs[r0][0], rqA32 = s.RQs[r0][32];
    float rqB0 = s.RQs[r1][0], rqB32 = s.RQs[r1][32];

    float m0s = -1e30f, m1s = -1e30f;
    float l0 = 0.f, l1 = 0.f;
    float b0a = 0.f, b0b = 0.f, b32a = 0.f, b32b = 0.f;
    float mW0 = -1e30f, mW1 = -1e30f;
    float acc[8][4];
#pragma unroll
    for (int ni = 0; ni < 8; ni++)
#pragma unroll
        for (int q = 0; q < 4; q++) acc[ni][q] = 0.f;

    int ig0 = i0 + r0, ig1 = i0 + r1;

#pragma unroll 2
    for (int jt = 0; jt < 16; jt++) {
        int buf = jt & 1;
        int j0 = jt * 64;
        asm volatile("cp.async.wait_group 0;\n");
        __syncthreads();      // KV[buf] visible
        if (jt + 1 < 16)
            load_kv_tile(s, buf ^ 1, Kb, Vb, j0 + 64, tid);
        asm volatile("cp.async.commit_group;\n");

        int dj = jt - 2 * bx;
        bool far_left  = (dj <= -2);
        bool far_right = (dj >= 3);
        bool diag = !(far_left || far_right);

        // ---- S = Q K^T ----
        float sf[8][4];
#pragma unroll
        for (int ni = 0; ni < 8; ni++)
#pragma unroll
            for (int q = 0; q < 4; q++) sf[ni][q] = 0.f;
#pragma unroll
        for (int ks = 0; ks < 4; ks++) {
            int kc = ks * 16 + lcol;
#pragma unroll
            for (int p = 0; p < 4; p++) {
                uint32_t b0, b1, b2, b3;
                ldsm4(b0, b1, b2, b3, &s.Ks[buf][p * 16 + lrow][kc]);
                mma_f16(sf[2 * p],     aq[ks][0], aq[ks][1], aq[ks][2], aq[ks][3], b0, b2);
                mma_f16(sf[2 * p + 1], aq[ks][0], aq[ks][1], aq[ks][2], aq[ks][3], b1, b3);
            }
        }

        // ---- diag tiles: per-element bias before max ----
        if (diag) {
#pragma unroll
            for (int ni = 0; ni < 8; ni++) {
#pragma unroll
                for (int e = 0; e < 2; e++) {
                    int j = j0 + ni * 8 + 2 * c + e;
                    int d0 = j - ig0; d0 = d0 < -CLIPV ? -CLIPV : (d0 > CLIPV ? CLIPV : d0);
                    int d1 = j - ig1; d1 = d1 < -CLIPV ? -CLIPV : (d1 > CLIPV ? CLIPV : d1);
                    sf[ni][e]     += s.RQs[r0][d0 + CLIPV];
                    sf[ni][2 + e] += s.RQs[r1][d1 + CLIPV];
                }
            }
        }

        // ---- max reduction (raw for far tiles; bias folded as offset) ----
        float mt0 = -1e30f, mt1 = -1e30f;
#pragma unroll
        for (int ni = 0; ni < 8; ni++) {
            mt0 = fmaxf(mt0, fmaxf(sf[ni][0], sf[ni][1]));
            mt1 = fmaxf(mt1, fmaxf(sf[ni][2], sf[ni][3]));
        }
        mt0 = fmaxf(mt0, __shfl_xor_sync(0xffffffffu, mt0, 1));
        mt0 = fmaxf(mt0, __shfl_xor_sync(0xffffffffu, mt0, 2));
        mt1 = fmaxf(mt1, __shfl_xor_sync(0xffffffffu, mt1, 1));
        mt1 = fmaxf(mt1, __shfl_xor_sync(0xffffffffu, mt1, 2));

        float mn0, mn1, off0, off1;
        if (!diag) {
            float rq0 = far_left ? rqA0 : rqA32;
            float rq1 = far_left ? rqB0 : rqB32;
            mn0 = fmaxf(m0s, mt0 + rq0);
            mn1 = fmaxf(m1s, mt1 + rq1);
            off0 = mn0 - rq0; off1 = mn1 - rq1;
        } else {
            mn0 = fmaxf(m0s, mt0);
            mn1 = fmaxf(m1s, mt1);
            off0 = mn0; off1 = mn1;
        }

        // ---- warp-vote alpha skip ----
        bool nochg = (mn0 == m0s) && (mn1 == m1s);
        bool skip = __all_sync(0xffffffffu, nochg);
        float al0 = 1.f, al1 = 1.f;
        if (!skip) {
            al0 = exp2f(m0s - mn0);
            al1 = exp2f(m1s - mn1);
        }

        // ---- P = exp2(S - off) directly in fp16 fragments ----
        uint32_t ap[4][4];
#pragma unroll
        for (int kk = 0; kk < 4; kk++) {
            ap[kk][0] = h2exp2(packh2(sf[2 * kk][0] - off0,     sf[2 * kk][1] - off0));
            ap[kk][1] = h2exp2(packh2(sf[2 * kk][2] - off1,     sf[2 * kk][3] - off1));
            ap[kk][2] = h2exp2(packh2(sf[2 * kk + 1][0] - off0, sf[2 * kk + 1][1] - off0));
            ap[kk][3] = h2exp2(packh2(sf[2 * kk + 1][2] - off1, sf[2 * kk + 1][3] - off1));
        }

        // ---- row sums: one-level hadd2 pairing, then fp32 ----
        float rs0, rs1;
        {
            uint32_t h0 = h2add(ap[0][0], ap[0][2]);
            uint32_t h1 = h2add(ap[1][0], ap[1][2]);
            uint32_t h2 = h2add(ap[2][0], ap[2][2]);
            uint32_t h3 = h2add(ap[3][0], ap[3][2]);
            float2 f0 = h2unpack(h0), f1 = h2unpack(h1);
            float2 f2 = h2unpack(h2), f3 = h2unpack(h3);
            rs0 = ((f0.x + f0.y) + (f1.x + f1.y)) + ((f2.x + f2.y) + (f3.x + f3.y));
            uint32_t k0 = h2add(ap[0][1], ap[0][3]);
            uint32_t k1 = h2add(ap[1][1], ap[1][3]);
            uint32_t k2 = h2add(ap[2][1], ap[2][3]);
            uint32_t k3 = h2add(ap[3][1], ap[3][3]);
            float2 e0 = h2unpack(k0), e1 = h2unpack(k1);
            float2 e2 = h2unpack(k2), e3 = h2unpack(k3);
            rs1 = ((e0.x + e0.y) + (e1.x + e1.y)) + ((e2.x + e2.y) + (e3.x + e3.y));
        }
        rs0 += __shfl_xor_sync(0xffffffffu, rs0, 1);
        rs0 += __shfl_xor_sync(0xffffffffu, rs0, 2);
        rs1 += __shfl_xor_sync(0xffffffffu, rs1, 1);
        rs1 += __shfl_xor_sync(0xffffffffu, rs1, 2);
        if (skip) { l0 += rs0; l1 += rs1; }
        else      { l0 = l0 * al0 + rs0; l1 = l1 * al1 + rs1; }

        // ---- bucket weights ----
        if (far_left) {
            if (skip) { b0a += rs0; b0b += rs1; }
            else {
                b0a = b0a * al0 + rs0;  b0b = b0b * al1 + rs1;
                b32a *= al0;            b32b *= al1;
            }
        } else if (far_right) {
            if (skip) { b32a += rs0; b32b += rs1; }
            else {
                b32a = b32a * al0 + rs0; b32b = b32b * al1 + rs1;
                b0a *= al0;              b0b *= al1;
            }
        } else {
            // interior rescale — skipped when no row's diag reference changed
            bool wno = (mW0 == mn0) && (mW1 == mn1);
            if (!__all_sync(0xffffffffu, wno)) {
                float wsc0 = exp2f(mW0 - mn0);
                float wsc1 = exp2f(mW1 - mn1);
#pragma unroll
                for (int e = 0; e < 2; e++) {
                    int rr0 = (2 * c + e - ig0) & 7;
                    int rr1 = (2 * c + e - ig1) & 7;
#pragma unroll
                    for (int tt = 0; tt < 4; tt++) {
                        int t0 = rr0 + 8 * tt;
                        int t1 = rr1 + 8 * tt;
                        if (t0 >= 1) s.Wb[r0][t0] *= wsc0;
                        if (t1 >= 1) s.Wb[r1][t1] *= wsc1;
                    }
                }
            }
            float c0a = 0.f, c0b = 0.f, c32a = 0.f, c32b = 0.f;
#pragma unroll
            for (int kk = 0; kk < 4; kk++) {
#pragma unroll
                for (int sub = 0; sub < 2; sub++) {   // ni = 2kk+sub
                    int ni = 2 * kk + sub;
                    float2 p0 = h2unpack(ap[kk][2 * sub]);       // row r0
                    float2 p1 = h2unpack(ap[kk][2 * sub + 1]);   // row r1
                    int jb = j0 + ni * 8 + 2 * c;
                    int d0 = jb - ig0;
                    int d1 = jb - ig1;
                    if (d0 <= -CLIPV) c0a += p0.x;
                    else if (d0 >= CLIPV) c32a += p0.x;
                    else s.Wb[r0][d0 + CLIPV] += p0.x;
                    if (d0 + 1 <= -CLIPV) c0a += p0.y;
                    else if (d0 + 1 >= CLIPV) c32a += p0.y;
                    else s.Wb[r0][d0 + 1 + CLIPV] += p0.y;
                    if (d1 <= -CLIPV) c0b += p1.x;
                    else if (d1 >= CLIPV) c32b += p1.x;
                    else s.Wb[r1][d1 + CLIPV] += p1.x;
                    if (d1 + 1 <= -CLIPV) c0b += p1.y;
                    else if (d1 + 1 >= CLIPV) c32b += p1.y;
                    else s.Wb[r1][d1 + 1 + CLIPV] += p1.y;
                }
            }
            c0a += __shfl_xor_sync(0xffffffffu, c0a, 1);
            c0a += __shfl_xor_sync(0xffffffffu, c0a, 2);
            c0b += __shfl_xor_sync(0xffffffffu, c0b, 1);
            c0b += __shfl_xor_sync(0xffffffffu, c0b, 2);
            c32a += __shfl_xor_sync(0xffffffffu, c32a, 1);
            c32a += __shfl_xor_sync(0xffffffffu, c32a, 2);
            c32b += __shfl_xor_sync(0xffffffffu, c32b, 1);
            c32b += __shfl_xor_sync(0xffffffffu, c32b, 2);
            if (skip) {
                b0a += c0a;   b0b += c0b;
                b32a += c32a; b32b += c32b;
            } else {
                b0a = b0a * al0 + c0a;   b0b = b0b * al1 + c0b;
                b32a = b32a * al0 + c32a; b32b = b32b * al1 + c32b;
            }
            mW0 = mn0; mW1 = mn1;
        }
        m0s = mn0; m1s = mn1;

        // ---- acc = acc*alpha (skipped when max unchanged) + P @ V ----
        if (!skip) {
#pragma unroll
            for (int ni = 0; ni < 8; ni++) {
                acc[ni][0] *= al0; acc[ni][1] *= al0;
                acc[ni][2] *= al1; acc[ni][3] *= al1;
            }
        }
#pragma unroll
        for (int kk = 0; kk < 4; kk++) {
#pragma unroll
            for (int p = 0; p < 4; p++) {
                uint32_t b0, b1, b2, b3;
                ldsm4t(b0, b1, b2, b3, &s.Vs[buf][kk * 16 + vrow][p * 16 + vcol]);
                mma_f16(acc[2 * p],     ap[kk][0], ap[kk][1], ap[kk][2], ap[kk][3], b0, b2);
                mma_f16(acc[2 * p + 1], ap[kk][0], ap[kk][1], ap[kk][2], ap[kk][3], b1, b3);
            }
        }
    }

    // ---- finalize boundary buckets into smem ----
    if (c == 0) {
        s.Wb[r0][0] = b0a;  s.Wb[r0][32] = b32a;
        s.Wb[r1][0] = b0b;  s.Wb[r1][32] = b32b;
    }
    __syncthreads();   // all bucket writes (scatter + boundary) visible

    // ---- rel_v epilogue via MMA: acc += W' @ relv (K=48 padded) ----
    {
        float ws0 = exp2f(mW0 - m0s);   // interior-bucket rescale to final max
        float ws1 = exp2f(mW1 - m1s);
        uint32_t aw[3][4];
#pragma unroll
        for (int kk = 0; kk < 3; kk++) {
#pragma unroll
            for (int half = 0; half < 2; half++) {
                int t0 = 16 * kk + 8 * half + 2 * c;
                int t1 = t0 + 1;
                float w0a = (t0 < NT) ? s.Wb[r0][t0] : 0.f;
                float w0b = (t1 < NT) ? s.Wb[r0][t1] : 0.f;
                float w1a = (t0 < NT) ? s.Wb[r1][t0] : 0.f;
                float w1b = (t1 < NT) ? s.Wb[r1][t1] : 0.f;
                if (t0 != 0 && t0 != 32) { w0a *= ws0; w1a *= ws1; }
                if (t1 != 0 && t1 != 32) { w0b *= ws0; w1b *= ws1; }
                aw[kk][half ? 2 : 0] = packh2(w0a, w0b);   // row r0
                aw[kk][half ? 3 : 1] = packh2(w1a, w1b);   // row r1
            }
        }
#pragma unroll
        for (int kk = 0; kk < 3; kk++) {
#pragma unroll
            for (int p = 0; p < 4; p++) {
                uint32_t b0, b1, b2, b3;
                ldsm4t(b0, b1, b2, b3, &s.relvh[kk * 16 + vrow][p * 16 + vcol]);
                mma_f16(acc[2 * p],     aw[kk][0], aw[kk][1], aw[kk][2], aw[kk][3], b0, b2);
                mma_f16(acc[2 * p + 1], aw[kk][0], aw[kk][1], aw[kk][2], aw[kk][3], b1, b3);
            }
        }
    }

    // ---- normalize and store ----
    {
        float li0 = 1.f / l0, li1 = 1.f / l1;
        int bb = bh >> 4, hh = bh & 15;
        __half* y0 = Y + ((size_t)(bb * 1024 + i0 + r0)) * 1024 + hh * 64;
        __half* y1 = Y + ((size_t)(bb * 1024 + i0 + r1)) * 1024 + hh * 64;
#pragma unroll
        for (int ni = 0; ni < 8; ni++) {
            int col = ni * 8 + 2 * c;
            *(uint32_t*)(y0 + col) = packh2(acc[ni][0] * li0, acc[ni][1] * li0);
            *(uint32_t*)(y1 + col) = packh2(acc[ni][2] * li1, acc[ni][3] * li1);
        }
    }
}

// ---------------------------------------------------------------------------

extern "C" void kernel_launch(void* const* d_in, const int* in_sizes, int n_in,
                              void* d_out, int out_size)
{
    const float* query = (const float*)d_in[0];
    const float* key   = (const float*)d_in[1];
    const float* value = (const float*)d_in[2];
    const float* wq = (const float*)d_in[3];
    const float* bq = (const float*)d_in[4];
    const float* wk = (const float*)d_in[5];
    const float* bk = (const float*)d_in[6];
    const float* wv = (const float*)d_in[7];
    const float* bv = (const float*)d_in[8];
    const float* wo = (const float*)d_in[9];
    const float* bo = (const float*)d_in[10];
    const float* relk = (const float*)d_in[11];
    const float* relv = (const float*)d_in[12];
    float* out = (float*)d_out;

    __half *Qp, *Kp, *Vp, *Yp, *Xq, *Xk, *Xv, *Wq, *Wk, *Wv, *Wo;
    cudaGetSymbolAddress((void**)&Qp, gQ);
    cudaGetSymbolAddress((void**)&Kp, gK);
    cudaGetSymbolAddress((void**)&Vp, gV);
    cudaGetSymbolAddress((void**)&Yp, gY);
    cudaGetSymbolAddress((void**)&Xq, gXq);
    cudaGetSymbolAddress((void**)&Xk, gXk);
    cudaGetSymbolAddress((void**)&Xv, gXv);
    cudaGetSymbolAddress((void**)&Wq, gWq);
    cudaGetSymbolAddress((void**)&Wk, gWk);
    cudaGetSymbolAddress((void**)&Wv, gWv);
    cudaGetSymbolAddress((void**)&Wo, gWo);

    convert7_kernel<<<dim3(512, 7), 256>>>(query, key, value, wq, wk, wv, wo,
                                           Xq, Xk, Xv, Wq, Wk, Wv, Wo);

    cudaFuncSetAttribute(qkv_gemm_kernel, cudaFuncAttributeMaxDynamicSharedMemorySize,
                         GS_TOTAL);
    cudaFuncSetAttribute(out_gemm_kernel, cudaFuncAttributeMaxDynamicSharedMemorySize,
                         GS_TOTAL);
    cudaFuncSetAttribute(attn_kernel, cudaFuncAttributeMaxDynamicSharedMemorySize,
                         (int)sizeof(AttnSmem));

    qkv_gemm_kernel<<<dim3(8, 32, 3), 256, GS_TOTAL>>>(Xq, Xk, Xv, Wq, Wk, Wv,
                                                       bq, bk, bv, Qp, Kp, Vp);

    attn_kernel<<<dim3(8, 64), 256, sizeof(AttnSmem)>>>(Qp, Kp, Vp, relk, relv, Yp);

    out_gemm_kernel<<<dim3(8, 32), 256, GS_TOTAL>>>(Yp, Wo, bo, out);
}